// round 7
// baseline (speedup 1.0000x reference)
#include <cuda_runtime.h>
#include <cuda_bf16.h>
#include <stdint.h>
#include <math.h>

// Problem constants
#define C_DIM 1536
#define L_Q   2400
#define L_KV  512
#define NH    12
#define HD    128
#define FF_DIM 8960
#define EPS   1e-6f

// ---------------- device scratch ----------------
__device__ __align__(256) float g_em[6 * C_DIM];
__device__ __align__(256) float g_q [L_Q * C_DIM];
__device__ __align__(256) float g_k [L_Q * C_DIM];
__device__ __align__(256) float g_v [L_Q * C_DIM];
__device__ __align__(256) float g_t [L_Q * C_DIM];
__device__ __align__(256) float g_s [NH * L_Q * L_Q];          // fp32 scores
__device__ __align__(256) unsigned short g_hh[L_Q * C_DIM], g_hl[L_Q * C_DIM];
__device__ __align__(256) unsigned short g_qh[L_Q * C_DIM], g_ql[L_Q * C_DIM];
__device__ __align__(256) unsigned short g_kh[L_Q * C_DIM], g_kl[L_Q * C_DIM];
__device__ __align__(256) unsigned short g_vth[C_DIM * L_Q], g_vtl[C_DIM * L_Q];
__device__ __align__(256) unsigned short g_yh[L_Q * C_DIM], g_yl[L_Q * C_DIM];
__device__ __align__(256) unsigned short g_oh[L_Q * C_DIM], g_ol[L_Q * C_DIM];
__device__ __align__(256) unsigned short g_cxh[L_KV * C_DIM], g_cxl[L_KV * C_DIM];
__device__ __align__(256) unsigned short g_ph[NH * L_Q * L_Q], g_pl[NH * L_Q * L_Q];
__device__ __align__(256) unsigned short g_ffh[L_Q * FF_DIM], g_ffl[L_Q * FF_DIM];
__device__ __align__(256) unsigned short g_wh[FF_DIM * C_DIM], g_wl[FF_DIM * C_DIM];

// ---------------- helpers ----------------
__device__ __forceinline__ float block_reduce(float v, float* sh, bool is_max) {
    __syncthreads();
    int lane = threadIdx.x & 31, warp = threadIdx.x >> 5;
    #pragma unroll
    for (int o = 16; o > 0; o >>= 1) {
        float other = __shfl_down_sync(0xffffffffu, v, o);
        v = is_max ? fmaxf(v, other) : v + other;
    }
    if (lane == 0) sh[warp] = v;
    __syncthreads();
    int nw = blockDim.x >> 5;
    if (warp == 0) {
        v = (lane < nw) ? sh[lane] : (is_max ? -INFINITY : 0.f);
        #pragma unroll
        for (int o = 16; o > 0; o >>= 1) {
            float other = __shfl_down_sync(0xffffffffu, v, o);
            v = is_max ? fmaxf(v, other) : v + other;
        }
        if (lane == 0) sh[0] = v;
    }
    __syncthreads();
    return sh[0];
}

__device__ __forceinline__ float gelu_tanh(float v) {
    float v3 = v * v * v;
    return 0.5f * v * (1.f + tanhf(0.7978845608028654f * (v + 0.044715f * v3)));
}

static __device__ __forceinline__ void split_bf16(float v, unsigned short& h, unsigned short& l) {
    __nv_bfloat16 hb = __float2bfloat16_rn(v);
    float r = v - __bfloat162float(hb);
    __nv_bfloat16 lb = __float2bfloat16_rn(r);
    h = *reinterpret_cast<unsigned short*>(&hb);
    l = *reinterpret_cast<unsigned short*>(&lb);
}

// ---------------- elementwise / norm kernels ----------------
__global__ void em_kernel(const float* __restrict__ e, const float* __restrict__ mod,
                          float* __restrict__ em) {
    int i = blockIdx.x * blockDim.x + threadIdx.x;
    if (i < 6 * C_DIM) em[i] = e[i] + mod[i];
}

__global__ void ln_mod_split_kernel(const float* __restrict__ x, const float* __restrict__ e0,
                                    const float* __restrict__ e1,
                                    unsigned short* __restrict__ oh, unsigned short* __restrict__ ol) {
    __shared__ float sh[32];
    long long row = blockIdx.x;
    const float* xr = x + row * C_DIM;
    float s = 0.f, s2 = 0.f;
    for (int c = threadIdx.x; c < C_DIM; c += blockDim.x) {
        float v = xr[c];
        s += v; s2 += v * v;
    }
    float S  = block_reduce(s,  sh, false);
    float S2 = block_reduce(s2, sh, false);
    float m   = S  * (1.f / C_DIM);
    float var = S2 * (1.f / C_DIM) - m * m;
    float inv = rsqrtf(var + EPS);
    for (int c = threadIdx.x; c < C_DIM; c += blockDim.x) {
        float v = e0[c] + (xr[c] - m) * inv * (1.f + e1[c]);
        unsigned short h, l; split_bf16(v, h, l);
        oh[row * C_DIM + c] = h;
        ol[row * C_DIM + c] = l;
    }
}

__global__ void rms_rope_split_kernel(const float* __restrict__ x, const float* __restrict__ w,
                                      const float* __restrict__ freqs,
                                      unsigned short* __restrict__ dh, unsigned short* __restrict__ dl) {
    __shared__ float sh[32];
    int row = blockIdx.x;
    const float* xr = x + (long long)row * C_DIM;
    float s2 = 0.f;
    for (int c = threadIdx.x; c < C_DIM; c += blockDim.x) {
        float v = xr[c]; s2 += v * v;
    }
    float S2 = block_reduce(s2, sh, false);
    float inv = rsqrtf(S2 * (1.f / C_DIM) + EPS);
    int f  = row / 1200;
    int rm = row % 1200;
    int hh = rm / 40;
    int ww = rm % 40;
    for (int p = threadIdx.x; p < NH * 64; p += blockDim.x) {
        int n = p >> 6, j = p & 63;
        int pos = (j < 22) ? f : ((j < 43) ? hh : ww);
        float cs = freqs[(pos * 64 + j) * 2 + 0];
        float sn = freqs[(pos * 64 + j) * 2 + 1];
        int c = n * HD + 2 * j;
        float a = xr[c] * inv * w[c];
        float b = xr[c + 1] * inv * w[c + 1];
        float o0 = a * cs - b * sn;
        float o1 = a * sn + b * cs;
        unsigned short h0, l0, h1, l1;
        split_bf16(o0, h0, l0); split_bf16(o1, h1, l1);
        long long o = (long long)row * C_DIM + c;
        dh[o] = h0; dl[o] = l0;
        dh[o + 1] = h1; dl[o + 1] = l1;
    }
}

__global__ void rms_split_kernel(const float* __restrict__ x, const float* __restrict__ w,
                                 unsigned short* __restrict__ dh, unsigned short* __restrict__ dl) {
    __shared__ float sh[32];
    long long row = blockIdx.x;
    const float* xr = x + row * C_DIM;
    float s2 = 0.f;
    for (int c = threadIdx.x; c < C_DIM; c += blockDim.x) {
        float v = xr[c]; s2 += v * v;
    }
    float S2 = block_reduce(s2, sh, false);
    float inv = rsqrtf(S2 * (1.f / C_DIM) + EPS);
    for (int c = threadIdx.x; c < C_DIM; c += blockDim.x) {
        float v = xr[c] * inv * w[c];
        unsigned short h, l; split_bf16(v, h, l);
        dh[row * C_DIM + c] = h;
        dl[row * C_DIM + c] = l;
    }
}

__global__ void conv_split_kernel(const float* __restrict__ src, long long n,
                                  unsigned short* __restrict__ dh, unsigned short* __restrict__ dl) {
    long long i = (long long)blockIdx.x * blockDim.x + threadIdx.x;
    if (i < n) {
        unsigned short h, l; split_bf16(src[i], h, l);
        dh[i] = h; dl[i] = l;
    }
}

__global__ void transpose_split_kernel(const float* __restrict__ src, int R, int Ccol,
                                       unsigned short* __restrict__ dh, unsigned short* __restrict__ dl) {
    __shared__ float tile[32][33];
    int bx = blockIdx.x, by = blockIdx.y;
    int tx = threadIdx.x, ty = threadIdx.y;  // 32 x 8
    #pragma unroll
    for (int i = 0; i < 4; i++) {
        int r = by * 32 + ty + i * 8;
        tile[ty + i * 8][tx] = src[(long long)r * Ccol + bx * 32 + tx];
    }
    __syncthreads();
    #pragma unroll
    for (int i = 0; i < 4; i++) {
        int ro = bx * 32 + ty + i * 8;
        int co = by * 32 + tx;
        float v = tile[tx][ty + i * 8];
        unsigned short h, l; split_bf16(v, h, l);
        dh[(long long)ro * R + co] = h;
        dl[(long long)ro * R + co] = l;
    }
}

__global__ void softmax_split_kernel(const float* __restrict__ s, int lk,
                                     unsigned short* __restrict__ ph, unsigned short* __restrict__ pl) {
    __shared__ float sh[32];
    long long row = blockIdx.x;
    const float* p = s + row * (long long)lk;
    float mx = -INFINITY;
    for (int i = threadIdx.x; i < lk; i += blockDim.x) mx = fmaxf(mx, p[i]);
    mx = block_reduce(mx, sh, true);
    float sum = 0.f;
    for (int i = threadIdx.x; i < lk; i += blockDim.x) sum += __expf(p[i] - mx);
    sum = block_reduce(sum, sh, false);
    float inv = 1.f / sum;
    for (int i = threadIdx.x; i < lk; i += blockDim.x) {
        float v = __expf(p[i] - mx) * inv;
        unsigned short h, l; split_bf16(v, h, l);
        ph[row * (long long)lk + i] = h;
        pl[row * (long long)lk + i] = l;
    }
}

__global__ void residual_mul_conv_kernel(const float* __restrict__ xin, const float* __restrict__ t,
                                         const float* __restrict__ ecol, float* __restrict__ out,
                                         unsigned short* __restrict__ oh, unsigned short* __restrict__ ol) {
    long long i = (long long)blockIdx.x * blockDim.x + threadIdx.x;
    if (i < (long long)L_Q * C_DIM) {
        float v = xin[i] + t[i] * ecol[i % C_DIM];
        out[i] = v;
        unsigned short h, l; split_bf16(v, h, l);
        oh[i] = h; ol[i] = l;
    }
}

__global__ void add_inplace_kernel(float* __restrict__ x, const float* __restrict__ t) {
    long long i = (long long)blockIdx.x * blockDim.x + threadIdx.x;
    if (i < (long long)L_Q * C_DIM) x[i] += t[i];
}

__global__ void addmul_inplace_kernel(float* __restrict__ x, const float* __restrict__ t,
                                      const float* __restrict__ ecol) {
    long long i = (long long)blockIdx.x * blockDim.x + threadIdx.x;
    if (i < (long long)L_Q * C_DIM) x[i] += t[i] * ecol[i % C_DIM];
}

// ---------------- common GEMM asm helpers ----------------
static __device__ __forceinline__ uint32_t smem_u32(const void* p) {
    uint32_t r;
    asm("{ .reg .u64 t; cvta.to.shared.u64 t, %1; cvt.u32.u64 %0, t; }" : "=r"(r) : "l"(p));
    return r;
}
static __device__ __forceinline__ void cpa16(uint32_t s, const void* g, uint32_t sz) {
    asm volatile("cp.async.cg.shared.global [%0], [%1], 16, %2;" :: "r"(s), "l"(g), "r"(sz));
}
static __device__ __forceinline__ void cpa_commit() {
    asm volatile("cp.async.commit_group;");
}
static __device__ __forceinline__ void cpa_wait1() {
    asm volatile("cp.async.wait_group 1;");
}
static __device__ __forceinline__ void cpa_wait2() {
    asm volatile("cp.async.wait_group 2;");
}
static __device__ __forceinline__ void ldm_x4(uint32_t* r, uint32_t addr) {
    asm volatile("ldmatrix.sync.aligned.m8n8.x4.shared.b16 {%0,%1,%2,%3}, [%4];"
                 : "=r"(r[0]), "=r"(r[1]), "=r"(r[2]), "=r"(r[3]) : "r"(addr));
}
static __device__ __forceinline__ void mma16816(float* c, const uint32_t* a, uint32_t b0, uint32_t b1) {
    asm volatile("mma.sync.aligned.m16n8k16.row.col.f32.bf16.bf16.f32 "
                 "{%0,%1,%2,%3}, {%4,%5,%6,%7}, {%8,%9}, {%0,%1,%2,%3};"
                 : "+f"(c[0]), "+f"(c[1]), "+f"(c[2]), "+f"(c[3])
                 : "r"(a[0]), "r"(a[1]), "r"(a[2]), "r"(a[3]), "r"(b0), "r"(b1));
}
// 64B-row-pair swizzled smem addr for (row, ch 0..3); conflict-free ldmatrix
static __device__ __forceinline__ uint32_t saddr(int row, int ch) {
    return (uint32_t)(((row >> 1) << 7) +
                      (((((row & 1) << 2) | ch) ^ ((row >> 1) & 3)) << 4));
}

// =====================================================================
// WIDE GEMM: 128x256x32, warp tile 64x64, 4-stage cp.async (192KB), N>128.
// =====================================================================
#define W_STG 49152
#define W_SA_H 0
#define W_SA_L 8192
#define W_SB_H 16384
#define W_SB_L 32768
#define W_SMEM (4 * W_STG)     // 196608

__global__ void __launch_bounds__(256, 1)
hgemmw_kernel(const unsigned short* __restrict__ Ah, const unsigned short* __restrict__ Al,
              int lda, long long sAz,
              const unsigned short* __restrict__ Bh, const unsigned short* __restrict__ Bl,
              int ldb, long long sBz,
              float* __restrict__ Cf, unsigned short* __restrict__ Ch, unsigned short* __restrict__ Cl,
              int ldc, long long sCz,
              int M, int N, int K,
              const float* __restrict__ bias, float scale, int act) {
    extern __shared__ char smem[];
    uint32_t sbase = smem_u32(smem);

    int tid = threadIdx.x, lane = tid & 31, warp = tid >> 5;
    int wm = warp & 1, wn = warp >> 1;       // 2 x 4 warps, warp tile 64x64

    long long zz = blockIdx.z;
    Ah += zz * sAz; Al += zz * sAz;
    Bh += zz * sBz; Bl += zz * sBz;
    if (Cf) Cf += zz * sCz;
    if (Ch) { Ch += zz * sCz; Cl += zz * sCz; }

    int bm = blockIdx.y * 128;
    int bn = blockIdx.x * 256;
    int mRem = M - bm; if (mRem > 128) mRem = 128;
    int nRem = N - bn; if (nRem > 256) nRem = 256;

    int nch = K >> 5;    // all K here are multiples of 32

    // slot bases: rowA0 = tid>>2, A slot i adds 64 rows; B slot j adds 64 rows
    int rowA0 = tid >> 2, ch0 = tid & 3;
    uint32_t soA0 = saddr(rowA0, ch0);          // +4096 per slot
    long long gA0 = (long long)(bm + rowA0) * lda + ch0 * 8;
    long long gB0 = (long long)(bn + rowA0) * ldb + ch0 * 8;
    uint32_t szA[2], szB[4];
    #pragma unroll
    for (int i = 0; i < 2; i++) szA[i] = (rowA0 + 64 * i < mRem) ? 16u : 0u;
    #pragma unroll
    for (int i = 0; i < 4; i++) szB[i] = (rowA0 + 64 * i < nRem) ? 16u : 0u;
    long long ldax = (long long)lda * 64, ldbx = (long long)ldb * 64;

    auto loadStage = [&](int c) {
        uint32_t sb = sbase + (uint32_t)((c & 3) * W_STG);
        long long k0 = (long long)(c << 5);
        #pragma unroll
        for (int i = 0; i < 2; i++) {
            cpa16(sb + W_SA_H + soA0 + i * 4096u, Ah + gA0 + i * ldax + k0, szA[i]);
            cpa16(sb + W_SA_L + soA0 + i * 4096u, Al + gA0 + i * ldax + k0, szA[i]);
        }
        #pragma unroll
        for (int i = 0; i < 4; i++) {
            cpa16(sb + W_SB_H + soA0 + i * 4096u, Bh + gB0 + i * ldbx + k0, szB[i]);
            cpa16(sb + W_SB_L + soA0 + i * 4096u, Bl + gB0 + i * ldbx + k0, szB[i]);
        }
    };

    // ldmatrix row terms
    int frow = lane & 15, fhalf = lane >> 4;
    uint32_t a_rt[4]; int a_sw[4], a_s[4];
    #pragma unroll
    for (int mi = 0; mi < 4; mi++) {
        int row = wm * 64 + mi * 16 + frow;
        a_rt[mi] = (uint32_t)((row >> 1) << 7);
        a_sw[mi] = (row & 1) << 2;
        a_s[mi]  = (row >> 1) & 3;
    }
    uint32_t b_rt[4]; int b_sw[4], b_s[4];
    #pragma unroll
    for (int nj = 0; nj < 4; nj++) {
        int row = wn * 64 + nj * 16 + frow;
        b_rt[nj] = (uint32_t)((row >> 1) << 7);
        b_sw[nj] = (row & 1) << 2;
        b_s[nj]  = (row >> 1) & 3;
    }

    float acc[4][8][4];
    #pragma unroll
    for (int mi = 0; mi < 4; mi++)
        #pragma unroll
        for (int ni = 0; ni < 8; ni++)
            #pragma unroll
            for (int q = 0; q < 4; q++) acc[mi][ni][q] = 0.f;

    // prologue: 3 stages in flight
    loadStage(0); cpa_commit();
    if (nch > 1) loadStage(1);
    cpa_commit();
    if (nch > 2) loadStage(2);
    cpa_commit();

    for (int c = 0; c < nch; c++) {
        cpa_wait2();
        __syncthreads();
        uint32_t sb = sbase + (uint32_t)((c & 3) * W_STG);

        #pragma unroll
        for (int k16 = 0; k16 < 2; k16++) {
            int chl = k16 * 2 + fhalf;
            uint32_t bH[4][4], bL[4][4];
            #pragma unroll
            for (int nj = 0; nj < 4; nj++) {
                uint32_t off = b_rt[nj] + (uint32_t)(((b_sw[nj] | chl) ^ b_s[nj]) << 4);
                ldm_x4(bH[nj], sb + W_SB_H + off);
                ldm_x4(bL[nj], sb + W_SB_L + off);
            }
            #pragma unroll
            for (int mi = 0; mi < 4; mi++) {
                uint32_t aH[4], aL[4];
                uint32_t off = a_rt[mi] + (uint32_t)(((a_sw[mi] | chl) ^ a_s[mi]) << 4);
                ldm_x4(aH, sb + W_SA_H + off);
                ldm_x4(aL, sb + W_SA_L + off);
                #pragma unroll
                for (int nj = 0; nj < 4; nj++) {
                    mma16816(acc[mi][nj*2+0], aH, bH[nj][0], bH[nj][2]);
                    mma16816(acc[mi][nj*2+1], aH, bH[nj][1], bH[nj][3]);
                    mma16816(acc[mi][nj*2+0], aH, bL[nj][0], bL[nj][2]);
                    mma16816(acc[mi][nj*2+1], aH, bL[nj][1], bL[nj][3]);
                    mma16816(acc[mi][nj*2+0], aL, bH[nj][0], bH[nj][2]);
                    mma16816(acc[mi][nj*2+1], aL, bH[nj][1], bH[nj][3]);
                }
            }
        }
        if (c + 3 < nch) loadStage(c + 3);
        cpa_commit();
    }

    // epilogue
    int row0 = lane >> 2;
    int col0 = (lane & 3) * 2;
    #pragma unroll
    for (int mi = 0; mi < 4; mi++) {
        #pragma unroll
        for (int ni = 0; ni < 8; ni++) {
            int gn = bn + wn * 64 + (ni >> 1) * 16 + (ni & 1) * 8 + col0;
            if (gn >= N) continue;
            float b0 = 0.f, b1 = 0.f;
            if (bias) { b0 = bias[gn]; b1 = bias[gn + 1]; }
            float* cc = acc[mi][ni];
            #pragma unroll
            for (int half = 0; half < 2; half++) {
                int gm = bm + wm * 64 + mi * 16 + row0 + half * 8;
                if (gm >= M) continue;
                float v0 = cc[half * 2 + 0] * scale + b0;
                float v1 = cc[half * 2 + 1] * scale + b1;
                if (act == 1) { v0 = gelu_tanh(v0); v1 = gelu_tanh(v1); }
                long long o = (long long)gm * ldc + gn;
                if (Cf) *reinterpret_cast<float2*>(Cf + o) = make_float2(v0, v1);
                if (Ch) {
                    unsigned short h0, l0, h1, l1;
                    split_bf16(v0, h0, l0); split_bf16(v1, h1, l1);
                    *reinterpret_cast<ushort2*>(Ch + o) = make_ushort2(h0, h1);
                    *reinterpret_cast<ushort2*>(Cl + o) = make_ushort2(l0, l1);
                }
            }
        }
    }
}

// =====================================================================
// NARROW GEMM (N<=128): 128x128x32, 3-stage, 2 CTAs/SM (R6 kernel).
// =====================================================================
#define STAGES 3
#define STG 32768
#define SA_H 0
#define SA_L 8192
#define SB_H 16384
#define SB_L 24576
#define HG_SMEM (STAGES * STG)

__global__ void __launch_bounds__(256, 2)
hgemm3_kernel(const unsigned short* __restrict__ Ah, const unsigned short* __restrict__ Al,
              int lda, long long sAz,
              const unsigned short* __restrict__ Bh, const unsigned short* __restrict__ Bl,
              int ldb, long long sBz,
              float* __restrict__ Cf, unsigned short* __restrict__ Ch, unsigned short* __restrict__ Cl,
              int ldc, long long sCz,
              int M, int N, int K,
              const float* __restrict__ bias, float scale, int act) {
    extern __shared__ char smem[];
    uint32_t sbase = smem_u32(smem);

    int tid = threadIdx.x, lane = tid & 31, warp = tid >> 5;
    int wm = warp & 1, wn = warp >> 1;

    long long zz = blockIdx.z;
    Ah += zz * sAz; Al += zz * sAz;
    Bh += zz * sBz; Bl += zz * sBz;
    if (Cf) Cf += zz * sCz;
    if (Ch) { Ch += zz * sCz; Cl += zz * sCz; }

    int bm = blockIdx.y * 128;
    int bn = blockIdx.x * 128;
    int mRem = M - bm; if (mRem > 128) mRem = 128;
    int nRem = N - bn; if (nRem > 128) nRem = 128;

    int nch = K >> 5;

    uint32_t so[2]; long long gA[2], gB[2]; uint32_t szA[2], szB[2];
    #pragma unroll
    for (int i = 0; i < 2; i++) {
        int idx = tid + i * 256;
        int row = idx >> 2, ch = idx & 3;
        so[i]  = saddr(row, ch);
        gA[i]  = (long long)(bm + row) * lda + ch * 8;
        gB[i]  = (long long)(bn + row) * ldb + ch * 8;
        szA[i] = (row < mRem) ? 16u : 0u;
        szB[i] = (row < nRem) ? 16u : 0u;
    }

    int frow = lane & 15, fhalf = lane >> 4;
    uint32_t a_rt[4]; int a_sw[4], a_s[4];
    #pragma unroll
    for (int mi = 0; mi < 4; mi++) {
        int row = wm * 64 + mi * 16 + frow;
        a_rt[mi] = (uint32_t)((row >> 1) << 7);
        a_sw[mi] = (row & 1) << 2;
        a_s[mi]  = (row >> 1) & 3;
    }
    uint32_t b_rt[2]; int b_sw[2], b_s[2];
    #pragma unroll
    for (int nj = 0; nj < 2; nj++) {
        int row = wn * 32 + nj * 16 + frow;
        b_rt[nj] = (uint32_t)((row >> 1) << 7);
        b_sw[nj] = (row & 1) << 2;
        b_s[nj]  = (row >> 1) & 3;
    }

    float acc[4][4][4];
    #pragma unroll
    for (int mi = 0; mi < 4; mi++)
        #pragma unroll
        for (int ni = 0; ni < 4; ni++)
            #pragma unroll
            for (int q = 0; q < 4; q++) acc[mi][ni][q] = 0.f;

    auto loadStage = [&](int c) {
        uint32_t sb = sbase + (uint32_t)((c % STAGES) * STG);
        long long k0 = (long long)(c << 5);
        #pragma unroll
        for (int i = 0; i < 2; i++) {
            cpa16(sb + SA_H + so[i], Ah + gA[i] + k0, szA[i]);
            cpa16(sb + SA_L + so[i], Al + gA[i] + k0, szA[i]);
            cpa16(sb + SB_H + so[i], Bh + gB[i] + k0, szB[i]);
            cpa16(sb + SB_L + so[i], Bl + gB[i] + k0, szB[i]);
        }
    };

    loadStage(0); cpa_commit();
    if (nch > 1) loadStage(1);
    cpa_commit();

    for (int c = 0; c < nch; c++) {
        cpa_wait1();
        __syncthreads();
        uint32_t sb = sbase + (uint32_t)((c % STAGES) * STG);

        #pragma unroll
        for (int k16 = 0; k16 < 2; k16++) {
            int chl = k16 * 2 + fhalf;
            uint32_t bH[2][4], bL[2][4];
            #pragma unroll
            for (int nj = 0; nj < 2; nj++) {
                uint32_t off = b_rt[nj] + (uint32_t)(((b_sw[nj] | chl) ^ b_s[nj]) << 4);
                ldm_x4(bH[nj], sb + SB_H + off);
                ldm_x4(bL[nj], sb + SB_L + off);
            }
            #pragma unroll
            for (int mi = 0; mi < 4; mi++) {
                uint32_t aH[4], aL[4];
                uint32_t off = a_rt[mi] + (uint32_t)(((a_sw[mi] | chl) ^ a_s[mi]) << 4);
                ldm_x4(aH, sb + SA_H + off);
                ldm_x4(aL, sb + SA_L + off);
                #pragma unroll
                for (int nj = 0; nj < 2; nj++) {
                    mma16816(acc[mi][nj*2+0], aH, bH[nj][0], bH[nj][2]);
                    mma16816(acc[mi][nj*2+1], aH, bH[nj][1], bH[nj][3]);
                    mma16816(acc[mi][nj*2+0], aH, bL[nj][0], bL[nj][2]);
                    mma16816(acc[mi][nj*2+1], aH, bL[nj][1], bL[nj][3]);
                    mma16816(acc[mi][nj*2+0], aL, bH[nj][0], bH[nj][2]);
                    mma16816(acc[mi][nj*2+1], aL, bH[nj][1], bH[nj][3]);
                }
            }
        }
        if (c + 2 < nch) loadStage(c + 2);
        cpa_commit();
    }

    int row0 = lane >> 2;
    int col0 = (lane & 3) * 2;
    #pragma unroll
    for (int mi = 0; mi < 4; mi++) {
        #pragma unroll
        for (int ni = 0; ni < 4; ni++) {
            int gn = bn + wn * 32 + ni * 8 + col0;
            if (gn >= N) continue;
            float b0 = 0.f, b1 = 0.f;
            if (bias) { b0 = bias[gn]; b1 = bias[gn + 1]; }
            float* cc = acc[mi][ni];
            #pragma unroll
            for (int half = 0; half < 2; half++) {
                int gm = bm + wm * 64 + mi * 16 + row0 + half * 8;
                if (gm >= M) continue;
                float v0 = cc[half * 2 + 0] * scale + b0;
                float v1 = cc[half * 2 + 1] * scale + b1;
                if (act == 1) { v0 = gelu_tanh(v0); v1 = gelu_tanh(v1); }
                long long o = (long long)gm * ldc + gn;
                if (Cf) *reinterpret_cast<float2*>(Cf + o) = make_float2(v0, v1);
                if (Ch) {
                    unsigned short h0, l0, h1, l1;
                    split_bf16(v0, h0, l0); split_bf16(v1, h1, l1);
                    *reinterpret_cast<ushort2*>(Ch + o) = make_ushort2(h0, h1);
                    *reinterpret_cast<ushort2*>(Cl + o) = make_ushort2(l0, l1);
                }
            }
        }
    }
}

// ---------------- host ----------------
static void hg(const unsigned short* Ah, const unsigned short* Al, int lda, long long sAz,
               const unsigned short* Bh, const unsigned short* Bl, int ldb, long long sBz,
               float* Cf, unsigned short* Ch, unsigned short* Cl, int ldc, long long sCz,
               int M, int N, int K, int Z, const float* bias, float scale, int act) {
    if (N > 128) {
        dim3 grid((N + 255) / 256, (M + 127) / 128, Z);
        hgemmw_kernel<<<grid, 256, W_SMEM>>>(Ah, Al, lda, sAz, Bh, Bl, ldb, sBz,
                                             Cf, Ch, Cl, ldc, sCz, M, N, K, bias, scale, act);
    } else {
        dim3 grid(1, (M + 127) / 128, Z);
        hgemm3_kernel<<<grid, 256, HG_SMEM>>>(Ah, Al, lda, sAz, Bh, Bl, ldb, sBz,
                                              Cf, Ch, Cl, ldc, sCz, M, N, K, bias, scale, act);
    }
}

static void trsplit(const float* src, int R, int Ccol, unsigned short* dh, unsigned short* dl) {
    dim3 grid(Ccol / 32, R / 32);
    transpose_split_kernel<<<grid, dim3(32, 8)>>>(src, R, Ccol, dh, dl);
}

extern "C" void kernel_launch(void* const* d_in, const int* in_sizes, int n_in,
                              void* d_out, int out_size) {
    const float* x        = (const float*)d_in[0];
    const float* e        = (const float*)d_in[1];
    const float* context  = (const float*)d_in[2];
    const float* freqs    = (const float*)d_in[3];
    const float* modulation = (const float*)d_in[7];
    const float* sa_q_w = (const float*)d_in[8];
    const float* sa_q_b = (const float*)d_in[9];
    const float* sa_k_w = (const float*)d_in[10];
    const float* sa_k_b = (const float*)d_in[11];
    const float* sa_v_w = (const float*)d_in[12];
    const float* sa_v_b = (const float*)d_in[13];
    const float* sa_o_w = (const float*)d_in[14];
    const float* sa_o_b = (const float*)d_in[15];
    const float* sa_nq_w = (const float*)d_in[16];
    const float* sa_nk_w = (const float*)d_in[17];
    const float* ca_q_w = (const float*)d_in[18];
    const float* ca_q_b = (const float*)d_in[19];
    const float* ca_k_w = (const float*)d_in[20];
    const float* ca_k_b = (const float*)d_in[21];
    const float* ca_v_w = (const float*)d_in[22];
    const float* ca_v_b = (const float*)d_in[23];
    const float* ca_o_w = (const float*)d_in[24];
    const float* ca_o_b = (const float*)d_in[25];
    const float* ca_nq_w = (const float*)d_in[26];
    const float* ca_nk_w = (const float*)d_in[27];
    const float* ffn_w1 = (const float*)d_in[28];
    const float* ffn_b1 = (const float*)d_in[29];
    const float* ffn_w2 = (const float*)d_in[30];
    const float* ffn_b2 = (const float*)d_in[31];
    float* out = (float*)d_out;

    cudaFuncSetAttribute(hgemm3_kernel,
                         cudaFuncAttributeMaxDynamicSharedMemorySize, HG_SMEM);
    cudaFuncSetAttribute(hgemmw_kernel,
                         cudaFuncAttributeMaxDynamicSharedMemorySize, W_SMEM);

    float *em, *q, *k, *v, *t, *s;
    unsigned short *hh, *hl, *qh, *ql, *kh, *kl, *vth, *vtl, *yh, *yl;
    unsigned short *oh, *ol, *cxh, *cxl, *ph, *pl, *ffh, *ffl, *wh, *wl;
    cudaGetSymbolAddress((void**)&em, g_em);
    cudaGetSymbolAddress((void**)&q,  g_q);
    cudaGetSymbolAddress((void**)&k,  g_k);
    cudaGetSymbolAddress((void**)&v,  g_v);
    cudaGetSymbolAddress((void**)&t,  g_t);
    cudaGetSymbolAddress((void**)&s,  g_s);
    cudaGetSymbolAddress((void**)&hh, g_hh);  cudaGetSymbolAddress((void**)&hl, g_hl);
    cudaGetSymbolAddress((void**)&qh, g_qh);  cudaGetSymbolAddress((void**)&ql, g_ql);
    cudaGetSymbolAddress((void**)&kh, g_kh);  cudaGetSymbolAddress((void**)&kl, g_kl);
    cudaGetSymbolAddress((void**)&vth, g_vth); cudaGetSymbolAddress((void**)&vtl, g_vtl);
    cudaGetSymbolAddress((void**)&yh, g_yh);  cudaGetSymbolAddress((void**)&yl, g_yl);
    cudaGetSymbolAddress((void**)&oh, g_oh);  cudaGetSymbolAddress((void**)&ol, g_ol);
    cudaGetSymbolAddress((void**)&cxh, g_cxh); cudaGetSymbolAddress((void**)&cxl, g_cxl);
    cudaGetSymbolAddress((void**)&ph, g_ph);  cudaGetSymbolAddress((void**)&pl, g_pl);
    cudaGetSymbolAddress((void**)&ffh, g_ffh); cudaGetSymbolAddress((void**)&ffl, g_ffl);
    cudaGetSymbolAddress((void**)&wh, g_wh);  cudaGetSymbolAddress((void**)&wl, g_wl);

    const float ascale = 0.08838834764831845f;   // 1/sqrt(128)
    const long long LC = (long long)L_Q * C_DIM;
    int eltBlocks = (int)((LC + 255) / 256);

    em_kernel<<<(6 * C_DIM + 255) / 256, 256>>>(e, modulation, em);

    // ================= self attention =================
    ln_mod_split_kernel<<<L_Q, 256>>>(x, em + 0 * C_DIM, em + 1 * C_DIM, hh, hl);
    trsplit(sa_q_w, C_DIM, C_DIM, wh, wl);
    hg(hh, hl, C_DIM, 0, wh, wl, C_DIM, 0, q, nullptr, nullptr, C_DIM, 0,
       L_Q, C_DIM, C_DIM, 1, sa_q_b, 1.f, 0);
    trsplit(sa_k_w, C_DIM, C_DIM, wh, wl);
    hg(hh, hl, C_DIM, 0, wh, wl, C_DIM, 0, k, nullptr, nullptr, C_DIM, 0,
       L_Q, C_DIM, C_DIM, 1, sa_k_b, 1.f, 0);
    trsplit(sa_v_w, C_DIM, C_DIM, wh, wl);
    hg(hh, hl, C_DIM, 0, wh, wl, C_DIM, 0, v, nullptr, nullptr, C_DIM, 0,
       L_Q, C_DIM, C_DIM, 1, sa_v_b, 1.f, 0);
    rms_rope_split_kernel<<<L_Q, 256>>>(q, sa_nq_w, freqs, qh, ql);
    rms_rope_split_kernel<<<L_Q, 256>>>(k, sa_nk_w, freqs, kh, kl);
    trsplit(v, L_Q, C_DIM, vth, vtl);
    hg(qh, ql, C_DIM, HD, kh, kl, C_DIM, HD, s, nullptr, nullptr,
       L_Q, (long long)L_Q * L_Q, L_Q, L_Q, HD, NH, nullptr, ascale, 0);
    softmax_split_kernel<<<NH * L_Q, 256>>>(s, L_Q, ph, pl);
    hg(ph, pl, L_Q, (long long)L_Q * L_Q, vth, vtl, L_Q, (long long)HD * L_Q,
       nullptr, yh, yl, C_DIM, HD, L_Q, HD, L_Q, NH, nullptr, 1.f, 0);
    trsplit(sa_o_w, C_DIM, C_DIM, wh, wl);
    hg(yh, yl, C_DIM, 0, wh, wl, C_DIM, 0, t, nullptr, nullptr, C_DIM, 0,
       L_Q, C_DIM, C_DIM, 1, sa_o_b, 1.f, 0);
    residual_mul_conv_kernel<<<eltBlocks, 256>>>(x, t, em + 2 * C_DIM, out, oh, ol);

    // ================= cross attention =================
    trsplit(ca_q_w, C_DIM, C_DIM, wh, wl);
    hg(oh, ol, C_DIM, 0, wh, wl, C_DIM, 0, q, nullptr, nullptr, C_DIM, 0,
       L_Q, C_DIM, C_DIM, 1, ca_q_b, 1.f, 0);
    rms_split_kernel<<<L_Q, 256>>>(q, ca_nq_w, qh, ql);
    conv_split_kernel<<<(int)(((long long)L_KV * C_DIM + 255) / 256), 256>>>(
        context, (long long)L_KV * C_DIM, cxh, cxl);
    trsplit(ca_k_w, C_DIM, C_DIM, wh, wl);
    hg(cxh, cxl, C_DIM, 0, wh, wl, C_DIM, 0, k, nullptr, nullptr, C_DIM, 0,
       L_KV, C_DIM, C_DIM, 1, ca_k_b, 1.f, 0);
    rms_split_kernel<<<L_KV, 256>>>(k, ca_nk_w, kh, kl);
    trsplit(ca_v_w, C_DIM, C_DIM, wh, wl);
    hg(cxh, cxl, C_DIM, 0, wh, wl, C_DIM, 0, v, nullptr, nullptr, C_DIM, 0,
       L_KV, C_DIM, C_DIM, 1, ca_v_b, 1.f, 0);
    trsplit(v, L_KV, C_DIM, vth, vtl);
    hg(qh, ql, C_DIM, HD, kh, kl, C_DIM, HD, s, nullptr, nullptr,
       L_KV, (long long)L_Q * L_KV, L_Q, L_KV, HD, NH, nullptr, ascale, 0);
    softmax_split_kernel<<<NH * L_Q, 256>>>(s, L_KV, ph, pl);
    hg(ph, pl, L_KV, (long long)L_Q * L_KV, vth, vtl, L_KV, (long long)HD * L_KV,
       nullptr, yh, yl, C_DIM, HD, L_Q, HD, L_KV, NH, nullptr, 1.f, 0);
    trsplit(ca_o_w, C_DIM, C_DIM, wh, wl);
    hg(yh, yl, C_DIM, 0, wh, wl, C_DIM, 0, t, nullptr, nullptr, C_DIM, 0,
       L_Q, C_DIM, C_DIM, 1, ca_o_b, 1.f, 0);
    add_inplace_kernel<<<eltBlocks, 256>>>(out, t);

    // ================= FFN =================
    ln_mod_split_kernel<<<L_Q, 256>>>(out, em + 3 * C_DIM, em + 4 * C_DIM, hh, hl);
    trsplit(ffn_w1, C_DIM, FF_DIM, wh, wl);
    hg(hh, hl, C_DIM, 0, wh, wl, C_DIM, 0, nullptr, ffh, ffl, FF_DIM, 0,
       L_Q, FF_DIM, C_DIM, 1, ffn_b1, 1.f, 1);
    trsplit(ffn_w2, FF_DIM, C_DIM, wh, wl);
    hg(ffh, ffl, FF_DIM, 0, wh, wl, FF_DIM, 0, t, nullptr, nullptr, C_DIM, 0,
       L_Q, C_DIM, FF_DIM, 1, ffn_b2, 1.f, 0);
    addmul_inplace_kernel<<<eltBlocks, 256>>>(out, t, em + 5 * C_DIM);
}

// round 8
// speedup vs baseline: 1.1067x; 1.1067x over previous
#include <cuda_runtime.h>
#include <cuda_fp16.h>
#include <stdint.h>
#include <math.h>

// Problem constants
#define C_DIM 1536
#define L_Q   2400
#define L_KV  512
#define NH    12
#define HD    128
#define FF_DIM 8960
#define EPS   1e-6f

// ---------------- device scratch ----------------
__device__ __align__(256) float g_em[6 * C_DIM];
__device__ __align__(256) float g_q [L_Q * C_DIM];
__device__ __align__(256) float g_t [L_Q * C_DIM];
__device__ __align__(256) float g_s [NH * L_Q * L_Q];     // fp32 scores / fused-proj scratch
__device__ __align__(256) float g_b3[3 * C_DIM];
__device__ __align__(256) unsigned short g_hh[L_Q * C_DIM], g_hl[L_Q * C_DIM];
__device__ __align__(256) unsigned short g_qh[L_Q * C_DIM], g_ql[L_Q * C_DIM];
__device__ __align__(256) unsigned short g_kh[L_Q * C_DIM], g_kl[L_Q * C_DIM];
__device__ __align__(256) unsigned short g_vth[C_DIM * L_Q];
__device__ __align__(256) unsigned short g_yh[L_Q * C_DIM], g_yl[L_Q * C_DIM];
__device__ __align__(256) unsigned short g_oh[L_Q * C_DIM], g_ol[L_Q * C_DIM];
__device__ __align__(256) unsigned short g_cxh[L_KV * C_DIM], g_cxl[L_KV * C_DIM];
__device__ __align__(256) unsigned short g_ph[NH * L_Q * L_Q], g_pl[NH * L_Q * L_Q];
__device__ __align__(256) unsigned short g_ffh[L_Q * FF_DIM], g_ffl[L_Q * FF_DIM];
__device__ __align__(256) unsigned short g_wh[FF_DIM * C_DIM];

// ---------------- helpers ----------------
__device__ __forceinline__ float block_reduce(float v, float* sh, bool is_max) {
    __syncthreads();
    int lane = threadIdx.x & 31, warp = threadIdx.x >> 5;
    #pragma unroll
    for (int o = 16; o > 0; o >>= 1) {
        float other = __shfl_down_sync(0xffffffffu, v, o);
        v = is_max ? fmaxf(v, other) : v + other;
    }
    if (lane == 0) sh[warp] = v;
    __syncthreads();
    int nw = blockDim.x >> 5;
    if (warp == 0) {
        v = (lane < nw) ? sh[lane] : (is_max ? -INFINITY : 0.f);
        #pragma unroll
        for (int o = 16; o > 0; o >>= 1) {
            float other = __shfl_down_sync(0xffffffffu, v, o);
            v = is_max ? fmaxf(v, other) : v + other;
        }
        if (lane == 0) sh[0] = v;
    }
    __syncthreads();
    return sh[0];
}

__device__ __forceinline__ float gelu_tanh(float v) {
    float v3 = v * v * v;
    return 0.5f * v * (1.f + tanhf(0.7978845608028654f * (v + 0.044715f * v3)));
}

static __device__ __forceinline__ void split_f16(float v, unsigned short& h, unsigned short& l) {
    __half hb = __float2half_rn(v);
    float r = v - __half2float(hb);
    __half lb = __float2half_rn(r);
    h = *reinterpret_cast<unsigned short*>(&hb);
    l = *reinterpret_cast<unsigned short*>(&lb);
}

// ---------------- elementwise / norm kernels ----------------
__global__ void em_kernel(const float* __restrict__ e, const float* __restrict__ mod,
                          float* __restrict__ em) {
    int i = blockIdx.x * blockDim.x + threadIdx.x;
    if (i < 6 * C_DIM) em[i] = e[i] + mod[i];
}

__global__ void pack3_kernel(const float* __restrict__ a, const float* __restrict__ b,
                             const float* __restrict__ c, float* __restrict__ d) {
    int i = blockIdx.x * blockDim.x + threadIdx.x;
    if (i < C_DIM) d[i] = a[i];
    else if (i < 2 * C_DIM) d[i] = b[i - C_DIM];
    else if (i < 3 * C_DIM) d[i] = c[i - 2 * C_DIM];
}

__global__ void pack2_kernel(const float* __restrict__ a, const float* __restrict__ b,
                             float* __restrict__ d) {
    int i = blockIdx.x * blockDim.x + threadIdx.x;
    if (i < C_DIM) d[i] = a[i];
    else if (i < 2 * C_DIM) d[i] = b[i - C_DIM];
}

__global__ void ln_mod_split_kernel(const float* __restrict__ x, const float* __restrict__ e0,
                                    const float* __restrict__ e1,
                                    unsigned short* __restrict__ oh, unsigned short* __restrict__ ol) {
    __shared__ float sh[32];
    long long row = blockIdx.x;
    const float* xr = x + row * C_DIM;
    float s = 0.f, s2 = 0.f;
    for (int c = threadIdx.x; c < C_DIM; c += blockDim.x) {
        float v = xr[c];
        s += v; s2 += v * v;
    }
    float S  = block_reduce(s,  sh, false);
    float S2 = block_reduce(s2, sh, false);
    float m   = S  * (1.f / C_DIM);
    float var = S2 * (1.f / C_DIM) - m * m;
    float inv = rsqrtf(var + EPS);
    for (int c = threadIdx.x; c < C_DIM; c += blockDim.x) {
        float v = e0[c] + (xr[c] - m) * inv * (1.f + e1[c]);
        unsigned short h, l; split_f16(v, h, l);
        oh[row * C_DIM + c] = h;
        ol[row * C_DIM + c] = l;
    }
}

// RMS + RoPE + split (strided input; dh/dl dense [L, C])
__global__ void rms_rope_split_kernel(const float* __restrict__ x, int ldx,
                                      const float* __restrict__ w,
                                      const float* __restrict__ freqs,
                                      unsigned short* __restrict__ dh, unsigned short* __restrict__ dl) {
    __shared__ float sh[32];
    int row = blockIdx.x;
    const float* xr = x + (long long)row * ldx;
    float s2 = 0.f;
    for (int c = threadIdx.x; c < C_DIM; c += blockDim.x) {
        float v = xr[c]; s2 += v * v;
    }
    float S2 = block_reduce(s2, sh, false);
    float inv = rsqrtf(S2 * (1.f / C_DIM) + EPS);
    int f  = row / 1200;
    int rm = row % 1200;
    int hh = rm / 40;
    int ww = rm % 40;
    for (int p = threadIdx.x; p < NH * 64; p += blockDim.x) {
        int n = p >> 6, j = p & 63;
        int pos = (j < 22) ? f : ((j < 43) ? hh : ww);
        float cs = freqs[(pos * 64 + j) * 2 + 0];
        float sn = freqs[(pos * 64 + j) * 2 + 1];
        int c = n * HD + 2 * j;
        float a = xr[c] * inv * w[c];
        float b = xr[c + 1] * inv * w[c + 1];
        float o0 = a * cs - b * sn;
        float o1 = a * sn + b * cs;
        unsigned short h0, l0, h1, l1;
        split_f16(o0, h0, l0); split_f16(o1, h1, l1);
        long long o = (long long)row * C_DIM + c;
        dh[o] = h0; dl[o] = l0;
        dh[o + 1] = h1; dl[o + 1] = l1;
    }
}

// RMS + split (strided input)
__global__ void rms_split_kernel(const float* __restrict__ x, int ldx,
                                 const float* __restrict__ w,
                                 unsigned short* __restrict__ dh, unsigned short* __restrict__ dl) {
    __shared__ float sh[32];
    long long row = blockIdx.x;
    const float* xr = x + row * ldx;
    float s2 = 0.f;
    for (int c = threadIdx.x; c < C_DIM; c += blockDim.x) {
        float v = xr[c]; s2 += v * v;
    }
    float S2 = block_reduce(s2, sh, false);
    float inv = rsqrtf(S2 * (1.f / C_DIM) + EPS);
    for (int c = threadIdx.x; c < C_DIM; c += blockDim.x) {
        float v = xr[c] * inv * w[c];
        unsigned short h, l; split_f16(v, h, l);
        dh[row * C_DIM + c] = h;
        dl[row * C_DIM + c] = l;
    }
}

__global__ void conv_split_kernel(const float* __restrict__ src, long long n,
                                  unsigned short* __restrict__ dh, unsigned short* __restrict__ dl) {
    long long i = (long long)blockIdx.x * blockDim.x + threadIdx.x;
    if (i < n) {
        unsigned short h, l; split_f16(src[i], h, l);
        dh[i] = h; dl[i] = l;
    }
}

// [R, Ccol] fp32 (row stride lds) -> [Ccol, R] fp16 HI ONLY
__global__ void transpose_h_kernel(const float* __restrict__ src, int R, int Ccol, int lds,
                                   unsigned short* __restrict__ dh) {
    __shared__ float tile[32][33];
    int bx = blockIdx.x, by = blockIdx.y;
    int tx = threadIdx.x, ty = threadIdx.y;  // 32 x 8
    #pragma unroll
    for (int i = 0; i < 4; i++) {
        int r = by * 32 + ty + i * 8;
        tile[ty + i * 8][tx] = src[(long long)r * lds + bx * 32 + tx];
    }
    __syncthreads();
    #pragma unroll
    for (int i = 0; i < 4; i++) {
        int ro = bx * 32 + ty + i * 8;
        int co = by * 32 + tx;
        __half hv = __float2half_rn(tile[tx][ty + i * 8]);
        dh[(long long)ro * R + co] = *reinterpret_cast<unsigned short*>(&hv);
    }
}

__global__ void softmax_split_kernel(const float* __restrict__ s, int lk,
                                     unsigned short* __restrict__ ph, unsigned short* __restrict__ pl) {
    __shared__ float sh[32];
    long long row = blockIdx.x;
    const float* p = s + row * (long long)lk;
    float mx = -INFINITY;
    for (int i = threadIdx.x; i < lk; i += blockDim.x) mx = fmaxf(mx, p[i]);
    mx = block_reduce(mx, sh, true);
    float sum = 0.f;
    for (int i = threadIdx.x; i < lk; i += blockDim.x) sum += __expf(p[i] - mx);
    sum = block_reduce(sum, sh, false);
    float inv = 1.f / sum;
    for (int i = threadIdx.x; i < lk; i += blockDim.x) {
        float v = __expf(p[i] - mx) * inv;
        unsigned short h, l; split_f16(v, h, l);
        ph[row * (long long)lk + i] = h;
        pl[row * (long long)lk + i] = l;
    }
}

__global__ void residual_mul_conv_kernel(const float* __restrict__ xin, const float* __restrict__ t,
                                         const float* __restrict__ ecol, float* __restrict__ out,
                                         unsigned short* __restrict__ oh, unsigned short* __restrict__ ol) {
    long long i = (long long)blockIdx.x * blockDim.x + threadIdx.x;
    if (i < (long long)L_Q * C_DIM) {
        float v = xin[i] + t[i] * ecol[i % C_DIM];
        out[i] = v;
        unsigned short h, l; split_f16(v, h, l);
        oh[i] = h; ol[i] = l;
    }
}

__global__ void add_inplace_kernel(float* __restrict__ x, const float* __restrict__ t) {
    long long i = (long long)blockIdx.x * blockDim.x + threadIdx.x;
    if (i < (long long)L_Q * C_DIM) x[i] += t[i];
}

__global__ void addmul_inplace_kernel(float* __restrict__ x, const float* __restrict__ t,
                                      const float* __restrict__ ecol) {
    long long i = (long long)blockIdx.x * blockDim.x + threadIdx.x;
    if (i < (long long)L_Q * C_DIM) x[i] += t[i] * ecol[i % C_DIM];
}

// ---------------- common GEMM asm helpers ----------------
static __device__ __forceinline__ uint32_t smem_u32(const void* p) {
    uint32_t r;
    asm("{ .reg .u64 t; cvta.to.shared.u64 t, %1; cvt.u32.u64 %0, t; }" : "=r"(r) : "l"(p));
    return r;
}
static __device__ __forceinline__ void cpa16(uint32_t s, const void* g, uint32_t sz) {
    asm volatile("cp.async.cg.shared.global [%0], [%1], 16, %2;" :: "r"(s), "l"(g), "r"(sz));
}
static __device__ __forceinline__ void cpa_commit() {
    asm volatile("cp.async.commit_group;");
}
static __device__ __forceinline__ void cpa_wait1() {
    asm volatile("cp.async.wait_group 1;");
}
static __device__ __forceinline__ void cpa_wait2() {
    asm volatile("cp.async.wait_group 2;");
}
static __device__ __forceinline__ void ldm_x4(uint32_t* r, uint32_t addr) {
    asm volatile("ldmatrix.sync.aligned.m8n8.x4.shared.b16 {%0,%1,%2,%3}, [%4];"
                 : "=r"(r[0]), "=r"(r[1]), "=r"(r[2]), "=r"(r[3]) : "r"(addr));
}
static __device__ __forceinline__ void mma16816(float* c, const uint32_t* a, uint32_t b0, uint32_t b1) {
    asm volatile("mma.sync.aligned.m16n8k16.row.col.f32.f16.f16.f32 "
                 "{%0,%1,%2,%3}, {%4,%5,%6,%7}, {%8,%9}, {%0,%1,%2,%3};"
                 : "+f"(c[0]), "+f"(c[1]), "+f"(c[2]), "+f"(c[3])
                 : "r"(a[0]), "r"(a[1]), "r"(a[2]), "r"(a[3]), "r"(b0), "r"(b1));
}
// 64B-row-pair swizzled smem addr for (row, ch 0..3); conflict-free ldmatrix
static __device__ __forceinline__ uint32_t saddr(int row, int ch) {
    return (uint32_t)(((row >> 1) << 7) +
                      (((((row & 1) << 2) | ch) ^ ((row >> 1) & 3)) << 4));
}

// =====================================================================
// WIDE GEMM: 128x256x32, warp tile 64x64, 4-stage cp.async, N>128.
//   2-product (A split, B hi) + optional 3rd product if Bl != nullptr.
// =====================================================================
#define W_STG 49152
#define W_SA_H 0
#define W_SA_L 8192
#define W_SB_H 16384
#define W_SB_L 32768
#define W_SMEM (4 * W_STG)     // 196608

__global__ void __launch_bounds__(256, 1)
hgemmw_kernel(const unsigned short* __restrict__ Ah, const unsigned short* __restrict__ Al,
              int lda, long long sAz,
              const unsigned short* __restrict__ Bh, const unsigned short* __restrict__ Bl,
              int ldb, long long sBz,
              float* __restrict__ Cf, unsigned short* __restrict__ Ch, unsigned short* __restrict__ Cl,
              int ldc, long long sCz,
              int M, int N, int K,
              const float* __restrict__ bias, float scale, int act) {
    extern __shared__ char smem[];
    uint32_t sbase = smem_u32(smem);

    int tid = threadIdx.x, lane = tid & 31, warp = tid >> 5;
    int wm = warp & 1, wn = warp >> 1;
    const bool useBl = (Bl != nullptr);

    long long zz = blockIdx.z;
    Ah += zz * sAz; Al += zz * sAz;
    Bh += zz * sBz; if (useBl) Bl += zz * sBz;
    if (Cf) Cf += zz * sCz;
    if (Ch) { Ch += zz * sCz; Cl += zz * sCz; }

    int bm = blockIdx.y * 128;
    int bn = blockIdx.x * 256;
    int mRem = M - bm; if (mRem > 128) mRem = 128;
    int nRem = N - bn; if (nRem > 256) nRem = 256;

    int nch = K >> 5;

    int rowA0 = tid >> 2, ch0 = tid & 3;
    uint32_t soA0 = saddr(rowA0, ch0);
    long long gA0 = (long long)(bm + rowA0) * lda + ch0 * 8;
    long long gB0 = (long long)(bn + rowA0) * ldb + ch0 * 8;
    uint32_t szA[2], szB[4];
    #pragma unroll
    for (int i = 0; i < 2; i++) szA[i] = (rowA0 + 64 * i < mRem) ? 16u : 0u;
    #pragma unroll
    for (int i = 0; i < 4; i++) szB[i] = (rowA0 + 64 * i < nRem) ? 16u : 0u;
    long long ldax = (long long)lda * 64, ldbx = (long long)ldb * 64;

    auto loadStage = [&](int c) {
        uint32_t sb = sbase + (uint32_t)((c & 3) * W_STG);
        long long k0 = (long long)(c << 5);
        #pragma unroll
        for (int i = 0; i < 2; i++) {
            cpa16(sb + W_SA_H + soA0 + i * 4096u, Ah + gA0 + i * ldax + k0, szA[i]);
            cpa16(sb + W_SA_L + soA0 + i * 4096u, Al + gA0 + i * ldax + k0, szA[i]);
        }
        #pragma unroll
        for (int i = 0; i < 4; i++)
            cpa16(sb + W_SB_H + soA0 + i * 4096u, Bh + gB0 + i * ldbx + k0, szB[i]);
        if (useBl) {
            #pragma unroll
            for (int i = 0; i < 4; i++)
                cpa16(sb + W_SB_L + soA0 + i * 4096u, Bl + gB0 + i * ldbx + k0, szB[i]);
        }
    };

    int frow = lane & 15, fhalf = lane >> 4;
    uint32_t a_rt[4]; int a_sw[4], a_s[4];
    #pragma unroll
    for (int mi = 0; mi < 4; mi++) {
        int row = wm * 64 + mi * 16 + frow;
        a_rt[mi] = (uint32_t)((row >> 1) << 7);
        a_sw[mi] = (row & 1) << 2;
        a_s[mi]  = (row >> 1) & 3;
    }
    uint32_t b_rt[4]; int b_sw[4], b_s[4];
    #pragma unroll
    for (int nj = 0; nj < 4; nj++) {
        int row = wn * 64 + nj * 16 + frow;
        b_rt[nj] = (uint32_t)((row >> 1) << 7);
        b_sw[nj] = (row & 1) << 2;
        b_s[nj]  = (row >> 1) & 3;
    }

    float acc[4][8][4];
    #pragma unroll
    for (int mi = 0; mi < 4; mi++)
        #pragma unroll
        for (int ni = 0; ni < 8; ni++)
            #pragma unroll
            for (int q = 0; q < 4; q++) acc[mi][ni][q] = 0.f;

    loadStage(0); cpa_commit();
    if (nch > 1) loadStage(1);
    cpa_commit();
    if (nch > 2) loadStage(2);
    cpa_commit();

    for (int c = 0; c < nch; c++) {
        cpa_wait2();
        __syncthreads();
        uint32_t sb = sbase + (uint32_t)((c & 3) * W_STG);

        #pragma unroll
        for (int k16 = 0; k16 < 2; k16++) {
            int chl = k16 * 2 + fhalf;
            uint32_t bH[4][4], bL[4][4];
            #pragma unroll
            for (int nj = 0; nj < 4; nj++) {
                uint32_t off = b_rt[nj] + (uint32_t)(((b_sw[nj] | chl) ^ b_s[nj]) << 4);
                ldm_x4(bH[nj], sb + W_SB_H + off);
                if (useBl) ldm_x4(bL[nj], sb + W_SB_L + off);
            }
            #pragma unroll
            for (int mi = 0; mi < 4; mi++) {
                uint32_t aH[4], aL[4];
                uint32_t off = a_rt[mi] + (uint32_t)(((a_sw[mi] | chl) ^ a_s[mi]) << 4);
                ldm_x4(aH, sb + W_SA_H + off);
                ldm_x4(aL, sb + W_SA_L + off);
                #pragma unroll
                for (int nj = 0; nj < 4; nj++) {
                    mma16816(acc[mi][nj*2+0], aH, bH[nj][0], bH[nj][2]);
                    mma16816(acc[mi][nj*2+1], aH, bH[nj][1], bH[nj][3]);
                    mma16816(acc[mi][nj*2+0], aL, bH[nj][0], bH[nj][2]);
                    mma16816(acc[mi][nj*2+1], aL, bH[nj][1], bH[nj][3]);
                    if (useBl) {
                        mma16816(acc[mi][nj*2+0], aH, bL[nj][0], bL[nj][2]);
                        mma16816(acc[mi][nj*2+1], aH, bL[nj][1], bL[nj][3]);
                    }
                }
            }
        }
        if (c + 3 < nch) loadStage(c + 3);
        cpa_commit();
    }

    int row0 = lane >> 2;
    int col0 = (lane & 3) * 2;
    #pragma unroll
    for (int mi = 0; mi < 4; mi++) {
        #pragma unroll
        for (int ni = 0; ni < 8; ni++) {
            int gn = bn + wn * 64 + (ni >> 1) * 16 + (ni & 1) * 8 + col0;
            if (gn >= N) continue;
            float b0 = 0.f, b1 = 0.f;
            if (bias) { b0 = bias[gn]; b1 = bias[gn + 1]; }
            float* cc = acc[mi][ni];
            #pragma unroll
            for (int half = 0; half < 2; half++) {
                int gm = bm + wm * 64 + mi * 16 + row0 + half * 8;
                if (gm >= M) continue;
                float v0 = cc[half * 2 + 0] * scale + b0;
                float v1 = cc[half * 2 + 1] * scale + b1;
                if (act == 1) { v0 = gelu_tanh(v0); v1 = gelu_tanh(v1); }
                long long o = (long long)gm * ldc + gn;
                if (Cf) *reinterpret_cast<float2*>(Cf + o) = make_float2(v0, v1);
                if (Ch) {
                    unsigned short h0, l0, h1, l1;
                    split_f16(v0, h0, l0); split_f16(v1, h1, l1);
                    *reinterpret_cast<ushort2*>(Ch + o) = make_ushort2(h0, h1);
                    *reinterpret_cast<ushort2*>(Cl + o) = make_ushort2(l0, l1);
                }
            }
        }
    }
}

// =====================================================================
// NARROW GEMM (N<=128): 128x128x32, 3-stage, 2 CTAs/SM, 2-product.
// =====================================================================
#define STAGES 3
#define STG 24576
#define SA_H 0
#define SA_L 8192
#define SB_H 16384
#define HG_SMEM (STAGES * STG)   // 73728

__global__ void __launch_bounds__(256, 2)
hgemm3_kernel(const unsigned short* __restrict__ Ah, const unsigned short* __restrict__ Al,
              int lda, long long sAz,
              const unsigned short* __restrict__ Bh,
              int ldb, long long sBz,
              float* __restrict__ Cf, unsigned short* __restrict__ Ch, unsigned short* __restrict__ Cl,
              int ldc, long long sCz,
              int M, int N, int K,
              const float* __restrict__ bias, float scale, int act) {
    extern __shared__ char smem[];
    uint32_t sbase = smem_u32(smem);

    int tid = threadIdx.x, lane = tid & 31, warp = tid >> 5;
    int wm = warp & 1, wn = warp >> 1;

    long long zz = blockIdx.z;
    Ah += zz * sAz; Al += zz * sAz;
    Bh += zz * sBz;
    if (Cf) Cf += zz * sCz;
    if (Ch) { Ch += zz * sCz; Cl += zz * sCz; }

    int bm = blockIdx.y * 128;
    int bn = blockIdx.x * 128;
    int mRem = M - bm; if (mRem > 128) mRem = 128;
    int nRem = N - bn; if (nRem > 128) nRem = 128;

    int nch = K >> 5;

    uint32_t so[2]; long long gA[2], gB[2]; uint32_t szA[2], szB[2];
    #pragma unroll
    for (int i = 0; i < 2; i++) {
        int idx = tid + i * 256;
        int row = idx >> 2, ch = idx & 3;
        so[i]  = saddr(row, ch);
        gA[i]  = (long long)(bm + row) * lda + ch * 8;
        gB[i]  = (long long)(bn + row) * ldb + ch * 8;
        szA[i] = (row < mRem) ? 16u : 0u;
        szB[i] = (row < nRem) ? 16u : 0u;
    }

    int frow = lane & 15, fhalf = lane >> 4;
    uint32_t a_rt[4]; int a_sw[4], a_s[4];
    #pragma unroll
    for (int mi = 0; mi < 4; mi++) {
        int row = wm * 64 + mi * 16 + frow;
        a_rt[mi] = (uint32_t)((row >> 1) << 7);
        a_sw[mi] = (row & 1) << 2;
        a_s[mi]  = (row >> 1) & 3;
    }
    uint32_t b_rt[2]; int b_sw[2], b_s[2];
    #pragma unroll
    for (int nj = 0; nj < 2; nj++) {
        int row = wn * 32 + nj * 16 + frow;
        b_rt[nj] = (uint32_t)((row >> 1) << 7);
        b_sw[nj] = (row & 1) << 2;
        b_s[nj]  = (row >> 1) & 3;
    }

    float acc[4][4][4];
    #pragma unroll
    for (int mi = 0; mi < 4; mi++)
        #pragma unroll
        for (int ni = 0; ni < 4; ni++)
            #pragma unroll
            for (int q = 0; q < 4; q++) acc[mi][ni][q] = 0.f;

    auto loadStage = [&](int c) {
        uint32_t sb = sbase + (uint32_t)((c % STAGES) * STG);
        long long k0 = (long long)(c << 5);
        #pragma unroll
        for (int i = 0; i < 2; i++) {
            cpa16(sb + SA_H + so[i], Ah + gA[i] + k0, szA[i]);
            cpa16(sb + SA_L + so[i], Al + gA[i] + k0, szA[i]);
            cpa16(sb + SB_H + so[i], Bh + gB[i] + k0, szB[i]);
        }
    };

    loadStage(0); cpa_commit();
    if (nch > 1) loadStage(1);
    cpa_commit();

    for (int c = 0; c < nch; c++) {
        cpa_wait1();
        __syncthreads();
        uint32_t sb = sbase + (uint32_t)((c % STAGES) * STG);

        #pragma unroll
        for (int k16 = 0; k16 < 2; k16++) {
            int chl = k16 * 2 + fhalf;
            uint32_t bH[2][4];
            #pragma unroll
            for (int nj = 0; nj < 2; nj++) {
                uint32_t off = b_rt[nj] + (uint32_t)(((b_sw[nj] | chl) ^ b_s[nj]) << 4);
                ldm_x4(bH[nj], sb + SB_H + off);
            }
            #pragma unroll
            for (int mi = 0; mi < 4; mi++) {
                uint32_t aH[4], aL[4];
                uint32_t off = a_rt[mi] + (uint32_t)(((a_sw[mi] | chl) ^ a_s[mi]) << 4);
                ldm_x4(aH, sb + SA_H + off);
                ldm_x4(aL, sb + SA_L + off);
                #pragma unroll
                for (int nj = 0; nj < 2; nj++) {
                    mma16816(acc[mi][nj*2+0], aH, bH[nj][0], bH[nj][2]);
                    mma16816(acc[mi][nj*2+1], aH, bH[nj][1], bH[nj][3]);
                    mma16816(acc[mi][nj*2+0], aL, bH[nj][0], bH[nj][2]);
                    mma16816(acc[mi][nj*2+1], aL, bH[nj][1], bH[nj][3]);
                }
            }
        }
        if (c + 2 < nch) loadStage(c + 2);
        cpa_commit();
    }

    int row0 = lane >> 2;
    int col0 = (lane & 3) * 2;
    #pragma unroll
    for (int mi = 0; mi < 4; mi++) {
        #pragma unroll
        for (int ni = 0; ni < 4; ni++) {
            int gn = bn + wn * 32 + ni * 8 + col0;
            if (gn >= N) continue;
            float b0 = 0.f, b1 = 0.f;
            if (bias) { b0 = bias[gn]; b1 = bias[gn + 1]; }
            float* cc = acc[mi][ni];
            #pragma unroll
            for (int half = 0; half < 2; half++) {
                int gm = bm + wm * 64 + mi * 16 + row0 + half * 8;
                if (gm >= M) continue;
                float v0 = cc[half * 2 + 0] * scale + b0;
                float v1 = cc[half * 2 + 1] * scale + b1;
                if (act == 1) { v0 = gelu_tanh(v0); v1 = gelu_tanh(v1); }
                long long o = (long long)gm * ldc + gn;
                if (Cf) *reinterpret_cast<float2*>(Cf + o) = make_float2(v0, v1);
                if (Ch) {
                    unsigned short h0, l0, h1, l1;
                    split_f16(v0, h0, l0); split_f16(v1, h1, l1);
                    *reinterpret_cast<ushort2*>(Ch + o) = make_ushort2(h0, h1);
                    *reinterpret_cast<ushort2*>(Cl + o) = make_ushort2(l0, l1);
                }
            }
        }
    }
}

// ---------------- host ----------------
static void hg(const unsigned short* Ah, const unsigned short* Al, int lda, long long sAz,
               const unsigned short* Bh, const unsigned short* Bl, int ldb, long long sBz,
               float* Cf, unsigned short* Ch, unsigned short* Cl, int ldc, long long sCz,
               int M, int N, int K, int Z, const float* bias, float scale, int act) {
    if (N > 128) {
        dim3 grid((N + 255) / 256, (M + 127) / 128, Z);
        hgemmw_kernel<<<grid, 256, W_SMEM>>>(Ah, Al, lda, sAz, Bh, Bl, ldb, sBz,
                                             Cf, Ch, Cl, ldc, sCz, M, N, K, bias, scale, act);
    } else {
        dim3 grid(1, (M + 127) / 128, Z);
        hgemm3_kernel<<<grid, 256, HG_SMEM>>>(Ah, Al, lda, sAz, Bh, ldb, sBz,
                                              Cf, Ch, Cl, ldc, sCz, M, N, K, bias, scale, act);
    }
}

static void trh(const float* src, int R, int Ccol, int lds, unsigned short* dh) {
    dim3 grid(Ccol / 32, R / 32);
    transpose_h_kernel<<<grid, dim3(32, 8)>>>(src, R, Ccol, lds, dh);
}

extern "C" void kernel_launch(void* const* d_in, const int* in_sizes, int n_in,
                              void* d_out, int out_size) {
    const float* x        = (const float*)d_in[0];
    const float* e        = (const float*)d_in[1];
    const float* context  = (const float*)d_in[2];
    const float* freqs    = (const float*)d_in[3];
    const float* modulation = (const float*)d_in[7];
    const float* sa_q_w = (const float*)d_in[8];
    const float* sa_q_b = (const float*)d_in[9];
    const float* sa_k_w = (const float*)d_in[10];
    const float* sa_k_b = (const float*)d_in[11];
    const float* sa_v_w = (const float*)d_in[12];
    const float* sa_v_b = (const float*)d_in[13];
    const float* sa_o_w = (const float*)d_in[14];
    const float* sa_o_b = (const float*)d_in[15];
    const float* sa_nq_w = (const float*)d_in[16];
    const float* sa_nk_w = (const float*)d_in[17];
    const float* ca_q_w = (const float*)d_in[18];
    const float* ca_q_b = (const float*)d_in[19];
    const float* ca_k_w = (const float*)d_in[20];
    const float* ca_k_b = (const float*)d_in[21];
    const float* ca_v_w = (const float*)d_in[22];
    const float* ca_v_b = (const float*)d_in[23];
    const float* ca_o_w = (const float*)d_in[24];
    const float* ca_o_b = (const float*)d_in[25];
    const float* ca_nq_w = (const float*)d_in[26];
    const float* ca_nk_w = (const float*)d_in[27];
    const float* ffn_w1 = (const float*)d_in[28];
    const float* ffn_b1 = (const float*)d_in[29];
    const float* ffn_w2 = (const float*)d_in[30];
    const float* ffn_b2 = (const float*)d_in[31];
    float* out = (float*)d_out;

    cudaFuncSetAttribute(hgemm3_kernel,
                         cudaFuncAttributeMaxDynamicSharedMemorySize, HG_SMEM);
    cudaFuncSetAttribute(hgemmw_kernel,
                         cudaFuncAttributeMaxDynamicSharedMemorySize, W_SMEM);

    float *em, *q, *t, *s, *b3;
    unsigned short *hh, *hl, *qh, *ql, *kh, *kl, *vth, *yh, *yl;
    unsigned short *oh, *ol, *cxh, *cxl, *ph, *pl, *ffh, *ffl, *wh;
    cudaGetSymbolAddress((void**)&em, g_em);
    cudaGetSymbolAddress((void**)&q,  g_q);
    cudaGetSymbolAddress((void**)&t,  g_t);
    cudaGetSymbolAddress((void**)&s,  g_s);
    cudaGetSymbolAddress((void**)&b3, g_b3);
    cudaGetSymbolAddress((void**)&hh, g_hh);  cudaGetSymbolAddress((void**)&hl, g_hl);
    cudaGetSymbolAddress((void**)&qh, g_qh);  cudaGetSymbolAddress((void**)&ql, g_ql);
    cudaGetSymbolAddress((void**)&kh, g_kh);  cudaGetSymbolAddress((void**)&kl, g_kl);
    cudaGetSymbolAddress((void**)&vth, g_vth);
    cudaGetSymbolAddress((void**)&yh, g_yh);  cudaGetSymbolAddress((void**)&yl, g_yl);
    cudaGetSymbolAddress((void**)&oh, g_oh);  cudaGetSymbolAddress((void**)&ol, g_ol);
    cudaGetSymbolAddress((void**)&cxh, g_cxh); cudaGetSymbolAddress((void**)&cxl, g_cxl);
    cudaGetSymbolAddress((void**)&ph, g_ph);  cudaGetSymbolAddress((void**)&pl, g_pl);
    cudaGetSymbolAddress((void**)&ffh, g_ffh); cudaGetSymbolAddress((void**)&ffl, g_ffl);
    cudaGetSymbolAddress((void**)&wh, g_wh);

    const float ascale = 0.08838834764831845f;   // 1/sqrt(128)
    const long long LC = (long long)L_Q * C_DIM;
    int eltBlocks = (int)((LC + 255) / 256);

    em_kernel<<<(6 * C_DIM + 255) / 256, 256>>>(e, modulation, em);

    // ================= self attention =================
    ln_mod_split_kernel<<<L_Q, 256>>>(x, em + 0 * C_DIM, em + 1 * C_DIM, hh, hl);
    // fused QKV: W = [Wq^T; Wk^T; Wv^T]  [4608, 1536]
    trh(sa_q_w, C_DIM, C_DIM, C_DIM, wh);
    trh(sa_k_w, C_DIM, C_DIM, C_DIM, wh + (long long)C_DIM * C_DIM);
    trh(sa_v_w, C_DIM, C_DIM, C_DIM, wh + 2LL * C_DIM * C_DIM);
    pack3_kernel<<<(3 * C_DIM + 255) / 256, 256>>>(sa_q_b, sa_k_b, sa_v_b, b3);
    float* qkv = s;   // alias scratch: [2400, 4608] fp32
    hg(hh, hl, C_DIM, 0, wh, nullptr, C_DIM, 0, qkv, nullptr, nullptr, 3 * C_DIM, 0,
       L_Q, 3 * C_DIM, C_DIM, 1, b3, 1.f, 0);
    rms_rope_split_kernel<<<L_Q, 256>>>(qkv + 0 * C_DIM, 3 * C_DIM, sa_nq_w, freqs, qh, ql);
    rms_rope_split_kernel<<<L_Q, 256>>>(qkv + 1 * C_DIM, 3 * C_DIM, sa_nk_w, freqs, kh, kl);
    trh(qkv + 2 * C_DIM, L_Q, C_DIM, 3 * C_DIM, vth);      // V^T [1536, 2400]
    // scores = scale * Q @ K^T per head (3-product: K lo included)
    hg(qh, ql, C_DIM, HD, kh, kl, C_DIM, HD, s, nullptr, nullptr,
       L_Q, (long long)L_Q * L_Q, L_Q, L_Q, HD, NH, nullptr, ascale, 0);
    softmax_split_kernel<<<NH * L_Q, 256>>>(s, L_Q, ph, pl);
    hg(ph, pl, L_Q, (long long)L_Q * L_Q, vth, nullptr, L_Q, (long long)HD * L_Q,
       nullptr, yh, yl, C_DIM, HD, L_Q, HD, L_Q, NH, nullptr, 1.f, 0);
    trh(sa_o_w, C_DIM, C_DIM, C_DIM, wh);
    hg(yh, yl, C_DIM, 0, wh, nullptr, C_DIM, 0, t, nullptr, nullptr, C_DIM, 0,
       L_Q, C_DIM, C_DIM, 1, sa_o_b, 1.f, 0);
    residual_mul_conv_kernel<<<eltBlocks, 256>>>(x, t, em + 2 * C_DIM, out, oh, ol);

    // ================= cross attention =================
    trh(ca_q_w, C_DIM, C_DIM, C_DIM, wh);
    hg(oh, ol, C_DIM, 0, wh, nullptr, C_DIM, 0, q, nullptr, nullptr, C_DIM, 0,
       L_Q, C_DIM, C_DIM, 1, ca_q_b, 1.f, 0);
    rms_split_kernel<<<L_Q, 256>>>(q, C_DIM, ca_nq_w, qh, ql);
    conv_split_kernel<<<(int)(((long long)L_KV * C_DIM + 255) / 256), 256>>>(
        context, (long long)L_KV * C_DIM, cxh, cxl);
    // fused KV: W = [Wk^T; Wv^T] [3072, 1536]
    trh(ca_k_w, C_DIM, C_DIM, C_DIM, wh);
    trh(ca_v_w, C_DIM, C_DIM, C_DIM, wh + (long long)C_DIM * C_DIM);
    pack2_kernel<<<(2 * C_DIM + 255) / 256, 256>>>(ca_k_b, ca_v_b, b3);
    float* kvbuf = s;   // [512, 3072] fp32
    hg(cxh, cxl, C_DIM, 0, wh, nullptr, C_DIM, 0, kvbuf, nullptr, nullptr, 2 * C_DIM, 0,
       L_KV, 2 * C_DIM, C_DIM, 1, b3, 1.f, 0);
    rms_split_kernel<<<L_KV, 256>>>(kvbuf + 0 * C_DIM, 2 * C_DIM, ca_nk_w, kh, kl);
    trh(kvbuf + 1 * C_DIM, L_KV, C_DIM, 2 * C_DIM, vth);   // V^T [1536, 512]
    hg(qh, ql, C_DIM, HD, kh, kl, C_DIM, HD, s, nullptr, nullptr,
       L_KV, (long long)L_Q * L_KV, L_Q, L_KV, HD, NH, nullptr, ascale, 0);
    softmax_split_kernel<<<NH * L_Q, 256>>>(s, L_KV, ph, pl);
    hg(ph, pl, L_KV, (long long)L_Q * L_KV, vth, nullptr, L_KV, (long long)HD * L_KV,
       nullptr, yh, yl, C_DIM, HD, L_Q, HD, L_KV, NH, nullptr, 1.f, 0);
    trh(ca_o_w, C_DIM, C_DIM, C_DIM, wh);
    hg(yh, yl, C_DIM, 0, wh, nullptr, C_DIM, 0, t, nullptr, nullptr, C_DIM, 0,
       L_Q, C_DIM, C_DIM, 1, ca_o_b, 1.f, 0);
    add_inplace_kernel<<<eltBlocks, 256>>>(out, t);

    // ================= FFN =================
    ln_mod_split_kernel<<<L_Q, 256>>>(out, em + 3 * C_DIM, em + 4 * C_DIM, hh, hl);
    trh(ffn_w1, C_DIM, FF_DIM, FF_DIM, wh);
    hg(hh, hl, C_DIM, 0, wh, nullptr, C_DIM, 0, nullptr, ffh, ffl, FF_DIM, 0,
       L_Q, FF_DIM, C_DIM, 1, ffn_b1, 1.f, 1);
    trh(ffn_w2, FF_DIM, C_DIM, C_DIM, wh);
    hg(ffh, ffl, FF_DIM, 0, wh, nullptr, FF_DIM, 0, t, nullptr, nullptr, C_DIM, 0,
       L_Q, C_DIM, FF_DIM, 1, ffn_b2, 1.f, 0);
    addmul_inplace_kernel<<<eltBlocks, 256>>>(out, t, em + 5 * C_DIM);
}

// round 9
// speedup vs baseline: 1.1529x; 1.0418x over previous
#include <cuda_runtime.h>
#include <cuda_fp16.h>
#include <stdint.h>
#include <math.h>

// Problem constants
#define C_DIM 1536
#define L_Q   2400
#define L_KV  512
#define NH    12
#define HD    128
#define FF_DIM 8960
#define EPS   1e-6f

// ---------------- device scratch ----------------
__device__ __align__(256) float g_em[6 * C_DIM];
__device__ __align__(256) float g_q [L_Q * C_DIM];
__device__ __align__(256) float g_t [L_Q * C_DIM];
__device__ __align__(256) float g_s [NH * L_Q * L_Q];     // fp32 scores / fused-proj scratch
__device__ __align__(256) float g_b3[3 * C_DIM];
__device__ __align__(256) float g_rinv[NH * L_Q];
__device__ __align__(256) unsigned short g_hh[L_Q * C_DIM], g_hl[L_Q * C_DIM];
__device__ __align__(256) unsigned short g_qh[L_Q * C_DIM], g_ql[L_Q * C_DIM];
__device__ __align__(256) unsigned short g_kh[L_Q * C_DIM], g_kl[L_Q * C_DIM];
__device__ __align__(256) unsigned short g_vth[C_DIM * L_Q];
__device__ __align__(256) unsigned short g_yh[L_Q * C_DIM], g_yl[L_Q * C_DIM];
__device__ __align__(256) unsigned short g_oh[L_Q * C_DIM], g_ol[L_Q * C_DIM];
__device__ __align__(256) unsigned short g_cxh[L_KV * C_DIM], g_cxl[L_KV * C_DIM];
__device__ __align__(256) unsigned short g_ph[NH * L_Q * L_Q];
__device__ __align__(256) unsigned short g_ffh[L_Q * FF_DIM];
__device__ __align__(256) unsigned short g_wh[FF_DIM * C_DIM];

// ---------------- helpers ----------------
__device__ __forceinline__ float block_reduce(float v, float* sh, bool is_max) {
    __syncthreads();
    int lane = threadIdx.x & 31, warp = threadIdx.x >> 5;
    #pragma unroll
    for (int o = 16; o > 0; o >>= 1) {
        float other = __shfl_down_sync(0xffffffffu, v, o);
        v = is_max ? fmaxf(v, other) : v + other;
    }
    if (lane == 0) sh[warp] = v;
    __syncthreads();
    int nw = blockDim.x >> 5;
    if (warp == 0) {
        v = (lane < nw) ? sh[lane] : (is_max ? -INFINITY : 0.f);
        #pragma unroll
        for (int o = 16; o > 0; o >>= 1) {
            float other = __shfl_down_sync(0xffffffffu, v, o);
            v = is_max ? fmaxf(v, other) : v + other;
        }
        if (lane == 0) sh[0] = v;
    }
    __syncthreads();
    return sh[0];
}

__device__ __forceinline__ float gelu_tanh(float v) {
    float v3 = v * v * v;
    return 0.5f * v * (1.f + tanhf(0.7978845608028654f * (v + 0.044715f * v3)));
}

static __device__ __forceinline__ void split_f16(float v, unsigned short& h, unsigned short& l) {
    __half hb = __float2half_rn(v);
    float r = v - __half2float(hb);
    __half lb = __float2half_rn(r);
    h = *reinterpret_cast<unsigned short*>(&hb);
    l = *reinterpret_cast<unsigned short*>(&lb);
}

// ---------------- elementwise / norm kernels ----------------
__global__ void em_kernel(const float* __restrict__ e, const float* __restrict__ mod,
                          float* __restrict__ em) {
    int i = blockIdx.x * blockDim.x + threadIdx.x;
    if (i < 6 * C_DIM) em[i] = e[i] + mod[i];
}

__global__ void pack3_kernel(const float* __restrict__ a, const float* __restrict__ b,
                             const float* __restrict__ c, float* __restrict__ d) {
    int i = blockIdx.x * blockDim.x + threadIdx.x;
    if (i < C_DIM) d[i] = a[i];
    else if (i < 2 * C_DIM) d[i] = b[i - C_DIM];
    else if (i < 3 * C_DIM) d[i] = c[i - 2 * C_DIM];
}

__global__ void pack2_kernel(const float* __restrict__ a, const float* __restrict__ b,
                             float* __restrict__ d) {
    int i = blockIdx.x * blockDim.x + threadIdx.x;
    if (i < C_DIM) d[i] = a[i];
    else if (i < 2 * C_DIM) d[i] = b[i - C_DIM];
}

// ol may be nullptr (hi-only mode)
__global__ void ln_mod_split_kernel(const float* __restrict__ x, const float* __restrict__ e0,
                                    const float* __restrict__ e1,
                                    unsigned short* __restrict__ oh, unsigned short* __restrict__ ol) {
    __shared__ float sh[32];
    long long row = blockIdx.x;
    const float* xr = x + row * C_DIM;
    float s = 0.f, s2 = 0.f;
    for (int c = threadIdx.x; c < C_DIM; c += blockDim.x) {
        float v = xr[c];
        s += v; s2 += v * v;
    }
    float S  = block_reduce(s,  sh, false);
    float S2 = block_reduce(s2, sh, false);
    float m   = S  * (1.f / C_DIM);
    float var = S2 * (1.f / C_DIM) - m * m;
    float inv = rsqrtf(var + EPS);
    for (int c = threadIdx.x; c < C_DIM; c += blockDim.x) {
        float v = e0[c] + (xr[c] - m) * inv * (1.f + e1[c]);
        unsigned short h, l; split_f16(v, h, l);
        oh[row * C_DIM + c] = h;
        if (ol) ol[row * C_DIM + c] = l;
    }
}

// RMS + RoPE + split (strided input; dh/dl dense [L, C])
__global__ void rms_rope_split_kernel(const float* __restrict__ x, int ldx,
                                      const float* __restrict__ w,
                                      const float* __restrict__ freqs,
                                      unsigned short* __restrict__ dh, unsigned short* __restrict__ dl) {
    __shared__ float sh[32];
    int row = blockIdx.x;
    const float* xr = x + (long long)row * ldx;
    float s2 = 0.f;
    for (int c = threadIdx.x; c < C_DIM; c += blockDim.x) {
        float v = xr[c]; s2 += v * v;
    }
    float S2 = block_reduce(s2, sh, false);
    float inv = rsqrtf(S2 * (1.f / C_DIM) + EPS);
    int f  = row / 1200;
    int rm = row % 1200;
    int hh = rm / 40;
    int ww = rm % 40;
    for (int p = threadIdx.x; p < NH * 64; p += blockDim.x) {
        int n = p >> 6, j = p & 63;
        int pos = (j < 22) ? f : ((j < 43) ? hh : ww);
        float cs = freqs[(pos * 64 + j) * 2 + 0];
        float sn = freqs[(pos * 64 + j) * 2 + 1];
        int c = n * HD + 2 * j;
        float a = xr[c] * inv * w[c];
        float b = xr[c + 1] * inv * w[c + 1];
        float o0 = a * cs - b * sn;
        float o1 = a * sn + b * cs;
        unsigned short h0, l0, h1, l1;
        split_f16(o0, h0, l0); split_f16(o1, h1, l1);
        long long o = (long long)row * C_DIM + c;
        dh[o] = h0; dl[o] = l0;
        dh[o + 1] = h1; dl[o + 1] = l1;
    }
}

// RMS + split (strided input)
__global__ void rms_split_kernel(const float* __restrict__ x, int ldx,
                                 const float* __restrict__ w,
                                 unsigned short* __restrict__ dh, unsigned short* __restrict__ dl) {
    __shared__ float sh[32];
    long long row = blockIdx.x;
    const float* xr = x + row * ldx;
    float s2 = 0.f;
    for (int c = threadIdx.x; c < C_DIM; c += blockDim.x) {
        float v = xr[c]; s2 += v * v;
    }
    float S2 = block_reduce(s2, sh, false);
    float inv = rsqrtf(S2 * (1.f / C_DIM) + EPS);
    for (int c = threadIdx.x; c < C_DIM; c += blockDim.x) {
        float v = xr[c] * inv * w[c];
        unsigned short h, l; split_f16(v, h, l);
        dh[row * C_DIM + c] = h;
        dl[row * C_DIM + c] = l;
    }
}

__global__ void conv_split_kernel(const float* __restrict__ src, long long n,
                                  unsigned short* __restrict__ dh, unsigned short* __restrict__ dl) {
    long long i = (long long)blockIdx.x * blockDim.x + threadIdx.x;
    if (i < n) {
        unsigned short h, l; split_f16(src[i], h, l);
        dh[i] = h; dl[i] = l;
    }
}

// [R, Ccol] fp32 (row stride lds) -> [Ccol, R] fp16 HI ONLY
__global__ void transpose_h_kernel(const float* __restrict__ src, int R, int Ccol, int lds,
                                   unsigned short* __restrict__ dh) {
    __shared__ float tile[32][33];
    int bx = blockIdx.x, by = blockIdx.y;
    int tx = threadIdx.x, ty = threadIdx.y;  // 32 x 8
    #pragma unroll
    for (int i = 0; i < 4; i++) {
        int r = by * 32 + ty + i * 8;
        tile[ty + i * 8][tx] = src[(long long)r * lds + bx * 32 + tx];
    }
    __syncthreads();
    #pragma unroll
    for (int i = 0; i < 4; i++) {
        int ro = bx * 32 + ty + i * 8;
        int co = by * 32 + tx;
        __half hv = __float2half_rn(tile[tx][ty + i * 8]);
        dh[(long long)ro * R + co] = *reinterpret_cast<unsigned short*>(&hv);
    }
}

// softmax: register-cached row, writes UNNORMALIZED exp (fp16) + 1/sum
__global__ void softmax_rowinv_kernel(const float* __restrict__ s, int lk,
                                      unsigned short* __restrict__ ph, float* __restrict__ rinv) {
    __shared__ float sh[32];
    long long row = blockIdx.x;
    const float* p = s + row * (long long)lk;
    float r[10];
    int n = 0;
    float mx = -INFINITY;
    for (int i = threadIdx.x; i < lk; i += blockDim.x) {
        float v = p[i];
        r[n++] = v;
        mx = fmaxf(mx, v);
    }
    mx = block_reduce(mx, sh, true);
    float sum = 0.f;
    n = 0;
    for (int i = threadIdx.x; i < lk; i += blockDim.x) {
        float e = __expf(r[n++] - mx);
        sum += e;
        __half hv = __float2half_rn(e);
        ph[row * (long long)lk + i] = *reinterpret_cast<unsigned short*>(&hv);
    }
    sum = block_reduce(sum, sh, false);
    if (threadIdx.x == 0) rinv[row] = 1.f / sum;
}

__global__ void residual_mul_conv_kernel(const float* __restrict__ xin, const float* __restrict__ t,
                                         const float* __restrict__ ecol, float* __restrict__ out,
                                         unsigned short* __restrict__ oh, unsigned short* __restrict__ ol) {
    long long i = (long long)blockIdx.x * blockDim.x + threadIdx.x;
    if (i < (long long)L_Q * C_DIM) {
        float v = xin[i] + t[i] * ecol[i % C_DIM];
        out[i] = v;
        unsigned short h, l; split_f16(v, h, l);
        oh[i] = h; ol[i] = l;
    }
}

__global__ void add_inplace_kernel(float* __restrict__ x, const float* __restrict__ t) {
    long long i = (long long)blockIdx.x * blockDim.x + threadIdx.x;
    if (i < (long long)L_Q * C_DIM) x[i] += t[i];
}

__global__ void addmul_inplace_kernel(float* __restrict__ x, const float* __restrict__ t,
                                      const float* __restrict__ ecol) {
    long long i = (long long)blockIdx.x * blockDim.x + threadIdx.x;
    if (i < (long long)L_Q * C_DIM) x[i] += t[i] * ecol[i % C_DIM];
}

// ---------------- common GEMM asm helpers ----------------
static __device__ __forceinline__ uint32_t smem_u32(const void* p) {
    uint32_t r;
    asm("{ .reg .u64 t; cvta.to.shared.u64 t, %1; cvt.u32.u64 %0, t; }" : "=r"(r) : "l"(p));
    return r;
}
static __device__ __forceinline__ void cpa16(uint32_t s, const void* g, uint32_t sz) {
    asm volatile("cp.async.cg.shared.global [%0], [%1], 16, %2;" :: "r"(s), "l"(g), "r"(sz));
}
static __device__ __forceinline__ void cpa_commit() {
    asm volatile("cp.async.commit_group;");
}
static __device__ __forceinline__ void cpa_wait1() {
    asm volatile("cp.async.wait_group 1;");
}
static __device__ __forceinline__ void cpa_wait2() {
    asm volatile("cp.async.wait_group 2;");
}
static __device__ __forceinline__ void ldm_x4(uint32_t* r, uint32_t addr) {
    asm volatile("ldmatrix.sync.aligned.m8n8.x4.shared.b16 {%0,%1,%2,%3}, [%4];"
                 : "=r"(r[0]), "=r"(r[1]), "=r"(r[2]), "=r"(r[3]) : "r"(addr));
}
static __device__ __forceinline__ void mma16816(float* c, const uint32_t* a, uint32_t b0, uint32_t b1) {
    asm volatile("mma.sync.aligned.m16n8k16.row.col.f32.f16.f16.f32 "
                 "{%0,%1,%2,%3}, {%4,%5,%6,%7}, {%8,%9}, {%0,%1,%2,%3};"
                 : "+f"(c[0]), "+f"(c[1]), "+f"(c[2]), "+f"(c[3])
                 : "r"(a[0]), "r"(a[1]), "r"(a[2]), "r"(a[3]), "r"(b0), "r"(b1));
}
// 64B-row-pair swizzled smem addr for (row, ch 0..3); conflict-free ldmatrix
static __device__ __forceinline__ uint32_t saddr(int row, int ch) {
    return (uint32_t)(((row >> 1) << 7) +
                      (((((row & 1) << 2) | ch) ^ ((row >> 1) & 3)) << 4));
}

// =====================================================================
// WIDE GEMM: 128x256x32, warp tile 64x64, 4-stage cp.async, N>128.
//   Products: Ah*Bh always; +Al*Bh if Al; +Ah*Bl if Bl.
// =====================================================================
#define W_STG 49152
#define W_SA_H 0
#define W_SA_L 8192
#define W_SB_H 16384
#define W_SB_L 32768
#define W_SMEM (4 * W_STG)

__global__ void __launch_bounds__(256, 1)
hgemmw_kernel(const unsigned short* __restrict__ Ah, const unsigned short* __restrict__ Al,
              int lda, long long sAz,
              const unsigned short* __restrict__ Bh, const unsigned short* __restrict__ Bl,
              int ldb, long long sBz,
              float* __restrict__ Cf, unsigned short* __restrict__ Ch, unsigned short* __restrict__ Cl,
              int ldc, long long sCz,
              const float* __restrict__ rowScale,
              int M, int N, int K,
              const float* __restrict__ bias, float scale, int act) {
    extern __shared__ char smem[];
    uint32_t sbase = smem_u32(smem);

    int tid = threadIdx.x, lane = tid & 31, warp = tid >> 5;
    int wm = warp & 1, wn = warp >> 1;
    const bool useAl = (Al != nullptr);
    const bool useBl = (Bl != nullptr);

    long long zz = blockIdx.z;
    Ah += zz * sAz; if (useAl) Al += zz * sAz;
    Bh += zz * sBz; if (useBl) Bl += zz * sBz;
    if (Cf) Cf += zz * sCz;
    if (Ch) Ch += zz * sCz;
    if (Cl) Cl += zz * sCz;
    if (rowScale) rowScale += zz * M;

    int bm = blockIdx.y * 128;
    int bn = blockIdx.x * 256;
    int mRem = M - bm; if (mRem > 128) mRem = 128;
    int nRem = N - bn; if (nRem > 256) nRem = 256;

    int nch = K >> 5;

    int rowA0 = tid >> 2, ch0 = tid & 3;
    uint32_t soA0 = saddr(rowA0, ch0);
    long long gA0 = (long long)(bm + rowA0) * lda + ch0 * 8;
    long long gB0 = (long long)(bn + rowA0) * ldb + ch0 * 8;
    uint32_t szA[2], szB[4];
    #pragma unroll
    for (int i = 0; i < 2; i++) szA[i] = (rowA0 + 64 * i < mRem) ? 16u : 0u;
    #pragma unroll
    for (int i = 0; i < 4; i++) szB[i] = (rowA0 + 64 * i < nRem) ? 16u : 0u;
    long long ldax = (long long)lda * 64, ldbx = (long long)ldb * 64;

    auto loadStage = [&](int c) {
        uint32_t sb = sbase + (uint32_t)((c & 3) * W_STG);
        long long k0 = (long long)(c << 5);
        #pragma unroll
        for (int i = 0; i < 2; i++) {
            cpa16(sb + W_SA_H + soA0 + i * 4096u, Ah + gA0 + i * ldax + k0, szA[i]);
            if (useAl)
                cpa16(sb + W_SA_L + soA0 + i * 4096u, Al + gA0 + i * ldax + k0, szA[i]);
        }
        #pragma unroll
        for (int i = 0; i < 4; i++)
            cpa16(sb + W_SB_H + soA0 + i * 4096u, Bh + gB0 + i * ldbx + k0, szB[i]);
        if (useBl) {
            #pragma unroll
            for (int i = 0; i < 4; i++)
                cpa16(sb + W_SB_L + soA0 + i * 4096u, Bl + gB0 + i * ldbx + k0, szB[i]);
        }
    };

    int frow = lane & 15, fhalf = lane >> 4;
    uint32_t a_rt[4]; int a_sw[4], a_s[4];
    #pragma unroll
    for (int mi = 0; mi < 4; mi++) {
        int row = wm * 64 + mi * 16 + frow;
        a_rt[mi] = (uint32_t)((row >> 1) << 7);
        a_sw[mi] = (row & 1) << 2;
        a_s[mi]  = (row >> 1) & 3;
    }
    uint32_t b_rt[4]; int b_sw[4], b_s[4];
    #pragma unroll
    for (int nj = 0; nj < 4; nj++) {
        int row = wn * 64 + nj * 16 + frow;
        b_rt[nj] = (uint32_t)((row >> 1) << 7);
        b_sw[nj] = (row & 1) << 2;
        b_s[nj]  = (row >> 1) & 3;
    }

    float acc[4][8][4];
    #pragma unroll
    for (int mi = 0; mi < 4; mi++)
        #pragma unroll
        for (int ni = 0; ni < 8; ni++)
            #pragma unroll
            for (int q = 0; q < 4; q++) acc[mi][ni][q] = 0.f;

    loadStage(0); cpa_commit();
    if (nch > 1) loadStage(1);
    cpa_commit();
    if (nch > 2) loadStage(2);
    cpa_commit();

    for (int c = 0; c < nch; c++) {
        cpa_wait2();
        __syncthreads();
        uint32_t sb = sbase + (uint32_t)((c & 3) * W_STG);

        #pragma unroll
        for (int k16 = 0; k16 < 2; k16++) {
            int chl = k16 * 2 + fhalf;
            uint32_t bH[4][4], bL[4][4];
            #pragma unroll
            for (int nj = 0; nj < 4; nj++) {
                uint32_t off = b_rt[nj] + (uint32_t)(((b_sw[nj] | chl) ^ b_s[nj]) << 4);
                ldm_x4(bH[nj], sb + W_SB_H + off);
                if (useBl) ldm_x4(bL[nj], sb + W_SB_L + off);
            }
            #pragma unroll
            for (int mi = 0; mi < 4; mi++) {
                uint32_t aH[4], aL[4];
                uint32_t off = a_rt[mi] + (uint32_t)(((a_sw[mi] | chl) ^ a_s[mi]) << 4);
                ldm_x4(aH, sb + W_SA_H + off);
                if (useAl) ldm_x4(aL, sb + W_SA_L + off);
                #pragma unroll
                for (int nj = 0; nj < 4; nj++) {
                    mma16816(acc[mi][nj*2+0], aH, bH[nj][0], bH[nj][2]);
                    mma16816(acc[mi][nj*2+1], aH, bH[nj][1], bH[nj][3]);
                    if (useAl) {
                        mma16816(acc[mi][nj*2+0], aL, bH[nj][0], bH[nj][2]);
                        mma16816(acc[mi][nj*2+1], aL, bH[nj][1], bH[nj][3]);
                    }
                    if (useBl) {
                        mma16816(acc[mi][nj*2+0], aH, bL[nj][0], bL[nj][2]);
                        mma16816(acc[mi][nj*2+1], aH, bL[nj][1], bL[nj][3]);
                    }
                }
            }
        }
        if (c + 3 < nch) loadStage(c + 3);
        cpa_commit();
    }

    int row0 = lane >> 2;
    int col0 = (lane & 3) * 2;
    #pragma unroll
    for (int mi = 0; mi < 4; mi++) {
        #pragma unroll
        for (int ni = 0; ni < 8; ni++) {
            int gn = bn + wn * 64 + (ni >> 1) * 16 + (ni & 1) * 8 + col0;
            if (gn >= N) continue;
            float b0 = 0.f, b1 = 0.f;
            if (bias) { b0 = bias[gn]; b1 = bias[gn + 1]; }
            float* cc = acc[mi][ni];
            #pragma unroll
            for (int half = 0; half < 2; half++) {
                int gm = bm + wm * 64 + mi * 16 + row0 + half * 8;
                if (gm >= M) continue;
                float rs = rowScale ? rowScale[gm] : 1.f;
                float v0 = cc[half * 2 + 0] * scale * rs + b0;
                float v1 = cc[half * 2 + 1] * scale * rs + b1;
                if (act == 1) { v0 = gelu_tanh(v0); v1 = gelu_tanh(v1); }
                long long o = (long long)gm * ldc + gn;
                if (Cf) *reinterpret_cast<float2*>(Cf + o) = make_float2(v0, v1);
                if (Ch) {
                    unsigned short h0, l0, h1, l1;
                    split_f16(v0, h0, l0); split_f16(v1, h1, l1);
                    *reinterpret_cast<ushort2*>(Ch + o) = make_ushort2(h0, h1);
                    if (Cl) *reinterpret_cast<ushort2*>(Cl + o) = make_ushort2(l0, l1);
                }
            }
        }
    }
}

// =====================================================================
// NARROW GEMM (N<=128): 128x128x32, 3-stage, 2 CTAs/SM.
//   Products: Ah*Bh; +Al*Bh if Al.
// =====================================================================
#define STAGES 3
#define STG 24576
#define SA_H 0
#define SA_L 8192
#define SB_H 16384
#define HG_SMEM (STAGES * STG)

__global__ void __launch_bounds__(256, 2)
hgemm3_kernel(const unsigned short* __restrict__ Ah, const unsigned short* __restrict__ Al,
              int lda, long long sAz,
              const unsigned short* __restrict__ Bh,
              int ldb, long long sBz,
              float* __restrict__ Cf, unsigned short* __restrict__ Ch, unsigned short* __restrict__ Cl,
              int ldc, long long sCz,
              const float* __restrict__ rowScale,
              int M, int N, int K,
              const float* __restrict__ bias, float scale, int act) {
    extern __shared__ char smem[];
    uint32_t sbase = smem_u32(smem);

    int tid = threadIdx.x, lane = tid & 31, warp = tid >> 5;
    int wm = warp & 1, wn = warp >> 1;
    const bool useAl = (Al != nullptr);

    long long zz = blockIdx.z;
    Ah += zz * sAz; if (useAl) Al += zz * sAz;
    Bh += zz * sBz;
    if (Cf) Cf += zz * sCz;
    if (Ch) Ch += zz * sCz;
    if (Cl) Cl += zz * sCz;
    if (rowScale) rowScale += zz * M;

    int bm = blockIdx.y * 128;
    int bn = blockIdx.x * 128;
    int mRem = M - bm; if (mRem > 128) mRem = 128;
    int nRem = N - bn; if (nRem > 128) nRem = 128;

    int nch = K >> 5;

    uint32_t so[2]; long long gA[2], gB[2]; uint32_t szA[2], szB[2];
    #pragma unroll
    for (int i = 0; i < 2; i++) {
        int idx = tid + i * 256;
        int row = idx >> 2, ch = idx & 3;
        so[i]  = saddr(row, ch);
        gA[i]  = (long long)(bm + row) * lda + ch * 8;
        gB[i]  = (long long)(bn + row) * ldb + ch * 8;
        szA[i] = (row < mRem) ? 16u : 0u;
        szB[i] = (row < nRem) ? 16u : 0u;
    }

    int frow = lane & 15, fhalf = lane >> 4;
    uint32_t a_rt[4]; int a_sw[4], a_s[4];
    #pragma unroll
    for (int mi = 0; mi < 4; mi++) {
        int row = wm * 64 + mi * 16 + frow;
        a_rt[mi] = (uint32_t)((row >> 1) << 7);
        a_sw[mi] = (row & 1) << 2;
        a_s[mi]  = (row >> 1) & 3;
    }
    uint32_t b_rt[2]; int b_sw[2], b_s[2];
    #pragma unroll
    for (int nj = 0; nj < 2; nj++) {
        int row = wn * 32 + nj * 16 + frow;
        b_rt[nj] = (uint32_t)((row >> 1) << 7);
        b_sw[nj] = (row & 1) << 2;
        b_s[nj]  = (row >> 1) & 3;
    }

    float acc[4][4][4];
    #pragma unroll
    for (int mi = 0; mi < 4; mi++)
        #pragma unroll
        for (int ni = 0; ni < 4; ni++)
            #pragma unroll
            for (int q = 0; q < 4; q++) acc[mi][ni][q] = 0.f;

    auto loadStage = [&](int c) {
        uint32_t sb = sbase + (uint32_t)((c % STAGES) * STG);
        long long k0 = (long long)(c << 5);
        #pragma unroll
        for (int i = 0; i < 2; i++) {
            cpa16(sb + SA_H + so[i], Ah + gA[i] + k0, szA[i]);
            if (useAl) cpa16(sb + SA_L + so[i], Al + gA[i] + k0, szA[i]);
            cpa16(sb + SB_H + so[i], Bh + gB[i] + k0, szB[i]);
        }
    };

    loadStage(0); cpa_commit();
    if (nch > 1) loadStage(1);
    cpa_commit();

    for (int c = 0; c < nch; c++) {
        cpa_wait1();
        __syncthreads();
        uint32_t sb = sbase + (uint32_t)((c % STAGES) * STG);

        #pragma unroll
        for (int k16 = 0; k16 < 2; k16++) {
            int chl = k16 * 2 + fhalf;
            uint32_t bH[2][4];
            #pragma unroll
            for (int nj = 0; nj < 2; nj++) {
                uint32_t off = b_rt[nj] + (uint32_t)(((b_sw[nj] | chl) ^ b_s[nj]) << 4);
                ldm_x4(bH[nj], sb + SB_H + off);
            }
            #pragma unroll
            for (int mi = 0; mi < 4; mi++) {
                uint32_t aH[4], aL[4];
                uint32_t off = a_rt[mi] + (uint32_t)(((a_sw[mi] | chl) ^ a_s[mi]) << 4);
                ldm_x4(aH, sb + SA_H + off);
                if (useAl) ldm_x4(aL, sb + SA_L + off);
                #pragma unroll
                for (int nj = 0; nj < 2; nj++) {
                    mma16816(acc[mi][nj*2+0], aH, bH[nj][0], bH[nj][2]);
                    mma16816(acc[mi][nj*2+1], aH, bH[nj][1], bH[nj][3]);
                    if (useAl) {
                        mma16816(acc[mi][nj*2+0], aL, bH[nj][0], bH[nj][2]);
                        mma16816(acc[mi][nj*2+1], aL, bH[nj][1], bH[nj][3]);
                    }
                }
            }
        }
        if (c + 2 < nch) loadStage(c + 2);
        cpa_commit();
    }

    int row0 = lane >> 2;
    int col0 = (lane & 3) * 2;
    #pragma unroll
    for (int mi = 0; mi < 4; mi++) {
        #pragma unroll
        for (int ni = 0; ni < 4; ni++) {
            int gn = bn + wn * 32 + ni * 8 + col0;
            if (gn >= N) continue;
            float b0 = 0.f, b1 = 0.f;
            if (bias) { b0 = bias[gn]; b1 = bias[gn + 1]; }
            float* cc = acc[mi][ni];
            #pragma unroll
            for (int half = 0; half < 2; half++) {
                int gm = bm + wm * 64 + mi * 16 + row0 + half * 8;
                if (gm >= M) continue;
                float rs = rowScale ? rowScale[gm] : 1.f;
                float v0 = cc[half * 2 + 0] * scale * rs + b0;
                float v1 = cc[half * 2 + 1] * scale * rs + b1;
                if (act == 1) { v0 = gelu_tanh(v0); v1 = gelu_tanh(v1); }
                long long o = (long long)gm * ldc + gn;
                if (Cf) *reinterpret_cast<float2*>(Cf + o) = make_float2(v0, v1);
                if (Ch) {
                    unsigned short h0, l0, h1, l1;
                    split_f16(v0, h0, l0); split_f16(v1, h1, l1);
                    *reinterpret_cast<ushort2*>(Ch + o) = make_ushort2(h0, h1);
                    if (Cl) *reinterpret_cast<ushort2*>(Cl + o) = make_ushort2(l0, l1);
                }
            }
        }
    }
}

// ---------------- host ----------------
static void hg(const unsigned short* Ah, const unsigned short* Al, int lda, long long sAz,
               const unsigned short* Bh, const unsigned short* Bl, int ldb, long long sBz,
               float* Cf, unsigned short* Ch, unsigned short* Cl, int ldc, long long sCz,
               const float* rowScale,
               int M, int N, int K, int Z, const float* bias, float scale, int act) {
    if (N > 128) {
        dim3 grid((N + 255) / 256, (M + 127) / 128, Z);
        hgemmw_kernel<<<grid, 256, W_SMEM>>>(Ah, Al, lda, sAz, Bh, Bl, ldb, sBz,
                                             Cf, Ch, Cl, ldc, sCz, rowScale,
                                             M, N, K, bias, scale, act);
    } else {
        dim3 grid(1, (M + 127) / 128, Z);
        hgemm3_kernel<<<grid, 256, HG_SMEM>>>(Ah, Al, lda, sAz, Bh, ldb, sBz,
                                              Cf, Ch, Cl, ldc, sCz, rowScale,
                                              M, N, K, bias, scale, act);
    }
}

static void trh(const float* src, int R, int Ccol, int lds, unsigned short* dh) {
    dim3 grid(Ccol / 32, R / 32);
    transpose_h_kernel<<<grid, dim3(32, 8)>>>(src, R, Ccol, lds, dh);
}

extern "C" void kernel_launch(void* const* d_in, const int* in_sizes, int n_in,
                              void* d_out, int out_size) {
    const float* x        = (const float*)d_in[0];
    const float* e        = (const float*)d_in[1];
    const float* context  = (const float*)d_in[2];
    const float* freqs    = (const float*)d_in[3];
    const float* modulation = (const float*)d_in[7];
    const float* sa_q_w = (const float*)d_in[8];
    const float* sa_q_b = (const float*)d_in[9];
    const float* sa_k_w = (const float*)d_in[10];
    const float* sa_k_b = (const float*)d_in[11];
    const float* sa_v_w = (const float*)d_in[12];
    const float* sa_v_b = (const float*)d_in[13];
    const float* sa_o_w = (const float*)d_in[14];
    const float* sa_o_b = (const float*)d_in[15];
    const float* sa_nq_w = (const float*)d_in[16];
    const float* sa_nk_w = (const float*)d_in[17];
    const float* ca_q_w = (const float*)d_in[18];
    const float* ca_q_b = (const float*)d_in[19];
    const float* ca_k_w = (const float*)d_in[20];
    const float* ca_k_b = (const float*)d_in[21];
    const float* ca_v_w = (const float*)d_in[22];
    const float* ca_v_b = (const float*)d_in[23];
    const float* ca_o_w = (const float*)d_in[24];
    const float* ca_o_b = (const float*)d_in[25];
    const float* ca_nq_w = (const float*)d_in[26];
    const float* ca_nk_w = (const float*)d_in[27];
    const float* ffn_w1 = (const float*)d_in[28];
    const float* ffn_b1 = (const float*)d_in[29];
    const float* ffn_w2 = (const float*)d_in[30];
    const float* ffn_b2 = (const float*)d_in[31];
    float* out = (float*)d_out;

    cudaFuncSetAttribute(hgemm3_kernel,
                         cudaFuncAttributeMaxDynamicSharedMemorySize, HG_SMEM);
    cudaFuncSetAttribute(hgemmw_kernel,
                         cudaFuncAttributeMaxDynamicSharedMemorySize, W_SMEM);

    float *em, *q, *t, *s, *b3, *rinv;
    unsigned short *hh, *hl, *qh, *ql, *kh, *kl, *vth, *yh, *yl;
    unsigned short *oh, *ol, *cxh, *cxl, *ph, *ffh, *wh;
    cudaGetSymbolAddress((void**)&em, g_em);
    cudaGetSymbolAddress((void**)&q,  g_q);
    cudaGetSymbolAddress((void**)&t,  g_t);
    cudaGetSymbolAddress((void**)&s,  g_s);
    cudaGetSymbolAddress((void**)&b3, g_b3);
    cudaGetSymbolAddress((void**)&rinv, g_rinv);
    cudaGetSymbolAddress((void**)&hh, g_hh);  cudaGetSymbolAddress((void**)&hl, g_hl);
    cudaGetSymbolAddress((void**)&qh, g_qh);  cudaGetSymbolAddress((void**)&ql, g_ql);
    cudaGetSymbolAddress((void**)&kh, g_kh);  cudaGetSymbolAddress((void**)&kl, g_kl);
    cudaGetSymbolAddress((void**)&vth, g_vth);
    cudaGetSymbolAddress((void**)&yh, g_yh);  cudaGetSymbolAddress((void**)&yl, g_yl);
    cudaGetSymbolAddress((void**)&oh, g_oh);  cudaGetSymbolAddress((void**)&ol, g_ol);
    cudaGetSymbolAddress((void**)&cxh, g_cxh); cudaGetSymbolAddress((void**)&cxl, g_cxl);
    cudaGetSymbolAddress((void**)&ph, g_ph);
    cudaGetSymbolAddress((void**)&ffh, g_ffh);
    cudaGetSymbolAddress((void**)&wh, g_wh);

    const float ascale = 0.08838834764831845f;   // 1/sqrt(128)
    const long long LC = (long long)L_Q * C_DIM;
    int eltBlocks = (int)((LC + 255) / 256);

    em_kernel<<<(6 * C_DIM + 255) / 256, 256>>>(e, modulation, em);

    // ================= self attention =================
    ln_mod_split_kernel<<<L_Q, 256>>>(x, em + 0 * C_DIM, em + 1 * C_DIM, hh, hl);
    trh(sa_q_w, C_DIM, C_DIM, C_DIM, wh);
    trh(sa_k_w, C_DIM, C_DIM, C_DIM, wh + (long long)C_DIM * C_DIM);
    trh(sa_v_w, C_DIM, C_DIM, C_DIM, wh + 2LL * C_DIM * C_DIM);
    pack3_kernel<<<(3 * C_DIM + 255) / 256, 256>>>(sa_q_b, sa_k_b, sa_v_b, b3);
    float* qkv = s;   // alias scratch: [2400, 4608] fp32
    hg(hh, hl, C_DIM, 0, wh, nullptr, C_DIM, 0, qkv, nullptr, nullptr, 3 * C_DIM, 0,
       nullptr, L_Q, 3 * C_DIM, C_DIM, 1, b3, 1.f, 0);
    rms_rope_split_kernel<<<L_Q, 256>>>(qkv + 0 * C_DIM, 3 * C_DIM, sa_nq_w, freqs, qh, ql);
    rms_rope_split_kernel<<<L_Q, 256>>>(qkv + 1 * C_DIM, 3 * C_DIM, sa_nk_w, freqs, kh, kl);
    trh(qkv + 2 * C_DIM, L_Q, C_DIM, 3 * C_DIM, vth);      // V^T [1536, 2400]
    // scores (3-product: q split + k lo)
    hg(qh, ql, C_DIM, HD, kh, kl, C_DIM, HD, s, nullptr, nullptr,
       L_Q, (long long)L_Q * L_Q, nullptr, L_Q, L_Q, HD, NH, nullptr, ascale, 0);
    softmax_rowinv_kernel<<<NH * L_Q, 256>>>(s, L_Q, ph, rinv);
    // PV: 1-product, row-scaled by 1/sum in epilogue
    hg(ph, nullptr, L_Q, (long long)L_Q * L_Q, vth, nullptr, L_Q, (long long)HD * L_Q,
       nullptr, yh, yl, C_DIM, HD, rinv, L_Q, HD, L_Q, NH, nullptr, 1.f, 0);
    trh(sa_o_w, C_DIM, C_DIM, C_DIM, wh);
    hg(yh, yl, C_DIM, 0, wh, nullptr, C_DIM, 0, t, nullptr, nullptr, C_DIM, 0,
       nullptr, L_Q, C_DIM, C_DIM, 1, sa_o_b, 1.f, 0);
    residual_mul_conv_kernel<<<eltBlocks, 256>>>(x, t, em + 2 * C_DIM, out, oh, ol);

    // ================= cross attention =================
    trh(ca_q_w, C_DIM, C_DIM, C_DIM, wh);
    hg(oh, ol, C_DIM, 0, wh, nullptr, C_DIM, 0, q, nullptr, nullptr, C_DIM, 0,
       nullptr, L_Q, C_DIM, C_DIM, 1, ca_q_b, 1.f, 0);
    rms_split_kernel<<<L_Q, 256>>>(q, C_DIM, ca_nq_w, qh, ql);
    conv_split_kernel<<<(int)(((long long)L_KV * C_DIM + 255) / 256), 256>>>(
        context, (long long)L_KV * C_DIM, cxh, cxl);
    trh(ca_k_w, C_DIM, C_DIM, C_DIM, wh);
    trh(ca_v_w, C_DIM, C_DIM, C_DIM, wh + (long long)C_DIM * C_DIM);
    pack2_kernel<<<(2 * C_DIM + 255) / 256, 256>>>(ca_k_b, ca_v_b, b3);
    float* kvbuf = s;   // [512, 3072] fp32
    hg(cxh, cxl, C_DIM, 0, wh, nullptr, C_DIM, 0, kvbuf, nullptr, nullptr, 2 * C_DIM, 0,
       nullptr, L_KV, 2 * C_DIM, C_DIM, 1, b3, 1.f, 0);
    rms_split_kernel<<<L_KV, 256>>>(kvbuf + 0 * C_DIM, 2 * C_DIM, ca_nk_w, kh, kl);
    trh(kvbuf + 1 * C_DIM, L_KV, C_DIM, 2 * C_DIM, vth);   // V^T [1536, 512]
    hg(qh, ql, C_DIM, HD, kh, kl, C_DIM, HD, s, nullptr, nullptr,
       L_KV, (long long)L_Q * L_KV, nullptr, L_Q, L_KV, HD, NH, nullptr, ascale, 0);
    softmax_rowinv_kernel<<<NH * L_Q, 256>>>(s, L_KV, ph, rinv);
    hg(ph, nullptr, L_KV, (long long)L_Q * L_KV, vth, nullptr, L_KV, (long long)HD * L_KV,
       nullptr, yh, yl, C_DIM, HD, rinv, L_Q, HD, L_KV, NH, nullptr, 1.f, 0);
    trh(ca_o_w, C_DIM, C_DIM, C_DIM, wh);
    hg(yh, yl, C_DIM, 0, wh, nullptr, C_DIM, 0, t, nullptr, nullptr, C_DIM, 0,
       nullptr, L_Q, C_DIM, C_DIM, 1, ca_o_b, 1.f, 0);
    add_inplace_kernel<<<eltBlocks, 256>>>(out, t);

    // ================= FFN =================
    ln_mod_split_kernel<<<L_Q, 256>>>(out, em + 3 * C_DIM, em + 4 * C_DIM, hh, nullptr);
    trh(ffn_w1, C_DIM, FF_DIM, FF_DIM, wh);
    hg(hh, nullptr, C_DIM, 0, wh, nullptr, C_DIM, 0, nullptr, ffh, nullptr, FF_DIM, 0,
       nullptr, L_Q, FF_DIM, C_DIM, 1, ffn_b1, 1.f, 1);   // 1-product + GELU
    trh(ffn_w2, FF_DIM, C_DIM, C_DIM, wh);
    hg(ffh, nullptr, FF_DIM, 0, wh, nullptr, FF_DIM, 0, t, nullptr, nullptr, C_DIM, 0,
       nullptr, L_Q, C_DIM, FF_DIM, 1, ffn_b2, 1.f, 0);   // 1-product
    addmul_inplace_kernel<<<eltBlocks, 256>>>(out, t, em + 5 * C_DIM);
}

// round 10
// speedup vs baseline: 1.1630x; 1.0088x over previous
#include <cuda_runtime.h>
#include <cuda_fp16.h>
#include <stdint.h>
#include <math.h>

// Problem constants
#define C_DIM 1536
#define L_Q   2400
#define L_KV  512
#define NH    12
#define HD    128
#define FF_DIM 8960
#define EPS   1e-6f

// ---------------- device scratch ----------------
__device__ __align__(256) float g_em[6 * C_DIM];
__device__ __align__(256) float g_q [L_Q * C_DIM];
__device__ __align__(256) float g_t [L_Q * C_DIM];
__device__ __align__(256) float g_s [L_Q * 3 * C_DIM];    // fused-proj fp32 scratch
__device__ __align__(256) float g_b3[3 * C_DIM];
__device__ __align__(256) float g_rinv[NH * L_Q];
__device__ __align__(256) unsigned short g_hh[L_Q * C_DIM], g_hl[L_Q * C_DIM];
__device__ __align__(256) unsigned short g_qh[L_Q * C_DIM], g_ql[L_Q * C_DIM];
__device__ __align__(256) unsigned short g_kh[L_Q * C_DIM];
__device__ __align__(256) unsigned short g_vth[C_DIM * L_Q];
__device__ __align__(256) unsigned short g_yh[L_Q * C_DIM], g_yl[L_Q * C_DIM];
__device__ __align__(256) unsigned short g_oh[L_Q * C_DIM], g_ol[L_Q * C_DIM];
__device__ __align__(256) unsigned short g_cxh[L_KV * C_DIM], g_cxl[L_KV * C_DIM];
__device__ __align__(256) unsigned short g_ph[NH * L_Q * L_Q];
__device__ __align__(256) unsigned short g_ffh[L_Q * FF_DIM];
__device__ __align__(256) unsigned short g_wh[FF_DIM * C_DIM];

// ---------------- helpers ----------------
__device__ __forceinline__ float block_reduce(float v, float* sh, bool is_max) {
    __syncthreads();
    int lane = threadIdx.x & 31, warp = threadIdx.x >> 5;
    #pragma unroll
    for (int o = 16; o > 0; o >>= 1) {
        float other = __shfl_down_sync(0xffffffffu, v, o);
        v = is_max ? fmaxf(v, other) : v + other;
    }
    if (lane == 0) sh[warp] = v;
    __syncthreads();
    int nw = blockDim.x >> 5;
    if (warp == 0) {
        v = (lane < nw) ? sh[lane] : (is_max ? -INFINITY : 0.f);
        #pragma unroll
        for (int o = 16; o > 0; o >>= 1) {
            float other = __shfl_down_sync(0xffffffffu, v, o);
            v = is_max ? fmaxf(v, other) : v + other;
        }
        if (lane == 0) sh[0] = v;
    }
    __syncthreads();
    return sh[0];
}

__device__ __forceinline__ float gelu_tanh(float v) {
    float v3 = v * v * v;
    return 0.5f * v * (1.f + tanhf(0.7978845608028654f * (v + 0.044715f * v3)));
}

static __device__ __forceinline__ void split_f16(float v, unsigned short& h, unsigned short& l) {
    __half hb = __float2half_rn(v);
    float r = v - __half2float(hb);
    __half lb = __float2half_rn(r);
    h = *reinterpret_cast<unsigned short*>(&hb);
    l = *reinterpret_cast<unsigned short*>(&lb);
}

// ---------------- elementwise / norm kernels ----------------
__global__ void em_kernel(const float* __restrict__ e, const float* __restrict__ mod,
                          float* __restrict__ em) {
    int i = blockIdx.x * blockDim.x + threadIdx.x;
    if (i < 6 * C_DIM) em[i] = e[i] + mod[i];
}

__global__ void pack3_kernel(const float* __restrict__ a, const float* __restrict__ b,
                             const float* __restrict__ c, float* __restrict__ d) {
    int i = blockIdx.x * blockDim.x + threadIdx.x;
    if (i < C_DIM) d[i] = a[i];
    else if (i < 2 * C_DIM) d[i] = b[i - C_DIM];
    else if (i < 3 * C_DIM) d[i] = c[i - 2 * C_DIM];
}

__global__ void pack2_kernel(const float* __restrict__ a, const float* __restrict__ b,
                             float* __restrict__ d) {
    int i = blockIdx.x * blockDim.x + threadIdx.x;
    if (i < C_DIM) d[i] = a[i];
    else if (i < 2 * C_DIM) d[i] = b[i - C_DIM];
}

// ol may be nullptr (hi-only mode)
__global__ void ln_mod_split_kernel(const float* __restrict__ x, const float* __restrict__ e0,
                                    const float* __restrict__ e1,
                                    unsigned short* __restrict__ oh, unsigned short* __restrict__ ol) {
    __shared__ float sh[32];
    long long row = blockIdx.x;
    const float* xr = x + row * C_DIM;
    float s = 0.f, s2 = 0.f;
    for (int c = threadIdx.x; c < C_DIM; c += blockDim.x) {
        float v = xr[c];
        s += v; s2 += v * v;
    }
    float S  = block_reduce(s,  sh, false);
    float S2 = block_reduce(s2, sh, false);
    float m   = S  * (1.f / C_DIM);
    float var = S2 * (1.f / C_DIM) - m * m;
    float inv = rsqrtf(var + EPS);
    for (int c = threadIdx.x; c < C_DIM; c += blockDim.x) {
        float v = e0[c] + (xr[c] - m) * inv * (1.f + e1[c]);
        unsigned short h, l; split_f16(v, h, l);
        oh[row * C_DIM + c] = h;
        if (ol) ol[row * C_DIM + c] = l;
    }
}

// RMS + RoPE + split (strided input; dl optional)
__global__ void rms_rope_split_kernel(const float* __restrict__ x, int ldx,
                                      const float* __restrict__ w,
                                      const float* __restrict__ freqs,
                                      unsigned short* __restrict__ dh, unsigned short* __restrict__ dl) {
    __shared__ float sh[32];
    int row = blockIdx.x;
    const float* xr = x + (long long)row * ldx;
    float s2 = 0.f;
    for (int c = threadIdx.x; c < C_DIM; c += blockDim.x) {
        float v = xr[c]; s2 += v * v;
    }
    float S2 = block_reduce(s2, sh, false);
    float inv = rsqrtf(S2 * (1.f / C_DIM) + EPS);
    int f  = row / 1200;
    int rm = row % 1200;
    int hh = rm / 40;
    int ww = rm % 40;
    for (int p = threadIdx.x; p < NH * 64; p += blockDim.x) {
        int n = p >> 6, j = p & 63;
        int pos = (j < 22) ? f : ((j < 43) ? hh : ww);
        float cs = freqs[(pos * 64 + j) * 2 + 0];
        float sn = freqs[(pos * 64 + j) * 2 + 1];
        int c = n * HD + 2 * j;
        float a = xr[c] * inv * w[c];
        float b = xr[c + 1] * inv * w[c + 1];
        float o0 = a * cs - b * sn;
        float o1 = a * sn + b * cs;
        unsigned short h0, l0, h1, l1;
        split_f16(o0, h0, l0); split_f16(o1, h1, l1);
        long long o = (long long)row * C_DIM + c;
        dh[o] = h0;
        dh[o + 1] = h1;
        if (dl) { dl[o] = l0; dl[o + 1] = l1; }
    }
}

// RMS + split (strided input; dl optional)
__global__ void rms_split_kernel(const float* __restrict__ x, int ldx,
                                 const float* __restrict__ w,
                                 unsigned short* __restrict__ dh, unsigned short* __restrict__ dl) {
    __shared__ float sh[32];
    long long row = blockIdx.x;
    const float* xr = x + row * ldx;
    float s2 = 0.f;
    for (int c = threadIdx.x; c < C_DIM; c += blockDim.x) {
        float v = xr[c]; s2 += v * v;
    }
    float S2 = block_reduce(s2, sh, false);
    float inv = rsqrtf(S2 * (1.f / C_DIM) + EPS);
    for (int c = threadIdx.x; c < C_DIM; c += blockDim.x) {
        float v = xr[c] * inv * w[c];
        unsigned short h, l; split_f16(v, h, l);
        dh[row * C_DIM + c] = h;
        if (dl) dl[row * C_DIM + c] = l;
    }
}

__global__ void conv_split_kernel(const float* __restrict__ src, long long n,
                                  unsigned short* __restrict__ dh, unsigned short* __restrict__ dl) {
    long long i = (long long)blockIdx.x * blockDim.x + threadIdx.x;
    if (i < n) {
        unsigned short h, l; split_f16(src[i], h, l);
        dh[i] = h; dl[i] = l;
    }
}

// [R, Ccol] fp32 (row stride lds) -> [Ccol, R] fp16 HI ONLY
__global__ void transpose_h_kernel(const float* __restrict__ src, int R, int Ccol, int lds,
                                   unsigned short* __restrict__ dh) {
    __shared__ float tile[32][33];
    int bx = blockIdx.x, by = blockIdx.y;
    int tx = threadIdx.x, ty = threadIdx.y;  // 32 x 8
    #pragma unroll
    for (int i = 0; i < 4; i++) {
        int r = by * 32 + ty + i * 8;
        tile[ty + i * 8][tx] = src[(long long)r * lds + bx * 32 + tx];
    }
    __syncthreads();
    #pragma unroll
    for (int i = 0; i < 4; i++) {
        int ro = bx * 32 + ty + i * 8;
        int co = by * 32 + tx;
        __half hv = __float2half_rn(tile[tx][ty + i * 8]);
        dh[(long long)ro * R + co] = *reinterpret_cast<unsigned short*>(&hv);
    }
}

// softmax over fp16 scores, IN PLACE: writes unnormalized exp (fp16) + 1/sum
__global__ void softmax_rowinv_h_kernel(unsigned short* __restrict__ sp, int lk,
                                        float* __restrict__ rinv) {
    __shared__ float sh[32];
    long long row = blockIdx.x;
    unsigned short* p = sp + row * (long long)lk;
    float r[10];
    int n = 0;
    float mx = -INFINITY;
    for (int i = threadIdx.x; i < lk; i += blockDim.x) {
        unsigned short u = p[i];
        float v = __half2float(*reinterpret_cast<__half*>(&u));
        r[n++] = v;
        mx = fmaxf(mx, v);
    }
    mx = block_reduce(mx, sh, true);
    float sum = 0.f;
    n = 0;
    for (int i = threadIdx.x; i < lk; i += blockDim.x) {
        float e = __expf(r[n++] - mx);
        sum += e;
        __half hv = __float2half_rn(e);
        p[i] = *reinterpret_cast<unsigned short*>(&hv);
    }
    sum = block_reduce(sum, sh, false);
    if (threadIdx.x == 0) rinv[row] = 1.f / sum;
}

__global__ void residual_mul_conv_kernel(const float* __restrict__ xin, const float* __restrict__ t,
                                         const float* __restrict__ ecol, float* __restrict__ out,
                                         unsigned short* __restrict__ oh, unsigned short* __restrict__ ol) {
    long long i = (long long)blockIdx.x * blockDim.x + threadIdx.x;
    if (i < (long long)L_Q * C_DIM) {
        float v = xin[i] + t[i] * ecol[i % C_DIM];
        out[i] = v;
        unsigned short h, l; split_f16(v, h, l);
        oh[i] = h; ol[i] = l;
    }
}

__global__ void add_inplace_kernel(float* __restrict__ x, const float* __restrict__ t) {
    long long i = (long long)blockIdx.x * blockDim.x + threadIdx.x;
    if (i < (long long)L_Q * C_DIM) x[i] += t[i];
}

__global__ void addmul_inplace_kernel(float* __restrict__ x, const float* __restrict__ t,
                                      const float* __restrict__ ecol) {
    long long i = (long long)blockIdx.x * blockDim.x + threadIdx.x;
    if (i < (long long)L_Q * C_DIM) x[i] += t[i] * ecol[i % C_DIM];
}

// ---------------- common GEMM asm helpers ----------------
static __device__ __forceinline__ uint32_t smem_u32(const void* p) {
    uint32_t r;
    asm("{ .reg .u64 t; cvta.to.shared.u64 t, %1; cvt.u32.u64 %0, t; }" : "=r"(r) : "l"(p));
    return r;
}
static __device__ __forceinline__ void cpa16(uint32_t s, const void* g, uint32_t sz) {
    asm volatile("cp.async.cg.shared.global [%0], [%1], 16, %2;" :: "r"(s), "l"(g), "r"(sz));
}
static __device__ __forceinline__ void cpa_commit() {
    asm volatile("cp.async.commit_group;");
}
static __device__ __forceinline__ void cpa_wait1() {
    asm volatile("cp.async.wait_group 1;");
}
static __device__ __forceinline__ void cpa_wait2() {
    asm volatile("cp.async.wait_group 2;");
}
static __device__ __forceinline__ void ldm_x4(uint32_t* r, uint32_t addr) {
    asm volatile("ldmatrix.sync.aligned.m8n8.x4.shared.b16 {%0,%1,%2,%3}, [%4];"
                 : "=r"(r[0]), "=r"(r[1]), "=r"(r[2]), "=r"(r[3]) : "r"(addr));
}
static __device__ __forceinline__ void mma16816(float* c, const uint32_t* a, uint32_t b0, uint32_t b1) {
    asm volatile("mma.sync.aligned.m16n8k16.row.col.f32.f16.f16.f32 "
                 "{%0,%1,%2,%3}, {%4,%5,%6,%7}, {%8,%9}, {%0,%1,%2,%3};"
                 : "+f"(c[0]), "+f"(c[1]), "+f"(c[2]), "+f"(c[3])
                 : "r"(a[0]), "r"(a[1]), "r"(a[2]), "r"(a[3]), "r"(b0), "r"(b1));
}
// 64B-row-pair swizzled smem addr for (row, ch 0..3); conflict-free ldmatrix
static __device__ __forceinline__ uint32_t saddr(int row, int ch) {
    return (uint32_t)(((row >> 1) << 7) +
                      (((((row & 1) << 2) | ch) ^ ((row >> 1) & 3)) << 4));
}

// =====================================================================
// WIDE GEMM: 128x256x32, warp tile 64x64, 4-stage cp.async, N>128.
//   Products: Ah*Bh always; +Al*Bh if Al; +Ah*Bl if Bl.
// =====================================================================
#define W_STG 49152
#define W_SA_H 0
#define W_SA_L 8192
#define W_SB_H 16384
#define W_SB_L 32768
#define W_SMEM (4 * W_STG)

__global__ void __launch_bounds__(256, 1)
hgemmw_kernel(const unsigned short* __restrict__ Ah, const unsigned short* __restrict__ Al,
              int lda, long long sAz,
              const unsigned short* __restrict__ Bh, const unsigned short* __restrict__ Bl,
              int ldb, long long sBz,
              float* __restrict__ Cf, unsigned short* __restrict__ Ch, unsigned short* __restrict__ Cl,
              int ldc, long long sCz,
              const float* __restrict__ rowScale,
              int M, int N, int K,
              const float* __restrict__ bias, float scale, int act) {
    extern __shared__ char smem[];
    uint32_t sbase = smem_u32(smem);

    int tid = threadIdx.x, lane = tid & 31, warp = tid >> 5;
    int wm = warp & 1, wn = warp >> 1;
    const bool useAl = (Al != nullptr);
    const bool useBl = (Bl != nullptr);

    long long zz = blockIdx.z;
    Ah += zz * sAz; if (useAl) Al += zz * sAz;
    Bh += zz * sBz; if (useBl) Bl += zz * sBz;
    if (Cf) Cf += zz * sCz;
    if (Ch) Ch += zz * sCz;
    if (Cl) Cl += zz * sCz;
    if (rowScale) rowScale += zz * M;

    int bm = blockIdx.y * 128;
    int bn = blockIdx.x * 256;
    int mRem = M - bm; if (mRem > 128) mRem = 128;
    int nRem = N - bn; if (nRem > 256) nRem = 256;

    int nch = K >> 5;

    int rowA0 = tid >> 2, ch0 = tid & 3;
    uint32_t soA0 = saddr(rowA0, ch0);
    long long gA0 = (long long)(bm + rowA0) * lda + ch0 * 8;
    long long gB0 = (long long)(bn + rowA0) * ldb + ch0 * 8;
    uint32_t szA[2], szB[4];
    #pragma unroll
    for (int i = 0; i < 2; i++) szA[i] = (rowA0 + 64 * i < mRem) ? 16u : 0u;
    #pragma unroll
    for (int i = 0; i < 4; i++) szB[i] = (rowA0 + 64 * i < nRem) ? 16u : 0u;
    long long ldax = (long long)lda * 64, ldbx = (long long)ldb * 64;

    auto loadStage = [&](int c) {
        uint32_t sb = sbase + (uint32_t)((c & 3) * W_STG);
        long long k0 = (long long)(c << 5);
        #pragma unroll
        for (int i = 0; i < 2; i++) {
            cpa16(sb + W_SA_H + soA0 + i * 4096u, Ah + gA0 + i * ldax + k0, szA[i]);
            if (useAl)
                cpa16(sb + W_SA_L + soA0 + i * 4096u, Al + gA0 + i * ldax + k0, szA[i]);
        }
        #pragma unroll
        for (int i = 0; i < 4; i++)
            cpa16(sb + W_SB_H + soA0 + i * 4096u, Bh + gB0 + i * ldbx + k0, szB[i]);
        if (useBl) {
            #pragma unroll
            for (int i = 0; i < 4; i++)
                cpa16(sb + W_SB_L + soA0 + i * 4096u, Bl + gB0 + i * ldbx + k0, szB[i]);
        }
    };

    int frow = lane & 15, fhalf = lane >> 4;
    uint32_t a_rt[4]; int a_sw[4], a_s[4];
    #pragma unroll
    for (int mi = 0; mi < 4; mi++) {
        int row = wm * 64 + mi * 16 + frow;
        a_rt[mi] = (uint32_t)((row >> 1) << 7);
        a_sw[mi] = (row & 1) << 2;
        a_s[mi]  = (row >> 1) & 3;
    }
    uint32_t b_rt[4]; int b_sw[4], b_s[4];
    #pragma unroll
    for (int nj = 0; nj < 4; nj++) {
        int row = wn * 64 + nj * 16 + frow;
        b_rt[nj] = (uint32_t)((row >> 1) << 7);
        b_sw[nj] = (row & 1) << 2;
        b_s[nj]  = (row >> 1) & 3;
    }

    float acc[4][8][4];
    #pragma unroll
    for (int mi = 0; mi < 4; mi++)
        #pragma unroll
        for (int ni = 0; ni < 8; ni++)
            #pragma unroll
            for (int q = 0; q < 4; q++) acc[mi][ni][q] = 0.f;

    loadStage(0); cpa_commit();
    if (nch > 1) loadStage(1);
    cpa_commit();
    if (nch > 2) loadStage(2);
    cpa_commit();

    for (int c = 0; c < nch; c++) {
        cpa_wait2();
        __syncthreads();
        uint32_t sb = sbase + (uint32_t)((c & 3) * W_STG);

        #pragma unroll
        for (int k16 = 0; k16 < 2; k16++) {
            int chl = k16 * 2 + fhalf;
            uint32_t bH[4][4], bL[4][4];
            #pragma unroll
            for (int nj = 0; nj < 4; nj++) {
                uint32_t off = b_rt[nj] + (uint32_t)(((b_sw[nj] | chl) ^ b_s[nj]) << 4);
                ldm_x4(bH[nj], sb + W_SB_H + off);
                if (useBl) ldm_x4(bL[nj], sb + W_SB_L + off);
            }
            #pragma unroll
            for (int mi = 0; mi < 4; mi++) {
                uint32_t aH[4], aL[4];
                uint32_t off = a_rt[mi] + (uint32_t)(((a_sw[mi] | chl) ^ a_s[mi]) << 4);
                ldm_x4(aH, sb + W_SA_H + off);
                if (useAl) ldm_x4(aL, sb + W_SA_L + off);
                #pragma unroll
                for (int nj = 0; nj < 4; nj++) {
                    mma16816(acc[mi][nj*2+0], aH, bH[nj][0], bH[nj][2]);
                    mma16816(acc[mi][nj*2+1], aH, bH[nj][1], bH[nj][3]);
                    if (useAl) {
                        mma16816(acc[mi][nj*2+0], aL, bH[nj][0], bH[nj][2]);
                        mma16816(acc[mi][nj*2+1], aL, bH[nj][1], bH[nj][3]);
                    }
                    if (useBl) {
                        mma16816(acc[mi][nj*2+0], aH, bL[nj][0], bL[nj][2]);
                        mma16816(acc[mi][nj*2+1], aH, bL[nj][1], bL[nj][3]);
                    }
                }
            }
        }
        if (c + 3 < nch) loadStage(c + 3);
        cpa_commit();
    }

    int row0 = lane >> 2;
    int col0 = (lane & 3) * 2;
    #pragma unroll
    for (int mi = 0; mi < 4; mi++) {
        #pragma unroll
        for (int ni = 0; ni < 8; ni++) {
            int gn = bn + wn * 64 + (ni >> 1) * 16 + (ni & 1) * 8 + col0;
            if (gn >= N) continue;
            float b0 = 0.f, b1 = 0.f;
            if (bias) { b0 = bias[gn]; b1 = bias[gn + 1]; }
            float* cc = acc[mi][ni];
            #pragma unroll
            for (int half = 0; half < 2; half++) {
                int gm = bm + wm * 64 + mi * 16 + row0 + half * 8;
                if (gm >= M) continue;
                float rs = rowScale ? rowScale[gm] : 1.f;
                float v0 = cc[half * 2 + 0] * scale * rs + b0;
                float v1 = cc[half * 2 + 1] * scale * rs + b1;
                if (act == 1) { v0 = gelu_tanh(v0); v1 = gelu_tanh(v1); }
                long long o = (long long)gm * ldc + gn;
                if (Cf) *reinterpret_cast<float2*>(Cf + o) = make_float2(v0, v1);
                if (Ch) {
                    unsigned short h0, l0, h1, l1;
                    split_f16(v0, h0, l0); split_f16(v1, h1, l1);
                    *reinterpret_cast<ushort2*>(Ch + o) = make_ushort2(h0, h1);
                    if (Cl) *reinterpret_cast<ushort2*>(Cl + o) = make_ushort2(l0, l1);
                }
            }
        }
    }
}

// =====================================================================
// NARROW GEMM (N<=128): 128x128x32, 3-stage, 2 CTAs/SM.
// =====================================================================
#define STAGES 3
#define STG 24576
#define SA_H 0
#define SA_L 8192
#define SB_H 16384
#define HG_SMEM (STAGES * STG)

__global__ void __launch_bounds__(256, 2)
hgemm3_kernel(const unsigned short* __restrict__ Ah, const unsigned short* __restrict__ Al,
              int lda, long long sAz,
              const unsigned short* __restrict__ Bh,
              int ldb, long long sBz,
              float* __restrict__ Cf, unsigned short* __restrict__ Ch, unsigned short* __restrict__ Cl,
              int ldc, long long sCz,
              const float* __restrict__ rowScale,
              int M, int N, int K,
              const float* __restrict__ bias, float scale, int act) {
    extern __shared__ char smem[];
    uint32_t sbase = smem_u32(smem);

    int tid = threadIdx.x, lane = tid & 31, warp = tid >> 5;
    int wm = warp & 1, wn = warp >> 1;
    const bool useAl = (Al != nullptr);

    long long zz = blockIdx.z;
    Ah += zz * sAz; if (useAl) Al += zz * sAz;
    Bh += zz * sBz;
    if (Cf) Cf += zz * sCz;
    if (Ch) Ch += zz * sCz;
    if (Cl) Cl += zz * sCz;
    if (rowScale) rowScale += zz * M;

    int bm = blockIdx.y * 128;
    int bn = blockIdx.x * 128;
    int mRem = M - bm; if (mRem > 128) mRem = 128;
    int nRem = N - bn; if (nRem > 128) nRem = 128;

    int nch = K >> 5;

    uint32_t so[2]; long long gA[2], gB[2]; uint32_t szA[2], szB[2];
    #pragma unroll
    for (int i = 0; i < 2; i++) {
        int idx = tid + i * 256;
        int row = idx >> 2, ch = idx & 3;
        so[i]  = saddr(row, ch);
        gA[i]  = (long long)(bm + row) * lda + ch * 8;
        gB[i]  = (long long)(bn + row) * ldb + ch * 8;
        szA[i] = (row < mRem) ? 16u : 0u;
        szB[i] = (row < nRem) ? 16u : 0u;
    }

    int frow = lane & 15, fhalf = lane >> 4;
    uint32_t a_rt[4]; int a_sw[4], a_s[4];
    #pragma unroll
    for (int mi = 0; mi < 4; mi++) {
        int row = wm * 64 + mi * 16 + frow;
        a_rt[mi] = (uint32_t)((row >> 1) << 7);
        a_sw[mi] = (row & 1) << 2;
        a_s[mi]  = (row >> 1) & 3;
    }
    uint32_t b_rt[2]; int b_sw[2], b_s[2];
    #pragma unroll
    for (int nj = 0; nj < 2; nj++) {
        int row = wn * 32 + nj * 16 + frow;
        b_rt[nj] = (uint32_t)((row >> 1) << 7);
        b_sw[nj] = (row & 1) << 2;
        b_s[nj]  = (row >> 1) & 3;
    }

    float acc[4][4][4];
    #pragma unroll
    for (int mi = 0; mi < 4; mi++)
        #pragma unroll
        for (int ni = 0; ni < 4; ni++)
            #pragma unroll
            for (int q = 0; q < 4; q++) acc[mi][ni][q] = 0.f;

    auto loadStage = [&](int c) {
        uint32_t sb = sbase + (uint32_t)((c % STAGES) * STG);
        long long k0 = (long long)(c << 5);
        #pragma unroll
        for (int i = 0; i < 2; i++) {
            cpa16(sb + SA_H + so[i], Ah + gA[i] + k0, szA[i]);
            if (useAl) cpa16(sb + SA_L + so[i], Al + gA[i] + k0, szA[i]);
            cpa16(sb + SB_H + so[i], Bh + gB[i] + k0, szB[i]);
        }
    };

    loadStage(0); cpa_commit();
    if (nch > 1) loadStage(1);
    cpa_commit();

    for (int c = 0; c < nch; c++) {
        cpa_wait1();
        __syncthreads();
        uint32_t sb = sbase + (uint32_t)((c % STAGES) * STG);

        #pragma unroll
        for (int k16 = 0; k16 < 2; k16++) {
            int chl = k16 * 2 + fhalf;
            uint32_t bH[2][4];
            #pragma unroll
            for (int nj = 0; nj < 2; nj++) {
                uint32_t off = b_rt[nj] + (uint32_t)(((b_sw[nj] | chl) ^ b_s[nj]) << 4);
                ldm_x4(bH[nj], sb + SB_H + off);
            }
            #pragma unroll
            for (int mi = 0; mi < 4; mi++) {
                uint32_t aH[4], aL[4];
                uint32_t off = a_rt[mi] + (uint32_t)(((a_sw[mi] | chl) ^ a_s[mi]) << 4);
                ldm_x4(aH, sb + SA_H + off);
                if (useAl) ldm_x4(aL, sb + SA_L + off);
                #pragma unroll
                for (int nj = 0; nj < 2; nj++) {
                    mma16816(acc[mi][nj*2+0], aH, bH[nj][0], bH[nj][2]);
                    mma16816(acc[mi][nj*2+1], aH, bH[nj][1], bH[nj][3]);
                    if (useAl) {
                        mma16816(acc[mi][nj*2+0], aL, bH[nj][0], bH[nj][2]);
                        mma16816(acc[mi][nj*2+1], aL, bH[nj][1], bH[nj][3]);
                    }
                }
            }
        }
        if (c + 2 < nch) loadStage(c + 2);
        cpa_commit();
    }

    int row0 = lane >> 2;
    int col0 = (lane & 3) * 2;
    #pragma unroll
    for (int mi = 0; mi < 4; mi++) {
        #pragma unroll
        for (int ni = 0; ni < 4; ni++) {
            int gn = bn + wn * 32 + ni * 8 + col0;
            if (gn >= N) continue;
            float b0 = 0.f, b1 = 0.f;
            if (bias) { b0 = bias[gn]; b1 = bias[gn + 1]; }
            float* cc = acc[mi][ni];
            #pragma unroll
            for (int half = 0; half < 2; half++) {
                int gm = bm + wm * 64 + mi * 16 + row0 + half * 8;
                if (gm >= M) continue;
                float rs = rowScale ? rowScale[gm] : 1.f;
                float v0 = cc[half * 2 + 0] * scale * rs + b0;
                float v1 = cc[half * 2 + 1] * scale * rs + b1;
                if (act == 1) { v0 = gelu_tanh(v0); v1 = gelu_tanh(v1); }
                long long o = (long long)gm * ldc + gn;
                if (Cf) *reinterpret_cast<float2*>(Cf + o) = make_float2(v0, v1);
                if (Ch) {
                    unsigned short h0, l0, h1, l1;
                    split_f16(v0, h0, l0); split_f16(v1, h1, l1);
                    *reinterpret_cast<ushort2*>(Ch + o) = make_ushort2(h0, h1);
                    if (Cl) *reinterpret_cast<ushort2*>(Cl + o) = make_ushort2(l0, l1);
                }
            }
        }
    }
}

// ---------------- host ----------------
static void hg(const unsigned short* Ah, const unsigned short* Al, int lda, long long sAz,
               const unsigned short* Bh, const unsigned short* Bl, int ldb, long long sBz,
               float* Cf, unsigned short* Ch, unsigned short* Cl, int ldc, long long sCz,
               const float* rowScale,
               int M, int N, int K, int Z, const float* bias, float scale, int act) {
    if (N > 128) {
        dim3 grid((N + 255) / 256, (M + 127) / 128, Z);
        hgemmw_kernel<<<grid, 256, W_SMEM>>>(Ah, Al, lda, sAz, Bh, Bl, ldb, sBz,
                                             Cf, Ch, Cl, ldc, sCz, rowScale,
                                             M, N, K, bias, scale, act);
    } else {
        dim3 grid(1, (M + 127) / 128, Z);
        hgemm3_kernel<<<grid, 256, HG_SMEM>>>(Ah, Al, lda, sAz, Bh, ldb, sBz,
                                              Cf, Ch, Cl, ldc, sCz, rowScale,
                                              M, N, K, bias, scale, act);
    }
}

static void trh(const float* src, int R, int Ccol, int lds, unsigned short* dh) {
    dim3 grid(Ccol / 32, R / 32);
    transpose_h_kernel<<<grid, dim3(32, 8)>>>(src, R, Ccol, lds, dh);
}

extern "C" void kernel_launch(void* const* d_in, const int* in_sizes, int n_in,
                              void* d_out, int out_size) {
    const float* x        = (const float*)d_in[0];
    const float* e        = (const float*)d_in[1];
    const float* context  = (const float*)d_in[2];
    const float* freqs    = (const float*)d_in[3];
    const float* modulation = (const float*)d_in[7];
    const float* sa_q_w = (const float*)d_in[8];
    const float* sa_q_b = (const float*)d_in[9];
    const float* sa_k_w = (const float*)d_in[10];
    const float* sa_k_b = (const float*)d_in[11];
    const float* sa_v_w = (const float*)d_in[12];
    const float* sa_v_b = (const float*)d_in[13];
    const float* sa_o_w = (const float*)d_in[14];
    const float* sa_o_b = (const float*)d_in[15];
    const float* sa_nq_w = (const float*)d_in[16];
    const float* sa_nk_w = (const float*)d_in[17];
    const float* ca_q_w = (const float*)d_in[18];
    const float* ca_q_b = (const float*)d_in[19];
    const float* ca_k_w = (const float*)d_in[20];
    const float* ca_k_b = (const float*)d_in[21];
    const float* ca_v_w = (const float*)d_in[22];
    const float* ca_v_b = (const float*)d_in[23];
    const float* ca_o_w = (const float*)d_in[24];
    const float* ca_o_b = (const float*)d_in[25];
    const float* ca_nq_w = (const float*)d_in[26];
    const float* ca_nk_w = (const float*)d_in[27];
    const float* ffn_w1 = (const float*)d_in[28];
    const float* ffn_b1 = (const float*)d_in[29];
    const float* ffn_w2 = (const float*)d_in[30];
    const float* ffn_b2 = (const float*)d_in[31];
    float* out = (float*)d_out;

    cudaFuncSetAttribute(hgemm3_kernel,
                         cudaFuncAttributeMaxDynamicSharedMemorySize, HG_SMEM);
    cudaFuncSetAttribute(hgemmw_kernel,
                         cudaFuncAttributeMaxDynamicSharedMemorySize, W_SMEM);

    float *em, *q, *t, *s, *b3, *rinv;
    unsigned short *hh, *hl, *qh, *ql, *kh, *vth, *yh, *yl;
    unsigned short *oh, *ol, *cxh, *cxl, *ph, *ffh, *wh;
    cudaGetSymbolAddress((void**)&em, g_em);
    cudaGetSymbolAddress((void**)&q,  g_q);
    cudaGetSymbolAddress((void**)&t,  g_t);
    cudaGetSymbolAddress((void**)&s,  g_s);
    cudaGetSymbolAddress((void**)&b3, g_b3);
    cudaGetSymbolAddress((void**)&rinv, g_rinv);
    cudaGetSymbolAddress((void**)&hh, g_hh);  cudaGetSymbolAddress((void**)&hl, g_hl);
    cudaGetSymbolAddress((void**)&qh, g_qh);  cudaGetSymbolAddress((void**)&ql, g_ql);
    cudaGetSymbolAddress((void**)&kh, g_kh);
    cudaGetSymbolAddress((void**)&vth, g_vth);
    cudaGetSymbolAddress((void**)&yh, g_yh);  cudaGetSymbolAddress((void**)&yl, g_yl);
    cudaGetSymbolAddress((void**)&oh, g_oh);  cudaGetSymbolAddress((void**)&ol, g_ol);
    cudaGetSymbolAddress((void**)&cxh, g_cxh); cudaGetSymbolAddress((void**)&cxl, g_cxl);
    cudaGetSymbolAddress((void**)&ph, g_ph);
    cudaGetSymbolAddress((void**)&ffh, g_ffh);
    cudaGetSymbolAddress((void**)&wh, g_wh);

    const float ascale = 0.08838834764831845f;   // 1/sqrt(128)
    const long long LC = (long long)L_Q * C_DIM;
    int eltBlocks = (int)((LC + 255) / 256);

    em_kernel<<<(6 * C_DIM + 255) / 256, 256>>>(e, modulation, em);

    // ================= self attention =================
    ln_mod_split_kernel<<<L_Q, 256>>>(x, em + 0 * C_DIM, em + 1 * C_DIM, hh, hl);
    trh(sa_q_w, C_DIM, C_DIM, C_DIM, wh);
    trh(sa_k_w, C_DIM, C_DIM, C_DIM, wh + (long long)C_DIM * C_DIM);
    trh(sa_v_w, C_DIM, C_DIM, C_DIM, wh + 2LL * C_DIM * C_DIM);
    pack3_kernel<<<(3 * C_DIM + 255) / 256, 256>>>(sa_q_b, sa_k_b, sa_v_b, b3);
    float* qkv = s;   // [2400, 4608] fp32
    hg(hh, hl, C_DIM, 0, wh, nullptr, C_DIM, 0, qkv, nullptr, nullptr, 3 * C_DIM, 0,
       nullptr, L_Q, 3 * C_DIM, C_DIM, 1, b3, 1.f, 0);
    rms_rope_split_kernel<<<L_Q, 256>>>(qkv + 0 * C_DIM, 3 * C_DIM, sa_nq_w, freqs, qh, ql);
    rms_rope_split_kernel<<<L_Q, 256>>>(qkv + 1 * C_DIM, 3 * C_DIM, sa_nk_w, freqs, kh, nullptr);
    trh(qkv + 2 * C_DIM, L_Q, C_DIM, 3 * C_DIM, vth);      // V^T [1536, 2400]
    // scores: 2-product (q split, k hi), fp16 output straight to ph
    hg(qh, ql, C_DIM, HD, kh, nullptr, C_DIM, HD, nullptr, ph, nullptr,
       L_Q, (long long)L_Q * L_Q, nullptr, L_Q, L_Q, HD, NH, nullptr, ascale, 0);
    softmax_rowinv_h_kernel<<<NH * L_Q, 256>>>(ph, L_Q, rinv);
    // PV: 1-product, row-scaled by 1/sum in epilogue
    hg(ph, nullptr, L_Q, (long long)L_Q * L_Q, vth, nullptr, L_Q, (long long)HD * L_Q,
       nullptr, yh, yl, C_DIM, HD, rinv, L_Q, HD, L_Q, NH, nullptr, 1.f, 0);
    trh(sa_o_w, C_DIM, C_DIM, C_DIM, wh);
    hg(yh, yl, C_DIM, 0, wh, nullptr, C_DIM, 0, t, nullptr, nullptr, C_DIM, 0,
       nullptr, L_Q, C_DIM, C_DIM, 1, sa_o_b, 1.f, 0);
    residual_mul_conv_kernel<<<eltBlocks, 256>>>(x, t, em + 2 * C_DIM, out, oh, ol);

    // ================= cross attention =================
    trh(ca_q_w, C_DIM, C_DIM, C_DIM, wh);
    hg(oh, ol, C_DIM, 0, wh, nullptr, C_DIM, 0, q, nullptr, nullptr, C_DIM, 0,
       nullptr, L_Q, C_DIM, C_DIM, 1, ca_q_b, 1.f, 0);
    rms_split_kernel<<<L_Q, 256>>>(q, C_DIM, ca_nq_w, qh, ql);
    conv_split_kernel<<<(int)(((long long)L_KV * C_DIM + 255) / 256), 256>>>(
        context, (long long)L_KV * C_DIM, cxh, cxl);
    trh(ca_k_w, C_DIM, C_DIM, C_DIM, wh);
    trh(ca_v_w, C_DIM, C_DIM, C_DIM, wh + (long long)C_DIM * C_DIM);
    pack2_kernel<<<(2 * C_DIM + 255) / 256, 256>>>(ca_k_b, ca_v_b, b3);
    float* kvbuf = s;   // [512, 3072] fp32
    hg(cxh, cxl, C_DIM, 0, wh, nullptr, C_DIM, 0, kvbuf, nullptr, nullptr, 2 * C_DIM, 0,
       nullptr, L_KV, 2 * C_DIM, C_DIM, 1, b3, 1.f, 0);
    rms_split_kernel<<<L_KV, 256>>>(kvbuf + 0 * C_DIM, 2 * C_DIM, ca_nk_w, kh, nullptr);
    trh(kvbuf + 1 * C_DIM, L_KV, C_DIM, 2 * C_DIM, vth);   // V^T [1536, 512]
    hg(qh, ql, C_DIM, HD, kh, nullptr, C_DIM, HD, nullptr, ph, nullptr,
       L_KV, (long long)L_Q * L_KV, nullptr, L_Q, L_KV, HD, NH, nullptr, ascale, 0);
    softmax_rowinv_h_kernel<<<NH * L_Q, 256>>>(ph, L_KV, rinv);
    hg(ph, nullptr, L_KV, (long long)L_Q * L_KV, vth, nullptr, L_KV, (long long)HD * L_KV,
       nullptr, yh, yl, C_DIM, HD, rinv, L_Q, HD, L_KV, NH, nullptr, 1.f, 0);
    trh(ca_o_w, C_DIM, C_DIM, C_DIM, wh);
    hg(yh, yl, C_DIM, 0, wh, nullptr, C_DIM, 0, t, nullptr, nullptr, C_DIM, 0,
       nullptr, L_Q, C_DIM, C_DIM, 1, ca_o_b, 1.f, 0);
    add_inplace_kernel<<<eltBlocks, 256>>>(out, t);

    // ================= FFN =================
    ln_mod_split_kernel<<<L_Q, 256>>>(out, em + 3 * C_DIM, em + 4 * C_DIM, hh, nullptr);
    trh(ffn_w1, C_DIM, FF_DIM, FF_DIM, wh);
    hg(hh, nullptr, C_DIM, 0, wh, nullptr, C_DIM, 0, nullptr, ffh, nullptr, FF_DIM, 0,
       nullptr, L_Q, FF_DIM, C_DIM, 1, ffn_b1, 1.f, 1);   // 1-product + GELU
    trh(ffn_w2, FF_DIM, C_DIM, C_DIM, wh);
    hg(ffh, nullptr, FF_DIM, 0, wh, nullptr, FF_DIM, 0, t, nullptr, nullptr, C_DIM, 0,
       nullptr, L_Q, C_DIM, FF_DIM, 1, ffn_b2, 1.f, 0);   // 1-product
    addmul_inplace_kernel<<<eltBlocks, 256>>>(out, t, em + 5 * C_DIM);
}

// round 11
// speedup vs baseline: 1.6403x; 1.4104x over previous
#include <cuda_runtime.h>
#include <cuda_fp16.h>
#include <stdint.h>
#include <math.h>

// Problem constants
#define C_DIM 1536
#define L_Q   2400
#define L_KV  512
#define NH    12
#define HD    128
#define FF_DIM 8960
#define EPS   1e-6f

// ---------------- device scratch ----------------
__device__ __align__(256) float g_em[6 * C_DIM];
__device__ __align__(256) float g_q [L_Q * C_DIM];
__device__ __align__(256) float g_t [L_Q * C_DIM];
__device__ __align__(256) float g_s [L_Q * 3 * C_DIM];    // fused-proj fp32 scratch
__device__ __align__(256) float g_b3[3 * C_DIM];
__device__ __align__(256) float g_rinv[NH * L_Q];
__device__ __align__(256) unsigned short g_hh[L_Q * C_DIM], g_hl[L_Q * C_DIM];
__device__ __align__(256) unsigned short g_qh[L_Q * C_DIM], g_ql[L_Q * C_DIM];
__device__ __align__(256) unsigned short g_kh[L_Q * C_DIM];
__device__ __align__(256) unsigned short g_vth[C_DIM * L_Q];
__device__ __align__(256) unsigned short g_yh[L_Q * C_DIM], g_yl[L_Q * C_DIM];
__device__ __align__(256) unsigned short g_oh[L_Q * C_DIM], g_ol[L_Q * C_DIM];
__device__ __align__(256) unsigned short g_cxh[L_KV * C_DIM], g_cxl[L_KV * C_DIM];
__device__ __align__(256) unsigned short g_ph[NH * L_Q * L_Q];
__device__ __align__(256) unsigned short g_ffh[L_Q * FF_DIM];
__device__ __align__(256) unsigned short g_wh[FF_DIM * C_DIM];

// ---------------- helpers ----------------
__device__ __forceinline__ float block_reduce(float v, float* sh, bool is_max) {
    __syncthreads();
    int lane = threadIdx.x & 31, warp = threadIdx.x >> 5;
    #pragma unroll
    for (int o = 16; o > 0; o >>= 1) {
        float other = __shfl_down_sync(0xffffffffu, v, o);
        v = is_max ? fmaxf(v, other) : v + other;
    }
    if (lane == 0) sh[warp] = v;
    __syncthreads();
    int nw = blockDim.x >> 5;
    if (warp == 0) {
        v = (lane < nw) ? sh[lane] : (is_max ? -INFINITY : 0.f);
        #pragma unroll
        for (int o = 16; o > 0; o >>= 1) {
            float other = __shfl_down_sync(0xffffffffu, v, o);
            v = is_max ? fmaxf(v, other) : v + other;
        }
        if (lane == 0) sh[0] = v;
    }
    __syncthreads();
    return sh[0];
}

__device__ __forceinline__ float gelu_tanh(float v) {
    float v3 = v * v * v;
    return 0.5f * v * (1.f + tanhf(0.7978845608028654f * (v + 0.044715f * v3)));
}

static __device__ __forceinline__ void split_f16(float v, unsigned short& h, unsigned short& l) {
    __half hb = __float2half_rn(v);
    float r = v - __half2float(hb);
    __half lb = __float2half_rn(r);
    h = *reinterpret_cast<unsigned short*>(&hb);
    l = *reinterpret_cast<unsigned short*>(&lb);
}

// ---------------- elementwise / norm kernels ----------------
__global__ void em_kernel(const float* __restrict__ e, const float* __restrict__ mod,
                          float* __restrict__ em) {
    int i = blockIdx.x * blockDim.x + threadIdx.x;
    if (i < 6 * C_DIM) em[i] = e[i] + mod[i];
}

__global__ void pack3_kernel(const float* __restrict__ a, const float* __restrict__ b,
                             const float* __restrict__ c, float* __restrict__ d) {
    int i = blockIdx.x * blockDim.x + threadIdx.x;
    if (i < C_DIM) d[i] = a[i];
    else if (i < 2 * C_DIM) d[i] = b[i - C_DIM];
    else if (i < 3 * C_DIM) d[i] = c[i - 2 * C_DIM];
}

__global__ void pack2_kernel(const float* __restrict__ a, const float* __restrict__ b,
                             float* __restrict__ d) {
    int i = blockIdx.x * blockDim.x + threadIdx.x;
    if (i < C_DIM) d[i] = a[i];
    else if (i < 2 * C_DIM) d[i] = b[i - C_DIM];
}

// ol may be nullptr (hi-only mode)
__global__ void ln_mod_split_kernel(const float* __restrict__ x, const float* __restrict__ e0,
                                    const float* __restrict__ e1,
                                    unsigned short* __restrict__ oh, unsigned short* __restrict__ ol) {
    __shared__ float sh[32];
    long long row = blockIdx.x;
    const float* xr = x + row * C_DIM;
    float s = 0.f, s2 = 0.f;
    for (int c = threadIdx.x; c < C_DIM; c += blockDim.x) {
        float v = xr[c];
        s += v; s2 += v * v;
    }
    float S  = block_reduce(s,  sh, false);
    float S2 = block_reduce(s2, sh, false);
    float m   = S  * (1.f / C_DIM);
    float var = S2 * (1.f / C_DIM) - m * m;
    float inv = rsqrtf(var + EPS);
    for (int c = threadIdx.x; c < C_DIM; c += blockDim.x) {
        float v = e0[c] + (xr[c] - m) * inv * (1.f + e1[c]);
        unsigned short h, l; split_f16(v, h, l);
        oh[row * C_DIM + c] = h;
        if (ol) ol[row * C_DIM + c] = l;
    }
}

// RMS + RoPE + split (strided input; dl optional)
__global__ void rms_rope_split_kernel(const float* __restrict__ x, int ldx,
                                      const float* __restrict__ w,
                                      const float* __restrict__ freqs,
                                      unsigned short* __restrict__ dh, unsigned short* __restrict__ dl) {
    __shared__ float sh[32];
    int row = blockIdx.x;
    const float* xr = x + (long long)row * ldx;
    float s2 = 0.f;
    for (int c = threadIdx.x; c < C_DIM; c += blockDim.x) {
        float v = xr[c]; s2 += v * v;
    }
    float S2 = block_reduce(s2, sh, false);
    float inv = rsqrtf(S2 * (1.f / C_DIM) + EPS);
    int f  = row / 1200;
    int rm = row % 1200;
    int hh = rm / 40;
    int ww = rm % 40;
    for (int p = threadIdx.x; p < NH * 64; p += blockDim.x) {
        int n = p >> 6, j = p & 63;
        int pos = (j < 22) ? f : ((j < 43) ? hh : ww);
        float cs = freqs[(pos * 64 + j) * 2 + 0];
        float sn = freqs[(pos * 64 + j) * 2 + 1];
        int c = n * HD + 2 * j;
        float a = xr[c] * inv * w[c];
        float b = xr[c + 1] * inv * w[c + 1];
        float o0 = a * cs - b * sn;
        float o1 = a * sn + b * cs;
        unsigned short h0, l0, h1, l1;
        split_f16(o0, h0, l0); split_f16(o1, h1, l1);
        long long o = (long long)row * C_DIM + c;
        dh[o] = h0;
        dh[o + 1] = h1;
        if (dl) { dl[o] = l0; dl[o + 1] = l1; }
    }
}

// RMS + split (strided input; dl optional)
__global__ void rms_split_kernel(const float* __restrict__ x, int ldx,
                                 const float* __restrict__ w,
                                 unsigned short* __restrict__ dh, unsigned short* __restrict__ dl) {
    __shared__ float sh[32];
    long long row = blockIdx.x;
    const float* xr = x + row * ldx;
    float s2 = 0.f;
    for (int c = threadIdx.x; c < C_DIM; c += blockDim.x) {
        float v = xr[c]; s2 += v * v;
    }
    float S2 = block_reduce(s2, sh, false);
    float inv = rsqrtf(S2 * (1.f / C_DIM) + EPS);
    for (int c = threadIdx.x; c < C_DIM; c += blockDim.x) {
        float v = xr[c] * inv * w[c];
        unsigned short h, l; split_f16(v, h, l);
        dh[row * C_DIM + c] = h;
        if (dl) dl[row * C_DIM + c] = l;
    }
}

__global__ void conv_split_kernel(const float* __restrict__ src, long long n,
                                  unsigned short* __restrict__ dh, unsigned short* __restrict__ dl) {
    long long i = (long long)blockIdx.x * blockDim.x + threadIdx.x;
    if (i < n) {
        unsigned short h, l; split_f16(src[i], h, l);
        dh[i] = h; dl[i] = l;
    }
}

// [R, Ccol] fp32 (row stride lds) -> [Ccol, R] fp16 HI ONLY
__global__ void transpose_h_kernel(const float* __restrict__ src, int R, int Ccol, int lds,
                                   unsigned short* __restrict__ dh) {
    __shared__ float tile[32][33];
    int bx = blockIdx.x, by = blockIdx.y;
    int tx = threadIdx.x, ty = threadIdx.y;  // 32 x 8
    #pragma unroll
    for (int i = 0; i < 4; i++) {
        int r = by * 32 + ty + i * 8;
        tile[ty + i * 8][tx] = src[(long long)r * lds + bx * 32 + tx];
    }
    __syncthreads();
    #pragma unroll
    for (int i = 0; i < 4; i++) {
        int ro = bx * 32 + ty + i * 8;
        int co = by * 32 + tx;
        __half hv = __float2half_rn(tile[tx][ty + i * 8]);
        dh[(long long)ro * R + co] = *reinterpret_cast<unsigned short*>(&hv);
    }
}

// softmax over fp16 scores, IN PLACE, vectorized uint4 (8 halves):
// writes unnormalized exp (fp16) + 1/sum.  lk % 8 == 0.
__global__ void softmax_rowinv_h_kernel(unsigned short* __restrict__ sp, int lk,
                                        float* __restrict__ rinv) {
    __shared__ float sh[32];
    long long row = blockIdx.x;
    uint4* p = reinterpret_cast<uint4*>(sp + row * (long long)lk);
    int nv = lk >> 3;
    uint4 r[2];
    int cnt = 0;
    float mx = -INFINITY;
    for (int i = threadIdx.x; i < nv; i += blockDim.x) {
        uint4 v = p[i];
        r[cnt++] = v;
        const unsigned short* u = reinterpret_cast<const unsigned short*>(&v);
        #pragma unroll
        for (int j = 0; j < 8; j++) {
            unsigned short us = u[j];
            mx = fmaxf(mx, __half2float(*reinterpret_cast<__half*>(&us)));
        }
    }
    mx = block_reduce(mx, sh, true);
    float sum = 0.f;
    cnt = 0;
    for (int i = threadIdx.x; i < nv; i += blockDim.x) {
        uint4 v = r[cnt++];
        unsigned short* u = reinterpret_cast<unsigned short*>(&v);
        #pragma unroll
        for (int j = 0; j < 8; j++) {
            unsigned short us = u[j];
            float e = __expf(__half2float(*reinterpret_cast<__half*>(&us)) - mx);
            sum += e;
            __half hv = __float2half_rn(e);
            u[j] = *reinterpret_cast<unsigned short*>(&hv);
        }
        p[i] = v;
    }
    sum = block_reduce(sum, sh, false);
    if (threadIdx.x == 0) rinv[row] = 1.f / sum;
}

__global__ void residual_mul_conv_kernel(const float* __restrict__ xin, const float* __restrict__ t,
                                         const float* __restrict__ ecol, float* __restrict__ out,
                                         unsigned short* __restrict__ oh, unsigned short* __restrict__ ol) {
    long long i = (long long)blockIdx.x * blockDim.x + threadIdx.x;
    if (i < (long long)L_Q * C_DIM) {
        float v = xin[i] + t[i] * ecol[i % C_DIM];
        out[i] = v;
        unsigned short h, l; split_f16(v, h, l);
        oh[i] = h; ol[i] = l;
    }
}

__global__ void add_inplace_kernel(float* __restrict__ x, const float* __restrict__ t) {
    long long i = (long long)blockIdx.x * blockDim.x + threadIdx.x;
    if (i < (long long)L_Q * C_DIM) x[i] += t[i];
}

__global__ void addmul_inplace_kernel(float* __restrict__ x, const float* __restrict__ t,
                                      const float* __restrict__ ecol) {
    long long i = (long long)blockIdx.x * blockDim.x + threadIdx.x;
    if (i < (long long)L_Q * C_DIM) x[i] += t[i] * ecol[i % C_DIM];
}

// ---------------- common GEMM asm helpers ----------------
static __device__ __forceinline__ uint32_t smem_u32(const void* p) {
    uint32_t r;
    asm("{ .reg .u64 t; cvta.to.shared.u64 t, %1; cvt.u32.u64 %0, t; }" : "=r"(r) : "l"(p));
    return r;
}
static __device__ __forceinline__ void cpa16(uint32_t s, const void* g, uint32_t sz) {
    asm volatile("cp.async.cg.shared.global [%0], [%1], 16, %2;" :: "r"(s), "l"(g), "r"(sz));
}
static __device__ __forceinline__ void cpa_commit() {
    asm volatile("cp.async.commit_group;");
}
static __device__ __forceinline__ void cpa_wait1() {
    asm volatile("cp.async.wait_group 1;");
}
static __device__ __forceinline__ void ldm_x4(uint32_t* r, uint32_t addr) {
    asm volatile("ldmatrix.sync.aligned.m8n8.x4.shared.b16 {%0,%1,%2,%3}, [%4];"
                 : "=r"(r[0]), "=r"(r[1]), "=r"(r[2]), "=r"(r[3]) : "r"(addr));
}
static __device__ __forceinline__ void mma16816(float* c, const uint32_t* a, uint32_t b0, uint32_t b1) {
    asm volatile("mma.sync.aligned.m16n8k16.row.col.f32.f16.f16.f32 "
                 "{%0,%1,%2,%3}, {%4,%5,%6,%7}, {%8,%9}, {%0,%1,%2,%3};"
                 : "+f"(c[0]), "+f"(c[1]), "+f"(c[2]), "+f"(c[3])
                 : "r"(a[0]), "r"(a[1]), "r"(a[2]), "r"(a[3]), "r"(b0), "r"(b1));
}
// 128B-row swizzled addr: row*128 + ((ch ^ (row&7))<<4), ch 0..7 (proven R5 layout)
static __device__ __forceinline__ uint32_t saddr128(int row, int ch) {
    return (uint32_t)(row * 128 + ((ch ^ (row & 7)) << 4));
}

// =====================================================================
// WIDE GEMM: 128x256x64, warp tile 64x64, 3-stage cp.async (192KB), N>128.
//   Products: Ah*Bh always; +Al*Bh if Al.   K % 64 == 0.
// =====================================================================
#define W_STG 65536
#define W_SA_H 0
#define W_SA_L 16384
#define W_SB_H 32768
#define W_SMEM (3 * W_STG)     // 196608

__global__ void __launch_bounds__(256, 1)
hgemmw_kernel(const unsigned short* __restrict__ Ah, const unsigned short* __restrict__ Al,
              int lda, long long sAz,
              const unsigned short* __restrict__ Bh,
              int ldb, long long sBz,
              float* __restrict__ Cf, unsigned short* __restrict__ Ch, unsigned short* __restrict__ Cl,
              int ldc, long long sCz,
              const float* __restrict__ rowScale,
              int M, int N, int K,
              const float* __restrict__ bias, float scale, int act) {
    extern __shared__ char smem[];
    uint32_t sbase = smem_u32(smem);

    int tid = threadIdx.x, lane = tid & 31, warp = tid >> 5;
    int wm = warp & 1, wn = warp >> 1;   // 2x4 warps, warp tile 64x64
    const bool useAl = (Al != nullptr);

    long long zz = blockIdx.z;
    Ah += zz * sAz; if (useAl) Al += zz * sAz;
    Bh += zz * sBz;
    if (Cf) Cf += zz * sCz;
    if (Ch) Ch += zz * sCz;
    if (Cl) Cl += zz * sCz;
    if (rowScale) rowScale += zz * M;

    int bm = blockIdx.y * 128;
    int bn = blockIdx.x * 256;
    int mRem = M - bm; if (mRem > 128) mRem = 128;
    int nRem = N - bn; if (nRem > 256) nRem = 256;

    int nch = K >> 6;   // K % 64 == 0 for all wide shapes

    // cp.async slots: row0 = tid>>3 (0..31), ch = tid&7; +32 rows per slot step
    int row0 = tid >> 3, ch0 = tid & 7;
    uint32_t so0 = saddr128(row0, ch0);            // +4096 per +32 rows
    long long gA0 = (long long)(bm + row0) * lda + ch0 * 8;
    long long gB0 = (long long)(bn + row0) * ldb + ch0 * 8;
    uint32_t szA[4], szB[8];
    #pragma unroll
    for (int i = 0; i < 4; i++) szA[i] = (row0 + 32 * i < mRem) ? 16u : 0u;
    #pragma unroll
    for (int i = 0; i < 8; i++) szB[i] = (row0 + 32 * i < nRem) ? 16u : 0u;
    long long ldax = (long long)lda * 32, ldbx = (long long)ldb * 32;

    auto loadStage = [&](int c) {
        uint32_t sb = sbase + (uint32_t)((c % 3) * W_STG);
        long long k0 = (long long)(c << 6);
        #pragma unroll
        for (int i = 0; i < 4; i++) {
            cpa16(sb + W_SA_H + so0 + i * 4096u, Ah + gA0 + i * ldax + k0, szA[i]);
            if (useAl)
                cpa16(sb + W_SA_L + so0 + i * 4096u, Al + gA0 + i * ldax + k0, szA[i]);
        }
        #pragma unroll
        for (int i = 0; i < 8; i++)
            cpa16(sb + W_SB_H + so0 + i * 4096u, Bh + gB0 + i * ldbx + k0, szB[i]);
    };

    // ldmatrix row terms
    int frow = lane & 15, fhalf = lane >> 4;
    uint32_t a_rb[4]; int a_x[4];
    #pragma unroll
    for (int mi = 0; mi < 4; mi++) {
        int row = wm * 64 + mi * 16 + frow;
        a_rb[mi] = (uint32_t)(row * 128);
        a_x[mi]  = row & 7;
    }
    uint32_t b_rb[4]; int b_x[4];
    #pragma unroll
    for (int nj = 0; nj < 4; nj++) {
        int row = wn * 64 + nj * 16 + frow;
        b_rb[nj] = (uint32_t)(row * 128);
        b_x[nj]  = row & 7;
    }

    float acc[4][8][4];
    #pragma unroll
    for (int mi = 0; mi < 4; mi++)
        #pragma unroll
        for (int ni = 0; ni < 8; ni++)
            #pragma unroll
            for (int q = 0; q < 4; q++) acc[mi][ni][q] = 0.f;

    loadStage(0); cpa_commit();
    if (nch > 1) loadStage(1);
    cpa_commit();

    for (int c = 0; c < nch; c++) {
        cpa_wait1();
        __syncthreads();
        uint32_t sb = sbase + (uint32_t)((c % 3) * W_STG);

        #pragma unroll
        for (int k16 = 0; k16 < 4; k16++) {
            int chl = k16 * 2 + fhalf;
            uint32_t bH[4][4];
            #pragma unroll
            for (int nj = 0; nj < 4; nj++) {
                uint32_t off = b_rb[nj] + (uint32_t)(((chl ^ b_x[nj])) << 4);
                ldm_x4(bH[nj], sb + W_SB_H + off);
            }
            #pragma unroll
            for (int mi = 0; mi < 4; mi++) {
                uint32_t aH[4], aL[4];
                uint32_t off = a_rb[mi] + (uint32_t)(((chl ^ a_x[mi])) << 4);
                ldm_x4(aH, sb + W_SA_H + off);
                if (useAl) ldm_x4(aL, sb + W_SA_L + off);
                #pragma unroll
                for (int nj = 0; nj < 4; nj++) {
                    mma16816(acc[mi][nj*2+0], aH, bH[nj][0], bH[nj][2]);
                    mma16816(acc[mi][nj*2+1], aH, bH[nj][1], bH[nj][3]);
                    if (useAl) {
                        mma16816(acc[mi][nj*2+0], aL, bH[nj][0], bH[nj][2]);
                        mma16816(acc[mi][nj*2+1], aL, bH[nj][1], bH[nj][3]);
                    }
                }
            }
        }
        if (c + 2 < nch) loadStage(c + 2);
        cpa_commit();
    }

    int erow = lane >> 2;
    int ecol = (lane & 3) * 2;
    #pragma unroll
    for (int mi = 0; mi < 4; mi++) {
        #pragma unroll
        for (int ni = 0; ni < 8; ni++) {
            int gn = bn + wn * 64 + (ni >> 1) * 16 + (ni & 1) * 8 + ecol;
            if (gn >= N) continue;
            float b0 = 0.f, b1 = 0.f;
            if (bias) { b0 = bias[gn]; b1 = bias[gn + 1]; }
            float* cc = acc[mi][ni];
            #pragma unroll
            for (int half = 0; half < 2; half++) {
                int gm = bm + wm * 64 + mi * 16 + erow + half * 8;
                if (gm >= M) continue;
                float rs = rowScale ? rowScale[gm] : 1.f;
                float v0 = cc[half * 2 + 0] * scale * rs + b0;
                float v1 = cc[half * 2 + 1] * scale * rs + b1;
                if (act == 1) { v0 = gelu_tanh(v0); v1 = gelu_tanh(v1); }
                long long o = (long long)gm * ldc + gn;
                if (Cf) *reinterpret_cast<float2*>(Cf + o) = make_float2(v0, v1);
                if (Ch) {
                    unsigned short h0, l0, h1, l1;
                    split_f16(v0, h0, l0); split_f16(v1, h1, l1);
                    *reinterpret_cast<ushort2*>(Ch + o) = make_ushort2(h0, h1);
                    if (Cl) *reinterpret_cast<ushort2*>(Cl + o) = make_ushort2(l0, l1);
                }
            }
        }
    }
}

// =====================================================================
// NARROW GEMM (N<=128, 1-product): 128x128x64, 3-stage (96KB), 2 CTAs/SM.
//   K-tail guarded (K % 8 == 0 required; zero-fill beyond K).
// =====================================================================
#define N_STG 32768
#define N_SA 0
#define N_SB 16384
#define HG_SMEM (3 * N_STG)   // 98304

__global__ void __launch_bounds__(256, 2)
hgemm3_kernel(const unsigned short* __restrict__ Ah,
              int lda, long long sAz,
              const unsigned short* __restrict__ Bh,
              int ldb, long long sBz,
              unsigned short* __restrict__ Ch, unsigned short* __restrict__ Cl,
              int ldc, long long sCz,
              const float* __restrict__ rowScale,
              int M, int N, int K,
              float scale) {
    extern __shared__ char smem[];
    uint32_t sbase = smem_u32(smem);

    int tid = threadIdx.x, lane = tid & 31, warp = tid >> 5;
    int wm = warp & 1, wn = warp >> 1;   // warp tile 64x32

    long long zz = blockIdx.z;
    Ah += zz * sAz;
    Bh += zz * sBz;
    Ch += zz * sCz; Cl += zz * sCz;
    if (rowScale) rowScale += zz * M;

    int bm = blockIdx.y * 128;
    int bn = blockIdx.x * 128;
    int mRem = M - bm; if (mRem > 128) mRem = 128;
    int nRem = N - bn; if (nRem > 128) nRem = 128;

    int nch = (K + 63) >> 6;

    int row0 = tid >> 3, ch0 = tid & 7;
    int ch8 = ch0 * 8;
    uint32_t so0 = saddr128(row0, ch0);
    long long gA0 = (long long)(bm + row0) * lda + ch8;
    long long gB0 = (long long)(bn + row0) * ldb + ch8;
    uint32_t szA[4], szB[4];
    #pragma unroll
    for (int i = 0; i < 4; i++) {
        szA[i] = (row0 + 32 * i < mRem) ? 16u : 0u;
        szB[i] = (row0 + 32 * i < nRem) ? 16u : 0u;
    }
    long long ldax = (long long)lda * 32, ldbx = (long long)ldb * 32;

    auto loadStage = [&](int c) {
        uint32_t sb = sbase + (uint32_t)((c % 3) * N_STG);
        long long k0 = (long long)(c << 6);
        uint32_t kok = ((int)(c << 6) + ch8 < K) ? 0xFFFFFFFFu : 0u;
        #pragma unroll
        for (int i = 0; i < 4; i++) {
            cpa16(sb + N_SA + so0 + i * 4096u, Ah + gA0 + i * ldax + k0, szA[i] & kok);
            cpa16(sb + N_SB + so0 + i * 4096u, Bh + gB0 + i * ldbx + k0, szB[i] & kok);
        }
    };

    int frow = lane & 15, fhalf = lane >> 4;
    uint32_t a_rb[4]; int a_x[4];
    #pragma unroll
    for (int mi = 0; mi < 4; mi++) {
        int row = wm * 64 + mi * 16 + frow;
        a_rb[mi] = (uint32_t)(row * 128);
        a_x[mi]  = row & 7;
    }
    uint32_t b_rb[2]; int b_x[2];
    #pragma unroll
    for (int nj = 0; nj < 2; nj++) {
        int row = wn * 32 + nj * 16 + frow;
        b_rb[nj] = (uint32_t)(row * 128);
        b_x[nj]  = row & 7;
    }

    float acc[4][4][4];
    #pragma unroll
    for (int mi = 0; mi < 4; mi++)
        #pragma unroll
        for (int ni = 0; ni < 4; ni++)
            #pragma unroll
            for (int q = 0; q < 4; q++) acc[mi][ni][q] = 0.f;

    loadStage(0); cpa_commit();
    if (nch > 1) loadStage(1);
    cpa_commit();

    for (int c = 0; c < nch; c++) {
        cpa_wait1();
        __syncthreads();
        uint32_t sb = sbase + (uint32_t)((c % 3) * N_STG);

        #pragma unroll
        for (int k16 = 0; k16 < 4; k16++) {
            int chl = k16 * 2 + fhalf;
            uint32_t bH[2][4];
            #pragma unroll
            for (int nj = 0; nj < 2; nj++) {
                uint32_t off = b_rb[nj] + (uint32_t)(((chl ^ b_x[nj])) << 4);
                ldm_x4(bH[nj], sb + N_SB + off);
            }
            #pragma unroll
            for (int mi = 0; mi < 4; mi++) {
                uint32_t aH[4];
                uint32_t off = a_rb[mi] + (uint32_t)(((chl ^ a_x[mi])) << 4);
                ldm_x4(aH, sb + N_SA + off);
                #pragma unroll
                for (int nj = 0; nj < 2; nj++) {
                    mma16816(acc[mi][nj*2+0], aH, bH[nj][0], bH[nj][2]);
                    mma16816(acc[mi][nj*2+1], aH, bH[nj][1], bH[nj][3]);
                }
            }
        }
        if (c + 2 < nch) loadStage(c + 2);
        cpa_commit();
    }

    int erow = lane >> 2;
    int ecol = (lane & 3) * 2;
    #pragma unroll
    for (int mi = 0; mi < 4; mi++) {
        #pragma unroll
        for (int ni = 0; ni < 4; ni++) {
            int gn = bn + wn * 32 + ni * 8 + ecol;
            if (gn >= N) continue;
            float* cc = acc[mi][ni];
            #pragma unroll
            for (int half = 0; half < 2; half++) {
                int gm = bm + wm * 64 + mi * 16 + erow + half * 8;
                if (gm >= M) continue;
                float rs = rowScale ? rowScale[gm] : 1.f;
                float v0 = cc[half * 2 + 0] * scale * rs;
                float v1 = cc[half * 2 + 1] * scale * rs;
                long long o = (long long)gm * ldc + gn;
                unsigned short h0, l0, h1, l1;
                split_f16(v0, h0, l0); split_f16(v1, h1, l1);
                *reinterpret_cast<ushort2*>(Ch + o) = make_ushort2(h0, h1);
                *reinterpret_cast<ushort2*>(Cl + o) = make_ushort2(l0, l1);
            }
        }
    }
}

// ---------------- host ----------------
static void hgw(const unsigned short* Ah, const unsigned short* Al, int lda, long long sAz,
                const unsigned short* Bh, int ldb, long long sBz,
                float* Cf, unsigned short* Ch, unsigned short* Cl, int ldc, long long sCz,
                const float* rowScale,
                int M, int N, int K, int Z, const float* bias, float scale, int act) {
    dim3 grid((N + 255) / 256, (M + 127) / 128, Z);
    hgemmw_kernel<<<grid, 256, W_SMEM>>>(Ah, Al, lda, sAz, Bh, ldb, sBz,
                                         Cf, Ch, Cl, ldc, sCz, rowScale,
                                         M, N, K, bias, scale, act);
}

static void hgn(const unsigned short* Ah, int lda, long long sAz,
                const unsigned short* Bh, int ldb, long long sBz,
                unsigned short* Ch, unsigned short* Cl, int ldc, long long sCz,
                const float* rowScale, int M, int N, int K, int Z, float scale) {
    dim3 grid(1, (M + 127) / 128, Z);
    hgemm3_kernel<<<grid, 256, HG_SMEM>>>(Ah, lda, sAz, Bh, ldb, sBz,
                                          Ch, Cl, ldc, sCz, rowScale, M, N, K, scale);
}

static void trh(const float* src, int R, int Ccol, int lds, unsigned short* dh) {
    dim3 grid(Ccol / 32, R / 32);
    transpose_h_kernel<<<grid, dim3(32, 8)>>>(src, R, Ccol, lds, dh);
}

extern "C" void kernel_launch(void* const* d_in, const int* in_sizes, int n_in,
                              void* d_out, int out_size) {
    const float* x        = (const float*)d_in[0];
    const float* e        = (const float*)d_in[1];
    const float* context  = (const float*)d_in[2];
    const float* freqs    = (const float*)d_in[3];
    const float* modulation = (const float*)d_in[7];
    const float* sa_q_w = (const float*)d_in[8];
    const float* sa_q_b = (const float*)d_in[9];
    const float* sa_k_w = (const float*)d_in[10];
    const float* sa_k_b = (const float*)d_in[11];
    const float* sa_v_w = (const float*)d_in[12];
    const float* sa_v_b = (const float*)d_in[13];
    const float* sa_o_w = (const float*)d_in[14];
    const float* sa_o_b = (const float*)d_in[15];
    const float* sa_nq_w = (const float*)d_in[16];
    const float* sa_nk_w = (const float*)d_in[17];
    const float* ca_q_w = (const float*)d_in[18];
    const float* ca_q_b = (const float*)d_in[19];
    const float* ca_k_w = (const float*)d_in[20];
    const float* ca_k_b = (const float*)d_in[21];
    const float* ca_v_w = (const float*)d_in[22];
    const float* ca_v_b = (const float*)d_in[23];
    const float* ca_o_w = (const float*)d_in[24];
    const float* ca_o_b = (const float*)d_in[25];
    const float* ca_nq_w = (const float*)d_in[26];
    const float* ca_nk_w = (const float*)d_in[27];
    const float* ffn_w1 = (const float*)d_in[28];
    const float* ffn_b1 = (const float*)d_in[29];
    const float* ffn_w2 = (const float*)d_in[30];
    const float* ffn_b2 = (const float*)d_in[31];
    float* out = (float*)d_out;

    cudaFuncSetAttribute(hgemm3_kernel,
                         cudaFuncAttributeMaxDynamicSharedMemorySize, HG_SMEM);
    cudaFuncSetAttribute(hgemmw_kernel,
                         cudaFuncAttributeMaxDynamicSharedMemorySize, W_SMEM);

    float *em, *q, *t, *s, *b3, *rinv;
    unsigned short *hh, *hl, *qh, *ql, *kh, *vth, *yh, *yl;
    unsigned short *oh, *ol, *cxh, *cxl, *ph, *ffh, *wh;
    cudaGetSymbolAddress((void**)&em, g_em);
    cudaGetSymbolAddress((void**)&q,  g_q);
    cudaGetSymbolAddress((void**)&t,  g_t);
    cudaGetSymbolAddress((void**)&s,  g_s);
    cudaGetSymbolAddress((void**)&b3, g_b3);
    cudaGetSymbolAddress((void**)&rinv, g_rinv);
    cudaGetSymbolAddress((void**)&hh, g_hh);  cudaGetSymbolAddress((void**)&hl, g_hl);
    cudaGetSymbolAddress((void**)&qh, g_qh);  cudaGetSymbolAddress((void**)&ql, g_ql);
    cudaGetSymbolAddress((void**)&kh, g_kh);
    cudaGetSymbolAddress((void**)&vth, g_vth);
    cudaGetSymbolAddress((void**)&yh, g_yh);  cudaGetSymbolAddress((void**)&yl, g_yl);
    cudaGetSymbolAddress((void**)&oh, g_oh);  cudaGetSymbolAddress((void**)&ol, g_ol);
    cudaGetSymbolAddress((void**)&cxh, g_cxh); cudaGetSymbolAddress((void**)&cxl, g_cxl);
    cudaGetSymbolAddress((void**)&ph, g_ph);
    cudaGetSymbolAddress((void**)&ffh, g_ffh);
    cudaGetSymbolAddress((void**)&wh, g_wh);

    const float ascale = 0.08838834764831845f;   // 1/sqrt(128)
    const long long LC = (long long)L_Q * C_DIM;
    int eltBlocks = (int)((LC + 255) / 256);

    em_kernel<<<(6 * C_DIM + 255) / 256, 256>>>(e, modulation, em);

    // ================= self attention =================
    ln_mod_split_kernel<<<L_Q, 256>>>(x, em + 0 * C_DIM, em + 1 * C_DIM, hh, hl);
    trh(sa_q_w, C_DIM, C_DIM, C_DIM, wh);
    trh(sa_k_w, C_DIM, C_DIM, C_DIM, wh + (long long)C_DIM * C_DIM);
    trh(sa_v_w, C_DIM, C_DIM, C_DIM, wh + 2LL * C_DIM * C_DIM);
    pack3_kernel<<<(3 * C_DIM + 255) / 256, 256>>>(sa_q_b, sa_k_b, sa_v_b, b3);
    float* qkv = s;   // [2400, 4608] fp32
    hgw(hh, hl, C_DIM, 0, wh, C_DIM, 0, qkv, nullptr, nullptr, 3 * C_DIM, 0,
        nullptr, L_Q, 3 * C_DIM, C_DIM, 1, b3, 1.f, 0);
    rms_rope_split_kernel<<<L_Q, 256>>>(qkv + 0 * C_DIM, 3 * C_DIM, sa_nq_w, freqs, qh, ql);
    rms_rope_split_kernel<<<L_Q, 256>>>(qkv + 1 * C_DIM, 3 * C_DIM, sa_nk_w, freqs, kh, nullptr);
    trh(qkv + 2 * C_DIM, L_Q, C_DIM, 3 * C_DIM, vth);      // V^T [1536, 2400]
    // scores: 2-product (q split, k hi), fp16 out to ph
    hgw(qh, ql, C_DIM, HD, kh, C_DIM, HD, nullptr, ph, nullptr,
        L_Q, (long long)L_Q * L_Q, nullptr, L_Q, L_Q, HD, NH, nullptr, ascale, 0);
    softmax_rowinv_h_kernel<<<NH * L_Q, 256>>>(ph, L_Q, rinv);
    // PV: 1-product, row-scaled by 1/sum
    hgn(ph, L_Q, (long long)L_Q * L_Q, vth, L_Q, (long long)HD * L_Q,
        yh, yl, C_DIM, HD, rinv, L_Q, HD, L_Q, NH, 1.f);
    trh(sa_o_w, C_DIM, C_DIM, C_DIM, wh);
    hgw(yh, yl, C_DIM, 0, wh, C_DIM, 0, t, nullptr, nullptr, C_DIM, 0,
        nullptr, L_Q, C_DIM, C_DIM, 1, sa_o_b, 1.f, 0);
    residual_mul_conv_kernel<<<eltBlocks, 256>>>(x, t, em + 2 * C_DIM, out, oh, ol);

    // ================= cross attention =================
    trh(ca_q_w, C_DIM, C_DIM, C_DIM, wh);
    hgw(oh, ol, C_DIM, 0, wh, C_DIM, 0, q, nullptr, nullptr, C_DIM, 0,
        nullptr, L_Q, C_DIM, C_DIM, 1, ca_q_b, 1.f, 0);
    rms_split_kernel<<<L_Q, 256>>>(q, C_DIM, ca_nq_w, qh, ql);
    conv_split_kernel<<<(int)(((long long)L_KV * C_DIM + 255) / 256), 256>>>(
        context, (long long)L_KV * C_DIM, cxh, cxl);
    trh(ca_k_w, C_DIM, C_DIM, C_DIM, wh);
    trh(ca_v_w, C_DIM, C_DIM, C_DIM, wh + (long long)C_DIM * C_DIM);
    pack2_kernel<<<(2 * C_DIM + 255) / 256, 256>>>(ca_k_b, ca_v_b, b3);
    float* kvbuf = s;   // [512, 3072] fp32
    hgw(cxh, cxl, C_DIM, 0, wh, C_DIM, 0, kvbuf, nullptr, nullptr, 2 * C_DIM, 0,
        nullptr, L_KV, 2 * C_DIM, C_DIM, 1, b3, 1.f, 0);
    rms_split_kernel<<<L_KV, 256>>>(kvbuf + 0 * C_DIM, 2 * C_DIM, ca_nk_w, kh, nullptr);
    trh(kvbuf + 1 * C_DIM, L_KV, C_DIM, 2 * C_DIM, vth);   // V^T [1536, 512]
    hgw(qh, ql, C_DIM, HD, kh, C_DIM, HD, nullptr, ph, nullptr,
        L_KV, (long long)L_Q * L_KV, nullptr, L_Q, L_KV, HD, NH, nullptr, ascale, 0);
    softmax_rowinv_h_kernel<<<NH * L_Q, 256>>>(ph, L_KV, rinv);
    hgn(ph, L_KV, (long long)L_Q * L_KV, vth, L_KV, (long long)HD * L_KV,
        yh, yl, C_DIM, HD, rinv, L_Q, HD, L_KV, NH, 1.f);
    trh(ca_o_w, C_DIM, C_DIM, C_DIM, wh);
    hgw(yh, yl, C_DIM, 0, wh, C_DIM, 0, t, nullptr, nullptr, C_DIM, 0,
        nullptr, L_Q, C_DIM, C_DIM, 1, ca_o_b, 1.f, 0);
    add_inplace_kernel<<<eltBlocks, 256>>>(out, t);

    // ================= FFN =================
    ln_mod_split_kernel<<<L_Q, 256>>>(out, em + 3 * C_DIM, em + 4 * C_DIM, hh, nullptr);
    trh(ffn_w1, C_DIM, FF_DIM, FF_DIM, wh);
    hgw(hh, nullptr, C_DIM, 0, wh, C_DIM, 0, nullptr, ffh, nullptr, FF_DIM, 0,
        nullptr, L_Q, FF_DIM, C_DIM, 1, ffn_b1, 1.f, 1);  // 1-product + GELU
    trh(ffn_w2, FF_DIM, C_DIM, C_DIM, wh);
    hgw(ffh, nullptr, FF_DIM, 0, wh, FF_DIM, 0, t, nullptr, nullptr, C_DIM, 0,
        nullptr, L_Q, C_DIM, FF_DIM, 1, ffn_b2, 1.f, 0);  // 1-product
    addmul_inplace_kernel<<<eltBlocks, 256>>>(out, t, em + 5 * C_DIM);
}

// round 12
// speedup vs baseline: 1.6936x; 1.0325x over previous
#include <cuda_runtime.h>
#include <cuda_fp16.h>
#include <stdint.h>
#include <math.h>

// Problem constants
#define C_DIM 1536
#define L_Q   2400
#define L_KV  512
#define NH    12
#define HD    128
#define FF_DIM 8960
#define EPS   1e-6f
#define L_PAD 2432

// ---------------- device scratch ----------------
__device__ __align__(256) float g_em[6 * C_DIM];
__device__ __align__(256) float g_q [L_Q * C_DIM];
__device__ __align__(256) float g_t [L_Q * C_DIM];
__device__ __align__(256) float g_s [L_Q * 3 * C_DIM];    // fused-proj fp32 scratch
__device__ __align__(256) float g_b3[3 * C_DIM];
__device__ __align__(256) float g_rinv[NH * L_Q];
__device__ __align__(256) unsigned short g_hh[L_Q * C_DIM], g_hl[L_Q * C_DIM];
__device__ __align__(256) unsigned short g_qh[L_Q * C_DIM], g_ql[L_Q * C_DIM];
__device__ __align__(256) unsigned short g_kh[L_Q * C_DIM];
__device__ __align__(256) unsigned short g_vth[C_DIM * L_PAD];
__device__ __align__(256) unsigned short g_yh[L_Q * C_DIM], g_yl[L_Q * C_DIM];
__device__ __align__(256) unsigned short g_oh[L_Q * C_DIM], g_ol[L_Q * C_DIM];
__device__ __align__(256) unsigned short g_cxh[L_KV * C_DIM], g_cxl[L_KV * C_DIM];
__device__ __align__(256) unsigned short g_ph[NH * L_Q * L_KV];
__device__ __align__(256) unsigned short g_ffh[L_Q * FF_DIM];
__device__ __align__(256) unsigned short g_wh[FF_DIM * C_DIM];

// ---------------- helpers ----------------
__device__ __forceinline__ float block_reduce(float v, float* sh, bool is_max) {
    __syncthreads();
    int lane = threadIdx.x & 31, warp = threadIdx.x >> 5;
    #pragma unroll
    for (int o = 16; o > 0; o >>= 1) {
        float other = __shfl_down_sync(0xffffffffu, v, o);
        v = is_max ? fmaxf(v, other) : v + other;
    }
    if (lane == 0) sh[warp] = v;
    __syncthreads();
    int nw = blockDim.x >> 5;
    if (warp == 0) {
        v = (lane < nw) ? sh[lane] : (is_max ? -INFINITY : 0.f);
        #pragma unroll
        for (int o = 16; o > 0; o >>= 1) {
            float other = __shfl_down_sync(0xffffffffu, v, o);
            v = is_max ? fmaxf(v, other) : v + other;
        }
        if (lane == 0) sh[0] = v;
    }
    __syncthreads();
    return sh[0];
}

__device__ __forceinline__ float gelu_tanh(float v) {
    float v3 = v * v * v;
    return 0.5f * v * (1.f + tanhf(0.7978845608028654f * (v + 0.044715f * v3)));
}

static __device__ __forceinline__ void split_f16(float v, unsigned short& h, unsigned short& l) {
    __half hb = __float2half_rn(v);
    float r = v - __half2float(hb);
    __half lb = __float2half_rn(r);
    h = *reinterpret_cast<unsigned short*>(&hb);
    l = *reinterpret_cast<unsigned short*>(&lb);
}

// ---------------- elementwise / norm kernels ----------------
__global__ void em_kernel(const float* __restrict__ e, const float* __restrict__ mod,
                          float* __restrict__ em) {
    int i = blockIdx.x * blockDim.x + threadIdx.x;
    if (i < 6 * C_DIM) em[i] = e[i] + mod[i];
}

__global__ void pack3_kernel(const float* __restrict__ a, const float* __restrict__ b,
                             const float* __restrict__ c, float* __restrict__ d) {
    int i = blockIdx.x * blockDim.x + threadIdx.x;
    if (i < C_DIM) d[i] = a[i];
    else if (i < 2 * C_DIM) d[i] = b[i - C_DIM];
    else if (i < 3 * C_DIM) d[i] = c[i - 2 * C_DIM];
}

__global__ void pack2_kernel(const float* __restrict__ a, const float* __restrict__ b,
                             float* __restrict__ d) {
    int i = blockIdx.x * blockDim.x + threadIdx.x;
    if (i < C_DIM) d[i] = a[i];
    else if (i < 2 * C_DIM) d[i] = b[i - C_DIM];
}

__global__ void zero_pad_kernel(unsigned short* __restrict__ vt) {
    int i = blockIdx.x * blockDim.x + threadIdx.x;
    int r = i >> 5, c = i & 31;
    if (r < C_DIM) vt[(long long)r * L_PAD + L_Q + c] = 0;
}

__global__ void ln_mod_split_kernel(const float* __restrict__ x, const float* __restrict__ e0,
                                    const float* __restrict__ e1,
                                    unsigned short* __restrict__ oh, unsigned short* __restrict__ ol) {
    __shared__ float sh[32];
    long long row = blockIdx.x;
    const float* xr = x + row * C_DIM;
    float s = 0.f, s2 = 0.f;
    for (int c = threadIdx.x; c < C_DIM; c += blockDim.x) {
        float v = xr[c];
        s += v; s2 += v * v;
    }
    float S  = block_reduce(s,  sh, false);
    float S2 = block_reduce(s2, sh, false);
    float m   = S  * (1.f / C_DIM);
    float var = S2 * (1.f / C_DIM) - m * m;
    float inv = rsqrtf(var + EPS);
    for (int c = threadIdx.x; c < C_DIM; c += blockDim.x) {
        float v = e0[c] + (xr[c] - m) * inv * (1.f + e1[c]);
        unsigned short h, l; split_f16(v, h, l);
        oh[row * C_DIM + c] = h;
        if (ol) ol[row * C_DIM + c] = l;
    }
}

__global__ void rms_rope_split_kernel(const float* __restrict__ x, int ldx,
                                      const float* __restrict__ w,
                                      const float* __restrict__ freqs,
                                      unsigned short* __restrict__ dh, unsigned short* __restrict__ dl) {
    __shared__ float sh[32];
    int row = blockIdx.x;
    const float* xr = x + (long long)row * ldx;
    float s2 = 0.f;
    for (int c = threadIdx.x; c < C_DIM; c += blockDim.x) {
        float v = xr[c]; s2 += v * v;
    }
    float S2 = block_reduce(s2, sh, false);
    float inv = rsqrtf(S2 * (1.f / C_DIM) + EPS);
    int f  = row / 1200;
    int rm = row % 1200;
    int hh = rm / 40;
    int ww = rm % 40;
    for (int p = threadIdx.x; p < NH * 64; p += blockDim.x) {
        int n = p >> 6, j = p & 63;
        int pos = (j < 22) ? f : ((j < 43) ? hh : ww);
        float cs = freqs[(pos * 64 + j) * 2 + 0];
        float sn = freqs[(pos * 64 + j) * 2 + 1];
        int c = n * HD + 2 * j;
        float a = xr[c] * inv * w[c];
        float b = xr[c + 1] * inv * w[c + 1];
        float o0 = a * cs - b * sn;
        float o1 = a * sn + b * cs;
        unsigned short h0, l0, h1, l1;
        split_f16(o0, h0, l0); split_f16(o1, h1, l1);
        long long o = (long long)row * C_DIM + c;
        dh[o] = h0;
        dh[o + 1] = h1;
        if (dl) { dl[o] = l0; dl[o + 1] = l1; }
    }
}

__global__ void rms_split_kernel(const float* __restrict__ x, int ldx,
                                 const float* __restrict__ w,
                                 unsigned short* __restrict__ dh, unsigned short* __restrict__ dl) {
    __shared__ float sh[32];
    long long row = blockIdx.x;
    const float* xr = x + row * ldx;
    float s2 = 0.f;
    for (int c = threadIdx.x; c < C_DIM; c += blockDim.x) {
        float v = xr[c]; s2 += v * v;
    }
    float S2 = block_reduce(s2, sh, false);
    float inv = rsqrtf(S2 * (1.f / C_DIM) + EPS);
    for (int c = threadIdx.x; c < C_DIM; c += blockDim.x) {
        float v = xr[c] * inv * w[c];
        unsigned short h, l; split_f16(v, h, l);
        dh[row * C_DIM + c] = h;
        if (dl) dl[row * C_DIM + c] = l;
    }
}

__global__ void conv_split_kernel(const float* __restrict__ src, long long n,
                                  unsigned short* __restrict__ dh, unsigned short* __restrict__ dl) {
    long long i = (long long)blockIdx.x * blockDim.x + threadIdx.x;
    if (i < n) {
        unsigned short h, l; split_f16(src[i], h, l);
        dh[i] = h; dl[i] = l;
    }
}

// [R, Ccol] fp32 (row stride lds) -> [Ccol, R(ldout)] fp16 HI ONLY
__global__ void transpose_h_kernel(const float* __restrict__ src, int R, int Ccol, int lds,
                                   unsigned short* __restrict__ dh, int ldout) {
    __shared__ float tile[32][33];
    int bx = blockIdx.x, by = blockIdx.y;
    int tx = threadIdx.x, ty = threadIdx.y;  // 32 x 8
    #pragma unroll
    for (int i = 0; i < 4; i++) {
        int r = by * 32 + ty + i * 8;
        tile[ty + i * 8][tx] = src[(long long)r * lds + bx * 32 + tx];
    }
    __syncthreads();
    #pragma unroll
    for (int i = 0; i < 4; i++) {
        int ro = bx * 32 + ty + i * 8;
        int co = by * 32 + tx;
        __half hv = __float2half_rn(tile[tx][ty + i * 8]);
        dh[(long long)ro * ldout + co] = *reinterpret_cast<unsigned short*>(&hv);
    }
}

// softmax over fp16 scores, IN PLACE, vectorized uint4
__global__ void softmax_rowinv_h_kernel(unsigned short* __restrict__ sp, int lk,
                                        float* __restrict__ rinv) {
    __shared__ float sh[32];
    long long row = blockIdx.x;
    uint4* p = reinterpret_cast<uint4*>(sp + row * (long long)lk);
    int nv = lk >> 3;
    uint4 r[2];
    int cnt = 0;
    float mx = -INFINITY;
    for (int i = threadIdx.x; i < nv; i += blockDim.x) {
        uint4 v = p[i];
        r[cnt++] = v;
        const unsigned short* u = reinterpret_cast<const unsigned short*>(&v);
        #pragma unroll
        for (int j = 0; j < 8; j++) {
            unsigned short us = u[j];
            mx = fmaxf(mx, __half2float(*reinterpret_cast<__half*>(&us)));
        }
    }
    mx = block_reduce(mx, sh, true);
    float sum = 0.f;
    cnt = 0;
    for (int i = threadIdx.x; i < nv; i += blockDim.x) {
        uint4 v = r[cnt++];
        unsigned short* u = reinterpret_cast<unsigned short*>(&v);
        #pragma unroll
        for (int j = 0; j < 8; j++) {
            unsigned short us = u[j];
            float e = __expf(__half2float(*reinterpret_cast<__half*>(&us)) - mx);
            sum += e;
            __half hv = __float2half_rn(e);
            u[j] = *reinterpret_cast<unsigned short*>(&hv);
        }
        p[i] = v;
    }
    sum = block_reduce(sum, sh, false);
    if (threadIdx.x == 0) rinv[row] = 1.f / sum;
}

__global__ void residual_mul_conv_kernel(const float* __restrict__ xin, const float* __restrict__ t,
                                         const float* __restrict__ ecol, float* __restrict__ out,
                                         unsigned short* __restrict__ oh, unsigned short* __restrict__ ol) {
    long long i = (long long)blockIdx.x * blockDim.x + threadIdx.x;
    if (i < (long long)L_Q * C_DIM) {
        float v = xin[i] + t[i] * ecol[i % C_DIM];
        out[i] = v;
        unsigned short h, l; split_f16(v, h, l);
        oh[i] = h; ol[i] = l;
    }
}

__global__ void add_inplace_kernel(float* __restrict__ x, const float* __restrict__ t) {
    long long i = (long long)blockIdx.x * blockDim.x + threadIdx.x;
    if (i < (long long)L_Q * C_DIM) x[i] += t[i];
}

__global__ void addmul_inplace_kernel(float* __restrict__ x, const float* __restrict__ t,
                                      const float* __restrict__ ecol) {
    long long i = (long long)blockIdx.x * blockDim.x + threadIdx.x;
    if (i < (long long)L_Q * C_DIM) x[i] += t[i] * ecol[i % C_DIM];
}

// ---------------- common GEMM asm helpers ----------------
static __device__ __forceinline__ uint32_t smem_u32(const void* p) {
    uint32_t r;
    asm("{ .reg .u64 t; cvta.to.shared.u64 t, %1; cvt.u32.u64 %0, t; }" : "=r"(r) : "l"(p));
    return r;
}
static __device__ __forceinline__ void cpa16(uint32_t s, const void* g, uint32_t sz) {
    asm volatile("cp.async.cg.shared.global [%0], [%1], 16, %2;" :: "r"(s), "l"(g), "r"(sz));
}
static __device__ __forceinline__ void cpa_commit() {
    asm volatile("cp.async.commit_group;");
}
static __device__ __forceinline__ void cpa_wait1() {
    asm volatile("cp.async.wait_group 1;");
}
static __device__ __forceinline__ void ldm_x4(uint32_t* r, uint32_t addr) {
    asm volatile("ldmatrix.sync.aligned.m8n8.x4.shared.b16 {%0,%1,%2,%3}, [%4];"
                 : "=r"(r[0]), "=r"(r[1]), "=r"(r[2]), "=r"(r[3]) : "r"(addr));
}
static __device__ __forceinline__ void mma16816(float* c, const uint32_t* a, uint32_t b0, uint32_t b1) {
    asm volatile("mma.sync.aligned.m16n8k16.row.col.f32.f16.f16.f32 "
                 "{%0,%1,%2,%3}, {%4,%5,%6,%7}, {%8,%9}, {%0,%1,%2,%3};"
                 : "+f"(c[0]), "+f"(c[1]), "+f"(c[2]), "+f"(c[3])
                 : "r"(a[0]), "r"(a[1]), "r"(a[2]), "r"(a[3]), "r"(b0), "r"(b1));
}
static __device__ __forceinline__ uint32_t saddr128(int row, int ch) {
    return (uint32_t)(row * 128 + ((ch ^ (row & 7)) << 4));
}
static __device__ __forceinline__ uint32_t saddr256(int row, int ch) {
    return (uint32_t)(row * 256 + ((ch ^ (row & 7)) << 4));
}

// =====================================================================
// WIDE GEMM: 128x256x64, warp tile 64x64, 3-stage cp.async (192KB), N>128.
// =====================================================================
#define W_STG 65536
#define W_SA_H 0
#define W_SA_L 16384
#define W_SB_H 32768
#define W_SMEM (3 * W_STG)

__global__ void __launch_bounds__(256, 1)
hgemmw_kernel(const unsigned short* __restrict__ Ah, const unsigned short* __restrict__ Al,
              int lda, long long sAz,
              const unsigned short* __restrict__ Bh,
              int ldb, long long sBz,
              float* __restrict__ Cf, unsigned short* __restrict__ Ch, unsigned short* __restrict__ Cl,
              int ldc, long long sCz,
              const float* __restrict__ rowScale,
              int M, int N, int K,
              const float* __restrict__ bias, float scale, int act) {
    extern __shared__ char smem[];
    uint32_t sbase = smem_u32(smem);

    int tid = threadIdx.x, lane = tid & 31, warp = tid >> 5;
    int wm = warp & 1, wn = warp >> 1;
    const bool useAl = (Al != nullptr);

    long long zz = blockIdx.z;
    Ah += zz * sAz; if (useAl) Al += zz * sAz;
    Bh += zz * sBz;
    if (Cf) Cf += zz * sCz;
    if (Ch) Ch += zz * sCz;
    if (Cl) Cl += zz * sCz;
    if (rowScale) rowScale += zz * M;

    int bm = blockIdx.y * 128;
    int bn = blockIdx.x * 256;
    int mRem = M - bm; if (mRem > 128) mRem = 128;
    int nRem = N - bn; if (nRem > 256) nRem = 256;

    int nch = K >> 6;

    int row0 = tid >> 3, ch0 = tid & 7;
    uint32_t so0 = saddr128(row0, ch0);
    long long gA0 = (long long)(bm + row0) * lda + ch0 * 8;
    long long gB0 = (long long)(bn + row0) * ldb + ch0 * 8;
    uint32_t szA[4], szB[8];
    #pragma unroll
    for (int i = 0; i < 4; i++) szA[i] = (row0 + 32 * i < mRem) ? 16u : 0u;
    #pragma unroll
    for (int i = 0; i < 8; i++) szB[i] = (row0 + 32 * i < nRem) ? 16u : 0u;
    long long ldax = (long long)lda * 32, ldbx = (long long)ldb * 32;

    auto loadStage = [&](int c) {
        uint32_t sb = sbase + (uint32_t)((c % 3) * W_STG);
        long long k0 = (long long)(c << 6);
        #pragma unroll
        for (int i = 0; i < 4; i++) {
            cpa16(sb + W_SA_H + so0 + i * 4096u, Ah + gA0 + i * ldax + k0, szA[i]);
            if (useAl)
                cpa16(sb + W_SA_L + so0 + i * 4096u, Al + gA0 + i * ldax + k0, szA[i]);
        }
        #pragma unroll
        for (int i = 0; i < 8; i++)
            cpa16(sb + W_SB_H + so0 + i * 4096u, Bh + gB0 + i * ldbx + k0, szB[i]);
    };

    int frow = lane & 15, fhalf = lane >> 4;
    uint32_t a_rb[4]; int a_x[4];
    #pragma unroll
    for (int mi = 0; mi < 4; mi++) {
        int row = wm * 64 + mi * 16 + frow;
        a_rb[mi] = (uint32_t)(row * 128);
        a_x[mi]  = row & 7;
    }
    uint32_t b_rb[4]; int b_x[4];
    #pragma unroll
    for (int nj = 0; nj < 4; nj++) {
        int row = wn * 64 + nj * 16 + frow;
        b_rb[nj] = (uint32_t)(row * 128);
        b_x[nj]  = row & 7;
    }

    float acc[4][8][4];
    #pragma unroll
    for (int mi = 0; mi < 4; mi++)
        #pragma unroll
        for (int ni = 0; ni < 8; ni++)
            #pragma unroll
            for (int q = 0; q < 4; q++) acc[mi][ni][q] = 0.f;

    loadStage(0); cpa_commit();
    if (nch > 1) loadStage(1);
    cpa_commit();

    for (int c = 0; c < nch; c++) {
        cpa_wait1();
        __syncthreads();
        uint32_t sb = sbase + (uint32_t)((c % 3) * W_STG);

        #pragma unroll
        for (int k16 = 0; k16 < 4; k16++) {
            int chl = k16 * 2 + fhalf;
            uint32_t bH[4][4];
            #pragma unroll
            for (int nj = 0; nj < 4; nj++) {
                uint32_t off = b_rb[nj] + (uint32_t)(((chl ^ b_x[nj])) << 4);
                ldm_x4(bH[nj], sb + W_SB_H + off);
            }
            #pragma unroll
            for (int mi = 0; mi < 4; mi++) {
                uint32_t aH[4], aL[4];
                uint32_t off = a_rb[mi] + (uint32_t)(((chl ^ a_x[mi])) << 4);
                ldm_x4(aH, sb + W_SA_H + off);
                if (useAl) ldm_x4(aL, sb + W_SA_L + off);
                #pragma unroll
                for (int nj = 0; nj < 4; nj++) {
                    mma16816(acc[mi][nj*2+0], aH, bH[nj][0], bH[nj][2]);
                    mma16816(acc[mi][nj*2+1], aH, bH[nj][1], bH[nj][3]);
                    if (useAl) {
                        mma16816(acc[mi][nj*2+0], aL, bH[nj][0], bH[nj][2]);
                        mma16816(acc[mi][nj*2+1], aL, bH[nj][1], bH[nj][3]);
                    }
                }
            }
        }
        if (c + 2 < nch) loadStage(c + 2);
        cpa_commit();
    }

    int erow = lane >> 2;
    int ecol = (lane & 3) * 2;
    #pragma unroll
    for (int mi = 0; mi < 4; mi++) {
        #pragma unroll
        for (int ni = 0; ni < 8; ni++) {
            int gn = bn + wn * 64 + (ni >> 1) * 16 + (ni & 1) * 8 + ecol;
            if (gn >= N) continue;
            float b0 = 0.f, b1 = 0.f;
            if (bias) { b0 = bias[gn]; b1 = bias[gn + 1]; }
            float* cc = acc[mi][ni];
            #pragma unroll
            for (int half = 0; half < 2; half++) {
                int gm = bm + wm * 64 + mi * 16 + erow + half * 8;
                if (gm >= M) continue;
                float rs = rowScale ? rowScale[gm] : 1.f;
                float v0 = cc[half * 2 + 0] * scale * rs + b0;
                float v1 = cc[half * 2 + 1] * scale * rs + b1;
                if (act == 1) { v0 = gelu_tanh(v0); v1 = gelu_tanh(v1); }
                long long o = (long long)gm * ldc + gn;
                if (Cf) *reinterpret_cast<float2*>(Cf + o) = make_float2(v0, v1);
                if (Ch) {
                    unsigned short h0, l0, h1, l1;
                    split_f16(v0, h0, l0); split_f16(v1, h1, l1);
                    *reinterpret_cast<ushort2*>(Ch + o) = make_ushort2(h0, h1);
                    if (Cl) *reinterpret_cast<ushort2*>(Cl + o) = make_ushort2(l0, l1);
                }
            }
        }
    }
}

// =====================================================================
// NARROW GEMM (N<=128, 1-product): 128x128x64, 3-stage (96KB), 2 CTAs/SM.
// =====================================================================
#define N_STG 32768
#define N_SA 0
#define N_SB 16384
#define HG_SMEM (3 * N_STG)

__global__ void __launch_bounds__(256, 2)
hgemm3_kernel(const unsigned short* __restrict__ Ah,
              int lda, long long sAz,
              const unsigned short* __restrict__ Bh,
              int ldb, long long sBz,
              unsigned short* __restrict__ Ch, unsigned short* __restrict__ Cl,
              int ldc, long long sCz,
              const float* __restrict__ rowScale,
              int M, int N, int K,
              float scale) {
    extern __shared__ char smem[];
    uint32_t sbase = smem_u32(smem);

    int tid = threadIdx.x, lane = tid & 31, warp = tid >> 5;
    int wm = warp & 1, wn = warp >> 1;

    long long zz = blockIdx.z;
    Ah += zz * sAz;
    Bh += zz * sBz;
    Ch += zz * sCz; Cl += zz * sCz;
    if (rowScale) rowScale += zz * M;

    int bm = blockIdx.y * 128;
    int bn = blockIdx.x * 128;
    int mRem = M - bm; if (mRem > 128) mRem = 128;
    int nRem = N - bn; if (nRem > 128) nRem = 128;

    int nch = (K + 63) >> 6;

    int row0 = tid >> 3, ch0 = tid & 7;
    int ch8 = ch0 * 8;
    uint32_t so0 = saddr128(row0, ch0);
    long long gA0 = (long long)(bm + row0) * lda + ch8;
    long long gB0 = (long long)(bn + row0) * ldb + ch8;
    uint32_t szA[4], szB[4];
    #pragma unroll
    for (int i = 0; i < 4; i++) {
        szA[i] = (row0 + 32 * i < mRem) ? 16u : 0u;
        szB[i] = (row0 + 32 * i < nRem) ? 16u : 0u;
    }
    long long ldax = (long long)lda * 32, ldbx = (long long)ldb * 32;

    auto loadStage = [&](int c) {
        uint32_t sb = sbase + (uint32_t)((c % 3) * N_STG);
        long long k0 = (long long)(c << 6);
        uint32_t kok = ((int)(c << 6) + ch8 < K) ? 0xFFFFFFFFu : 0u;
        #pragma unroll
        for (int i = 0; i < 4; i++) {
            cpa16(sb + N_SA + so0 + i * 4096u, Ah + gA0 + i * ldax + k0, szA[i] & kok);
            cpa16(sb + N_SB + so0 + i * 4096u, Bh + gB0 + i * ldbx + k0, szB[i] & kok);
        }
    };

    int frow = lane & 15, fhalf = lane >> 4;
    uint32_t a_rb[4]; int a_x[4];
    #pragma unroll
    for (int mi = 0; mi < 4; mi++) {
        int row = wm * 64 + mi * 16 + frow;
        a_rb[mi] = (uint32_t)(row * 128);
        a_x[mi]  = row & 7;
    }
    uint32_t b_rb[2]; int b_x[2];
    #pragma unroll
    for (int nj = 0; nj < 2; nj++) {
        int row = wn * 32 + nj * 16 + frow;
        b_rb[nj] = (uint32_t)(row * 128);
        b_x[nj]  = row & 7;
    }

    float acc[4][4][4];
    #pragma unroll
    for (int mi = 0; mi < 4; mi++)
        #pragma unroll
        for (int ni = 0; ni < 4; ni++)
            #pragma unroll
            for (int q = 0; q < 4; q++) acc[mi][ni][q] = 0.f;

    loadStage(0); cpa_commit();
    if (nch > 1) loadStage(1);
    cpa_commit();

    for (int c = 0; c < nch; c++) {
        cpa_wait1();
        __syncthreads();
        uint32_t sb = sbase + (uint32_t)((c % 3) * N_STG);

        #pragma unroll
        for (int k16 = 0; k16 < 4; k16++) {
            int chl = k16 * 2 + fhalf;
            uint32_t bH[2][4];
            #pragma unroll
            for (int nj = 0; nj < 2; nj++) {
                uint32_t off = b_rb[nj] + (uint32_t)(((chl ^ b_x[nj])) << 4);
                ldm_x4(bH[nj], sb + N_SB + off);
            }
            #pragma unroll
            for (int mi = 0; mi < 4; mi++) {
                uint32_t aH[4];
                uint32_t off = a_rb[mi] + (uint32_t)(((chl ^ a_x[mi])) << 4);
                ldm_x4(aH, sb + N_SA + off);
                #pragma unroll
                for (int nj = 0; nj < 2; nj++) {
                    mma16816(acc[mi][nj*2+0], aH, bH[nj][0], bH[nj][2]);
                    mma16816(acc[mi][nj*2+1], aH, bH[nj][1], bH[nj][3]);
                }
            }
        }
        if (c + 2 < nch) loadStage(c + 2);
        cpa_commit();
    }

    int erow = lane >> 2;
    int ecol = (lane & 3) * 2;
    #pragma unroll
    for (int mi = 0; mi < 4; mi++) {
        #pragma unroll
        for (int ni = 0; ni < 4; ni++) {
            int gn = bn + wn * 32 + ni * 8 + ecol;
            if (gn >= N) continue;
            float* cc = acc[mi][ni];
            #pragma unroll
            for (int half = 0; half < 2; half++) {
                int gm = bm + wm * 64 + mi * 16 + erow + half * 8;
                if (gm >= M) continue;
                float rs = rowScale ? rowScale[gm] : 1.f;
                float v0 = cc[half * 2 + 0] * scale * rs;
                float v1 = cc[half * 2 + 1] * scale * rs;
                long long o = (long long)gm * ldc + gn;
                unsigned short h0, l0, h1, l1;
                split_f16(v0, h0, l0); split_f16(v1, h1, l1);
                *reinterpret_cast<ushort2*>(Ch + o) = make_ushort2(h0, h1);
                *reinterpret_cast<ushort2*>(Cl + o) = make_ushort2(l0, l1);
            }
        }
    }
}

// =====================================================================
// FUSED SELF-ATTENTION (flash-style). Grid (NH, 19). 256 thr, 8 warps.
//   Each warp owns 16 q rows. Q hi/lo resident; K/V chunks double-buffered;
//   P overwrites the consumed K buffer. Online softmax in fp32.
// =====================================================================
#define FL_QH 0
#define FL_QL 32768
#define FL_KP0 65536
#define FL_KP1 98304
#define FL_V0 131072
#define FL_V1 163840
#define FL_SMEM 196608

__global__ void __launch_bounds__(256, 1)
flash_kernel(const unsigned short* __restrict__ qh, const unsigned short* __restrict__ ql,
             const unsigned short* __restrict__ kh, const unsigned short* __restrict__ vt,
             unsigned short* __restrict__ yh, unsigned short* __restrict__ yl,
             float ascale) {
    extern __shared__ char smem[];
    uint32_t sb = smem_u32(smem);
    int tid = threadIdx.x, lane = tid & 31, warp = tid >> 5;
    int head = blockIdx.x;
    int q0 = blockIdx.y * 128;

    const unsigned short* kbase = kh + head * HD;
    const unsigned short* vbase = vt + (long long)(head * HD) * L_PAD;

    auto loadQ = [&]() {
        #pragma unroll
        for (int i = 0; i < 8; i++) {
            int idx = tid + i * 256;
            int row = idx >> 4, ch = idx & 15;
            uint32_t sz = (q0 + row < L_Q) ? 16u : 0u;
            long long g = (long long)(q0 + row) * C_DIM + head * HD + ch * 8;
            uint32_t so = saddr256(row, ch);
            cpa16(sb + FL_QH + so, qh + g, sz);
            cpa16(sb + FL_QL + so, ql + g, sz);
        }
    };
    auto loadKV = [&](int c) {
        uint32_t kb = sb + ((c & 1) ? FL_KP1 : FL_KP0);
        uint32_t vb = sb + ((c & 1) ? FL_V1 : FL_V0);
        int kv0 = c * 128;
        #pragma unroll
        for (int i = 0; i < 8; i++) {
            int idx = tid + i * 256;
            int row = idx >> 4, ch = idx & 15;
            uint32_t so = saddr256(row, ch);
            uint32_t sz = (kv0 + row < L_Q) ? 16u : 0u;
            cpa16(kb + so, kbase + (long long)(kv0 + row) * C_DIM + ch * 8, sz);
            cpa16(vb + so, vbase + (long long)row * L_PAD + kv0 + ch * 8, 16u);
        }
    };

    int frow = lane & 15, fhalf = lane >> 4;
    int fx = frow & 7;
    uint32_t a_rb = (uint32_t)((warp * 16 + frow) * 256);
    uint32_t b_rb[8];
    #pragma unroll
    for (int nj = 0; nj < 8; nj++) b_rb[nj] = (uint32_t)((nj * 16 + frow) * 256);

    float m[2] = {-INFINITY, -INFINITY};
    float l[2] = {0.f, 0.f};
    float o[8][2][4];
    #pragma unroll
    for (int dj = 0; dj < 8; dj++)
        #pragma unroll
        for (int t = 0; t < 2; t++)
            #pragma unroll
            for (int q = 0; q < 4; q++) o[dj][t][q] = 0.f;

    loadQ(); loadKV(0); cpa_commit();
    loadKV(1); cpa_commit();

    const int nch = (L_Q + 127) / 128;   // 19
    for (int c = 0; c < nch; c++) {
        cpa_wait1();
        __syncthreads();
        uint32_t kb = sb + ((c & 1) ? FL_KP1 : FL_KP0);
        uint32_t vb = sb + ((c & 1) ? FL_V1 : FL_V0);
        int kvRem = L_Q - c * 128; if (kvRem > 128) kvRem = 128;

        // ---- S = Q K^T ----
        float sacc[8][2][4];
        #pragma unroll
        for (int nj = 0; nj < 8; nj++)
            #pragma unroll
            for (int t = 0; t < 2; t++)
                #pragma unroll
                for (int q = 0; q < 4; q++) sacc[nj][t][q] = 0.f;

        #pragma unroll
        for (int kk = 0; kk < 8; kk++) {
            int chl = kk * 2 + fhalf;
            uint32_t aoff = a_rb + (uint32_t)((chl ^ fx) << 4);
            uint32_t aH[4], aL[4];
            ldm_x4(aH, sb + FL_QH + aoff);
            ldm_x4(aL, sb + FL_QL + aoff);
            #pragma unroll
            for (int nj = 0; nj < 8; nj++) {
                uint32_t bH[4];
                ldm_x4(bH, kb + b_rb[nj] + (uint32_t)((chl ^ fx) << 4));
                mma16816(sacc[nj][0], aH, bH[0], bH[2]);
                mma16816(sacc[nj][1], aH, bH[1], bH[3]);
                mma16816(sacc[nj][0], aL, bH[0], bH[2]);
                mma16816(sacc[nj][1], aL, bH[1], bH[3]);
            }
        }
        __syncthreads();   // all warps done reading K before P overwrites it

        // ---- online softmax (rows erow / erow+8; 4 lanes share a row) ----
        int ec = (lane & 3) * 2;
        #pragma unroll
        for (int half = 0; half < 2; half++) {
            float mc = -INFINITY;
            #pragma unroll
            for (int nj = 0; nj < 8; nj++)
                #pragma unroll
                for (int t = 0; t < 2; t++)
                    #pragma unroll
                    for (int j = 0; j < 2; j++) {
                        int col = nj * 16 + t * 8 + ec + j;
                        float v = sacc[nj][t][half * 2 + j] * ascale;
                        sacc[nj][t][half * 2 + j] = v;
                        if (col < kvRem) mc = fmaxf(mc, v);
                    }
            mc = fmaxf(mc, __shfl_xor_sync(0xffffffffu, mc, 1));
            mc = fmaxf(mc, __shfl_xor_sync(0xffffffffu, mc, 2));
            float mn = fmaxf(m[half], mc);
            float corr = __expf(m[half] - mn);
            m[half] = mn;
            float ls = 0.f;
            #pragma unroll
            for (int nj = 0; nj < 8; nj++)
                #pragma unroll
                for (int t = 0; t < 2; t++)
                    #pragma unroll
                    for (int j = 0; j < 2; j++) {
                        int col = nj * 16 + t * 8 + ec + j;
                        float p = (col < kvRem)
                                ? __expf(sacc[nj][t][half * 2 + j] - mn) : 0.f;
                        sacc[nj][t][half * 2 + j] = p;
                        ls += p;
                    }
            l[half] = l[half] * corr + ls;
            #pragma unroll
            for (int dj = 0; dj < 8; dj++)
                #pragma unroll
                for (int t = 0; t < 2; t++)
                    #pragma unroll
                    for (int j = 0; j < 2; j++)
                        o[dj][t][half * 2 + j] *= corr;
        }

        // ---- store P (fp16) into K buffer (own rows only) ----
        #pragma unroll
        for (int half = 0; half < 2; half++) {
            int row = warp * 16 + (lane >> 2) + half * 8;
            #pragma unroll
            for (int nj = 0; nj < 8; nj++)
                #pragma unroll
                for (int t = 0; t < 2; t++) {
                    int col = nj * 16 + t * 8 + ec;
                    __half p0 = __float2half_rn(sacc[nj][t][half * 2 + 0]);
                    __half p1 = __float2half_rn(sacc[nj][t][half * 2 + 1]);
                    uint32_t addr = kb + (uint32_t)(row * 256 +
                                    (((col >> 3) ^ (row & 7)) << 4) + (col & 7) * 2);
                    uint32_t pk = (uint32_t)*reinterpret_cast<unsigned short*>(&p0)
                                | ((uint32_t)*reinterpret_cast<unsigned short*>(&p1) << 16);
                    asm volatile("st.shared.u32 [%0], %1;" :: "r"(addr), "r"(pk));
                }
        }
        __syncwarp();

        // ---- O += P V ----
        #pragma unroll
        for (int kk = 0; kk < 8; kk++) {
            int chl = kk * 2 + fhalf;
            uint32_t aP[4];
            ldm_x4(aP, kb + a_rb + (uint32_t)((chl ^ fx) << 4));
            #pragma unroll
            for (int dj = 0; dj < 8; dj++) {
                uint32_t bV[4];
                ldm_x4(bV, vb + b_rb[dj] + (uint32_t)((chl ^ fx) << 4));
                mma16816(o[dj][0], aP, bV[0], bV[2]);
                mma16816(o[dj][1], aP, bV[1], bV[3]);
            }
        }
        __syncthreads();   // PV done everywhere before prefetch overwrites bufs
        if (c + 2 < nch) loadKV(c + 2);
        cpa_commit();
    }

    // ---- epilogue: O /= l, write yh/yl ----
    int ec = (lane & 3) * 2;
    #pragma unroll
    for (int half = 0; half < 2; half++) {
        float ls = l[half];
        ls += __shfl_xor_sync(0xffffffffu, ls, 1);
        ls += __shfl_xor_sync(0xffffffffu, ls, 2);
        float inv = 1.f / ls;
        int gm = q0 + warp * 16 + (lane >> 2) + half * 8;
        if (gm >= L_Q) continue;
        #pragma unroll
        for (int dj = 0; dj < 8; dj++)
            #pragma unroll
            for (int t = 0; t < 2; t++) {
                int gd = head * HD + dj * 16 + t * 8 + ec;
                float v0 = o[dj][t][half * 2 + 0] * inv;
                float v1 = o[dj][t][half * 2 + 1] * inv;
                unsigned short h0, l0_, h1, l1_;
                split_f16(v0, h0, l0_); split_f16(v1, h1, l1_);
                long long off = (long long)gm * C_DIM + gd;
                *reinterpret_cast<ushort2*>(yh + off) = make_ushort2(h0, h1);
                *reinterpret_cast<ushort2*>(yl + off) = make_ushort2(l0_, l1_);
            }
    }
}

// ---------------- host ----------------
static void hgw(const unsigned short* Ah, const unsigned short* Al, int lda, long long sAz,
                const unsigned short* Bh, int ldb, long long sBz,
                float* Cf, unsigned short* Ch, unsigned short* Cl, int ldc, long long sCz,
                const float* rowScale,
                int M, int N, int K, int Z, const float* bias, float scale, int act) {
    dim3 grid((N + 255) / 256, (M + 127) / 128, Z);
    hgemmw_kernel<<<grid, 256, W_SMEM>>>(Ah, Al, lda, sAz, Bh, ldb, sBz,
                                         Cf, Ch, Cl, ldc, sCz, rowScale,
                                         M, N, K, bias, scale, act);
}

static void hgn(const unsigned short* Ah, int lda, long long sAz,
                const unsigned short* Bh, int ldb, long long sBz,
                unsigned short* Ch, unsigned short* Cl, int ldc, long long sCz,
                const float* rowScale, int M, int N, int K, int Z, float scale) {
    dim3 grid(1, (M + 127) / 128, Z);
    hgemm3_kernel<<<grid, 256, HG_SMEM>>>(Ah, lda, sAz, Bh, ldb, sBz,
                                          Ch, Cl, ldc, sCz, rowScale, M, N, K, scale);
}

static void trh(const float* src, int R, int Ccol, int lds, unsigned short* dh, int ldout) {
    dim3 grid(Ccol / 32, R / 32);
    transpose_h_kernel<<<grid, dim3(32, 8)>>>(src, R, Ccol, lds, dh, ldout);
}

extern "C" void kernel_launch(void* const* d_in, const int* in_sizes, int n_in,
                              void* d_out, int out_size) {
    const float* x        = (const float*)d_in[0];
    const float* e        = (const float*)d_in[1];
    const float* context  = (const float*)d_in[2];
    const float* freqs    = (const float*)d_in[3];
    const float* modulation = (const float*)d_in[7];
    const float* sa_q_w = (const float*)d_in[8];
    const float* sa_q_b = (const float*)d_in[9];
    const float* sa_k_w = (const float*)d_in[10];
    const float* sa_k_b = (const float*)d_in[11];
    const float* sa_v_w = (const float*)d_in[12];
    const float* sa_v_b = (const float*)d_in[13];
    const float* sa_o_w = (const float*)d_in[14];
    const float* sa_o_b = (const float*)d_in[15];
    const float* sa_nq_w = (const float*)d_in[16];
    const float* sa_nk_w = (const float*)d_in[17];
    const float* ca_q_w = (const float*)d_in[18];
    const float* ca_q_b = (const float*)d_in[19];
    const float* ca_k_w = (const float*)d_in[20];
    const float* ca_k_b = (const float*)d_in[21];
    const float* ca_v_w = (const float*)d_in[22];
    const float* ca_v_b = (const float*)d_in[23];
    const float* ca_o_w = (const float*)d_in[24];
    const float* ca_o_b = (const float*)d_in[25];
    const float* ca_nq_w = (const float*)d_in[26];
    const float* ca_nk_w = (const float*)d_in[27];
    const float* ffn_w1 = (const float*)d_in[28];
    const float* ffn_b1 = (const float*)d_in[29];
    const float* ffn_w2 = (const float*)d_in[30];
    const float* ffn_b2 = (const float*)d_in[31];
    float* out = (float*)d_out;

    cudaFuncSetAttribute(hgemm3_kernel,
                         cudaFuncAttributeMaxDynamicSharedMemorySize, HG_SMEM);
    cudaFuncSetAttribute(hgemmw_kernel,
                         cudaFuncAttributeMaxDynamicSharedMemorySize, W_SMEM);
    cudaFuncSetAttribute(flash_kernel,
                         cudaFuncAttributeMaxDynamicSharedMemorySize, FL_SMEM);

    float *em, *q, *t, *s, *b3, *rinv;
    unsigned short *hh, *hl, *qh, *ql, *kh, *vth, *yh, *yl;
    unsigned short *oh, *ol, *cxh, *cxl, *ph, *ffh, *wh;
    cudaGetSymbolAddress((void**)&em, g_em);
    cudaGetSymbolAddress((void**)&q,  g_q);
    cudaGetSymbolAddress((void**)&t,  g_t);
    cudaGetSymbolAddress((void**)&s,  g_s);
    cudaGetSymbolAddress((void**)&b3, g_b3);
    cudaGetSymbolAddress((void**)&rinv, g_rinv);
    cudaGetSymbolAddress((void**)&hh, g_hh);  cudaGetSymbolAddress((void**)&hl, g_hl);
    cudaGetSymbolAddress((void**)&qh, g_qh);  cudaGetSymbolAddress((void**)&ql, g_ql);
    cudaGetSymbolAddress((void**)&kh, g_kh);
    cudaGetSymbolAddress((void**)&vth, g_vth);
    cudaGetSymbolAddress((void**)&yh, g_yh);  cudaGetSymbolAddress((void**)&yl, g_yl);
    cudaGetSymbolAddress((void**)&oh, g_oh);  cudaGetSymbolAddress((void**)&ol, g_ol);
    cudaGetSymbolAddress((void**)&cxh, g_cxh); cudaGetSymbolAddress((void**)&cxl, g_cxl);
    cudaGetSymbolAddress((void**)&ph, g_ph);
    cudaGetSymbolAddress((void**)&ffh, g_ffh);
    cudaGetSymbolAddress((void**)&wh, g_wh);

    const float ascale = 0.08838834764831845f;   // 1/sqrt(128)
    const long long LC = (long long)L_Q * C_DIM;
    int eltBlocks = (int)((LC + 255) / 256);

    em_kernel<<<(6 * C_DIM + 255) / 256, 256>>>(e, modulation, em);

    // ================= self attention =================
    ln_mod_split_kernel<<<L_Q, 256>>>(x, em + 0 * C_DIM, em + 1 * C_DIM, hh, hl);
    trh(sa_q_w, C_DIM, C_DIM, C_DIM, wh, C_DIM);
    trh(sa_k_w, C_DIM, C_DIM, C_DIM, wh + (long long)C_DIM * C_DIM, C_DIM);
    trh(sa_v_w, C_DIM, C_DIM, C_DIM, wh + 2LL * C_DIM * C_DIM, C_DIM);
    pack3_kernel<<<(3 * C_DIM + 255) / 256, 256>>>(sa_q_b, sa_k_b, sa_v_b, b3);
    float* qkv = s;   // [2400, 4608] fp32
    hgw(hh, hl, C_DIM, 0, wh, C_DIM, 0, qkv, nullptr, nullptr, 3 * C_DIM, 0,
        nullptr, L_Q, 3 * C_DIM, C_DIM, 1, b3, 1.f, 0);
    rms_rope_split_kernel<<<L_Q, 256>>>(qkv + 0 * C_DIM, 3 * C_DIM, sa_nq_w, freqs, qh, ql);
    rms_rope_split_kernel<<<L_Q, 256>>>(qkv + 1 * C_DIM, 3 * C_DIM, sa_nk_w, freqs, kh, nullptr);
    trh(qkv + 2 * C_DIM, L_Q, C_DIM, 3 * C_DIM, vth, L_PAD);   // V^T [1536, 2432]
    zero_pad_kernel<<<(C_DIM * 32 + 255) / 256, 256>>>(vth);
    // fused flash attention -> yh/yl
    flash_kernel<<<dim3(NH, (L_Q + 127) / 128), 256, FL_SMEM>>>(
        qh, ql, kh, vth, yh, yl, ascale);
    trh(sa_o_w, C_DIM, C_DIM, C_DIM, wh, C_DIM);
    hgw(yh, yl, C_DIM, 0, wh, C_DIM, 0, t, nullptr, nullptr, C_DIM, 0,
        nullptr, L_Q, C_DIM, C_DIM, 1, sa_o_b, 1.f, 0);
    residual_mul_conv_kernel<<<eltBlocks, 256>>>(x, t, em + 2 * C_DIM, out, oh, ol);

    // ================= cross attention =================
    trh(ca_q_w, C_DIM, C_DIM, C_DIM, wh, C_DIM);
    hgw(oh, ol, C_DIM, 0, wh, C_DIM, 0, q, nullptr, nullptr, C_DIM, 0,
        nullptr, L_Q, C_DIM, C_DIM, 1, ca_q_b, 1.f, 0);
    rms_split_kernel<<<L_Q, 256>>>(q, C_DIM, ca_nq_w, qh, ql);
    conv_split_kernel<<<(int)(((long long)L_KV * C_DIM + 255) / 256), 256>>>(
        context, (long long)L_KV * C_DIM, cxh, cxl);
    trh(ca_k_w, C_DIM, C_DIM, C_DIM, wh, C_DIM);
    trh(ca_v_w, C_DIM, C_DIM, C_DIM, wh + (long long)C_DIM * C_DIM, C_DIM);
    pack2_kernel<<<(2 * C_DIM + 255) / 256, 256>>>(ca_k_b, ca_v_b, b3);
    float* kvbuf = s;   // [512, 3072] fp32
    hgw(cxh, cxl, C_DIM, 0, wh, C_DIM, 0, kvbuf, nullptr, nullptr, 2 * C_DIM, 0,
        nullptr, L_KV, 2 * C_DIM, C_DIM, 1, b3, 1.f, 0);
    rms_split_kernel<<<L_KV, 256>>>(kvbuf + 0 * C_DIM, 2 * C_DIM, ca_nk_w, kh, nullptr);
    trh(kvbuf + 1 * C_DIM, L_KV, C_DIM, 2 * C_DIM, vth, L_KV);   // V^T [1536, 512]
    hgw(qh, ql, C_DIM, HD, kh, C_DIM, HD, nullptr, ph, nullptr,
        L_KV, (long long)L_Q * L_KV, nullptr, L_Q, L_KV, HD, NH, nullptr, ascale, 0);
    softmax_rowinv_h_kernel<<<NH * L_Q, 256>>>(ph, L_KV, rinv);
    hgn(ph, L_KV, (long long)L_Q * L_KV, vth, L_KV, (long long)HD * L_KV,
        yh, yl, C_DIM, HD, rinv, L_Q, HD, L_KV, NH, 1.f);
    trh(ca_o_w, C_DIM, C_DIM, C_DIM, wh, C_DIM);
    hgw(yh, yl, C_DIM, 0, wh, C_DIM, 0, t, nullptr, nullptr, C_DIM, 0,
        nullptr, L_Q, C_DIM, C_DIM, 1, ca_o_b, 1.f, 0);
    add_inplace_kernel<<<eltBlocks, 256>>>(out, t);

    // ================= FFN =================
    ln_mod_split_kernel<<<L_Q, 256>>>(out, em + 3 * C_DIM, em + 4 * C_DIM, hh, nullptr);
    trh(ffn_w1, C_DIM, FF_DIM, FF_DIM, wh, C_DIM);
    hgw(hh, nullptr, C_DIM, 0, wh, C_DIM, 0, nullptr, ffh, nullptr, FF_DIM, 0,
        nullptr, L_Q, FF_DIM, C_DIM, 1, ffn_b1, 1.f, 1);  // 1-product + GELU
    trh(ffn_w2, FF_DIM, C_DIM, C_DIM, wh, FF_DIM);
    hgw(ffh, nullptr, FF_DIM, 0, wh, FF_DIM, 0, t, nullptr, nullptr, C_DIM, 0,
        nullptr, L_Q, C_DIM, FF_DIM, 1, ffn_b2, 1.f, 0);  // 1-product
    addmul_inplace_kernel<<<eltBlocks, 256>>>(out, t, em + 5 * C_DIM);
}

// round 13
// speedup vs baseline: 1.7267x; 1.0195x over previous
#include <cuda_runtime.h>
#include <cuda_fp16.h>
#include <stdint.h>
#include <math.h>

// Problem constants
#define C_DIM 1536
#define L_Q   2400
#define L_KV  512
#define NH    12
#define HD    128
#define FF_DIM 8960
#define EPS   1e-6f
#define L_PAD 2432

// ---------------- device scratch ----------------
__device__ __align__(256) float g_em[6 * C_DIM];
__device__ __align__(256) float g_q [L_Q * C_DIM];
__device__ __align__(256) float g_t [L_Q * C_DIM];
__device__ __align__(256) float g_s [L_Q * 3 * C_DIM];    // fused-proj fp32 scratch
__device__ __align__(256) float g_b3[3 * C_DIM];
__device__ __align__(256) float g_rinv[NH * L_Q];
__device__ __align__(256) unsigned short g_hh[L_Q * C_DIM], g_hl[L_Q * C_DIM];
__device__ __align__(256) unsigned short g_qh[L_Q * C_DIM], g_ql[L_Q * C_DIM];
__device__ __align__(256) unsigned short g_kh[L_Q * C_DIM];
__device__ __align__(256) unsigned short g_vth[C_DIM * L_PAD];
__device__ __align__(256) unsigned short g_yh[L_Q * C_DIM];
__device__ __align__(256) unsigned short g_oh[L_Q * C_DIM];
__device__ __align__(256) unsigned short g_cxh[L_KV * C_DIM], g_cxl[L_KV * C_DIM];
__device__ __align__(256) unsigned short g_ph[NH * L_Q * L_KV];
__device__ __align__(256) unsigned short g_ffh[L_Q * FF_DIM];
__device__ __align__(256) unsigned short g_wh[FF_DIM * C_DIM];

// ---------------- helpers ----------------
__device__ __forceinline__ float block_reduce(float v, float* sh, bool is_max) {
    __syncthreads();
    int lane = threadIdx.x & 31, warp = threadIdx.x >> 5;
    #pragma unroll
    for (int o = 16; o > 0; o >>= 1) {
        float other = __shfl_down_sync(0xffffffffu, v, o);
        v = is_max ? fmaxf(v, other) : v + other;
    }
    if (lane == 0) sh[warp] = v;
    __syncthreads();
    int nw = blockDim.x >> 5;
    if (warp == 0) {
        v = (lane < nw) ? sh[lane] : (is_max ? -INFINITY : 0.f);
        #pragma unroll
        for (int o = 16; o > 0; o >>= 1) {
            float other = __shfl_down_sync(0xffffffffu, v, o);
            v = is_max ? fmaxf(v, other) : v + other;
        }
        if (lane == 0) sh[0] = v;
    }
    __syncthreads();
    return sh[0];
}

__device__ __forceinline__ float gelu_tanh(float v) {
    float v3 = v * v * v;
    return 0.5f * v * (1.f + tanhf(0.7978845608028654f * (v + 0.044715f * v3)));
}

static __device__ __forceinline__ void split_f16(float v, unsigned short& h, unsigned short& l) {
    __half hb = __float2half_rn(v);
    float r = v - __half2float(hb);
    __half lb = __float2half_rn(r);
    h = *reinterpret_cast<unsigned short*>(&hb);
    l = *reinterpret_cast<unsigned short*>(&lb);
}

// ---------------- elementwise / norm kernels ----------------
__global__ void em_kernel(const float* __restrict__ e, const float* __restrict__ mod,
                          float* __restrict__ em) {
    int i = blockIdx.x * blockDim.x + threadIdx.x;
    if (i < 6 * C_DIM) em[i] = e[i] + mod[i];
}

__global__ void pack3_kernel(const float* __restrict__ a, const float* __restrict__ b,
                             const float* __restrict__ c, float* __restrict__ d) {
    int i = blockIdx.x * blockDim.x + threadIdx.x;
    if (i < C_DIM) d[i] = a[i];
    else if (i < 2 * C_DIM) d[i] = b[i - C_DIM];
    else if (i < 3 * C_DIM) d[i] = c[i - 2 * C_DIM];
}

__global__ void pack2_kernel(const float* __restrict__ a, const float* __restrict__ b,
                             float* __restrict__ d) {
    int i = blockIdx.x * blockDim.x + threadIdx.x;
    if (i < C_DIM) d[i] = a[i];
    else if (i < 2 * C_DIM) d[i] = b[i - C_DIM];
}

__global__ void zero_pad_kernel(unsigned short* __restrict__ vt) {
    int i = blockIdx.x * blockDim.x + threadIdx.x;
    int r = i >> 5, c = i & 31;
    if (r < C_DIM) vt[(long long)r * L_PAD + L_Q + c] = 0;
}

__global__ void ln_mod_split_kernel(const float* __restrict__ x, const float* __restrict__ e0,
                                    const float* __restrict__ e1,
                                    unsigned short* __restrict__ oh, unsigned short* __restrict__ ol) {
    __shared__ float sh[32];
    long long row = blockIdx.x;
    const float* xr = x + row * C_DIM;
    float s = 0.f, s2 = 0.f;
    for (int c = threadIdx.x; c < C_DIM; c += blockDim.x) {
        float v = xr[c];
        s += v; s2 += v * v;
    }
    float S  = block_reduce(s,  sh, false);
    float S2 = block_reduce(s2, sh, false);
    float m   = S  * (1.f / C_DIM);
    float var = S2 * (1.f / C_DIM) - m * m;
    float inv = rsqrtf(var + EPS);
    for (int c = threadIdx.x; c < C_DIM; c += blockDim.x) {
        float v = e0[c] + (xr[c] - m) * inv * (1.f + e1[c]);
        unsigned short h, l; split_f16(v, h, l);
        oh[row * C_DIM + c] = h;
        if (ol) ol[row * C_DIM + c] = l;
    }
}

// fused: x += t; then h = e0 + LN(x)*(1+e1)  (hi only)
__global__ void add_ln_mod_split_kernel(float* __restrict__ x, const float* __restrict__ t,
                                        const float* __restrict__ e0, const float* __restrict__ e1,
                                        unsigned short* __restrict__ oh) {
    __shared__ float sh[32];
    long long row = blockIdx.x;
    float* xr = x + row * C_DIM;
    const float* tr = t + row * C_DIM;
    float s = 0.f, s2 = 0.f;
    for (int c = threadIdx.x; c < C_DIM; c += blockDim.x) {
        float v = xr[c] + tr[c];
        xr[c] = v;
        s += v; s2 += v * v;
    }
    float S  = block_reduce(s,  sh, false);
    float S2 = block_reduce(s2, sh, false);
    float m   = S  * (1.f / C_DIM);
    float var = S2 * (1.f / C_DIM) - m * m;
    float inv = rsqrtf(var + EPS);
    for (int c = threadIdx.x; c < C_DIM; c += blockDim.x) {
        float v = e0[c] + (xr[c] - m) * inv * (1.f + e1[c]);
        __half hv = __float2half_rn(v);
        oh[row * C_DIM + c] = *reinterpret_cast<unsigned short*>(&hv);
    }
}

__global__ void rms_rope_split_kernel(const float* __restrict__ x, int ldx,
                                      const float* __restrict__ w,
                                      const float* __restrict__ freqs,
                                      unsigned short* __restrict__ dh, unsigned short* __restrict__ dl) {
    __shared__ float sh[32];
    int row = blockIdx.x;
    const float* xr = x + (long long)row * ldx;
    float s2 = 0.f;
    for (int c = threadIdx.x; c < C_DIM; c += blockDim.x) {
        float v = xr[c]; s2 += v * v;
    }
    float S2 = block_reduce(s2, sh, false);
    float inv = rsqrtf(S2 * (1.f / C_DIM) + EPS);
    int f  = row / 1200;
    int rm = row % 1200;
    int hh = rm / 40;
    int ww = rm % 40;
    for (int p = threadIdx.x; p < NH * 64; p += blockDim.x) {
        int n = p >> 6, j = p & 63;
        int pos = (j < 22) ? f : ((j < 43) ? hh : ww);
        float cs = freqs[(pos * 64 + j) * 2 + 0];
        float sn = freqs[(pos * 64 + j) * 2 + 1];
        int c = n * HD + 2 * j;
        float a = xr[c] * inv * w[c];
        float b = xr[c + 1] * inv * w[c + 1];
        float o0 = a * cs - b * sn;
        float o1 = a * sn + b * cs;
        unsigned short h0, l0, h1, l1;
        split_f16(o0, h0, l0); split_f16(o1, h1, l1);
        long long o = (long long)row * C_DIM + c;
        dh[o] = h0;
        dh[o + 1] = h1;
        if (dl) { dl[o] = l0; dl[o + 1] = l1; }
    }
}

__global__ void rms_split_kernel(const float* __restrict__ x, int ldx,
                                 const float* __restrict__ w,
                                 unsigned short* __restrict__ dh, unsigned short* __restrict__ dl) {
    __shared__ float sh[32];
    long long row = blockIdx.x;
    const float* xr = x + row * ldx;
    float s2 = 0.f;
    for (int c = threadIdx.x; c < C_DIM; c += blockDim.x) {
        float v = xr[c]; s2 += v * v;
    }
    float S2 = block_reduce(s2, sh, false);
    float inv = rsqrtf(S2 * (1.f / C_DIM) + EPS);
    for (int c = threadIdx.x; c < C_DIM; c += blockDim.x) {
        float v = xr[c] * inv * w[c];
        unsigned short h, l; split_f16(v, h, l);
        dh[row * C_DIM + c] = h;
        if (dl) dl[row * C_DIM + c] = l;
    }
}

__global__ void conv_split_kernel(const float* __restrict__ src, long long n,
                                  unsigned short* __restrict__ dh, unsigned short* __restrict__ dl) {
    long long i = (long long)blockIdx.x * blockDim.x + threadIdx.x;
    if (i < n) {
        unsigned short h, l; split_f16(src[i], h, l);
        dh[i] = h; dl[i] = l;
    }
}

// [R, Ccol] fp32 (row stride lds) -> [Ccol, R(ldout)] fp16 HI ONLY
__global__ void transpose_h_kernel(const float* __restrict__ src, int R, int Ccol, int lds,
                                   unsigned short* __restrict__ dh, int ldout) {
    __shared__ float tile[32][33];
    int bx = blockIdx.x, by = blockIdx.y;
    int tx = threadIdx.x, ty = threadIdx.y;  // 32 x 8
    #pragma unroll
    for (int i = 0; i < 4; i++) {
        int r = by * 32 + ty + i * 8;
        tile[ty + i * 8][tx] = src[(long long)r * lds + bx * 32 + tx];
    }
    __syncthreads();
    #pragma unroll
    for (int i = 0; i < 4; i++) {
        int ro = bx * 32 + ty + i * 8;
        int co = by * 32 + tx;
        __half hv = __float2half_rn(tile[tx][ty + i * 8]);
        dh[(long long)ro * ldout + co] = *reinterpret_cast<unsigned short*>(&hv);
    }
}

// softmax over fp16 scores, IN PLACE, vectorized uint4
__global__ void softmax_rowinv_h_kernel(unsigned short* __restrict__ sp, int lk,
                                        float* __restrict__ rinv) {
    __shared__ float sh[32];
    long long row = blockIdx.x;
    uint4* p = reinterpret_cast<uint4*>(sp + row * (long long)lk);
    int nv = lk >> 3;
    uint4 r[2];
    int cnt = 0;
    float mx = -INFINITY;
    for (int i = threadIdx.x; i < nv; i += blockDim.x) {
        uint4 v = p[i];
        r[cnt++] = v;
        const unsigned short* u = reinterpret_cast<const unsigned short*>(&v);
        #pragma unroll
        for (int j = 0; j < 8; j++) {
            unsigned short us = u[j];
            mx = fmaxf(mx, __half2float(*reinterpret_cast<__half*>(&us)));
        }
    }
    mx = block_reduce(mx, sh, true);
    float sum = 0.f;
    cnt = 0;
    for (int i = threadIdx.x; i < nv; i += blockDim.x) {
        uint4 v = r[cnt++];
        unsigned short* u = reinterpret_cast<unsigned short*>(&v);
        #pragma unroll
        for (int j = 0; j < 8; j++) {
            unsigned short us = u[j];
            float e = __expf(__half2float(*reinterpret_cast<__half*>(&us)) - mx);
            sum += e;
            __half hv = __float2half_rn(e);
            u[j] = *reinterpret_cast<unsigned short*>(&hv);
        }
        p[i] = v;
    }
    sum = block_reduce(sum, sh, false);
    if (threadIdx.x == 0) rinv[row] = 1.f / sum;
}

// out = xin + t*e; emit hi only
__global__ void residual_mul_conv_kernel(const float* __restrict__ xin, const float* __restrict__ t,
                                         const float* __restrict__ ecol, float* __restrict__ out,
                                         unsigned short* __restrict__ oh) {
    long long i = (long long)blockIdx.x * blockDim.x + threadIdx.x;
    if (i < (long long)L_Q * C_DIM) {
        float v = xin[i] + t[i] * ecol[i % C_DIM];
        out[i] = v;
        __half hv = __float2half_rn(v);
        oh[i] = *reinterpret_cast<unsigned short*>(&hv);
    }
}

__global__ void addmul_inplace_kernel(float* __restrict__ x, const float* __restrict__ t,
                                      const float* __restrict__ ecol) {
    long long i = (long long)blockIdx.x * blockDim.x + threadIdx.x;
    if (i < (long long)L_Q * C_DIM) x[i] += t[i] * ecol[i % C_DIM];
}

// ---------------- common GEMM asm helpers ----------------
static __device__ __forceinline__ uint32_t smem_u32(const void* p) {
    uint32_t r;
    asm("{ .reg .u64 t; cvta.to.shared.u64 t, %1; cvt.u32.u64 %0, t; }" : "=r"(r) : "l"(p));
    return r;
}
static __device__ __forceinline__ void cpa16(uint32_t s, const void* g, uint32_t sz) {
    asm volatile("cp.async.cg.shared.global [%0], [%1], 16, %2;" :: "r"(s), "l"(g), "r"(sz));
}
static __device__ __forceinline__ void cpa_commit() {
    asm volatile("cp.async.commit_group;");
}
static __device__ __forceinline__ void cpa_wait1() {
    asm volatile("cp.async.wait_group 1;");
}
static __device__ __forceinline__ void ldm_x4(uint32_t* r, uint32_t addr) {
    asm volatile("ldmatrix.sync.aligned.m8n8.x4.shared.b16 {%0,%1,%2,%3}, [%4];"
                 : "=r"(r[0]), "=r"(r[1]), "=r"(r[2]), "=r"(r[3]) : "r"(addr));
}
static __device__ __forceinline__ void mma16816(float* c, const uint32_t* a, uint32_t b0, uint32_t b1) {
    asm volatile("mma.sync.aligned.m16n8k16.row.col.f32.f16.f16.f32 "
                 "{%0,%1,%2,%3}, {%4,%5,%6,%7}, {%8,%9}, {%0,%1,%2,%3};"
                 : "+f"(c[0]), "+f"(c[1]), "+f"(c[2]), "+f"(c[3])
                 : "r"(a[0]), "r"(a[1]), "r"(a[2]), "r"(a[3]), "r"(b0), "r"(b1));
}
static __device__ __forceinline__ uint32_t saddr128(int row, int ch) {
    return (uint32_t)(row * 128 + ((ch ^ (row & 7)) << 4));
}
static __device__ __forceinline__ uint32_t saddr256(int row, int ch) {
    return (uint32_t)(row * 256 + ((ch ^ (row & 7)) << 4));
}

// =====================================================================
// WIDE GEMM: 128x256x64, warp tile 64x64, 3-stage cp.async (192KB), N>128.
// =====================================================================
#define W_STG 65536
#define W_SA_H 0
#define W_SA_L 16384
#define W_SB_H 32768
#define W_SMEM (3 * W_STG)

__global__ void __launch_bounds__(256, 1)
hgemmw_kernel(const unsigned short* __restrict__ Ah, const unsigned short* __restrict__ Al,
              int lda, long long sAz,
              const unsigned short* __restrict__ Bh,
              int ldb, long long sBz,
              float* __restrict__ Cf, unsigned short* __restrict__ Ch, unsigned short* __restrict__ Cl,
              int ldc, long long sCz,
              const float* __restrict__ rowScale,
              int M, int N, int K,
              const float* __restrict__ bias, float scale, int act) {
    extern __shared__ char smem[];
    uint32_t sbase = smem_u32(smem);

    int tid = threadIdx.x, lane = tid & 31, warp = tid >> 5;
    int wm = warp & 1, wn = warp >> 1;
    const bool useAl = (Al != nullptr);

    long long zz = blockIdx.z;
    Ah += zz * sAz; if (useAl) Al += zz * sAz;
    Bh += zz * sBz;
    if (Cf) Cf += zz * sCz;
    if (Ch) Ch += zz * sCz;
    if (Cl) Cl += zz * sCz;
    if (rowScale) rowScale += zz * M;

    int bm = blockIdx.y * 128;
    int bn = blockIdx.x * 256;
    int mRem = M - bm; if (mRem > 128) mRem = 128;
    int nRem = N - bn; if (nRem > 256) nRem = 256;

    int nch = K >> 6;

    int row0 = tid >> 3, ch0 = tid & 7;
    uint32_t so0 = saddr128(row0, ch0);
    long long gA0 = (long long)(bm + row0) * lda + ch0 * 8;
    long long gB0 = (long long)(bn + row0) * ldb + ch0 * 8;
    uint32_t szA[4], szB[8];
    #pragma unroll
    for (int i = 0; i < 4; i++) szA[i] = (row0 + 32 * i < mRem) ? 16u : 0u;
    #pragma unroll
    for (int i = 0; i < 8; i++) szB[i] = (row0 + 32 * i < nRem) ? 16u : 0u;
    long long ldax = (long long)lda * 32, ldbx = (long long)ldb * 32;

    auto loadStage = [&](int c) {
        uint32_t sb = sbase + (uint32_t)((c % 3) * W_STG);
        long long k0 = (long long)(c << 6);
        #pragma unroll
        for (int i = 0; i < 4; i++) {
            cpa16(sb + W_SA_H + so0 + i * 4096u, Ah + gA0 + i * ldax + k0, szA[i]);
            if (useAl)
                cpa16(sb + W_SA_L + so0 + i * 4096u, Al + gA0 + i * ldax + k0, szA[i]);
        }
        #pragma unroll
        for (int i = 0; i < 8; i++)
            cpa16(sb + W_SB_H + so0 + i * 4096u, Bh + gB0 + i * ldbx + k0, szB[i]);
    };

    int frow = lane & 15, fhalf = lane >> 4;
    uint32_t a_rb[4]; int a_x[4];
    #pragma unroll
    for (int mi = 0; mi < 4; mi++) {
        int row = wm * 64 + mi * 16 + frow;
        a_rb[mi] = (uint32_t)(row * 128);
        a_x[mi]  = row & 7;
    }
    uint32_t b_rb[4]; int b_x[4];
    #pragma unroll
    for (int nj = 0; nj < 4; nj++) {
        int row = wn * 64 + nj * 16 + frow;
        b_rb[nj] = (uint32_t)(row * 128);
        b_x[nj]  = row & 7;
    }

    float acc[4][8][4];
    #pragma unroll
    for (int mi = 0; mi < 4; mi++)
        #pragma unroll
        for (int ni = 0; ni < 8; ni++)
            #pragma unroll
            for (int q = 0; q < 4; q++) acc[mi][ni][q] = 0.f;

    loadStage(0); cpa_commit();
    if (nch > 1) loadStage(1);
    cpa_commit();

    for (int c = 0; c < nch; c++) {
        cpa_wait1();
        __syncthreads();
        uint32_t sb = sbase + (uint32_t)((c % 3) * W_STG);

        #pragma unroll
        for (int k16 = 0; k16 < 4; k16++) {
            int chl = k16 * 2 + fhalf;
            uint32_t bH[4][4];
            #pragma unroll
            for (int nj = 0; nj < 4; nj++) {
                uint32_t off = b_rb[nj] + (uint32_t)(((chl ^ b_x[nj])) << 4);
                ldm_x4(bH[nj], sb + W_SB_H + off);
            }
            #pragma unroll
            for (int mi = 0; mi < 4; mi++) {
                uint32_t aH[4], aL[4];
                uint32_t off = a_rb[mi] + (uint32_t)(((chl ^ a_x[mi])) << 4);
                ldm_x4(aH, sb + W_SA_H + off);
                if (useAl) ldm_x4(aL, sb + W_SA_L + off);
                #pragma unroll
                for (int nj = 0; nj < 4; nj++) {
                    mma16816(acc[mi][nj*2+0], aH, bH[nj][0], bH[nj][2]);
                    mma16816(acc[mi][nj*2+1], aH, bH[nj][1], bH[nj][3]);
                    if (useAl) {
                        mma16816(acc[mi][nj*2+0], aL, bH[nj][0], bH[nj][2]);
                        mma16816(acc[mi][nj*2+1], aL, bH[nj][1], bH[nj][3]);
                    }
                }
            }
        }
        if (c + 2 < nch) loadStage(c + 2);
        cpa_commit();
    }

    int erow = lane >> 2;
    int ecol = (lane & 3) * 2;
    #pragma unroll
    for (int mi = 0; mi < 4; mi++) {
        #pragma unroll
        for (int ni = 0; ni < 8; ni++) {
            int gn = bn + wn * 64 + (ni >> 1) * 16 + (ni & 1) * 8 + ecol;
            if (gn >= N) continue;
            float b0 = 0.f, b1 = 0.f;
            if (bias) { b0 = bias[gn]; b1 = bias[gn + 1]; }
            float* cc = acc[mi][ni];
            #pragma unroll
            for (int half = 0; half < 2; half++) {
                int gm = bm + wm * 64 + mi * 16 + erow + half * 8;
                if (gm >= M) continue;
                float rs = rowScale ? rowScale[gm] : 1.f;
                float v0 = cc[half * 2 + 0] * scale * rs + b0;
                float v1 = cc[half * 2 + 1] * scale * rs + b1;
                if (act == 1) { v0 = gelu_tanh(v0); v1 = gelu_tanh(v1); }
                long long o = (long long)gm * ldc + gn;
                if (Cf) *reinterpret_cast<float2*>(Cf + o) = make_float2(v0, v1);
                if (Ch) {
                    unsigned short h0, l0, h1, l1;
                    split_f16(v0, h0, l0); split_f16(v1, h1, l1);
                    *reinterpret_cast<ushort2*>(Ch + o) = make_ushort2(h0, h1);
                    if (Cl) *reinterpret_cast<ushort2*>(Cl + o) = make_ushort2(l0, l1);
                }
            }
        }
    }
}

// =====================================================================
// NARROW GEMM (N<=128, 1-product): 128x128x64, 3-stage (96KB), 2 CTAs/SM.
// =====================================================================
#define N_STG 32768
#define N_SA 0
#define N_SB 16384
#define HG_SMEM (3 * N_STG)

__global__ void __launch_bounds__(256, 2)
hgemm3_kernel(const unsigned short* __restrict__ Ah,
              int lda, long long sAz,
              const unsigned short* __restrict__ Bh,
              int ldb, long long sBz,
              unsigned short* __restrict__ Ch,
              int ldc, long long sCz,
              const float* __restrict__ rowScale,
              int M, int N, int K,
              float scale) {
    extern __shared__ char smem[];
    uint32_t sbase = smem_u32(smem);

    int tid = threadIdx.x, lane = tid & 31, warp = tid >> 5;
    int wm = warp & 1, wn = warp >> 1;

    long long zz = blockIdx.z;
    Ah += zz * sAz;
    Bh += zz * sBz;
    Ch += zz * sCz;
    if (rowScale) rowScale += zz * M;

    int bm = blockIdx.y * 128;
    int bn = blockIdx.x * 128;
    int mRem = M - bm; if (mRem > 128) mRem = 128;
    int nRem = N - bn; if (nRem > 128) nRem = 128;

    int nch = (K + 63) >> 6;

    int row0 = tid >> 3, ch0 = tid & 7;
    int ch8 = ch0 * 8;
    uint32_t so0 = saddr128(row0, ch0);
    long long gA0 = (long long)(bm + row0) * lda + ch8;
    long long gB0 = (long long)(bn + row0) * ldb + ch8;
    uint32_t szA[4], szB[4];
    #pragma unroll
    for (int i = 0; i < 4; i++) {
        szA[i] = (row0 + 32 * i < mRem) ? 16u : 0u;
        szB[i] = (row0 + 32 * i < nRem) ? 16u : 0u;
    }
    long long ldax = (long long)lda * 32, ldbx = (long long)ldb * 32;

    auto loadStage = [&](int c) {
        uint32_t sb = sbase + (uint32_t)((c % 3) * N_STG);
        long long k0 = (long long)(c << 6);
        uint32_t kok = ((int)(c << 6) + ch8 < K) ? 0xFFFFFFFFu : 0u;
        #pragma unroll
        for (int i = 0; i < 4; i++) {
            cpa16(sb + N_SA + so0 + i * 4096u, Ah + gA0 + i * ldax + k0, szA[i] & kok);
            cpa16(sb + N_SB + so0 + i * 4096u, Bh + gB0 + i * ldbx + k0, szB[i] & kok);
        }
    };

    int frow = lane & 15, fhalf = lane >> 4;
    uint32_t a_rb[4]; int a_x[4];
    #pragma unroll
    for (int mi = 0; mi < 4; mi++) {
        int row = wm * 64 + mi * 16 + frow;
        a_rb[mi] = (uint32_t)(row * 128);
        a_x[mi]  = row & 7;
    }
    uint32_t b_rb[2]; int b_x[2];
    #pragma unroll
    for (int nj = 0; nj < 2; nj++) {
        int row = wn * 32 + nj * 16 + frow;
        b_rb[nj] = (uint32_t)(row * 128);
        b_x[nj]  = row & 7;
    }

    float acc[4][4][4];
    #pragma unroll
    for (int mi = 0; mi < 4; mi++)
        #pragma unroll
        for (int ni = 0; ni < 4; ni++)
            #pragma unroll
            for (int q = 0; q < 4; q++) acc[mi][ni][q] = 0.f;

    loadStage(0); cpa_commit();
    if (nch > 1) loadStage(1);
    cpa_commit();

    for (int c = 0; c < nch; c++) {
        cpa_wait1();
        __syncthreads();
        uint32_t sb = sbase + (uint32_t)((c % 3) * N_STG);

        #pragma unroll
        for (int k16 = 0; k16 < 4; k16++) {
            int chl = k16 * 2 + fhalf;
            uint32_t bH[2][4];
            #pragma unroll
            for (int nj = 0; nj < 2; nj++) {
                uint32_t off = b_rb[nj] + (uint32_t)(((chl ^ b_x[nj])) << 4);
                ldm_x4(bH[nj], sb + N_SB + off);
            }
            #pragma unroll
            for (int mi = 0; mi < 4; mi++) {
                uint32_t aH[4];
                uint32_t off = a_rb[mi] + (uint32_t)(((chl ^ a_x[mi])) << 4);
                ldm_x4(aH, sb + N_SA + off);
                #pragma unroll
                for (int nj = 0; nj < 2; nj++) {
                    mma16816(acc[mi][nj*2+0], aH, bH[nj][0], bH[nj][2]);
                    mma16816(acc[mi][nj*2+1], aH, bH[nj][1], bH[nj][3]);
                }
            }
        }
        if (c + 2 < nch) loadStage(c + 2);
        cpa_commit();
    }

    int erow = lane >> 2;
    int ecol = (lane & 3) * 2;
    #pragma unroll
    for (int mi = 0; mi < 4; mi++) {
        #pragma unroll
        for (int ni = 0; ni < 4; ni++) {
            int gn = bn + wn * 32 + ni * 8 + ecol;
            if (gn >= N) continue;
            float* cc = acc[mi][ni];
            #pragma unroll
            for (int half = 0; half < 2; half++) {
                int gm = bm + wm * 64 + mi * 16 + erow + half * 8;
                if (gm >= M) continue;
                float rs = rowScale ? rowScale[gm] : 1.f;
                float v0 = cc[half * 2 + 0] * scale * rs;
                float v1 = cc[half * 2 + 1] * scale * rs;
                long long o = (long long)gm * ldc + gn;
                __half h0 = __float2half_rn(v0);
                __half h1 = __float2half_rn(v1);
                *reinterpret_cast<ushort2*>(Ch + o) = make_ushort2(
                    *reinterpret_cast<unsigned short*>(&h0),
                    *reinterpret_cast<unsigned short*>(&h1));
            }
        }
    }
}

// =====================================================================
// FUSED SELF-ATTENTION (flash-style). Grid (NH, 19). 256 thr, 8 warps.
// =====================================================================
#define FL_QH 0
#define FL_QL 32768
#define FL_KP0 65536
#define FL_KP1 98304
#define FL_V0 131072
#define FL_V1 163840
#define FL_SMEM 196608

__global__ void __launch_bounds__(256, 1)
flash_kernel(const unsigned short* __restrict__ qh, const unsigned short* __restrict__ ql,
             const unsigned short* __restrict__ kh, const unsigned short* __restrict__ vt,
             unsigned short* __restrict__ yh,
             float ascale) {
    extern __shared__ char smem[];
    uint32_t sb = smem_u32(smem);
    int tid = threadIdx.x, lane = tid & 31, warp = tid >> 5;
    int head = blockIdx.x;
    int q0 = blockIdx.y * 128;

    const unsigned short* kbase = kh + head * HD;
    const unsigned short* vbase = vt + (long long)(head * HD) * L_PAD;

    auto loadQ = [&]() {
        #pragma unroll
        for (int i = 0; i < 8; i++) {
            int idx = tid + i * 256;
            int row = idx >> 4, ch = idx & 15;
            uint32_t sz = (q0 + row < L_Q) ? 16u : 0u;
            long long g = (long long)(q0 + row) * C_DIM + head * HD + ch * 8;
            uint32_t so = saddr256(row, ch);
            cpa16(sb + FL_QH + so, qh + g, sz);
            cpa16(sb + FL_QL + so, ql + g, sz);
        }
    };
    auto loadKV = [&](int c) {
        uint32_t kb = sb + ((c & 1) ? FL_KP1 : FL_KP0);
        uint32_t vb = sb + ((c & 1) ? FL_V1 : FL_V0);
        int kv0 = c * 128;
        #pragma unroll
        for (int i = 0; i < 8; i++) {
            int idx = tid + i * 256;
            int row = idx >> 4, ch = idx & 15;
            uint32_t so = saddr256(row, ch);
            uint32_t sz = (kv0 + row < L_Q) ? 16u : 0u;
            cpa16(kb + so, kbase + (long long)(kv0 + row) * C_DIM + ch * 8, sz);
            cpa16(vb + so, vbase + (long long)row * L_PAD + kv0 + ch * 8, 16u);
        }
    };

    int frow = lane & 15, fhalf = lane >> 4;
    int fx = frow & 7;
    uint32_t a_rb = (uint32_t)((warp * 16 + frow) * 256);
    uint32_t b_rb[8];
    #pragma unroll
    for (int nj = 0; nj < 8; nj++) b_rb[nj] = (uint32_t)((nj * 16 + frow) * 256);

    float m[2] = {-INFINITY, -INFINITY};
    float l[2] = {0.f, 0.f};
    float o[8][2][4];
    #pragma unroll
    for (int dj = 0; dj < 8; dj++)
        #pragma unroll
        for (int t = 0; t < 2; t++)
            #pragma unroll
            for (int q = 0; q < 4; q++) o[dj][t][q] = 0.f;

    loadQ(); loadKV(0); cpa_commit();
    loadKV(1); cpa_commit();

    const int nch = (L_Q + 127) / 128;   // 19
    for (int c = 0; c < nch; c++) {
        cpa_wait1();
        __syncthreads();
        uint32_t kb = sb + ((c & 1) ? FL_KP1 : FL_KP0);
        uint32_t vb = sb + ((c & 1) ? FL_V1 : FL_V0);
        int kvRem = L_Q - c * 128; if (kvRem > 128) kvRem = 128;

        float sacc[8][2][4];
        #pragma unroll
        for (int nj = 0; nj < 8; nj++)
            #pragma unroll
            for (int t = 0; t < 2; t++)
                #pragma unroll
                for (int q = 0; q < 4; q++) sacc[nj][t][q] = 0.f;

        #pragma unroll
        for (int kk = 0; kk < 8; kk++) {
            int chl = kk * 2 + fhalf;
            uint32_t aoff = a_rb + (uint32_t)((chl ^ fx) << 4);
            uint32_t aH[4], aL[4];
            ldm_x4(aH, sb + FL_QH + aoff);
            ldm_x4(aL, sb + FL_QL + aoff);
            #pragma unroll
            for (int nj = 0; nj < 8; nj++) {
                uint32_t bH[4];
                ldm_x4(bH, kb + b_rb[nj] + (uint32_t)((chl ^ fx) << 4));
                mma16816(sacc[nj][0], aH, bH[0], bH[2]);
                mma16816(sacc[nj][1], aH, bH[1], bH[3]);
                mma16816(sacc[nj][0], aL, bH[0], bH[2]);
                mma16816(sacc[nj][1], aL, bH[1], bH[3]);
            }
        }
        __syncthreads();

        int ec = (lane & 3) * 2;
        #pragma unroll
        for (int half = 0; half < 2; half++) {
            float mc = -INFINITY;
            #pragma unroll
            for (int nj = 0; nj < 8; nj++)
                #pragma unroll
                for (int t = 0; t < 2; t++)
                    #pragma unroll
                    for (int j = 0; j < 2; j++) {
                        int col = nj * 16 + t * 8 + ec + j;
                        float v = sacc[nj][t][half * 2 + j] * ascale;
                        sacc[nj][t][half * 2 + j] = v;
                        if (col < kvRem) mc = fmaxf(mc, v);
                    }
            mc = fmaxf(mc, __shfl_xor_sync(0xffffffffu, mc, 1));
            mc = fmaxf(mc, __shfl_xor_sync(0xffffffffu, mc, 2));
            float mn = fmaxf(m[half], mc);
            float corr = __expf(m[half] - mn);
            m[half] = mn;
            float ls = 0.f;
            #pragma unroll
            for (int nj = 0; nj < 8; nj++)
                #pragma unroll
                for (int t = 0; t < 2; t++)
                    #pragma unroll
                    for (int j = 0; j < 2; j++) {
                        int col = nj * 16 + t * 8 + ec + j;
                        float p = (col < kvRem)
                                ? __expf(sacc[nj][t][half * 2 + j] - mn) : 0.f;
                        sacc[nj][t][half * 2 + j] = p;
                        ls += p;
                    }
            l[half] = l[half] * corr + ls;
            #pragma unroll
            for (int dj = 0; dj < 8; dj++)
                #pragma unroll
                for (int t = 0; t < 2; t++)
                    #pragma unroll
                    for (int j = 0; j < 2; j++)
                        o[dj][t][half * 2 + j] *= corr;
        }

        #pragma unroll
        for (int half = 0; half < 2; half++) {
            int row = warp * 16 + (lane >> 2) + half * 8;
            #pragma unroll
            for (int nj = 0; nj < 8; nj++)
                #pragma unroll
                for (int t = 0; t < 2; t++) {
                    int col = nj * 16 + t * 8 + ec;
                    __half p0 = __float2half_rn(sacc[nj][t][half * 2 + 0]);
                    __half p1 = __float2half_rn(sacc[nj][t][half * 2 + 1]);
                    uint32_t addr = kb + (uint32_t)(row * 256 +
                                    (((col >> 3) ^ (row & 7)) << 4) + (col & 7) * 2);
                    uint32_t pk = (uint32_t)*reinterpret_cast<unsigned short*>(&p0)
                                | ((uint32_t)*reinterpret_cast<unsigned short*>(&p1) << 16);
                    asm volatile("st.shared.u32 [%0], %1;" :: "r"(addr), "r"(pk));
                }
        }
        __syncwarp();

        #pragma unroll
        for (int kk = 0; kk < 8; kk++) {
            int chl = kk * 2 + fhalf;
            uint32_t aP[4];
            ldm_x4(aP, kb + a_rb + (uint32_t)((chl ^ fx) << 4));
            #pragma unroll
            for (int dj = 0; dj < 8; dj++) {
                uint32_t bV[4];
                ldm_x4(bV, vb + b_rb[dj] + (uint32_t)((chl ^ fx) << 4));
                mma16816(o[dj][0], aP, bV[0], bV[2]);
                mma16816(o[dj][1], aP, bV[1], bV[3]);
            }
        }
        __syncthreads();
        if (c + 2 < nch) loadKV(c + 2);
        cpa_commit();
    }

    int ec = (lane & 3) * 2;
    #pragma unroll
    for (int half = 0; half < 2; half++) {
        float ls = l[half];
        ls += __shfl_xor_sync(0xffffffffu, ls, 1);
        ls += __shfl_xor_sync(0xffffffffu, ls, 2);
        float inv = 1.f / ls;
        int gm = q0 + warp * 16 + (lane >> 2) + half * 8;
        if (gm >= L_Q) continue;
        #pragma unroll
        for (int dj = 0; dj < 8; dj++)
            #pragma unroll
            for (int t = 0; t < 2; t++) {
                int gd = head * HD + dj * 16 + t * 8 + ec;
                float v0 = o[dj][t][half * 2 + 0] * inv;
                float v1 = o[dj][t][half * 2 + 1] * inv;
                __half h0 = __float2half_rn(v0);
                __half h1 = __float2half_rn(v1);
                long long off = (long long)gm * C_DIM + gd;
                *reinterpret_cast<ushort2*>(yh + off) = make_ushort2(
                    *reinterpret_cast<unsigned short*>(&h0),
                    *reinterpret_cast<unsigned short*>(&h1));
            }
    }
}

// ---------------- host ----------------
static void hgw(const unsigned short* Ah, const unsigned short* Al, int lda, long long sAz,
                const unsigned short* Bh, int ldb, long long sBz,
                float* Cf, unsigned short* Ch, unsigned short* Cl, int ldc, long long sCz,
                const float* rowScale,
                int M, int N, int K, int Z, const float* bias, float scale, int act) {
    dim3 grid((N + 255) / 256, (M + 127) / 128, Z);
    hgemmw_kernel<<<grid, 256, W_SMEM>>>(Ah, Al, lda, sAz, Bh, ldb, sBz,
                                         Cf, Ch, Cl, ldc, sCz, rowScale,
                                         M, N, K, bias, scale, act);
}

static void hgn(const unsigned short* Ah, int lda, long long sAz,
                const unsigned short* Bh, int ldb, long long sBz,
                unsigned short* Ch, int ldc, long long sCz,
                const float* rowScale, int M, int N, int K, int Z, float scale) {
    dim3 grid(1, (M + 127) / 128, Z);
    hgemm3_kernel<<<grid, 256, HG_SMEM>>>(Ah, lda, sAz, Bh, ldb, sBz,
                                          Ch, ldc, sCz, rowScale, M, N, K, scale);
}

static void trh(const float* src, int R, int Ccol, int lds, unsigned short* dh, int ldout) {
    dim3 grid(Ccol / 32, R / 32);
    transpose_h_kernel<<<grid, dim3(32, 8)>>>(src, R, Ccol, lds, dh, ldout);
}

extern "C" void kernel_launch(void* const* d_in, const int* in_sizes, int n_in,
                              void* d_out, int out_size) {
    const float* x        = (const float*)d_in[0];
    const float* e        = (const float*)d_in[1];
    const float* context  = (const float*)d_in[2];
    const float* freqs    = (const float*)d_in[3];
    const float* modulation = (const float*)d_in[7];
    const float* sa_q_w = (const float*)d_in[8];
    const float* sa_q_b = (const float*)d_in[9];
    const float* sa_k_w = (const float*)d_in[10];
    const float* sa_k_b = (const float*)d_in[11];
    const float* sa_v_w = (const float*)d_in[12];
    const float* sa_v_b = (const float*)d_in[13];
    const float* sa_o_w = (const float*)d_in[14];
    const float* sa_o_b = (const float*)d_in[15];
    const float* sa_nq_w = (const float*)d_in[16];
    const float* sa_nk_w = (const float*)d_in[17];
    const float* ca_q_w = (const float*)d_in[18];
    const float* ca_q_b = (const float*)d_in[19];
    const float* ca_k_w = (const float*)d_in[20];
    const float* ca_k_b = (const float*)d_in[21];
    const float* ca_v_w = (const float*)d_in[22];
    const float* ca_v_b = (const float*)d_in[23];
    const float* ca_o_w = (const float*)d_in[24];
    const float* ca_o_b = (const float*)d_in[25];
    const float* ca_nq_w = (const float*)d_in[26];
    const float* ca_nk_w = (const float*)d_in[27];
    const float* ffn_w1 = (const float*)d_in[28];
    const float* ffn_b1 = (const float*)d_in[29];
    const float* ffn_w2 = (const float*)d_in[30];
    const float* ffn_b2 = (const float*)d_in[31];
    float* out = (float*)d_out;

    cudaFuncSetAttribute(hgemm3_kernel,
                         cudaFuncAttributeMaxDynamicSharedMemorySize, HG_SMEM);
    cudaFuncSetAttribute(hgemmw_kernel,
                         cudaFuncAttributeMaxDynamicSharedMemorySize, W_SMEM);
    cudaFuncSetAttribute(flash_kernel,
                         cudaFuncAttributeMaxDynamicSharedMemorySize, FL_SMEM);

    float *em, *q, *t, *s, *b3, *rinv;
    unsigned short *hh, *hl, *qh, *ql, *kh, *vth, *yh;
    unsigned short *oh, *cxh, *cxl, *ph, *ffh, *wh;
    cudaGetSymbolAddress((void**)&em, g_em);
    cudaGetSymbolAddress((void**)&q,  g_q);
    cudaGetSymbolAddress((void**)&t,  g_t);
    cudaGetSymbolAddress((void**)&s,  g_s);
    cudaGetSymbolAddress((void**)&b3, g_b3);
    cudaGetSymbolAddress((void**)&rinv, g_rinv);
    cudaGetSymbolAddress((void**)&hh, g_hh);  cudaGetSymbolAddress((void**)&hl, g_hl);
    cudaGetSymbolAddress((void**)&qh, g_qh);  cudaGetSymbolAddress((void**)&ql, g_ql);
    cudaGetSymbolAddress((void**)&kh, g_kh);
    cudaGetSymbolAddress((void**)&vth, g_vth);
    cudaGetSymbolAddress((void**)&yh, g_yh);
    cudaGetSymbolAddress((void**)&oh, g_oh);
    cudaGetSymbolAddress((void**)&cxh, g_cxh); cudaGetSymbolAddress((void**)&cxl, g_cxl);
    cudaGetSymbolAddress((void**)&ph, g_ph);
    cudaGetSymbolAddress((void**)&ffh, g_ffh);
    cudaGetSymbolAddress((void**)&wh, g_wh);

    const float ascale = 0.08838834764831845f;   // 1/sqrt(128)
    const long long LC = (long long)L_Q * C_DIM;
    int eltBlocks = (int)((LC + 255) / 256);

    em_kernel<<<(6 * C_DIM + 255) / 256, 256>>>(e, modulation, em);

    // ================= self attention =================
    ln_mod_split_kernel<<<L_Q, 256>>>(x, em + 0 * C_DIM, em + 1 * C_DIM, hh, hl);
    trh(sa_q_w, C_DIM, C_DIM, C_DIM, wh, C_DIM);
    trh(sa_k_w, C_DIM, C_DIM, C_DIM, wh + (long long)C_DIM * C_DIM, C_DIM);
    trh(sa_v_w, C_DIM, C_DIM, C_DIM, wh + 2LL * C_DIM * C_DIM, C_DIM);
    pack3_kernel<<<(3 * C_DIM + 255) / 256, 256>>>(sa_q_b, sa_k_b, sa_v_b, b3);
    float* qkv = s;   // [2400, 4608] fp32
    hgw(hh, hl, C_DIM, 0, wh, C_DIM, 0, qkv, nullptr, nullptr, 3 * C_DIM, 0,
        nullptr, L_Q, 3 * C_DIM, C_DIM, 1, b3, 1.f, 0);
    rms_rope_split_kernel<<<L_Q, 256>>>(qkv + 0 * C_DIM, 3 * C_DIM, sa_nq_w, freqs, qh, ql);
    rms_rope_split_kernel<<<L_Q, 256>>>(qkv + 1 * C_DIM, 3 * C_DIM, sa_nk_w, freqs, kh, nullptr);
    trh(qkv + 2 * C_DIM, L_Q, C_DIM, 3 * C_DIM, vth, L_PAD);   // V^T [1536, 2432]
    zero_pad_kernel<<<(C_DIM * 32 + 255) / 256, 256>>>(vth);
    flash_kernel<<<dim3(NH, (L_Q + 127) / 128), 256, FL_SMEM>>>(
        qh, ql, kh, vth, yh, ascale);
    trh(sa_o_w, C_DIM, C_DIM, C_DIM, wh, C_DIM);
    // O-proj: 1-product
    hgw(yh, nullptr, C_DIM, 0, wh, C_DIM, 0, t, nullptr, nullptr, C_DIM, 0,
        nullptr, L_Q, C_DIM, C_DIM, 1, sa_o_b, 1.f, 0);
    residual_mul_conv_kernel<<<eltBlocks, 256>>>(x, t, em + 2 * C_DIM, out, oh);

    // ================= cross attention =================
    trh(ca_q_w, C_DIM, C_DIM, C_DIM, wh, C_DIM);
    // q-proj: 1-product
    hgw(oh, nullptr, C_DIM, 0, wh, C_DIM, 0, q, nullptr, nullptr, C_DIM, 0,
        nullptr, L_Q, C_DIM, C_DIM, 1, ca_q_b, 1.f, 0);
    rms_split_kernel<<<L_Q, 256>>>(q, C_DIM, ca_nq_w, qh, ql);
    conv_split_kernel<<<(int)(((long long)L_KV * C_DIM + 255) / 256), 256>>>(
        context, (long long)L_KV * C_DIM, cxh, cxl);
    trh(ca_k_w, C_DIM, C_DIM, C_DIM, wh, C_DIM);
    trh(ca_v_w, C_DIM, C_DIM, C_DIM, wh + (long long)C_DIM * C_DIM, C_DIM);
    pack2_kernel<<<(2 * C_DIM + 255) / 256, 256>>>(ca_k_b, ca_v_b, b3);
    float* kvbuf = s;   // [512, 3072] fp32
    hgw(cxh, cxl, C_DIM, 0, wh, C_DIM, 0, kvbuf, nullptr, nullptr, 2 * C_DIM, 0,
        nullptr, L_KV, 2 * C_DIM, C_DIM, 1, b3, 1.f, 0);
    rms_split_kernel<<<L_KV, 256>>>(kvbuf + 0 * C_DIM, 2 * C_DIM, ca_nk_w, kh, nullptr);
    trh(kvbuf + 1 * C_DIM, L_KV, C_DIM, 2 * C_DIM, vth, L_KV);   // V^T [1536, 512]
    hgw(qh, ql, C_DIM, HD, kh, C_DIM, HD, nullptr, ph, nullptr,
        L_KV, (long long)L_Q * L_KV, nullptr, L_Q, L_KV, HD, NH, nullptr, ascale, 0);
    softmax_rowinv_h_kernel<<<NH * L_Q, 256>>>(ph, L_KV, rinv);
    hgn(ph, L_KV, (long long)L_Q * L_KV, vth, L_KV, (long long)HD * L_KV,
        yh, C_DIM, HD, rinv, L_Q, HD, L_KV, NH, 1.f);
    trh(ca_o_w, C_DIM, C_DIM, C_DIM, wh, C_DIM);
    // o-proj: 1-product
    hgw(yh, nullptr, C_DIM, 0, wh, C_DIM, 0, t, nullptr, nullptr, C_DIM, 0,
        nullptr, L_Q, C_DIM, C_DIM, 1, ca_o_b, 1.f, 0);
    // fused: out += t; then FFN LN -> hh
    add_ln_mod_split_kernel<<<L_Q, 256>>>(out, t, em + 3 * C_DIM, em + 4 * C_DIM, hh);

    // ================= FFN =================
    trh(ffn_w1, C_DIM, FF_DIM, FF_DIM, wh, C_DIM);
    hgw(hh, nullptr, C_DIM, 0, wh, C_DIM, 0, nullptr, ffh, nullptr, FF_DIM, 0,
        nullptr, L_Q, FF_DIM, C_DIM, 1, ffn_b1, 1.f, 1);  // 1-product + GELU
    trh(ffn_w2, FF_DIM, C_DIM, C_DIM, wh, FF_DIM);
    hgw(ffh, nullptr, FF_DIM, 0, wh, FF_DIM, 0, t, nullptr, nullptr, C_DIM, 0,
        nullptr, L_Q, C_DIM, FF_DIM, 1, ffn_b2, 1.f, 0);  // 1-product
    addmul_inplace_kernel<<<eltBlocks, 256>>>(out, t, em + 5 * C_DIM);
}

// round 14
// speedup vs baseline: 2.2409x; 1.2978x over previous
#include <cuda_runtime.h>
#include <cuda_fp16.h>
#include <stdint.h>
#include <math.h>

// Problem constants
#define C_DIM 1536
#define L_Q   2400
#define L_KV  512
#define NH    12
#define HD    128
#define FF_DIM 8960
#define EPS   1e-6f
#define L_PAD 2432

// ---------------- device scratch ----------------
__device__ __align__(256) float g_em[6 * C_DIM];
__device__ __align__(256) float g_q [L_Q * C_DIM];
__device__ __align__(256) float g_t [L_Q * C_DIM];
__device__ __align__(256) float g_s [L_Q * 3 * C_DIM];    // fused-proj fp32 scratch
__device__ __align__(256) float g_b3[3 * C_DIM];
__device__ __align__(256) unsigned short g_hh[L_Q * C_DIM], g_hl[L_Q * C_DIM];
__device__ __align__(256) unsigned short g_qh[L_Q * C_DIM], g_ql[L_Q * C_DIM];
__device__ __align__(256) unsigned short g_kh[L_Q * C_DIM];
__device__ __align__(256) unsigned short g_vth[C_DIM * L_PAD];
__device__ __align__(256) unsigned short g_yh[L_Q * C_DIM];
__device__ __align__(256) unsigned short g_oh[L_Q * C_DIM];
__device__ __align__(256) unsigned short g_cxh[L_KV * C_DIM], g_cxl[L_KV * C_DIM];
__device__ __align__(256) unsigned short g_ffh[L_Q * FF_DIM];
__device__ __align__(256) unsigned short g_wh[FF_DIM * C_DIM];

// ---------------- helpers ----------------
__device__ __forceinline__ float block_reduce(float v, float* sh, bool is_max) {
    __syncthreads();
    int lane = threadIdx.x & 31, warp = threadIdx.x >> 5;
    #pragma unroll
    for (int o = 16; o > 0; o >>= 1) {
        float other = __shfl_down_sync(0xffffffffu, v, o);
        v = is_max ? fmaxf(v, other) : v + other;
    }
    if (lane == 0) sh[warp] = v;
    __syncthreads();
    int nw = blockDim.x >> 5;
    if (warp == 0) {
        v = (lane < nw) ? sh[lane] : (is_max ? -INFINITY : 0.f);
        #pragma unroll
        for (int o = 16; o > 0; o >>= 1) {
            float other = __shfl_down_sync(0xffffffffu, v, o);
            v = is_max ? fmaxf(v, other) : v + other;
        }
        if (lane == 0) sh[0] = v;
    }
    __syncthreads();
    return sh[0];
}

__device__ __forceinline__ float gelu_tanh(float v) {
    float v3 = v * v * v;
    return 0.5f * v * (1.f + tanhf(0.7978845608028654f * (v + 0.044715f * v3)));
}

static __device__ __forceinline__ void split_f16(float v, unsigned short& h, unsigned short& l) {
    __half hb = __float2half_rn(v);
    float r = v - __half2float(hb);
    __half lb = __float2half_rn(r);
    h = *reinterpret_cast<unsigned short*>(&hb);
    l = *reinterpret_cast<unsigned short*>(&lb);
}

// ---------------- elementwise / norm kernels ----------------
__global__ void em_kernel(const float* __restrict__ e, const float* __restrict__ mod,
                          float* __restrict__ em) {
    int i = blockIdx.x * blockDim.x + threadIdx.x;
    if (i < 6 * C_DIM) em[i] = e[i] + mod[i];
}

__global__ void pack3_kernel(const float* __restrict__ a, const float* __restrict__ b,
                             const float* __restrict__ c, float* __restrict__ d) {
    int i = blockIdx.x * blockDim.x + threadIdx.x;
    if (i < C_DIM) d[i] = a[i];
    else if (i < 2 * C_DIM) d[i] = b[i - C_DIM];
    else if (i < 3 * C_DIM) d[i] = c[i - 2 * C_DIM];
}

__global__ void pack2_kernel(const float* __restrict__ a, const float* __restrict__ b,
                             float* __restrict__ d) {
    int i = blockIdx.x * blockDim.x + threadIdx.x;
    if (i < C_DIM) d[i] = a[i];
    else if (i < 2 * C_DIM) d[i] = b[i - C_DIM];
}

__global__ void zero_pad_kernel(unsigned short* __restrict__ vt) {
    int i = blockIdx.x * blockDim.x + threadIdx.x;
    int r = i >> 5, c = i & 31;
    if (r < C_DIM) vt[(long long)r * L_PAD + L_Q + c] = 0;
}

__global__ void ln_mod_split_kernel(const float* __restrict__ x, const float* __restrict__ e0,
                                    const float* __restrict__ e1,
                                    unsigned short* __restrict__ oh, unsigned short* __restrict__ ol) {
    __shared__ float sh[32];
    long long row = blockIdx.x;
    const float* xr = x + row * C_DIM;
    float s = 0.f, s2 = 0.f;
    for (int c = threadIdx.x; c < C_DIM; c += blockDim.x) {
        float v = xr[c];
        s += v; s2 += v * v;
    }
    float S  = block_reduce(s,  sh, false);
    float S2 = block_reduce(s2, sh, false);
    float m   = S  * (1.f / C_DIM);
    float var = S2 * (1.f / C_DIM) - m * m;
    float inv = rsqrtf(var + EPS);
    for (int c = threadIdx.x; c < C_DIM; c += blockDim.x) {
        float v = e0[c] + (xr[c] - m) * inv * (1.f + e1[c]);
        unsigned short h, l; split_f16(v, h, l);
        oh[row * C_DIM + c] = h;
        if (ol) ol[row * C_DIM + c] = l;
    }
}

// fused: x += t; then h = e0 + LN(x)*(1+e1)  (hi only)
__global__ void add_ln_mod_split_kernel(float* __restrict__ x, const float* __restrict__ t,
                                        const float* __restrict__ e0, const float* __restrict__ e1,
                                        unsigned short* __restrict__ oh) {
    __shared__ float sh[32];
    long long row = blockIdx.x;
    float* xr = x + row * C_DIM;
    const float* tr = t + row * C_DIM;
    float s = 0.f, s2 = 0.f;
    for (int c = threadIdx.x; c < C_DIM; c += blockDim.x) {
        float v = xr[c] + tr[c];
        xr[c] = v;
        s += v; s2 += v * v;
    }
    float S  = block_reduce(s,  sh, false);
    float S2 = block_reduce(s2, sh, false);
    float m   = S  * (1.f / C_DIM);
    float var = S2 * (1.f / C_DIM) - m * m;
    float inv = rsqrtf(var + EPS);
    for (int c = threadIdx.x; c < C_DIM; c += blockDim.x) {
        float v = e0[c] + (xr[c] - m) * inv * (1.f + e1[c]);
        __half hv = __float2half_rn(v);
        oh[row * C_DIM + c] = *reinterpret_cast<unsigned short*>(&hv);
    }
}

__global__ void rms_rope_split_kernel(const float* __restrict__ x, int ldx,
                                      const float* __restrict__ w,
                                      const float* __restrict__ freqs,
                                      unsigned short* __restrict__ dh, unsigned short* __restrict__ dl) {
    __shared__ float sh[32];
    int row = blockIdx.x;
    const float* xr = x + (long long)row * ldx;
    float s2 = 0.f;
    for (int c = threadIdx.x; c < C_DIM; c += blockDim.x) {
        float v = xr[c]; s2 += v * v;
    }
    float S2 = block_reduce(s2, sh, false);
    float inv = rsqrtf(S2 * (1.f / C_DIM) + EPS);
    int f  = row / 1200;
    int rm = row % 1200;
    int hh = rm / 40;
    int ww = rm % 40;
    for (int p = threadIdx.x; p < NH * 64; p += blockDim.x) {
        int n = p >> 6, j = p & 63;
        int pos = (j < 22) ? f : ((j < 43) ? hh : ww);
        float cs = freqs[(pos * 64 + j) * 2 + 0];
        float sn = freqs[(pos * 64 + j) * 2 + 1];
        int c = n * HD + 2 * j;
        float a = xr[c] * inv * w[c];
        float b = xr[c + 1] * inv * w[c + 1];
        float o0 = a * cs - b * sn;
        float o1 = a * sn + b * cs;
        unsigned short h0, l0, h1, l1;
        split_f16(o0, h0, l0); split_f16(o1, h1, l1);
        long long o = (long long)row * C_DIM + c;
        dh[o] = h0;
        dh[o + 1] = h1;
        if (dl) { dl[o] = l0; dl[o + 1] = l1; }
    }
}

__global__ void rms_split_kernel(const float* __restrict__ x, int ldx,
                                 const float* __restrict__ w,
                                 unsigned short* __restrict__ dh, unsigned short* __restrict__ dl) {
    __shared__ float sh[32];
    long long row = blockIdx.x;
    const float* xr = x + row * ldx;
    float s2 = 0.f;
    for (int c = threadIdx.x; c < C_DIM; c += blockDim.x) {
        float v = xr[c]; s2 += v * v;
    }
    float S2 = block_reduce(s2, sh, false);
    float inv = rsqrtf(S2 * (1.f / C_DIM) + EPS);
    for (int c = threadIdx.x; c < C_DIM; c += blockDim.x) {
        float v = xr[c] * inv * w[c];
        unsigned short h, l; split_f16(v, h, l);
        dh[row * C_DIM + c] = h;
        if (dl) dl[row * C_DIM + c] = l;
    }
}

__global__ void conv_split_kernel(const float* __restrict__ src, long long n,
                                  unsigned short* __restrict__ dh, unsigned short* __restrict__ dl) {
    long long i = (long long)blockIdx.x * blockDim.x + threadIdx.x;
    if (i < n) {
        unsigned short h, l; split_f16(src[i], h, l);
        dh[i] = h; dl[i] = l;
    }
}

// [R, Ccol] fp32 (row stride lds) -> [Ccol, R(ldout)] fp16 HI ONLY
__global__ void transpose_h_kernel(const float* __restrict__ src, int R, int Ccol, int lds,
                                   unsigned short* __restrict__ dh, int ldout) {
    __shared__ float tile[32][33];
    int bx = blockIdx.x, by = blockIdx.y;
    int tx = threadIdx.x, ty = threadIdx.y;  // 32 x 8
    #pragma unroll
    for (int i = 0; i < 4; i++) {
        int r = by * 32 + ty + i * 8;
        tile[ty + i * 8][tx] = src[(long long)r * lds + bx * 32 + tx];
    }
    __syncthreads();
    #pragma unroll
    for (int i = 0; i < 4; i++) {
        int ro = bx * 32 + ty + i * 8;
        int co = by * 32 + tx;
        __half hv = __float2half_rn(tile[tx][ty + i * 8]);
        dh[(long long)ro * ldout + co] = *reinterpret_cast<unsigned short*>(&hv);
    }
}

// out = xin + t*e; emit hi only
__global__ void residual_mul_conv_kernel(const float* __restrict__ xin, const float* __restrict__ t,
                                         const float* __restrict__ ecol, float* __restrict__ out,
                                         unsigned short* __restrict__ oh) {
    long long i = (long long)blockIdx.x * blockDim.x + threadIdx.x;
    if (i < (long long)L_Q * C_DIM) {
        float v = xin[i] + t[i] * ecol[i % C_DIM];
        out[i] = v;
        __half hv = __float2half_rn(v);
        oh[i] = *reinterpret_cast<unsigned short*>(&hv);
    }
}

__global__ void addmul_inplace_kernel(float* __restrict__ x, const float* __restrict__ t,
                                      const float* __restrict__ ecol) {
    long long i = (long long)blockIdx.x * blockDim.x + threadIdx.x;
    if (i < (long long)L_Q * C_DIM) x[i] += t[i] * ecol[i % C_DIM];
}

// ---------------- common GEMM asm helpers ----------------
static __device__ __forceinline__ uint32_t smem_u32(const void* p) {
    uint32_t r;
    asm("{ .reg .u64 t; cvta.to.shared.u64 t, %1; cvt.u32.u64 %0, t; }" : "=r"(r) : "l"(p));
    return r;
}
static __device__ __forceinline__ void cpa16(uint32_t s, const void* g, uint32_t sz) {
    asm volatile("cp.async.cg.shared.global [%0], [%1], 16, %2;" :: "r"(s), "l"(g), "r"(sz));
}
static __device__ __forceinline__ void cpa_commit() {
    asm volatile("cp.async.commit_group;");
}
static __device__ __forceinline__ void cpa_wait1() {
    asm volatile("cp.async.wait_group 1;");
}
static __device__ __forceinline__ void cpa_wait2() {
    asm volatile("cp.async.wait_group 2;");
}
static __device__ __forceinline__ void ldm_x4(uint32_t* r, uint32_t addr) {
    asm volatile("ldmatrix.sync.aligned.m8n8.x4.shared.b16 {%0,%1,%2,%3}, [%4];"
                 : "=r"(r[0]), "=r"(r[1]), "=r"(r[2]), "=r"(r[3]) : "r"(addr));
}
static __device__ __forceinline__ void mma16816(float* c, const uint32_t* a, uint32_t b0, uint32_t b1) {
    asm volatile("mma.sync.aligned.m16n8k16.row.col.f32.f16.f16.f32 "
                 "{%0,%1,%2,%3}, {%4,%5,%6,%7}, {%8,%9}, {%0,%1,%2,%3};"
                 : "+f"(c[0]), "+f"(c[1]), "+f"(c[2]), "+f"(c[3])
                 : "r"(a[0]), "r"(a[1]), "r"(a[2]), "r"(a[3]), "r"(b0), "r"(b1));
}
static __device__ __forceinline__ uint32_t saddr128(int row, int ch) {
    return (uint32_t)(row * 128 + ((ch ^ (row & 7)) << 4));
}
static __device__ __forceinline__ uint32_t saddr256(int row, int ch) {
    return (uint32_t)(row * 256 + ((ch ^ (row & 7)) << 4));
}

// =====================================================================
// WIDE GEMM: 128x256x64, warp tile 64x64, templated on USEAL.
//   USEAL: 3 stages x 64KB.  !USEAL: 4 stages x 48KB.  Both 192KB.
// =====================================================================
#define W_SMEM 196608

template<bool USEAL>
__global__ void __launch_bounds__(256, 1)
hgemmw_kernel(const unsigned short* __restrict__ Ah, const unsigned short* __restrict__ Al,
              int lda, long long sAz,
              const unsigned short* __restrict__ Bh,
              int ldb, long long sBz,
              float* __restrict__ Cf, unsigned short* __restrict__ Ch,
              int ldc, long long sCz,
              int M, int N, int K,
              const float* __restrict__ bias, float scale, int act) {
    constexpr uint32_t STG   = USEAL ? 65536u : 49152u;
    constexpr int      NSTG  = USEAL ? 3 : 4;
    constexpr uint32_t SA_H  = 0;
    constexpr uint32_t SA_L  = 16384;                 // only if USEAL
    constexpr uint32_t SB_H  = USEAL ? 32768u : 16384u;

    extern __shared__ char smem[];
    uint32_t sbase = smem_u32(smem);

    int tid = threadIdx.x, lane = tid & 31, warp = tid >> 5;
    int wm = warp & 1, wn = warp >> 1;

    long long zz = blockIdx.z;
    Ah += zz * sAz; if (USEAL) Al += zz * sAz;
    Bh += zz * sBz;
    if (Cf) Cf += zz * sCz;
    if (Ch) Ch += zz * sCz;

    int bm = blockIdx.y * 128;
    int bn = blockIdx.x * 256;
    int mRem = M - bm; if (mRem > 128) mRem = 128;
    int nRem = N - bn; if (nRem > 256) nRem = 256;

    int nch = K >> 6;

    int row0 = tid >> 3, ch0 = tid & 7;
    uint32_t so0 = saddr128(row0, ch0);
    long long gA0 = (long long)(bm + row0) * lda + ch0 * 8;
    long long gB0 = (long long)(bn + row0) * ldb + ch0 * 8;
    uint32_t szA[4], szB[8];
    #pragma unroll
    for (int i = 0; i < 4; i++) szA[i] = (row0 + 32 * i < mRem) ? 16u : 0u;
    #pragma unroll
    for (int i = 0; i < 8; i++) szB[i] = (row0 + 32 * i < nRem) ? 16u : 0u;
    long long ldax = (long long)lda * 32, ldbx = (long long)ldb * 32;

    auto loadStage = [&](int c) {
        uint32_t sb = sbase + (uint32_t)((c % NSTG) * STG);
        long long k0 = (long long)(c << 6);
        #pragma unroll
        for (int i = 0; i < 4; i++) {
            cpa16(sb + SA_H + so0 + i * 4096u, Ah + gA0 + i * ldax + k0, szA[i]);
            if (USEAL)
                cpa16(sb + SA_L + so0 + i * 4096u, Al + gA0 + i * ldax + k0, szA[i]);
        }
        #pragma unroll
        for (int i = 0; i < 8; i++)
            cpa16(sb + SB_H + so0 + i * 4096u, Bh + gB0 + i * ldbx + k0, szB[i]);
    };

    int frow = lane & 15, fhalf = lane >> 4;
    uint32_t a_rb[4]; int a_x[4];
    #pragma unroll
    for (int mi = 0; mi < 4; mi++) {
        int row = wm * 64 + mi * 16 + frow;
        a_rb[mi] = (uint32_t)(row * 128);
        a_x[mi]  = row & 7;
    }
    uint32_t b_rb[4]; int b_x[4];
    #pragma unroll
    for (int nj = 0; nj < 4; nj++) {
        int row = wn * 64 + nj * 16 + frow;
        b_rb[nj] = (uint32_t)(row * 128);
        b_x[nj]  = row & 7;
    }

    float acc[4][8][4];
    #pragma unroll
    for (int mi = 0; mi < 4; mi++)
        #pragma unroll
        for (int ni = 0; ni < 8; ni++)
            #pragma unroll
            for (int q = 0; q < 4; q++) acc[mi][ni][q] = 0.f;

    #pragma unroll
    for (int p = 0; p < NSTG - 1; p++) {
        if (p < nch) loadStage(p);
        cpa_commit();
    }

    for (int c = 0; c < nch; c++) {
        if (NSTG == 3) cpa_wait1(); else cpa_wait2();
        __syncthreads();
        uint32_t sb = sbase + (uint32_t)((c % NSTG) * STG);

        #pragma unroll
        for (int k16 = 0; k16 < 4; k16++) {
            int chl = k16 * 2 + fhalf;
            uint32_t bH[4][4];
            #pragma unroll
            for (int nj = 0; nj < 4; nj++) {
                uint32_t off = b_rb[nj] + (uint32_t)(((chl ^ b_x[nj])) << 4);
                ldm_x4(bH[nj], sb + SB_H + off);
            }
            #pragma unroll
            for (int mi = 0; mi < 4; mi++) {
                uint32_t aH[4], aL[4];
                uint32_t off = a_rb[mi] + (uint32_t)(((chl ^ a_x[mi])) << 4);
                ldm_x4(aH, sb + SA_H + off);
                if (USEAL) ldm_x4(aL, sb + SA_L + off);
                #pragma unroll
                for (int nj = 0; nj < 4; nj++) {
                    mma16816(acc[mi][nj*2+0], aH, bH[nj][0], bH[nj][2]);
                    mma16816(acc[mi][nj*2+1], aH, bH[nj][1], bH[nj][3]);
                    if (USEAL) {
                        mma16816(acc[mi][nj*2+0], aL, bH[nj][0], bH[nj][2]);
                        mma16816(acc[mi][nj*2+1], aL, bH[nj][1], bH[nj][3]);
                    }
                }
            }
        }
        if (c + NSTG - 1 < nch) loadStage(c + NSTG - 1);
        cpa_commit();
    }

    int erow = lane >> 2;
    int ecol = (lane & 3) * 2;
    #pragma unroll
    for (int mi = 0; mi < 4; mi++) {
        #pragma unroll
        for (int ni = 0; ni < 8; ni++) {
            int gn = bn + wn * 64 + (ni >> 1) * 16 + (ni & 1) * 8 + ecol;
            if (gn >= N) continue;
            float b0 = 0.f, b1 = 0.f;
            if (bias) { b0 = bias[gn]; b1 = bias[gn + 1]; }
            float* cc = acc[mi][ni];
            #pragma unroll
            for (int half = 0; half < 2; half++) {
                int gm = bm + wm * 64 + mi * 16 + erow + half * 8;
                if (gm >= M) continue;
                float v0 = cc[half * 2 + 0] * scale + b0;
                float v1 = cc[half * 2 + 1] * scale + b1;
                if (act == 1) { v0 = gelu_tanh(v0); v1 = gelu_tanh(v1); }
                long long o = (long long)gm * ldc + gn;
                if (Cf) *reinterpret_cast<float2*>(Cf + o) = make_float2(v0, v1);
                if (Ch) {
                    __half h0 = __float2half_rn(v0);
                    __half h1 = __float2half_rn(v1);
                    *reinterpret_cast<ushort2*>(Ch + o) = make_ushort2(
                        *reinterpret_cast<unsigned short*>(&h0),
                        *reinterpret_cast<unsigned short*>(&h1));
                }
            }
        }
    }
}

// =====================================================================
// FUSED ATTENTION (flash-style), generalized over (lkv, ldv).
//   Grid (NH, ceil(L_Q/128)). 256 thr, 8 warps, each warp 16 q rows.
// =====================================================================
#define FL_QH 0
#define FL_QL 32768
#define FL_KP0 65536
#define FL_KP1 98304
#define FL_V0 131072
#define FL_V1 163840
#define FL_SMEM 196608

__global__ void __launch_bounds__(256, 1)
flash_kernel(const unsigned short* __restrict__ qh, const unsigned short* __restrict__ ql,
             const unsigned short* __restrict__ kh, const unsigned short* __restrict__ vt,
             unsigned short* __restrict__ yh,
             float ascale, int lkv, int ldv) {
    extern __shared__ char smem[];
    uint32_t sb = smem_u32(smem);
    int tid = threadIdx.x, lane = tid & 31, warp = tid >> 5;
    int head = blockIdx.x;
    int q0 = blockIdx.y * 128;

    const unsigned short* kbase = kh + head * HD;
    const unsigned short* vbase = vt + (long long)(head * HD) * ldv;

    auto loadQ = [&]() {
        #pragma unroll
        for (int i = 0; i < 8; i++) {
            int idx = tid + i * 256;
            int row = idx >> 4, ch = idx & 15;
            uint32_t sz = (q0 + row < L_Q) ? 16u : 0u;
            long long g = (long long)(q0 + row) * C_DIM + head * HD + ch * 8;
            uint32_t so = saddr256(row, ch);
            cpa16(sb + FL_QH + so, qh + g, sz);
            cpa16(sb + FL_QL + so, ql + g, sz);
        }
    };
    auto loadKV = [&](int c) {
        uint32_t kb = sb + ((c & 1) ? FL_KP1 : FL_KP0);
        uint32_t vb = sb + ((c & 1) ? FL_V1 : FL_V0);
        int kv0 = c * 128;
        #pragma unroll
        for (int i = 0; i < 8; i++) {
            int idx = tid + i * 256;
            int row = idx >> 4, ch = idx & 15;
            uint32_t so = saddr256(row, ch);
            uint32_t sz = (kv0 + row < lkv) ? 16u : 0u;
            cpa16(kb + so, kbase + (long long)(kv0 + row) * C_DIM + ch * 8, sz);
            cpa16(vb + so, vbase + (long long)row * ldv + kv0 + ch * 8, 16u);
        }
    };

    int frow = lane & 15, fhalf = lane >> 4;
    int fx = frow & 7;
    uint32_t a_rb = (uint32_t)((warp * 16 + frow) * 256);
    uint32_t b_rb[8];
    #pragma unroll
    for (int nj = 0; nj < 8; nj++) b_rb[nj] = (uint32_t)((nj * 16 + frow) * 256);

    float m[2] = {-INFINITY, -INFINITY};
    float l[2] = {0.f, 0.f};
    float o[8][2][4];
    #pragma unroll
    for (int dj = 0; dj < 8; dj++)
        #pragma unroll
        for (int t = 0; t < 2; t++)
            #pragma unroll
            for (int q = 0; q < 4; q++) o[dj][t][q] = 0.f;

    loadQ(); loadKV(0); cpa_commit();
    const int nch = (lkv + 127) / 128;
    if (nch > 1) loadKV(1);
    cpa_commit();

    for (int c = 0; c < nch; c++) {
        cpa_wait1();
        __syncthreads();
        uint32_t kb = sb + ((c & 1) ? FL_KP1 : FL_KP0);
        uint32_t vb = sb + ((c & 1) ? FL_V1 : FL_V0);
        int kvRem = lkv - c * 128; if (kvRem > 128) kvRem = 128;

        float sacc[8][2][4];
        #pragma unroll
        for (int nj = 0; nj < 8; nj++)
            #pragma unroll
            for (int t = 0; t < 2; t++)
                #pragma unroll
                for (int q = 0; q < 4; q++) sacc[nj][t][q] = 0.f;

        #pragma unroll
        for (int kk = 0; kk < 8; kk++) {
            int chl = kk * 2 + fhalf;
            uint32_t aoff = a_rb + (uint32_t)((chl ^ fx) << 4);
            uint32_t aH[4], aL[4];
            ldm_x4(aH, sb + FL_QH + aoff);
            ldm_x4(aL, sb + FL_QL + aoff);
            #pragma unroll
            for (int nj = 0; nj < 8; nj++) {
                uint32_t bH[4];
                ldm_x4(bH, kb + b_rb[nj] + (uint32_t)((chl ^ fx) << 4));
                mma16816(sacc[nj][0], aH, bH[0], bH[2]);
                mma16816(sacc[nj][1], aH, bH[1], bH[3]);
                mma16816(sacc[nj][0], aL, bH[0], bH[2]);
                mma16816(sacc[nj][1], aL, bH[1], bH[3]);
            }
        }
        __syncthreads();

        int ec = (lane & 3) * 2;
        #pragma unroll
        for (int half = 0; half < 2; half++) {
            float mc = -INFINITY;
            #pragma unroll
            for (int nj = 0; nj < 8; nj++)
                #pragma unroll
                for (int t = 0; t < 2; t++)
                    #pragma unroll
                    for (int j = 0; j < 2; j++) {
                        int col = nj * 16 + t * 8 + ec + j;
                        float v = sacc[nj][t][half * 2 + j] * ascale;
                        sacc[nj][t][half * 2 + j] = v;
                        if (col < kvRem) mc = fmaxf(mc, v);
                    }
            mc = fmaxf(mc, __shfl_xor_sync(0xffffffffu, mc, 1));
            mc = fmaxf(mc, __shfl_xor_sync(0xffffffffu, mc, 2));
            float mn = fmaxf(m[half], mc);
            float corr = __expf(m[half] - mn);
            m[half] = mn;
            float ls = 0.f;
            #pragma unroll
            for (int nj = 0; nj < 8; nj++)
                #pragma unroll
                for (int t = 0; t < 2; t++)
                    #pragma unroll
                    for (int j = 0; j < 2; j++) {
                        int col = nj * 16 + t * 8 + ec + j;
                        float p = (col < kvRem)
                                ? __expf(sacc[nj][t][half * 2 + j] - mn) : 0.f;
                        sacc[nj][t][half * 2 + j] = p;
                        ls += p;
                    }
            l[half] = l[half] * corr + ls;
            #pragma unroll
            for (int dj = 0; dj < 8; dj++)
                #pragma unroll
                for (int t = 0; t < 2; t++)
                    #pragma unroll
                    for (int j = 0; j < 2; j++)
                        o[dj][t][half * 2 + j] *= corr;
        }

        #pragma unroll
        for (int half = 0; half < 2; half++) {
            int row = warp * 16 + (lane >> 2) + half * 8;
            #pragma unroll
            for (int nj = 0; nj < 8; nj++)
                #pragma unroll
                for (int t = 0; t < 2; t++) {
                    int col = nj * 16 + t * 8 + ec;
                    __half p0 = __float2half_rn(sacc[nj][t][half * 2 + 0]);
                    __half p1 = __float2half_rn(sacc[nj][t][half * 2 + 1]);
                    uint32_t addr = kb + (uint32_t)(row * 256 +
                                    (((col >> 3) ^ (row & 7)) << 4) + (col & 7) * 2);
                    uint32_t pk = (uint32_t)*reinterpret_cast<unsigned short*>(&p0)
                                | ((uint32_t)*reinterpret_cast<unsigned short*>(&p1) << 16);
                    asm volatile("st.shared.u32 [%0], %1;" :: "r"(addr), "r"(pk));
                }
        }
        __syncwarp();

        #pragma unroll
        for (int kk = 0; kk < 8; kk++) {
            int chl = kk * 2 + fhalf;
            uint32_t aP[4];
            ldm_x4(aP, kb + a_rb + (uint32_t)((chl ^ fx) << 4));
            #pragma unroll
            for (int dj = 0; dj < 8; dj++) {
                uint32_t bV[4];
                ldm_x4(bV, vb + b_rb[dj] + (uint32_t)((chl ^ fx) << 4));
                mma16816(o[dj][0], aP, bV[0], bV[2]);
                mma16816(o[dj][1], aP, bV[1], bV[3]);
            }
        }
        __syncthreads();
        if (c + 2 < nch) loadKV(c + 2);
        cpa_commit();
    }

    int ec = (lane & 3) * 2;
    #pragma unroll
    for (int half = 0; half < 2; half++) {
        float ls = l[half];
        ls += __shfl_xor_sync(0xffffffffu, ls, 1);
        ls += __shfl_xor_sync(0xffffffffu, ls, 2);
        float inv = 1.f / ls;
        int gm = q0 + warp * 16 + (lane >> 2) + half * 8;
        if (gm >= L_Q) continue;
        #pragma unroll
        for (int dj = 0; dj < 8; dj++)
            #pragma unroll
            for (int t = 0; t < 2; t++) {
                int gd = head * HD + dj * 16 + t * 8 + ec;
                float v0 = o[dj][t][half * 2 + 0] * inv;
                float v1 = o[dj][t][half * 2 + 1] * inv;
                __half h0 = __float2half_rn(v0);
                __half h1 = __float2half_rn(v1);
                long long off = (long long)gm * C_DIM + gd;
                *reinterpret_cast<ushort2*>(yh + off) = make_ushort2(
                    *reinterpret_cast<unsigned short*>(&h0),
                    *reinterpret_cast<unsigned short*>(&h1));
            }
    }
}

// ---------------- host ----------------
static void hgw(const unsigned short* Ah, const unsigned short* Al, int lda, long long sAz,
                const unsigned short* Bh, int ldb, long long sBz,
                float* Cf, unsigned short* Ch, int ldc, long long sCz,
                int M, int N, int K, int Z, const float* bias, float scale, int act) {
    dim3 grid((N + 255) / 256, (M + 127) / 128, Z);
    if (Al)
        hgemmw_kernel<true><<<grid, 256, W_SMEM>>>(Ah, Al, lda, sAz, Bh, ldb, sBz,
                                                   Cf, Ch, ldc, sCz, M, N, K, bias, scale, act);
    else
        hgemmw_kernel<false><<<grid, 256, W_SMEM>>>(Ah, nullptr, lda, sAz, Bh, ldb, sBz,
                                                    Cf, Ch, ldc, sCz, M, N, K, bias, scale, act);
}

static void trh(const float* src, int R, int Ccol, int lds, unsigned short* dh, int ldout) {
    dim3 grid(Ccol / 32, R / 32);
    transpose_h_kernel<<<grid, dim3(32, 8)>>>(src, R, Ccol, lds, dh, ldout);
}

extern "C" void kernel_launch(void* const* d_in, const int* in_sizes, int n_in,
                              void* d_out, int out_size) {
    const float* x        = (const float*)d_in[0];
    const float* e        = (const float*)d_in[1];
    const float* context  = (const float*)d_in[2];
    const float* freqs    = (const float*)d_in[3];
    const float* modulation = (const float*)d_in[7];
    const float* sa_q_w = (const float*)d_in[8];
    const float* sa_q_b = (const float*)d_in[9];
    const float* sa_k_w = (const float*)d_in[10];
    const float* sa_k_b = (const float*)d_in[11];
    const float* sa_v_w = (const float*)d_in[12];
    const float* sa_v_b = (const float*)d_in[13];
    const float* sa_o_w = (const float*)d_in[14];
    const float* sa_o_b = (const float*)d_in[15];
    const float* sa_nq_w = (const float*)d_in[16];
    const float* sa_nk_w = (const float*)d_in[17];
    const float* ca_q_w = (const float*)d_in[18];
    const float* ca_q_b = (const float*)d_in[19];
    const float* ca_k_w = (const float*)d_in[20];
    const float* ca_k_b = (const float*)d_in[21];
    const float* ca_v_w = (const float*)d_in[22];
    const float* ca_v_b = (const float*)d_in[23];
    const float* ca_o_w = (const float*)d_in[24];
    const float* ca_o_b = (const float*)d_in[25];
    const float* ca_nq_w = (const float*)d_in[26];
    const float* ca_nk_w = (const float*)d_in[27];
    const float* ffn_w1 = (const float*)d_in[28];
    const float* ffn_b1 = (const float*)d_in[29];
    const float* ffn_w2 = (const float*)d_in[30];
    const float* ffn_b2 = (const float*)d_in[31];
    float* out = (float*)d_out;

    cudaFuncSetAttribute(hgemmw_kernel<true>,
                         cudaFuncAttributeMaxDynamicSharedMemorySize, W_SMEM);
    cudaFuncSetAttribute(hgemmw_kernel<false>,
                         cudaFuncAttributeMaxDynamicSharedMemorySize, W_SMEM);
    cudaFuncSetAttribute(flash_kernel,
                         cudaFuncAttributeMaxDynamicSharedMemorySize, FL_SMEM);

    float *em, *q, *t, *s, *b3;
    unsigned short *hh, *hl, *qh, *ql, *kh, *vth, *yh;
    unsigned short *oh, *cxh, *cxl, *ffh, *wh;
    cudaGetSymbolAddress((void**)&em, g_em);
    cudaGetSymbolAddress((void**)&q,  g_q);
    cudaGetSymbolAddress((void**)&t,  g_t);
    cudaGetSymbolAddress((void**)&s,  g_s);
    cudaGetSymbolAddress((void**)&b3, g_b3);
    cudaGetSymbolAddress((void**)&hh, g_hh);  cudaGetSymbolAddress((void**)&hl, g_hl);
    cudaGetSymbolAddress((void**)&qh, g_qh);  cudaGetSymbolAddress((void**)&ql, g_ql);
    cudaGetSymbolAddress((void**)&kh, g_kh);
    cudaGetSymbolAddress((void**)&vth, g_vth);
    cudaGetSymbolAddress((void**)&yh, g_yh);
    cudaGetSymbolAddress((void**)&oh, g_oh);
    cudaGetSymbolAddress((void**)&cxh, g_cxh); cudaGetSymbolAddress((void**)&cxl, g_cxl);
    cudaGetSymbolAddress((void**)&ffh, g_ffh);
    cudaGetSymbolAddress((void**)&wh, g_wh);

    const float ascale = 0.08838834764831845f;   // 1/sqrt(128)
    const long long LC = (long long)L_Q * C_DIM;
    int eltBlocks = (int)((LC + 255) / 256);

    em_kernel<<<(6 * C_DIM + 255) / 256, 256>>>(e, modulation, em);

    // ================= self attention =================
    ln_mod_split_kernel<<<L_Q, 256>>>(x, em + 0 * C_DIM, em + 1 * C_DIM, hh, hl);
    trh(sa_q_w, C_DIM, C_DIM, C_DIM, wh, C_DIM);
    trh(sa_k_w, C_DIM, C_DIM, C_DIM, wh + (long long)C_DIM * C_DIM, C_DIM);
    trh(sa_v_w, C_DIM, C_DIM, C_DIM, wh + 2LL * C_DIM * C_DIM, C_DIM);
    pack3_kernel<<<(3 * C_DIM + 255) / 256, 256>>>(sa_q_b, sa_k_b, sa_v_b, b3);
    float* qkv = s;   // [2400, 4608] fp32
    hgw(hh, hl, C_DIM, 0, wh, C_DIM, 0, qkv, nullptr, 3 * C_DIM, 0,
        L_Q, 3 * C_DIM, C_DIM, 1, b3, 1.f, 0);
    rms_rope_split_kernel<<<L_Q, 256>>>(qkv + 0 * C_DIM, 3 * C_DIM, sa_nq_w, freqs, qh, ql);
    rms_rope_split_kernel<<<L_Q, 256>>>(qkv + 1 * C_DIM, 3 * C_DIM, sa_nk_w, freqs, kh, nullptr);
    trh(qkv + 2 * C_DIM, L_Q, C_DIM, 3 * C_DIM, vth, L_PAD);   // V^T [1536, 2432]
    zero_pad_kernel<<<(C_DIM * 32 + 255) / 256, 256>>>(vth);
    flash_kernel<<<dim3(NH, (L_Q + 127) / 128), 256, FL_SMEM>>>(
        qh, ql, kh, vth, yh, ascale, L_Q, L_PAD);
    trh(sa_o_w, C_DIM, C_DIM, C_DIM, wh, C_DIM);
    hgw(yh, nullptr, C_DIM, 0, wh, C_DIM, 0, t, nullptr, C_DIM, 0,
        L_Q, C_DIM, C_DIM, 1, sa_o_b, 1.f, 0);
    residual_mul_conv_kernel<<<eltBlocks, 256>>>(x, t, em + 2 * C_DIM, out, oh);

    // ================= cross attention =================
    trh(ca_q_w, C_DIM, C_DIM, C_DIM, wh, C_DIM);
    hgw(oh, nullptr, C_DIM, 0, wh, C_DIM, 0, q, nullptr, C_DIM, 0,
        L_Q, C_DIM, C_DIM, 1, ca_q_b, 1.f, 0);
    rms_split_kernel<<<L_Q, 256>>>(q, C_DIM, ca_nq_w, qh, ql);
    conv_split_kernel<<<(int)(((long long)L_KV * C_DIM + 255) / 256), 256>>>(
        context, (long long)L_KV * C_DIM, cxh, cxl);
    trh(ca_k_w, C_DIM, C_DIM, C_DIM, wh, C_DIM);
    trh(ca_v_w, C_DIM, C_DIM, C_DIM, wh + (long long)C_DIM * C_DIM, C_DIM);
    pack2_kernel<<<(2 * C_DIM + 255) / 256, 256>>>(ca_k_b, ca_v_b, b3);
    float* kvbuf = s;   // [512, 3072] fp32
    hgw(cxh, cxl, C_DIM, 0, wh, C_DIM, 0, kvbuf, nullptr, 2 * C_DIM, 0,
        L_KV, 2 * C_DIM, C_DIM, 1, b3, 1.f, 0);
    rms_split_kernel<<<L_KV, 256>>>(kvbuf + 0 * C_DIM, 2 * C_DIM, ca_nk_w, kh, nullptr);
    trh(kvbuf + 1 * C_DIM, L_KV, C_DIM, 2 * C_DIM, vth, L_KV);   // V^T [1536, 512]
    // fused cross attention (lkv = 512, ldv = 512)
    flash_kernel<<<dim3(NH, (L_Q + 127) / 128), 256, FL_SMEM>>>(
        qh, ql, kh, vth, yh, ascale, L_KV, L_KV);
    trh(ca_o_w, C_DIM, C_DIM, C_DIM, wh, C_DIM);
    hgw(yh, nullptr, C_DIM, 0, wh, C_DIM, 0, t, nullptr, C_DIM, 0,
        L_Q, C_DIM, C_DIM, 1, ca_o_b, 1.f, 0);
    add_ln_mod_split_kernel<<<L_Q, 256>>>(out, t, em + 3 * C_DIM, em + 4 * C_DIM, hh);

    // ================= FFN =================
    trh(ffn_w1, C_DIM, FF_DIM, FF_DIM, wh, C_DIM);
    hgw(hh, nullptr, C_DIM, 0, wh, C_DIM, 0, nullptr, ffh, FF_DIM, 0,
        L_Q, FF_DIM, C_DIM, 1, ffn_b1, 1.f, 1);  // 1-product + GELU
    trh(ffn_w2, FF_DIM, C_DIM, C_DIM, wh, FF_DIM);
    hgw(ffh, nullptr, FF_DIM, 0, wh, FF_DIM, 0, t, nullptr, C_DIM, 0,
        L_Q, C_DIM, FF_DIM, 1, ffn_b2, 1.f, 0);  // 1-product
    addmul_inplace_kernel<<<eltBlocks, 256>>>(out, t, em + 5 * C_DIM);
}

// round 15
// speedup vs baseline: 2.2521x; 1.0050x over previous
#include <cuda_runtime.h>
#include <cuda_fp16.h>
#include <stdint.h>
#include <math.h>

// Problem constants
#define C_DIM 1536
#define L_Q   2400
#define L_KV  512
#define NH    12
#define HD    128
#define FF_DIM 8960
#define EPS   1e-6f
#define L_PAD 2432

// ---------------- device scratch ----------------
__device__ __align__(256) float g_em[6 * C_DIM];
__device__ __align__(256) float g_q [L_Q * C_DIM];
__device__ __align__(256) float g_t [L_Q * C_DIM];
__device__ __align__(256) float g_s [L_Q * 3 * C_DIM];    // fused-proj fp32 scratch
__device__ __align__(256) float g_b3[3 * C_DIM];
__device__ __align__(256) unsigned short g_hh[L_Q * C_DIM], g_hl[L_Q * C_DIM];
__device__ __align__(256) unsigned short g_qh[L_Q * C_DIM];
__device__ __align__(256) unsigned short g_kh[L_Q * C_DIM];
__device__ __align__(256) unsigned short g_vth[C_DIM * L_PAD];
__device__ __align__(256) unsigned short g_yh[L_Q * C_DIM];
__device__ __align__(256) unsigned short g_oh[L_Q * C_DIM];
__device__ __align__(256) unsigned short g_cxh[L_KV * C_DIM], g_cxl[L_KV * C_DIM];
__device__ __align__(256) unsigned short g_ffh[L_Q * FF_DIM];
__device__ __align__(256) unsigned short g_wh[FF_DIM * C_DIM];

// ---------------- helpers ----------------
__device__ __forceinline__ float block_reduce(float v, float* sh, bool is_max) {
    __syncthreads();
    int lane = threadIdx.x & 31, warp = threadIdx.x >> 5;
    #pragma unroll
    for (int o = 16; o > 0; o >>= 1) {
        float other = __shfl_down_sync(0xffffffffu, v, o);
        v = is_max ? fmaxf(v, other) : v + other;
    }
    if (lane == 0) sh[warp] = v;
    __syncthreads();
    int nw = blockDim.x >> 5;
    if (warp == 0) {
        v = (lane < nw) ? sh[lane] : (is_max ? -INFINITY : 0.f);
        #pragma unroll
        for (int o = 16; o > 0; o >>= 1) {
            float other = __shfl_down_sync(0xffffffffu, v, o);
            v = is_max ? fmaxf(v, other) : v + other;
        }
        if (lane == 0) sh[0] = v;
    }
    __syncthreads();
    return sh[0];
}

__device__ __forceinline__ float gelu_tanh(float v) {
    float v3 = v * v * v;
    return 0.5f * v * (1.f + tanhf(0.7978845608028654f * (v + 0.044715f * v3)));
}

static __device__ __forceinline__ void split_f16(float v, unsigned short& h, unsigned short& l) {
    __half hb = __float2half_rn(v);
    float r = v - __half2float(hb);
    __half lb = __float2half_rn(r);
    h = *reinterpret_cast<unsigned short*>(&hb);
    l = *reinterpret_cast<unsigned short*>(&lb);
}

// ---------------- elementwise / norm kernels ----------------
__global__ void em_kernel(const float* __restrict__ e, const float* __restrict__ mod,
                          float* __restrict__ em) {
    int i = blockIdx.x * blockDim.x + threadIdx.x;
    if (i < 6 * C_DIM) em[i] = e[i] + mod[i];
}

__global__ void pack3_kernel(const float* __restrict__ a, const float* __restrict__ b,
                             const float* __restrict__ c, float* __restrict__ d) {
    int i = blockIdx.x * blockDim.x + threadIdx.x;
    if (i < C_DIM) d[i] = a[i];
    else if (i < 2 * C_DIM) d[i] = b[i - C_DIM];
    else if (i < 3 * C_DIM) d[i] = c[i - 2 * C_DIM];
}

__global__ void pack2_kernel(const float* __restrict__ a, const float* __restrict__ b,
                             float* __restrict__ d) {
    int i = blockIdx.x * blockDim.x + threadIdx.x;
    if (i < C_DIM) d[i] = a[i];
    else if (i < 2 * C_DIM) d[i] = b[i - C_DIM];
}

__global__ void zero_pad_kernel(unsigned short* __restrict__ vt) {
    int i = blockIdx.x * blockDim.x + threadIdx.x;
    int r = i >> 5, c = i & 31;
    if (r < C_DIM) vt[(long long)r * L_PAD + L_Q + c] = 0;
}

__global__ void ln_mod_split_kernel(const float* __restrict__ x, const float* __restrict__ e0,
                                    const float* __restrict__ e1,
                                    unsigned short* __restrict__ oh, unsigned short* __restrict__ ol) {
    __shared__ float sh[32];
    long long row = blockIdx.x;
    const float* xr = x + row * C_DIM;
    float s = 0.f, s2 = 0.f;
    for (int c = threadIdx.x; c < C_DIM; c += blockDim.x) {
        float v = xr[c];
        s += v; s2 += v * v;
    }
    float S  = block_reduce(s,  sh, false);
    float S2 = block_reduce(s2, sh, false);
    float m   = S  * (1.f / C_DIM);
    float var = S2 * (1.f / C_DIM) - m * m;
    float inv = rsqrtf(var + EPS);
    for (int c = threadIdx.x; c < C_DIM; c += blockDim.x) {
        float v = e0[c] + (xr[c] - m) * inv * (1.f + e1[c]);
        unsigned short h, l; split_f16(v, h, l);
        oh[row * C_DIM + c] = h;
        if (ol) ol[row * C_DIM + c] = l;
    }
}

__global__ void rms_rope_split_kernel(const float* __restrict__ x, int ldx,
                                      const float* __restrict__ w,
                                      const float* __restrict__ freqs,
                                      unsigned short* __restrict__ dh) {
    __shared__ float sh[32];
    int row = blockIdx.x;
    const float* xr = x + (long long)row * ldx;
    float s2 = 0.f;
    for (int c = threadIdx.x; c < C_DIM; c += blockDim.x) {
        float v = xr[c]; s2 += v * v;
    }
    float S2 = block_reduce(s2, sh, false);
    float inv = rsqrtf(S2 * (1.f / C_DIM) + EPS);
    int f  = row / 1200;
    int rm = row % 1200;
    int hh = rm / 40;
    int ww = rm % 40;
    for (int p = threadIdx.x; p < NH * 64; p += blockDim.x) {
        int n = p >> 6, j = p & 63;
        int pos = (j < 22) ? f : ((j < 43) ? hh : ww);
        float cs = freqs[(pos * 64 + j) * 2 + 0];
        float sn = freqs[(pos * 64 + j) * 2 + 1];
        int c = n * HD + 2 * j;
        float a = xr[c] * inv * w[c];
        float b = xr[c + 1] * inv * w[c + 1];
        float o0 = a * cs - b * sn;
        float o1 = a * sn + b * cs;
        __half h0 = __float2half_rn(o0);
        __half h1 = __float2half_rn(o1);
        long long o = (long long)row * C_DIM + c;
        *reinterpret_cast<ushort2*>(dh + o) = make_ushort2(
            *reinterpret_cast<unsigned short*>(&h0),
            *reinterpret_cast<unsigned short*>(&h1));
    }
}

__global__ void rms_split_kernel(const float* __restrict__ x, int ldx,
                                 const float* __restrict__ w,
                                 unsigned short* __restrict__ dh) {
    __shared__ float sh[32];
    long long row = blockIdx.x;
    const float* xr = x + row * ldx;
    float s2 = 0.f;
    for (int c = threadIdx.x; c < C_DIM; c += blockDim.x) {
        float v = xr[c]; s2 += v * v;
    }
    float S2 = block_reduce(s2, sh, false);
    float inv = rsqrtf(S2 * (1.f / C_DIM) + EPS);
    for (int c = threadIdx.x; c < C_DIM; c += blockDim.x) {
        float v = xr[c] * inv * w[c];
        __half hv = __float2half_rn(v);
        dh[row * C_DIM + c] = *reinterpret_cast<unsigned short*>(&hv);
    }
}

__global__ void conv_split_kernel(const float* __restrict__ src, long long n,
                                  unsigned short* __restrict__ dh, unsigned short* __restrict__ dl) {
    long long i = (long long)blockIdx.x * blockDim.x + threadIdx.x;
    if (i < n) {
        unsigned short h, l; split_f16(src[i], h, l);
        dh[i] = h; dl[i] = l;
    }
}

// [R, Ccol] fp32 (row stride lds) -> [Ccol, R(ldout)] fp16 HI ONLY
__global__ void transpose_h_kernel(const float* __restrict__ src, int R, int Ccol, int lds,
                                   unsigned short* __restrict__ dh, int ldout) {
    __shared__ float tile[32][33];
    int bx = blockIdx.x, by = blockIdx.y;
    int tx = threadIdx.x, ty = threadIdx.y;  // 32 x 8
    #pragma unroll
    for (int i = 0; i < 4; i++) {
        int r = by * 32 + ty + i * 8;
        tile[ty + i * 8][tx] = src[(long long)r * lds + bx * 32 + tx];
    }
    __syncthreads();
    #pragma unroll
    for (int i = 0; i < 4; i++) {
        int ro = bx * 32 + ty + i * 8;
        int co = by * 32 + tx;
        __half hv = __float2half_rn(tile[tx][ty + i * 8]);
        dh[(long long)ro * ldout + co] = *reinterpret_cast<unsigned short*>(&hv);
    }
}

// ---------------- common GEMM asm helpers ----------------
static __device__ __forceinline__ uint32_t smem_u32(const void* p) {
    uint32_t r;
    asm("{ .reg .u64 t; cvta.to.shared.u64 t, %1; cvt.u32.u64 %0, t; }" : "=r"(r) : "l"(p));
    return r;
}
static __device__ __forceinline__ void cpa16(uint32_t s, const void* g, uint32_t sz) {
    asm volatile("cp.async.cg.shared.global [%0], [%1], 16, %2;" :: "r"(s), "l"(g), "r"(sz));
}
static __device__ __forceinline__ void cpa_commit() {
    asm volatile("cp.async.commit_group;");
}
static __device__ __forceinline__ void cpa_wait1() {
    asm volatile("cp.async.wait_group 1;");
}
static __device__ __forceinline__ void cpa_wait2() {
    asm volatile("cp.async.wait_group 2;");
}
static __device__ __forceinline__ void ldm_x4(uint32_t* r, uint32_t addr) {
    asm volatile("ldmatrix.sync.aligned.m8n8.x4.shared.b16 {%0,%1,%2,%3}, [%4];"
                 : "=r"(r[0]), "=r"(r[1]), "=r"(r[2]), "=r"(r[3]) : "r"(addr));
}
static __device__ __forceinline__ void mma16816(float* c, const uint32_t* a, uint32_t b0, uint32_t b1) {
    asm volatile("mma.sync.aligned.m16n8k16.row.col.f32.f16.f16.f32 "
                 "{%0,%1,%2,%3}, {%4,%5,%6,%7}, {%8,%9}, {%0,%1,%2,%3};"
                 : "+f"(c[0]), "+f"(c[1]), "+f"(c[2]), "+f"(c[3])
                 : "r"(a[0]), "r"(a[1]), "r"(a[2]), "r"(a[3]), "r"(b0), "r"(b1));
}
static __device__ __forceinline__ uint32_t saddr128(int row, int ch) {
    return (uint32_t)(row * 128 + ((ch ^ (row & 7)) << 4));
}
static __device__ __forceinline__ uint32_t saddr256(int row, int ch) {
    return (uint32_t)(row * 256 + ((ch ^ (row & 7)) << 4));
}

// =====================================================================
// WIDE GEMM: 128x256x64, warp tile 64x64, templated on USEAL.
//   USEAL: 3 stages x 64KB.  !USEAL: 4 stages x 48KB.  Both 192KB.
//   Epilogue: v = acc*scale + bias; [gelu]; if resid: v = resid + v*ecol.
// =====================================================================
#define W_SMEM 196608

template<bool USEAL>
__global__ void __launch_bounds__(256, 1)
hgemmw_kernel(const unsigned short* __restrict__ Ah, const unsigned short* __restrict__ Al,
              int lda, long long sAz,
              const unsigned short* __restrict__ Bh,
              int ldb, long long sBz,
              float* __restrict__ Cf, unsigned short* __restrict__ Ch,
              int ldc, long long sCz,
              const float* __restrict__ resid, const float* __restrict__ ecol,
              int M, int N, int K,
              const float* __restrict__ bias, float scale, int act) {
    constexpr uint32_t STG   = USEAL ? 65536u : 49152u;
    constexpr int      NSTG  = USEAL ? 3 : 4;
    constexpr uint32_t SA_H  = 0;
    constexpr uint32_t SA_L  = 16384;
    constexpr uint32_t SB_H  = USEAL ? 32768u : 16384u;

    extern __shared__ char smem[];
    uint32_t sbase = smem_u32(smem);

    int tid = threadIdx.x, lane = tid & 31, warp = tid >> 5;
    int wm = warp & 1, wn = warp >> 1;

    long long zz = blockIdx.z;
    Ah += zz * sAz; if (USEAL) Al += zz * sAz;
    Bh += zz * sBz;
    if (Cf) Cf += zz * sCz;
    if (Ch) Ch += zz * sCz;

    int bm = blockIdx.y * 128;
    int bn = blockIdx.x * 256;
    int mRem = M - bm; if (mRem > 128) mRem = 128;
    int nRem = N - bn; if (nRem > 256) nRem = 256;

    int nch = K >> 6;

    int row0 = tid >> 3, ch0 = tid & 7;
    uint32_t so0 = saddr128(row0, ch0);
    long long gA0 = (long long)(bm + row0) * lda + ch0 * 8;
    long long gB0 = (long long)(bn + row0) * ldb + ch0 * 8;
    uint32_t szA[4], szB[8];
    #pragma unroll
    for (int i = 0; i < 4; i++) szA[i] = (row0 + 32 * i < mRem) ? 16u : 0u;
    #pragma unroll
    for (int i = 0; i < 8; i++) szB[i] = (row0 + 32 * i < nRem) ? 16u : 0u;
    long long ldax = (long long)lda * 32, ldbx = (long long)ldb * 32;

    auto loadStage = [&](int c) {
        uint32_t sb = sbase + (uint32_t)((c % NSTG) * STG);
        long long k0 = (long long)(c << 6);
        #pragma unroll
        for (int i = 0; i < 4; i++) {
            cpa16(sb + SA_H + so0 + i * 4096u, Ah + gA0 + i * ldax + k0, szA[i]);
            if (USEAL)
                cpa16(sb + SA_L + so0 + i * 4096u, Al + gA0 + i * ldax + k0, szA[i]);
        }
        #pragma unroll
        for (int i = 0; i < 8; i++)
            cpa16(sb + SB_H + so0 + i * 4096u, Bh + gB0 + i * ldbx + k0, szB[i]);
    };

    int frow = lane & 15, fhalf = lane >> 4;
    uint32_t a_rb[4]; int a_x[4];
    #pragma unroll
    for (int mi = 0; mi < 4; mi++) {
        int row = wm * 64 + mi * 16 + frow;
        a_rb[mi] = (uint32_t)(row * 128);
        a_x[mi]  = row & 7;
    }
    uint32_t b_rb[4]; int b_x[4];
    #pragma unroll
    for (int nj = 0; nj < 4; nj++) {
        int row = wn * 64 + nj * 16 + frow;
        b_rb[nj] = (uint32_t)(row * 128);
        b_x[nj]  = row & 7;
    }

    float acc[4][8][4];
    #pragma unroll
    for (int mi = 0; mi < 4; mi++)
        #pragma unroll
        for (int ni = 0; ni < 8; ni++)
            #pragma unroll
            for (int q = 0; q < 4; q++) acc[mi][ni][q] = 0.f;

    #pragma unroll
    for (int p = 0; p < NSTG - 1; p++) {
        if (p < nch) loadStage(p);
        cpa_commit();
    }

    for (int c = 0; c < nch; c++) {
        if (NSTG == 3) cpa_wait1(); else cpa_wait2();
        __syncthreads();
        uint32_t sb = sbase + (uint32_t)((c % NSTG) * STG);

        #pragma unroll
        for (int k16 = 0; k16 < 4; k16++) {
            int chl = k16 * 2 + fhalf;
            uint32_t bH[4][4];
            #pragma unroll
            for (int nj = 0; nj < 4; nj++) {
                uint32_t off = b_rb[nj] + (uint32_t)(((chl ^ b_x[nj])) << 4);
                ldm_x4(bH[nj], sb + SB_H + off);
            }
            #pragma unroll
            for (int mi = 0; mi < 4; mi++) {
                uint32_t aH[4], aL[4];
                uint32_t off = a_rb[mi] + (uint32_t)(((chl ^ a_x[mi])) << 4);
                ldm_x4(aH, sb + SA_H + off);
                if (USEAL) ldm_x4(aL, sb + SA_L + off);
                #pragma unroll
                for (int nj = 0; nj < 4; nj++) {
                    mma16816(acc[mi][nj*2+0], aH, bH[nj][0], bH[nj][2]);
                    mma16816(acc[mi][nj*2+1], aH, bH[nj][1], bH[nj][3]);
                    if (USEAL) {
                        mma16816(acc[mi][nj*2+0], aL, bH[nj][0], bH[nj][2]);
                        mma16816(acc[mi][nj*2+1], aL, bH[nj][1], bH[nj][3]);
                    }
                }
            }
        }
        if (c + NSTG - 1 < nch) loadStage(c + NSTG - 1);
        cpa_commit();
    }

    int erow = lane >> 2;
    int ecolL = (lane & 3) * 2;
    #pragma unroll
    for (int mi = 0; mi < 4; mi++) {
        #pragma unroll
        for (int ni = 0; ni < 8; ni++) {
            int gn = bn + wn * 64 + (ni >> 1) * 16 + (ni & 1) * 8 + ecolL;
            if (gn >= N) continue;
            float b0 = 0.f, b1 = 0.f;
            if (bias) { b0 = bias[gn]; b1 = bias[gn + 1]; }
            float e0 = 1.f, e1 = 1.f;
            if (ecol) { e0 = ecol[gn]; e1 = ecol[gn + 1]; }
            float* cc = acc[mi][ni];
            #pragma unroll
            for (int half = 0; half < 2; half++) {
                int gm = bm + wm * 64 + mi * 16 + erow + half * 8;
                if (gm >= M) continue;
                float v0 = cc[half * 2 + 0] * scale + b0;
                float v1 = cc[half * 2 + 1] * scale + b1;
                if (act == 1) { v0 = gelu_tanh(v0); v1 = gelu_tanh(v1); }
                long long o = (long long)gm * ldc + gn;
                if (resid) {
                    v0 = resid[o]     + v0 * e0;
                    v1 = resid[o + 1] + v1 * e1;
                }
                if (Cf) *reinterpret_cast<float2*>(Cf + o) = make_float2(v0, v1);
                if (Ch) {
                    __half h0 = __float2half_rn(v0);
                    __half h1 = __float2half_rn(v1);
                    *reinterpret_cast<ushort2*>(Ch + o) = make_ushort2(
                        *reinterpret_cast<unsigned short*>(&h0),
                        *reinterpret_cast<unsigned short*>(&h1));
                }
            }
        }
    }
}

// =====================================================================
// FUSED ATTENTION (flash-style), q hi-only. Grid (NH, ceil(L_Q/128)).
// =====================================================================
#define FL_QH 0
#define FL_KP0 32768
#define FL_KP1 65536
#define FL_V0 98304
#define FL_V1 131072
#define FL_SMEM 163840

__global__ void __launch_bounds__(256, 1)
flash_kernel(const unsigned short* __restrict__ qh,
             const unsigned short* __restrict__ kh, const unsigned short* __restrict__ vt,
             unsigned short* __restrict__ yh,
             float ascale, int lkv, int ldv) {
    extern __shared__ char smem[];
    uint32_t sb = smem_u32(smem);
    int tid = threadIdx.x, lane = tid & 31, warp = tid >> 5;
    int head = blockIdx.x;
    int q0 = blockIdx.y * 128;

    const unsigned short* kbase = kh + head * HD;
    const unsigned short* vbase = vt + (long long)(head * HD) * ldv;

    auto loadQ = [&]() {
        #pragma unroll
        for (int i = 0; i < 8; i++) {
            int idx = tid + i * 256;
            int row = idx >> 4, ch = idx & 15;
            uint32_t sz = (q0 + row < L_Q) ? 16u : 0u;
            long long g = (long long)(q0 + row) * C_DIM + head * HD + ch * 8;
            cpa16(sb + FL_QH + saddr256(row, ch), qh + g, sz);
        }
    };
    auto loadKV = [&](int c) {
        uint32_t kb = sb + ((c & 1) ? FL_KP1 : FL_KP0);
        uint32_t vb = sb + ((c & 1) ? FL_V1 : FL_V0);
        int kv0 = c * 128;
        #pragma unroll
        for (int i = 0; i < 8; i++) {
            int idx = tid + i * 256;
            int row = idx >> 4, ch = idx & 15;
            uint32_t so = saddr256(row, ch);
            uint32_t sz = (kv0 + row < lkv) ? 16u : 0u;
            cpa16(kb + so, kbase + (long long)(kv0 + row) * C_DIM + ch * 8, sz);
            cpa16(vb + so, vbase + (long long)row * ldv + kv0 + ch * 8, 16u);
        }
    };

    int frow = lane & 15, fhalf = lane >> 4;
    int fx = frow & 7;
    uint32_t a_rb = (uint32_t)((warp * 16 + frow) * 256);
    uint32_t b_rb[8];
    #pragma unroll
    for (int nj = 0; nj < 8; nj++) b_rb[nj] = (uint32_t)((nj * 16 + frow) * 256);

    float m[2] = {-INFINITY, -INFINITY};
    float l[2] = {0.f, 0.f};
    float o[8][2][4];
    #pragma unroll
    for (int dj = 0; dj < 8; dj++)
        #pragma unroll
        for (int t = 0; t < 2; t++)
            #pragma unroll
            for (int q = 0; q < 4; q++) o[dj][t][q] = 0.f;

    loadQ(); loadKV(0); cpa_commit();
    const int nch = (lkv + 127) / 128;
    if (nch > 1) loadKV(1);
    cpa_commit();

    for (int c = 0; c < nch; c++) {
        cpa_wait1();
        __syncthreads();
        uint32_t kb = sb + ((c & 1) ? FL_KP1 : FL_KP0);
        uint32_t vb = sb + ((c & 1) ? FL_V1 : FL_V0);
        int kvRem = lkv - c * 128; if (kvRem > 128) kvRem = 128;

        float sacc[8][2][4];
        #pragma unroll
        for (int nj = 0; nj < 8; nj++)
            #pragma unroll
            for (int t = 0; t < 2; t++)
                #pragma unroll
                for (int q = 0; q < 4; q++) sacc[nj][t][q] = 0.f;

        #pragma unroll
        for (int kk = 0; kk < 8; kk++) {
            int chl = kk * 2 + fhalf;
            uint32_t aH[4];
            ldm_x4(aH, sb + FL_QH + a_rb + (uint32_t)((chl ^ fx) << 4));
            #pragma unroll
            for (int nj = 0; nj < 8; nj++) {
                uint32_t bH[4];
                ldm_x4(bH, kb + b_rb[nj] + (uint32_t)((chl ^ fx) << 4));
                mma16816(sacc[nj][0], aH, bH[0], bH[2]);
                mma16816(sacc[nj][1], aH, bH[1], bH[3]);
            }
        }
        __syncthreads();

        int ec = (lane & 3) * 2;
        #pragma unroll
        for (int half = 0; half < 2; half++) {
            float mc = -INFINITY;
            #pragma unroll
            for (int nj = 0; nj < 8; nj++)
                #pragma unroll
                for (int t = 0; t < 2; t++)
                    #pragma unroll
                    for (int j = 0; j < 2; j++) {
                        int col = nj * 16 + t * 8 + ec + j;
                        float v = sacc[nj][t][half * 2 + j] * ascale;
                        sacc[nj][t][half * 2 + j] = v;
                        if (col < kvRem) mc = fmaxf(mc, v);
                    }
            mc = fmaxf(mc, __shfl_xor_sync(0xffffffffu, mc, 1));
            mc = fmaxf(mc, __shfl_xor_sync(0xffffffffu, mc, 2));
            float mn = fmaxf(m[half], mc);
            float corr = __expf(m[half] - mn);
            m[half] = mn;
            float ls = 0.f;
            #pragma unroll
            for (int nj = 0; nj < 8; nj++)
                #pragma unroll
                for (int t = 0; t < 2; t++)
                    #pragma unroll
                    for (int j = 0; j < 2; j++) {
                        int col = nj * 16 + t * 8 + ec + j;
                        float p = (col < kvRem)
                                ? __expf(sacc[nj][t][half * 2 + j] - mn) : 0.f;
                        sacc[nj][t][half * 2 + j] = p;
                        ls += p;
                    }
            l[half] = l[half] * corr + ls;
            #pragma unroll
            for (int dj = 0; dj < 8; dj++)
                #pragma unroll
                for (int t = 0; t < 2; t++)
                    #pragma unroll
                    for (int j = 0; j < 2; j++)
                        o[dj][t][half * 2 + j] *= corr;
        }

        #pragma unroll
        for (int half = 0; half < 2; half++) {
            int row = warp * 16 + (lane >> 2) + half * 8;
            #pragma unroll
            for (int nj = 0; nj < 8; nj++)
                #pragma unroll
                for (int t = 0; t < 2; t++) {
                    int col = nj * 16 + t * 8 + ec;
                    __half p0 = __float2half_rn(sacc[nj][t][half * 2 + 0]);
                    __half p1 = __float2half_rn(sacc[nj][t][half * 2 + 1]);
                    uint32_t addr = kb + (uint32_t)(row * 256 +
                                    (((col >> 3) ^ (row & 7)) << 4) + (col & 7) * 2);
                    uint32_t pk = (uint32_t)*reinterpret_cast<unsigned short*>(&p0)
                                | ((uint32_t)*reinterpret_cast<unsigned short*>(&p1) << 16);
                    asm volatile("st.shared.u32 [%0], %1;" :: "r"(addr), "r"(pk));
                }
        }
        __syncwarp();

        #pragma unroll
        for (int kk = 0; kk < 8; kk++) {
            int chl = kk * 2 + fhalf;
            uint32_t aP[4];
            ldm_x4(aP, kb + a_rb + (uint32_t)((chl ^ fx) << 4));
            #pragma unroll
            for (int dj = 0; dj < 8; dj++) {
                uint32_t bV[4];
                ldm_x4(bV, vb + b_rb[dj] + (uint32_t)((chl ^ fx) << 4));
                mma16816(o[dj][0], aP, bV[0], bV[2]);
                mma16816(o[dj][1], aP, bV[1], bV[3]);
            }
        }
        __syncthreads();
        if (c + 2 < nch) loadKV(c + 2);
        cpa_commit();
    }

    int ec = (lane & 3) * 2;
    #pragma unroll
    for (int half = 0; half < 2; half++) {
        float ls = l[half];
        ls += __shfl_xor_sync(0xffffffffu, ls, 1);
        ls += __shfl_xor_sync(0xffffffffu, ls, 2);
        float inv = 1.f / ls;
        int gm = q0 + warp * 16 + (lane >> 2) + half * 8;
        if (gm >= L_Q) continue;
        #pragma unroll
        for (int dj = 0; dj < 8; dj++)
            #pragma unroll
            for (int t = 0; t < 2; t++) {
                int gd = head * HD + dj * 16 + t * 8 + ec;
                float v0 = o[dj][t][half * 2 + 0] * inv;
                float v1 = o[dj][t][half * 2 + 1] * inv;
                __half h0 = __float2half_rn(v0);
                __half h1 = __float2half_rn(v1);
                long long off = (long long)gm * C_DIM + gd;
                *reinterpret_cast<ushort2*>(yh + off) = make_ushort2(
                    *reinterpret_cast<unsigned short*>(&h0),
                    *reinterpret_cast<unsigned short*>(&h1));
            }
    }
}

// ---------------- host ----------------
static void hgw(const unsigned short* Ah, const unsigned short* Al, int lda, long long sAz,
                const unsigned short* Bh, int ldb, long long sBz,
                float* Cf, unsigned short* Ch, int ldc, long long sCz,
                const float* resid, const float* ecol,
                int M, int N, int K, int Z, const float* bias, float scale, int act) {
    dim3 grid((N + 255) / 256, (M + 127) / 128, Z);
    if (Al)
        hgemmw_kernel<true><<<grid, 256, W_SMEM>>>(Ah, Al, lda, sAz, Bh, ldb, sBz,
                                                   Cf, Ch, ldc, sCz, resid, ecol,
                                                   M, N, K, bias, scale, act);
    else
        hgemmw_kernel<false><<<grid, 256, W_SMEM>>>(Ah, nullptr, lda, sAz, Bh, ldb, sBz,
                                                    Cf, Ch, ldc, sCz, resid, ecol,
                                                    M, N, K, bias, scale, act);
}

static void trh(const float* src, int R, int Ccol, int lds, unsigned short* dh, int ldout) {
    dim3 grid(Ccol / 32, R / 32);
    transpose_h_kernel<<<grid, dim3(32, 8)>>>(src, R, Ccol, lds, dh, ldout);
}

extern "C" void kernel_launch(void* const* d_in, const int* in_sizes, int n_in,
                              void* d_out, int out_size) {
    const float* x        = (const float*)d_in[0];
    const float* e        = (const float*)d_in[1];
    const float* context  = (const float*)d_in[2];
    const float* freqs    = (const float*)d_in[3];
    const float* modulation = (const float*)d_in[7];
    const float* sa_q_w = (const float*)d_in[8];
    const float* sa_q_b = (const float*)d_in[9];
    const float* sa_k_w = (const float*)d_in[10];
    const float* sa_k_b = (const float*)d_in[11];
    const float* sa_v_w = (const float*)d_in[12];
    const float* sa_v_b = (const float*)d_in[13];
    const float* sa_o_w = (const float*)d_in[14];
    const float* sa_o_b = (const float*)d_in[15];
    const float* sa_nq_w = (const float*)d_in[16];
    const float* sa_nk_w = (const float*)d_in[17];
    const float* ca_q_w = (const float*)d_in[18];
    const float* ca_q_b = (const float*)d_in[19];
    const float* ca_k_w = (const float*)d_in[20];
    const float* ca_k_b = (const float*)d_in[21];
    const float* ca_v_w = (const float*)d_in[22];
    const float* ca_v_b = (const float*)d_in[23];
    const float* ca_o_w = (const float*)d_in[24];
    const float* ca_o_b = (const float*)d_in[25];
    const float* ca_nq_w = (const float*)d_in[26];
    const float* ca_nk_w = (const float*)d_in[27];
    const float* ffn_w1 = (const float*)d_in[28];
    const float* ffn_b1 = (const float*)d_in[29];
    const float* ffn_w2 = (const float*)d_in[30];
    const float* ffn_b2 = (const float*)d_in[31];
    float* out = (float*)d_out;

    cudaFuncSetAttribute(hgemmw_kernel<true>,
                         cudaFuncAttributeMaxDynamicSharedMemorySize, W_SMEM);
    cudaFuncSetAttribute(hgemmw_kernel<false>,
                         cudaFuncAttributeMaxDynamicSharedMemorySize, W_SMEM);
    cudaFuncSetAttribute(flash_kernel,
                         cudaFuncAttributeMaxDynamicSharedMemorySize, FL_SMEM);

    float *em, *q, *t, *s, *b3;
    unsigned short *hh, *hl, *qh, *kh, *vth, *yh;
    unsigned short *oh, *cxh, *cxl, *ffh, *wh;
    cudaGetSymbolAddress((void**)&em, g_em);
    cudaGetSymbolAddress((void**)&q,  g_q);
    cudaGetSymbolAddress((void**)&t,  g_t);
    cudaGetSymbolAddress((void**)&s,  g_s);
    cudaGetSymbolAddress((void**)&b3, g_b3);
    cudaGetSymbolAddress((void**)&hh, g_hh);  cudaGetSymbolAddress((void**)&hl, g_hl);
    cudaGetSymbolAddress((void**)&qh, g_qh);
    cudaGetSymbolAddress((void**)&kh, g_kh);
    cudaGetSymbolAddress((void**)&vth, g_vth);
    cudaGetSymbolAddress((void**)&yh, g_yh);
    cudaGetSymbolAddress((void**)&oh, g_oh);
    cudaGetSymbolAddress((void**)&cxh, g_cxh); cudaGetSymbolAddress((void**)&cxl, g_cxl);
    cudaGetSymbolAddress((void**)&ffh, g_ffh);
    cudaGetSymbolAddress((void**)&wh, g_wh);

    const float ascale = 0.08838834764831845f;   // 1/sqrt(128)

    em_kernel<<<(6 * C_DIM + 255) / 256, 256>>>(e, modulation, em);

    // ================= self attention =================
    ln_mod_split_kernel<<<L_Q, 256>>>(x, em + 0 * C_DIM, em + 1 * C_DIM, hh, hl);
    trh(sa_q_w, C_DIM, C_DIM, C_DIM, wh, C_DIM);
    trh(sa_k_w, C_DIM, C_DIM, C_DIM, wh + (long long)C_DIM * C_DIM, C_DIM);
    trh(sa_v_w, C_DIM, C_DIM, C_DIM, wh + 2LL * C_DIM * C_DIM, C_DIM);
    pack3_kernel<<<(3 * C_DIM + 255) / 256, 256>>>(sa_q_b, sa_k_b, sa_v_b, b3);
    float* qkv = s;   // [2400, 4608] fp32
    hgw(hh, hl, C_DIM, 0, wh, C_DIM, 0, qkv, nullptr, 3 * C_DIM, 0,
        nullptr, nullptr, L_Q, 3 * C_DIM, C_DIM, 1, b3, 1.f, 0);
    rms_rope_split_kernel<<<L_Q, 256>>>(qkv + 0 * C_DIM, 3 * C_DIM, sa_nq_w, freqs, qh);
    rms_rope_split_kernel<<<L_Q, 256>>>(qkv + 1 * C_DIM, 3 * C_DIM, sa_nk_w, freqs, kh);
    trh(qkv + 2 * C_DIM, L_Q, C_DIM, 3 * C_DIM, vth, L_PAD);   // V^T [1536, 2432]
    zero_pad_kernel<<<(C_DIM * 32 + 255) / 256, 256>>>(vth);
    flash_kernel<<<dim3(NH, (L_Q + 127) / 128), 256, FL_SMEM>>>(
        qh, kh, vth, yh, ascale, L_Q, L_PAD);
    trh(sa_o_w, C_DIM, C_DIM, C_DIM, wh, C_DIM);
    // O-proj + residual fused: out = x + (y@W+b)*e2 ; oh = f16(out)
    hgw(yh, nullptr, C_DIM, 0, wh, C_DIM, 0, out, oh, C_DIM, 0,
        x, em + 2 * C_DIM, L_Q, C_DIM, C_DIM, 1, sa_o_b, 1.f, 0);

    // ================= cross attention =================
    trh(ca_q_w, C_DIM, C_DIM, C_DIM, wh, C_DIM);
    hgw(oh, nullptr, C_DIM, 0, wh, C_DIM, 0, q, nullptr, C_DIM, 0,
        nullptr, nullptr, L_Q, C_DIM, C_DIM, 1, ca_q_b, 1.f, 0);
    rms_split_kernel<<<L_Q, 256>>>(q, C_DIM, ca_nq_w, qh);
    conv_split_kernel<<<(int)(((long long)L_KV * C_DIM + 255) / 256), 256>>>(
        context, (long long)L_KV * C_DIM, cxh, cxl);
    trh(ca_k_w, C_DIM, C_DIM, C_DIM, wh, C_DIM);
    trh(ca_v_w, C_DIM, C_DIM, C_DIM, wh + (long long)C_DIM * C_DIM, C_DIM);
    pack2_kernel<<<(2 * C_DIM + 255) / 256, 256>>>(ca_k_b, ca_v_b, b3);
    float* kvbuf = s;   // [512, 3072] fp32
    hgw(cxh, cxl, C_DIM, 0, wh, C_DIM, 0, kvbuf, nullptr, 2 * C_DIM, 0,
        nullptr, nullptr, L_KV, 2 * C_DIM, C_DIM, 1, b3, 1.f, 0);
    rms_split_kernel<<<L_KV, 256>>>(kvbuf + 0 * C_DIM, 2 * C_DIM, ca_nk_w, kh);
    trh(kvbuf + 1 * C_DIM, L_KV, C_DIM, 2 * C_DIM, vth, L_KV);   // V^T [1536, 512]
    flash_kernel<<<dim3(NH, (L_Q + 127) / 128), 256, FL_SMEM>>>(
        qh, kh, vth, yh, ascale, L_KV, L_KV);
    trh(ca_o_w, C_DIM, C_DIM, C_DIM, wh, C_DIM);
    // o-proj + add fused: out += y@W+b
    hgw(yh, nullptr, C_DIM, 0, wh, C_DIM, 0, out, nullptr, C_DIM, 0,
        out, nullptr, L_Q, C_DIM, C_DIM, 1, ca_o_b, 1.f, 0);

    // ================= FFN =================
    ln_mod_split_kernel<<<L_Q, 256>>>(out, em + 3 * C_DIM, em + 4 * C_DIM, hh, nullptr);
    trh(ffn_w1, C_DIM, FF_DIM, FF_DIM, wh, C_DIM);
    hgw(hh, nullptr, C_DIM, 0, wh, C_DIM, 0, nullptr, ffh, FF_DIM, 0,
        nullptr, nullptr, L_Q, FF_DIM, C_DIM, 1, ffn_b1, 1.f, 1);
    trh(ffn_w2, FF_DIM, C_DIM, C_DIM, wh, FF_DIM);
    // FFN2 + residual fused: out += (ff@W2+b2)*e5
    hgw(ffh, nullptr, FF_DIM, 0, wh, FF_DIM, 0, out, nullptr, C_DIM, 0,
        out, em + 5 * C_DIM, L_Q, C_DIM, FF_DIM, 1, ffn_b2, 1.f, 0);
}

// round 16
// speedup vs baseline: 2.5522x; 1.1333x over previous
#include <cuda_runtime.h>
#include <cuda_fp16.h>
#include <stdint.h>
#include <math.h>

// Problem constants
#define C_DIM 1536
#define L_Q   2400
#define L_KV  512
#define NH    12
#define HD    128
#define FF_DIM 8960
#define EPS   1e-6f
#define L_PAD 2432

// ---------------- device scratch ----------------
__device__ __align__(256) float g_em[6 * C_DIM];
__device__ __align__(256) float g_q [L_Q * C_DIM];
__device__ __align__(256) float g_s [L_Q * 3 * C_DIM];    // fused-proj fp32 scratch
__device__ __align__(256) float g_b3[3 * C_DIM];
__device__ __align__(256) unsigned short g_hh[L_Q * C_DIM];
__device__ __align__(256) unsigned short g_qh[L_Q * C_DIM];
__device__ __align__(256) unsigned short g_kh[L_Q * C_DIM];
__device__ __align__(256) unsigned short g_vth[C_DIM * L_PAD];
__device__ __align__(256) unsigned short g_yh[L_Q * C_DIM];
__device__ __align__(256) unsigned short g_oh[L_Q * C_DIM];
__device__ __align__(256) unsigned short g_cxh[L_KV * C_DIM];
__device__ __align__(256) unsigned short g_ffh[L_Q * FF_DIM];
__device__ __align__(256) unsigned short g_wA[8 * C_DIM * C_DIM];          // 8 CxC weights^T
__device__ __align__(256) unsigned short g_wF[2 * FF_DIM * C_DIM];         // ffn w1^T, w2^T

// ---------------- helpers ----------------
__device__ __forceinline__ float block_reduce(float v, float* sh, bool is_max) {
    __syncthreads();
    int lane = threadIdx.x & 31, warp = threadIdx.x >> 5;
    #pragma unroll
    for (int o = 16; o > 0; o >>= 1) {
        float other = __shfl_down_sync(0xffffffffu, v, o);
        v = is_max ? fmaxf(v, other) : v + other;
    }
    if (lane == 0) sh[warp] = v;
    __syncthreads();
    int nw = blockDim.x >> 5;
    if (warp == 0) {
        v = (lane < nw) ? sh[lane] : (is_max ? -INFINITY : 0.f);
        #pragma unroll
        for (int o = 16; o > 0; o >>= 1) {
            float other = __shfl_down_sync(0xffffffffu, v, o);
            v = is_max ? fmaxf(v, other) : v + other;
        }
        if (lane == 0) sh[0] = v;
    }
    __syncthreads();
    return sh[0];
}

__device__ __forceinline__ float gelu_tanh(float v) {
    float v3 = v * v * v;
    return 0.5f * v * (1.f + tanhf(0.7978845608028654f * (v + 0.044715f * v3)));
}

// ---------------- elementwise / norm kernels ----------------
__global__ void em_kernel(const float* __restrict__ e, const float* __restrict__ mod,
                          float* __restrict__ em) {
    int i = blockIdx.x * blockDim.x + threadIdx.x;
    if (i < 6 * C_DIM) em[i] = e[i] + mod[i];
}

__global__ void pack3_kernel(const float* __restrict__ a, const float* __restrict__ b,
                             const float* __restrict__ c, float* __restrict__ d) {
    int i = blockIdx.x * blockDim.x + threadIdx.x;
    if (i < C_DIM) d[i] = a[i];
    else if (i < 2 * C_DIM) d[i] = b[i - C_DIM];
    else if (i < 3 * C_DIM) d[i] = c[i - 2 * C_DIM];
}

__global__ void pack2_kernel(const float* __restrict__ a, const float* __restrict__ b,
                             float* __restrict__ d) {
    int i = blockIdx.x * blockDim.x + threadIdx.x;
    if (i < C_DIM) d[i] = a[i];
    else if (i < 2 * C_DIM) d[i] = b[i - C_DIM];
}

__global__ void zero_pad_kernel(unsigned short* __restrict__ vt) {
    int i = blockIdx.x * blockDim.x + threadIdx.x;
    int r = i >> 5, c = i & 31;
    if (r < C_DIM) vt[(long long)r * L_PAD + L_Q + c] = 0;
}

// LN + modulation -> fp16 hi only
__global__ void ln_mod_split_kernel(const float* __restrict__ x, const float* __restrict__ e0,
                                    const float* __restrict__ e1,
                                    unsigned short* __restrict__ oh) {
    __shared__ float sh[32];
    long long row = blockIdx.x;
    const float* xr = x + row * C_DIM;
    float s = 0.f, s2 = 0.f;
    for (int c = threadIdx.x; c < C_DIM; c += blockDim.x) {
        float v = xr[c];
        s += v; s2 += v * v;
    }
    float S  = block_reduce(s,  sh, false);
    float S2 = block_reduce(s2, sh, false);
    float m   = S  * (1.f / C_DIM);
    float var = S2 * (1.f / C_DIM) - m * m;
    float inv = rsqrtf(var + EPS);
    for (int c = threadIdx.x; c < C_DIM; c += blockDim.x) {
        float v = e0[c] + (xr[c] - m) * inv * (1.f + e1[c]);
        __half hv = __float2half_rn(v);
        oh[row * C_DIM + c] = *reinterpret_cast<unsigned short*>(&hv);
    }
}

__global__ void rms_rope_split_kernel(const float* __restrict__ x, int ldx,
                                      const float* __restrict__ w,
                                      const float* __restrict__ freqs,
                                      unsigned short* __restrict__ dh) {
    __shared__ float sh[32];
    int row = blockIdx.x;
    const float* xr = x + (long long)row * ldx;
    float s2 = 0.f;
    for (int c = threadIdx.x; c < C_DIM; c += blockDim.x) {
        float v = xr[c]; s2 += v * v;
    }
    float S2 = block_reduce(s2, sh, false);
    float inv = rsqrtf(S2 * (1.f / C_DIM) + EPS);
    int f  = row / 1200;
    int rm = row % 1200;
    int hh = rm / 40;
    int ww = rm % 40;
    for (int p = threadIdx.x; p < NH * 64; p += blockDim.x) {
        int n = p >> 6, j = p & 63;
        int pos = (j < 22) ? f : ((j < 43) ? hh : ww);
        float cs = freqs[(pos * 64 + j) * 2 + 0];
        float sn = freqs[(pos * 64 + j) * 2 + 1];
        int c = n * HD + 2 * j;
        float a = xr[c] * inv * w[c];
        float b = xr[c + 1] * inv * w[c + 1];
        float o0 = a * cs - b * sn;
        float o1 = a * sn + b * cs;
        __half h0 = __float2half_rn(o0);
        __half h1 = __float2half_rn(o1);
        long long o = (long long)row * C_DIM + c;
        *reinterpret_cast<ushort2*>(dh + o) = make_ushort2(
            *reinterpret_cast<unsigned short*>(&h0),
            *reinterpret_cast<unsigned short*>(&h1));
    }
}

__global__ void rms_split_kernel(const float* __restrict__ x, int ldx,
                                 const float* __restrict__ w,
                                 unsigned short* __restrict__ dh) {
    __shared__ float sh[32];
    long long row = blockIdx.x;
    const float* xr = x + row * ldx;
    float s2 = 0.f;
    for (int c = threadIdx.x; c < C_DIM; c += blockDim.x) {
        float v = xr[c]; s2 += v * v;
    }
    float S2 = block_reduce(s2, sh, false);
    float inv = rsqrtf(S2 * (1.f / C_DIM) + EPS);
    for (int c = threadIdx.x; c < C_DIM; c += blockDim.x) {
        float v = xr[c] * inv * w[c];
        __half hv = __float2half_rn(v);
        dh[row * C_DIM + c] = *reinterpret_cast<unsigned short*>(&hv);
    }
}

__global__ void conv_h_kernel(const float* __restrict__ src, long long n,
                              unsigned short* __restrict__ dh) {
    long long i = (long long)blockIdx.x * blockDim.x + threadIdx.x;
    if (i < n) {
        __half hv = __float2half_rn(src[i]);
        dh[i] = *reinterpret_cast<unsigned short*>(&hv);
    }
}

// [R, Ccol] fp32 (row stride lds) -> [Ccol, R(ldout)] fp16 HI ONLY
__global__ void transpose_h_kernel(const float* __restrict__ src, int R, int Ccol, int lds,
                                   unsigned short* __restrict__ dh, int ldout) {
    __shared__ float tile[32][33];
    int bx = blockIdx.x, by = blockIdx.y;
    int tx = threadIdx.x, ty = threadIdx.y;  // 32 x 8
    #pragma unroll
    for (int i = 0; i < 4; i++) {
        int r = by * 32 + ty + i * 8;
        tile[ty + i * 8][tx] = src[(long long)r * lds + bx * 32 + tx];
    }
    __syncthreads();
    #pragma unroll
    for (int i = 0; i < 4; i++) {
        int ro = bx * 32 + ty + i * 8;
        int co = by * 32 + tx;
        __half hv = __float2half_rn(tile[tx][ty + i * 8]);
        dh[(long long)ro * ldout + co] = *reinterpret_cast<unsigned short*>(&hv);
    }
}

// batched transpose of 8 CxC weights; grid (48, 48, 8)
__global__ void trh8_kernel(const float* p0, const float* p1, const float* p2, const float* p3,
                            const float* p4, const float* p5, const float* p6, const float* p7,
                            unsigned short* __restrict__ dst) {
    __shared__ float tile[32][33];
    const float* srcs[8] = {p0, p1, p2, p3, p4, p5, p6, p7};
    const float* src = srcs[blockIdx.z];
    unsigned short* dh = dst + (long long)blockIdx.z * C_DIM * C_DIM;
    int bx = blockIdx.x, by = blockIdx.y;
    int tx = threadIdx.x, ty = threadIdx.y;
    #pragma unroll
    for (int i = 0; i < 4; i++) {
        int r = by * 32 + ty + i * 8;
        tile[ty + i * 8][tx] = src[(long long)r * C_DIM + bx * 32 + tx];
    }
    __syncthreads();
    #pragma unroll
    for (int i = 0; i < 4; i++) {
        int ro = bx * 32 + ty + i * 8;
        int co = by * 32 + tx;
        __half hv = __float2half_rn(tile[tx][ty + i * 8]);
        dh[(long long)ro * C_DIM + co] = *reinterpret_cast<unsigned short*>(&hv);
    }
}

// ---------------- common GEMM asm helpers ----------------
static __device__ __forceinline__ uint32_t smem_u32(const void* p) {
    uint32_t r;
    asm("{ .reg .u64 t; cvta.to.shared.u64 t, %1; cvt.u32.u64 %0, t; }" : "=r"(r) : "l"(p));
    return r;
}
static __device__ __forceinline__ void cpa16(uint32_t s, const void* g, uint32_t sz) {
    asm volatile("cp.async.cg.shared.global [%0], [%1], 16, %2;" :: "r"(s), "l"(g), "r"(sz));
}
static __device__ __forceinline__ void cpa_commit() {
    asm volatile("cp.async.commit_group;");
}
static __device__ __forceinline__ void cpa_wait1() {
    asm volatile("cp.async.wait_group 1;");
}
static __device__ __forceinline__ void cpa_wait2() {
    asm volatile("cp.async.wait_group 2;");
}
static __device__ __forceinline__ void ldm_x4(uint32_t* r, uint32_t addr) {
    asm volatile("ldmatrix.sync.aligned.m8n8.x4.shared.b16 {%0,%1,%2,%3}, [%4];"
                 : "=r"(r[0]), "=r"(r[1]), "=r"(r[2]), "=r"(r[3]) : "r"(addr));
}
static __device__ __forceinline__ void mma16816(float* c, const uint32_t* a, uint32_t b0, uint32_t b1) {
    asm volatile("mma.sync.aligned.m16n8k16.row.col.f32.f16.f16.f32 "
                 "{%0,%1,%2,%3}, {%4,%5,%6,%7}, {%8,%9}, {%0,%1,%2,%3};"
                 : "+f"(c[0]), "+f"(c[1]), "+f"(c[2]), "+f"(c[3])
                 : "r"(a[0]), "r"(a[1]), "r"(a[2]), "r"(a[3]), "r"(b0), "r"(b1));
}
static __device__ __forceinline__ uint32_t saddr128(int row, int ch) {
    return (uint32_t)(row * 128 + ((ch ^ (row & 7)) << 4));
}
static __device__ __forceinline__ uint32_t saddr256(int row, int ch) {
    return (uint32_t)(row * 256 + ((ch ^ (row & 7)) << 4));
}

// epilogue helper
static __device__ __forceinline__ void epi_store(
    float v0, float v1, long long o,
    float* Cf, unsigned short* Ch,
    const float* resid, float e0, float e1) {
    if (resid) {
        v0 = resid[o]     + v0 * e0;
        v1 = resid[o + 1] + v1 * e1;
    }
    if (Cf) *reinterpret_cast<float2*>(Cf + o) = make_float2(v0, v1);
    if (Ch) {
        __half h0 = __float2half_rn(v0);
        __half h1 = __float2half_rn(v1);
        *reinterpret_cast<ushort2*>(Ch + o) = make_ushort2(
            *reinterpret_cast<unsigned short*>(&h0),
            *reinterpret_cast<unsigned short*>(&h1));
    }
}

// =====================================================================
// WIDE GEMM (1-product): 128x256x64, warp tile 64x64, 4 stages x 48KB.
// =====================================================================
#define W_STG 49152
#define W_SA 0
#define W_SB 16384
#define W_SMEM (4 * W_STG)

__global__ void __launch_bounds__(256, 1)
hgemmw_kernel(const unsigned short* __restrict__ Ah, int lda,
              const unsigned short* __restrict__ Bh, int ldb,
              float* __restrict__ Cf, unsigned short* __restrict__ Ch, int ldc,
              const float* __restrict__ resid, const float* __restrict__ ecol,
              int M, int N, int K,
              const float* __restrict__ bias, float scale, int act) {
    extern __shared__ char smem[];
    uint32_t sbase = smem_u32(smem);

    int tid = threadIdx.x, lane = tid & 31, warp = tid >> 5;
    int wm = warp & 1, wn = warp >> 1;

    int bm = blockIdx.y * 128;
    int bn = blockIdx.x * 256;
    int mRem = M - bm; if (mRem > 128) mRem = 128;
    int nRem = N - bn; if (nRem > 256) nRem = 256;

    int nch = K >> 6;

    int row0 = tid >> 3, ch0 = tid & 7;
    uint32_t so0 = saddr128(row0, ch0);
    long long gA0 = (long long)(bm + row0) * lda + ch0 * 8;
    long long gB0 = (long long)(bn + row0) * ldb + ch0 * 8;
    uint32_t szA[4], szB[8];
    #pragma unroll
    for (int i = 0; i < 4; i++) szA[i] = (row0 + 32 * i < mRem) ? 16u : 0u;
    #pragma unroll
    for (int i = 0; i < 8; i++) szB[i] = (row0 + 32 * i < nRem) ? 16u : 0u;
    long long ldax = (long long)lda * 32, ldbx = (long long)ldb * 32;

    auto loadStage = [&](int c) {
        uint32_t sb = sbase + (uint32_t)((c & 3) * W_STG);
        long long k0 = (long long)(c << 6);
        #pragma unroll
        for (int i = 0; i < 4; i++)
            cpa16(sb + W_SA + so0 + i * 4096u, Ah + gA0 + i * ldax + k0, szA[i]);
        #pragma unroll
        for (int i = 0; i < 8; i++)
            cpa16(sb + W_SB + so0 + i * 4096u, Bh + gB0 + i * ldbx + k0, szB[i]);
    };

    int frow = lane & 15, fhalf = lane >> 4;
    uint32_t a_rb[4]; int a_x[4];
    #pragma unroll
    for (int mi = 0; mi < 4; mi++) {
        int row = wm * 64 + mi * 16 + frow;
        a_rb[mi] = (uint32_t)(row * 128);
        a_x[mi]  = row & 7;
    }
    uint32_t b_rb[4]; int b_x[4];
    #pragma unroll
    for (int nj = 0; nj < 4; nj++) {
        int row = wn * 64 + nj * 16 + frow;
        b_rb[nj] = (uint32_t)(row * 128);
        b_x[nj]  = row & 7;
    }

    float acc[4][8][4];
    #pragma unroll
    for (int mi = 0; mi < 4; mi++)
        #pragma unroll
        for (int ni = 0; ni < 8; ni++)
            #pragma unroll
            for (int q = 0; q < 4; q++) acc[mi][ni][q] = 0.f;

    #pragma unroll
    for (int p = 0; p < 3; p++) {
        if (p < nch) loadStage(p);
        cpa_commit();
    }

    for (int c = 0; c < nch; c++) {
        cpa_wait2();
        __syncthreads();
        uint32_t sb = sbase + (uint32_t)((c & 3) * W_STG);

        #pragma unroll
        for (int k16 = 0; k16 < 4; k16++) {
            int chl = k16 * 2 + fhalf;
            uint32_t bH[4][4];
            #pragma unroll
            for (int nj = 0; nj < 4; nj++) {
                uint32_t off = b_rb[nj] + (uint32_t)(((chl ^ b_x[nj])) << 4);
                ldm_x4(bH[nj], sb + W_SB + off);
            }
            #pragma unroll
            for (int mi = 0; mi < 4; mi++) {
                uint32_t aH[4];
                uint32_t off = a_rb[mi] + (uint32_t)(((chl ^ a_x[mi])) << 4);
                ldm_x4(aH, sb + W_SA + off);
                #pragma unroll
                for (int nj = 0; nj < 4; nj++) {
                    mma16816(acc[mi][nj*2+0], aH, bH[nj][0], bH[nj][2]);
                    mma16816(acc[mi][nj*2+1], aH, bH[nj][1], bH[nj][3]);
                }
            }
        }
        if (c + 3 < nch) loadStage(c + 3);
        cpa_commit();
    }

    int erow = lane >> 2;
    int ecolL = (lane & 3) * 2;
    #pragma unroll
    for (int mi = 0; mi < 4; mi++) {
        #pragma unroll
        for (int ni = 0; ni < 8; ni++) {
            int gn = bn + wn * 64 + (ni >> 1) * 16 + (ni & 1) * 8 + ecolL;
            if (gn >= N) continue;
            float b0 = 0.f, b1 = 0.f;
            if (bias) { b0 = bias[gn]; b1 = bias[gn + 1]; }
            float e0 = 1.f, e1 = 1.f;
            if (ecol) { e0 = ecol[gn]; e1 = ecol[gn + 1]; }
            float* cc = acc[mi][ni];
            #pragma unroll
            for (int half = 0; half < 2; half++) {
                int gm = bm + wm * 64 + mi * 16 + erow + half * 8;
                if (gm >= M) continue;
                float v0 = cc[half * 2 + 0] * scale + b0;
                float v1 = cc[half * 2 + 1] * scale + b1;
                if (act == 1) { v0 = gelu_tanh(v0); v1 = gelu_tanh(v1); }
                epi_store(v0, v1, (long long)gm * ldc + gn, Cf, Ch, resid, e0, e1);
            }
        }
    }
}

// =====================================================================
// NARROW GEMM (1-product): 128x128x64, 3 stages x 32KB, 2 CTAs/SM.
// =====================================================================
#define N_STG 32768
#define N_SA 0
#define N_SB 16384
#define HG_SMEM (3 * N_STG)

__global__ void __launch_bounds__(256, 2)
hgemmn_kernel(const unsigned short* __restrict__ Ah, int lda,
              const unsigned short* __restrict__ Bh, int ldb,
              float* __restrict__ Cf, unsigned short* __restrict__ Ch, int ldc,
              const float* __restrict__ resid, const float* __restrict__ ecol,
              int M, int N, int K,
              const float* __restrict__ bias, float scale, int act) {
    extern __shared__ char smem[];
    uint32_t sbase = smem_u32(smem);

    int tid = threadIdx.x, lane = tid & 31, warp = tid >> 5;
    int wm = warp & 1, wn = warp >> 1;   // warp tile 64x32

    int bm = blockIdx.y * 128;
    int bn = blockIdx.x * 128;
    int mRem = M - bm; if (mRem > 128) mRem = 128;
    int nRem = N - bn; if (nRem > 128) nRem = 128;

    int nch = K >> 6;

    int row0 = tid >> 3, ch0 = tid & 7;
    uint32_t so0 = saddr128(row0, ch0);
    long long gA0 = (long long)(bm + row0) * lda + ch0 * 8;
    long long gB0 = (long long)(bn + row0) * ldb + ch0 * 8;
    uint32_t szA[4], szB[4];
    #pragma unroll
    for (int i = 0; i < 4; i++) {
        szA[i] = (row0 + 32 * i < mRem) ? 16u : 0u;
        szB[i] = (row0 + 32 * i < nRem) ? 16u : 0u;
    }
    long long ldax = (long long)lda * 32, ldbx = (long long)ldb * 32;

    auto loadStage = [&](int c) {
        uint32_t sb = sbase + (uint32_t)((c % 3) * N_STG);
        long long k0 = (long long)(c << 6);
        #pragma unroll
        for (int i = 0; i < 4; i++) {
            cpa16(sb + N_SA + so0 + i * 4096u, Ah + gA0 + i * ldax + k0, szA[i]);
            cpa16(sb + N_SB + so0 + i * 4096u, Bh + gB0 + i * ldbx + k0, szB[i]);
        }
    };

    int frow = lane & 15, fhalf = lane >> 4;
    uint32_t a_rb[4]; int a_x[4];
    #pragma unroll
    for (int mi = 0; mi < 4; mi++) {
        int row = wm * 64 + mi * 16 + frow;
        a_rb[mi] = (uint32_t)(row * 128);
        a_x[mi]  = row & 7;
    }
    uint32_t b_rb[2]; int b_x[2];
    #pragma unroll
    for (int nj = 0; nj < 2; nj++) {
        int row = wn * 32 + nj * 16 + frow;
        b_rb[nj] = (uint32_t)(row * 128);
        b_x[nj]  = row & 7;
    }

    float acc[4][4][4];
    #pragma unroll
    for (int mi = 0; mi < 4; mi++)
        #pragma unroll
        for (int ni = 0; ni < 4; ni++)
            #pragma unroll
            for (int q = 0; q < 4; q++) acc[mi][ni][q] = 0.f;

    loadStage(0); cpa_commit();
    if (nch > 1) loadStage(1);
    cpa_commit();

    for (int c = 0; c < nch; c++) {
        cpa_wait1();
        __syncthreads();
        uint32_t sb = sbase + (uint32_t)((c % 3) * N_STG);

        #pragma unroll
        for (int k16 = 0; k16 < 4; k16++) {
            int chl = k16 * 2 + fhalf;
            uint32_t bH[2][4];
            #pragma unroll
            for (int nj = 0; nj < 2; nj++) {
                uint32_t off = b_rb[nj] + (uint32_t)(((chl ^ b_x[nj])) << 4);
                ldm_x4(bH[nj], sb + N_SB + off);
            }
            #pragma unroll
            for (int mi = 0; mi < 4; mi++) {
                uint32_t aH[4];
                uint32_t off = a_rb[mi] + (uint32_t)(((chl ^ a_x[mi])) << 4);
                ldm_x4(aH, sb + N_SA + off);
                #pragma unroll
                for (int nj = 0; nj < 2; nj++) {
                    mma16816(acc[mi][nj*2+0], aH, bH[nj][0], bH[nj][2]);
                    mma16816(acc[mi][nj*2+1], aH, bH[nj][1], bH[nj][3]);
                }
            }
        }
        if (c + 2 < nch) loadStage(c + 2);
        cpa_commit();
    }

    int erow = lane >> 2;
    int ecolL = (lane & 3) * 2;
    #pragma unroll
    for (int mi = 0; mi < 4; mi++) {
        #pragma unroll
        for (int ni = 0; ni < 4; ni++) {
            int gn = bn + wn * 32 + ni * 8 + ecolL;
            if (gn >= N) continue;
            float b0 = 0.f, b1 = 0.f;
            if (bias) { b0 = bias[gn]; b1 = bias[gn + 1]; }
            float e0 = 1.f, e1 = 1.f;
            if (ecol) { e0 = ecol[gn]; e1 = ecol[gn + 1]; }
            float* cc = acc[mi][ni];
            #pragma unroll
            for (int half = 0; half < 2; half++) {
                int gm = bm + wm * 64 + mi * 16 + erow + half * 8;
                if (gm >= M) continue;
                float v0 = cc[half * 2 + 0] * scale + b0;
                float v1 = cc[half * 2 + 1] * scale + b1;
                if (act == 1) { v0 = gelu_tanh(v0); v1 = gelu_tanh(v1); }
                epi_store(v0, v1, (long long)gm * ldc + gn, Cf, Ch, resid, e0, e1);
            }
        }
    }
}

// =====================================================================
// FUSED ATTENTION (flash-style), q hi-only. Grid (NH, ceil(L_Q/128)).
// =====================================================================
#define FL_QH 0
#define FL_KP0 32768
#define FL_KP1 65536
#define FL_V0 98304
#define FL_V1 131072
#define FL_SMEM 163840

__global__ void __launch_bounds__(256, 1)
flash_kernel(const unsigned short* __restrict__ qh,
             const unsigned short* __restrict__ kh, const unsigned short* __restrict__ vt,
             unsigned short* __restrict__ yh,
             float ascale, int lkv, int ldv) {
    extern __shared__ char smem[];
    uint32_t sb = smem_u32(smem);
    int tid = threadIdx.x, lane = tid & 31, warp = tid >> 5;
    int head = blockIdx.x;
    int q0 = blockIdx.y * 128;

    const unsigned short* kbase = kh + head * HD;
    const unsigned short* vbase = vt + (long long)(head * HD) * ldv;

    auto loadQ = [&]() {
        #pragma unroll
        for (int i = 0; i < 8; i++) {
            int idx = tid + i * 256;
            int row = idx >> 4, ch = idx & 15;
            uint32_t sz = (q0 + row < L_Q) ? 16u : 0u;
            long long g = (long long)(q0 + row) * C_DIM + head * HD + ch * 8;
            cpa16(sb + FL_QH + saddr256(row, ch), qh + g, sz);
        }
    };
    auto loadKV = [&](int c) {
        uint32_t kb = sb + ((c & 1) ? FL_KP1 : FL_KP0);
        uint32_t vb = sb + ((c & 1) ? FL_V1 : FL_V0);
        int kv0 = c * 128;
        #pragma unroll
        for (int i = 0; i < 8; i++) {
            int idx = tid + i * 256;
            int row = idx >> 4, ch = idx & 15;
            uint32_t so = saddr256(row, ch);
            uint32_t sz = (kv0 + row < lkv) ? 16u : 0u;
            cpa16(kb + so, kbase + (long long)(kv0 + row) * C_DIM + ch * 8, sz);
            cpa16(vb + so, vbase + (long long)row * ldv + kv0 + ch * 8, 16u);
        }
    };

    int frow = lane & 15, fhalf = lane >> 4;
    int fx = frow & 7;
    uint32_t a_rb = (uint32_t)((warp * 16 + frow) * 256);
    uint32_t b_rb[8];
    #pragma unroll
    for (int nj = 0; nj < 8; nj++) b_rb[nj] = (uint32_t)((nj * 16 + frow) * 256);

    float m[2] = {-INFINITY, -INFINITY};
    float l[2] = {0.f, 0.f};
    float o[8][2][4];
    #pragma unroll
    for (int dj = 0; dj < 8; dj++)
        #pragma unroll
        for (int t = 0; t < 2; t++)
            #pragma unroll
            for (int q = 0; q < 4; q++) o[dj][t][q] = 0.f;

    loadQ(); loadKV(0); cpa_commit();
    const int nch = (lkv + 127) / 128;
    if (nch > 1) loadKV(1);
    cpa_commit();

    for (int c = 0; c < nch; c++) {
        cpa_wait1();
        __syncthreads();
        uint32_t kb = sb + ((c & 1) ? FL_KP1 : FL_KP0);
        uint32_t vb = sb + ((c & 1) ? FL_V1 : FL_V0);
        int kvRem = lkv - c * 128; if (kvRem > 128) kvRem = 128;

        float sacc[8][2][4];
        #pragma unroll
        for (int nj = 0; nj < 8; nj++)
            #pragma unroll
            for (int t = 0; t < 2; t++)
                #pragma unroll
                for (int q = 0; q < 4; q++) sacc[nj][t][q] = 0.f;

        #pragma unroll
        for (int kk = 0; kk < 8; kk++) {
            int chl = kk * 2 + fhalf;
            uint32_t aH[4];
            ldm_x4(aH, sb + FL_QH + a_rb + (uint32_t)((chl ^ fx) << 4));
            #pragma unroll
            for (int nj = 0; nj < 8; nj++) {
                uint32_t bH[4];
                ldm_x4(bH, kb + b_rb[nj] + (uint32_t)((chl ^ fx) << 4));
                mma16816(sacc[nj][0], aH, bH[0], bH[2]);
                mma16816(sacc[nj][1], aH, bH[1], bH[3]);
            }
        }
        __syncthreads();

        int ec = (lane & 3) * 2;
        #pragma unroll
        for (int half = 0; half < 2; half++) {
            float mc = -INFINITY;
            #pragma unroll
            for (int nj = 0; nj < 8; nj++)
                #pragma unroll
                for (int t = 0; t < 2; t++)
                    #pragma unroll
                    for (int j = 0; j < 2; j++) {
                        int col = nj * 16 + t * 8 + ec + j;
                        float v = sacc[nj][t][half * 2 + j] * ascale;
                        sacc[nj][t][half * 2 + j] = v;
                        if (col < kvRem) mc = fmaxf(mc, v);
                    }
            mc = fmaxf(mc, __shfl_xor_sync(0xffffffffu, mc, 1));
            mc = fmaxf(mc, __shfl_xor_sync(0xffffffffu, mc, 2));
            float mn = fmaxf(m[half], mc);
            float corr = __expf(m[half] - mn);
            m[half] = mn;
            float ls = 0.f;
            #pragma unroll
            for (int nj = 0; nj < 8; nj++)
                #pragma unroll
                for (int t = 0; t < 2; t++)
                    #pragma unroll
                    for (int j = 0; j < 2; j++) {
                        int col = nj * 16 + t * 8 + ec + j;
                        float p = (col < kvRem)
                                ? __expf(sacc[nj][t][half * 2 + j] - mn) : 0.f;
                        sacc[nj][t][half * 2 + j] = p;
                        ls += p;
                    }
            l[half] = l[half] * corr + ls;
            #pragma unroll
            for (int dj = 0; dj < 8; dj++)
                #pragma unroll
                for (int t = 0; t < 2; t++)
                    #pragma unroll
                    for (int j = 0; j < 2; j++)
                        o[dj][t][half * 2 + j] *= corr;
        }

        #pragma unroll
        for (int half = 0; half < 2; half++) {
            int row = warp * 16 + (lane >> 2) + half * 8;
            #pragma unroll
            for (int nj = 0; nj < 8; nj++)
                #pragma unroll
                for (int t = 0; t < 2; t++) {
                    int col = nj * 16 + t * 8 + ec;
                    __half p0 = __float2half_rn(sacc[nj][t][half * 2 + 0]);
                    __half p1 = __float2half_rn(sacc[nj][t][half * 2 + 1]);
                    uint32_t addr = kb + (uint32_t)(row * 256 +
                                    (((col >> 3) ^ (row & 7)) << 4) + (col & 7) * 2);
                    uint32_t pk = (uint32_t)*reinterpret_cast<unsigned short*>(&p0)
                                | ((uint32_t)*reinterpret_cast<unsigned short*>(&p1) << 16);
                    asm volatile("st.shared.u32 [%0], %1;" :: "r"(addr), "r"(pk));
                }
        }
        __syncwarp();

        #pragma unroll
        for (int kk = 0; kk < 8; kk++) {
            int chl = kk * 2 + fhalf;
            uint32_t aP[4];
            ldm_x4(aP, kb + a_rb + (uint32_t)((chl ^ fx) << 4));
            #pragma unroll
            for (int dj = 0; dj < 8; dj++) {
                uint32_t bV[4];
                ldm_x4(bV, vb + b_rb[dj] + (uint32_t)((chl ^ fx) << 4));
                mma16816(o[dj][0], aP, bV[0], bV[2]);
                mma16816(o[dj][1], aP, bV[1], bV[3]);
            }
        }
        __syncthreads();
        if (c + 2 < nch) loadKV(c + 2);
        cpa_commit();
    }

    int ec = (lane & 3) * 2;
    #pragma unroll
    for (int half = 0; half < 2; half++) {
        float ls = l[half];
        ls += __shfl_xor_sync(0xffffffffu, ls, 1);
        ls += __shfl_xor_sync(0xffffffffu, ls, 2);
        float inv = 1.f / ls;
        int gm = q0 + warp * 16 + (lane >> 2) + half * 8;
        if (gm >= L_Q) continue;
        #pragma unroll
        for (int dj = 0; dj < 8; dj++)
            #pragma unroll
            for (int t = 0; t < 2; t++) {
                int gd = head * HD + dj * 16 + t * 8 + ec;
                float v0 = o[dj][t][half * 2 + 0] * inv;
                float v1 = o[dj][t][half * 2 + 1] * inv;
                __half h0 = __float2half_rn(v0);
                __half h1 = __float2half_rn(v1);
                long long off = (long long)gm * C_DIM + gd;
                *reinterpret_cast<ushort2*>(yh + off) = make_ushort2(
                    *reinterpret_cast<unsigned short*>(&h0),
                    *reinterpret_cast<unsigned short*>(&h1));
            }
    }
}

// ---------------- host ----------------
static void hgw(const unsigned short* Ah, int lda, const unsigned short* Bh, int ldb,
                float* Cf, unsigned short* Ch, int ldc,
                const float* resid, const float* ecol,
                int M, int N, int K, const float* bias, float scale, int act) {
    dim3 grid((N + 255) / 256, (M + 127) / 128);
    hgemmw_kernel<<<grid, 256, W_SMEM>>>(Ah, lda, Bh, ldb, Cf, Ch, ldc,
                                         resid, ecol, M, N, K, bias, scale, act);
}

static void hgn(const unsigned short* Ah, int lda, const unsigned short* Bh, int ldb,
                float* Cf, unsigned short* Ch, int ldc,
                const float* resid, const float* ecol,
                int M, int N, int K, const float* bias, float scale, int act) {
    dim3 grid((N + 127) / 128, (M + 127) / 128);
    hgemmn_kernel<<<grid, 256, HG_SMEM>>>(Ah, lda, Bh, ldb, Cf, Ch, ldc,
                                          resid, ecol, M, N, K, bias, scale, act);
}

static void trh(const float* src, int R, int Ccol, int lds, unsigned short* dh, int ldout) {
    dim3 grid(Ccol / 32, R / 32);
    transpose_h_kernel<<<grid, dim3(32, 8)>>>(src, R, Ccol, lds, dh, ldout);
}

extern "C" void kernel_launch(void* const* d_in, const int* in_sizes, int n_in,
                              void* d_out, int out_size) {
    const float* x        = (const float*)d_in[0];
    const float* e        = (const float*)d_in[1];
    const float* context  = (const float*)d_in[2];
    const float* freqs    = (const float*)d_in[3];
    const float* modulation = (const float*)d_in[7];
    const float* sa_q_w = (const float*)d_in[8];
    const float* sa_q_b = (const float*)d_in[9];
    const float* sa_k_w = (const float*)d_in[10];
    const float* sa_k_b = (const float*)d_in[11];
    const float* sa_v_w = (const float*)d_in[12];
    const float* sa_v_b = (const float*)d_in[13];
    const float* sa_o_w = (const float*)d_in[14];
    const float* sa_o_b = (const float*)d_in[15];
    const float* sa_nq_w = (const float*)d_in[16];
    const float* sa_nk_w = (const float*)d_in[17];
    const float* ca_q_w = (const float*)d_in[18];
    const float* ca_q_b = (const float*)d_in[19];
    const float* ca_k_w = (const float*)d_in[20];
    const float* ca_k_b = (const float*)d_in[21];
    const float* ca_v_w = (const float*)d_in[22];
    const float* ca_v_b = (const float*)d_in[23];
    const float* ca_o_w = (const float*)d_in[24];
    const float* ca_o_b = (const float*)d_in[25];
    const float* ca_nq_w = (const float*)d_in[26];
    const float* ca_nk_w = (const float*)d_in[27];
    const float* ffn_w1 = (const float*)d_in[28];
    const float* ffn_b1 = (const float*)d_in[29];
    const float* ffn_w2 = (const float*)d_in[30];
    const float* ffn_b2 = (const float*)d_in[31];
    float* out = (float*)d_out;

    cudaFuncSetAttribute(hgemmw_kernel,
                         cudaFuncAttributeMaxDynamicSharedMemorySize, W_SMEM);
    cudaFuncSetAttribute(hgemmn_kernel,
                         cudaFuncAttributeMaxDynamicSharedMemorySize, HG_SMEM);
    cudaFuncSetAttribute(flash_kernel,
                         cudaFuncAttributeMaxDynamicSharedMemorySize, FL_SMEM);

    float *em, *q, *s, *b3;
    unsigned short *hh, *qh, *kh, *vth, *yh, *oh, *cxh, *ffh, *wA, *wF;
    cudaGetSymbolAddress((void**)&em, g_em);
    cudaGetSymbolAddress((void**)&q,  g_q);
    cudaGetSymbolAddress((void**)&s,  g_s);
    cudaGetSymbolAddress((void**)&b3, g_b3);
    cudaGetSymbolAddress((void**)&hh, g_hh);
    cudaGetSymbolAddress((void**)&qh, g_qh);
    cudaGetSymbolAddress((void**)&kh, g_kh);
    cudaGetSymbolAddress((void**)&vth, g_vth);
    cudaGetSymbolAddress((void**)&yh, g_yh);
    cudaGetSymbolAddress((void**)&oh, g_oh);
    cudaGetSymbolAddress((void**)&cxh, g_cxh);
    cudaGetSymbolAddress((void**)&ffh, g_ffh);
    cudaGetSymbolAddress((void**)&wA, g_wA);
    cudaGetSymbolAddress((void**)&wF, g_wF);

    const float ascale = 0.08838834764831845f;   // 1/sqrt(128)
    const long long CC = (long long)C_DIM * C_DIM;

    em_kernel<<<(6 * C_DIM + 255) / 256, 256>>>(e, modulation, em);
    // all 8 CxC weight transposes in one launch
    trh8_kernel<<<dim3(48, 48, 8), dim3(32, 8)>>>(
        sa_q_w, sa_k_w, sa_v_w, sa_o_w, ca_q_w, ca_k_w, ca_v_w, ca_o_w, wA);
    trh(ffn_w1, C_DIM, FF_DIM, FF_DIM, wF, C_DIM);               // [8960,1536]
    trh(ffn_w2, FF_DIM, C_DIM, C_DIM, wF + (long long)C_DIM * FF_DIM, FF_DIM);
    pack3_kernel<<<(3 * C_DIM + 255) / 256, 256>>>(sa_q_b, sa_k_b, sa_v_b, b3);

    // ================= self attention =================
    ln_mod_split_kernel<<<L_Q, 256>>>(x, em + 0 * C_DIM, em + 1 * C_DIM, hh);
    float* qkv = s;   // [2400, 4608] fp32
    hgw(hh, C_DIM, wA, C_DIM, qkv, nullptr, 3 * C_DIM,
        nullptr, nullptr, L_Q, 3 * C_DIM, C_DIM, b3, 1.f, 0);
    rms_rope_split_kernel<<<L_Q, 256>>>(qkv + 0 * C_DIM, 3 * C_DIM, sa_nq_w, freqs, qh);
    rms_rope_split_kernel<<<L_Q, 256>>>(qkv + 1 * C_DIM, 3 * C_DIM, sa_nk_w, freqs, kh);
    trh(qkv + 2 * C_DIM, L_Q, C_DIM, 3 * C_DIM, vth, L_PAD);     // V^T [1536, 2432]
    zero_pad_kernel<<<(C_DIM * 32 + 255) / 256, 256>>>(vth);
    flash_kernel<<<dim3(NH, (L_Q + 127) / 128), 256, FL_SMEM>>>(
        qh, kh, vth, yh, ascale, L_Q, L_PAD);
    // O-proj + residual fused (narrow)
    hgn(yh, C_DIM, wA + 3 * CC, C_DIM, out, oh, C_DIM,
        x, em + 2 * C_DIM, L_Q, C_DIM, C_DIM, sa_o_b, 1.f, 0);

    // ================= cross attention =================
    hgn(oh, C_DIM, wA + 4 * CC, C_DIM, q, nullptr, C_DIM,
        nullptr, nullptr, L_Q, C_DIM, C_DIM, ca_q_b, 1.f, 0);
    rms_split_kernel<<<L_Q, 256>>>(q, C_DIM, ca_nq_w, qh);
    conv_h_kernel<<<(int)(((long long)L_KV * C_DIM + 255) / 256), 256>>>(
        context, (long long)L_KV * C_DIM, cxh);
    pack2_kernel<<<(2 * C_DIM + 255) / 256, 256>>>(ca_k_b, ca_v_b, b3);
    float* kvbuf = s;   // [512, 3072] fp32
    hgn(cxh, C_DIM, wA + 5 * CC, C_DIM, kvbuf, nullptr, 2 * C_DIM,
        nullptr, nullptr, L_KV, 2 * C_DIM, C_DIM, b3, 1.f, 0);
    rms_split_kernel<<<L_KV, 256>>>(kvbuf + 0 * C_DIM, 2 * C_DIM, ca_nk_w, kh);
    trh(kvbuf + 1 * C_DIM, L_KV, C_DIM, 2 * C_DIM, vth, L_KV);   // V^T [1536, 512]
    flash_kernel<<<dim3(NH, (L_Q + 127) / 128), 256, FL_SMEM>>>(
        qh, kh, vth, yh, ascale, L_KV, L_KV);
    // cross o-proj + add fused (narrow)
    hgn(yh, C_DIM, wA + 7 * CC, C_DIM, out, nullptr, C_DIM,
        out, nullptr, L_Q, C_DIM, C_DIM, ca_o_b, 1.f, 0);

    // ================= FFN =================
    ln_mod_split_kernel<<<L_Q, 256>>>(out, em + 3 * C_DIM, em + 4 * C_DIM, hh);
    hgw(hh, C_DIM, wF, C_DIM, nullptr, ffh, FF_DIM,
        nullptr, nullptr, L_Q, FF_DIM, C_DIM, ffn_b1, 1.f, 1);   // + GELU
    // FFN2 + residual fused (narrow)
    hgn(ffh, FF_DIM, wF + (long long)C_DIM * FF_DIM, FF_DIM, out, nullptr, C_DIM,
        out, em + 5 * C_DIM, L_Q, C_DIM, FF_DIM, ffn_b2, 1.f, 0);
}